// round 1
// baseline (speedup 1.0000x reference)
#include <cuda_runtime.h>

// ---------------------------------------------------------------------------
// BertAttention (DeBERTa disentangled attention) — round 1: fp32 tiled SGEMMs
// B=1, S=2048, H=768, NH=12, D=64, SPAN=512
// ---------------------------------------------------------------------------

constexpr int S    = 2048;
constexpr int H    = 768;
constexpr int NH   = 12;
constexpr int D    = 64;
constexpr int LPOS = 1024;  // 2*SPAN
constexpr float SCALE  = 0.07216878364870322f;  // 1/sqrt(64*3)
constexpr float NEGMAX = -3.402823466e38f;

// ---------------------------- scratch (device globals) ---------------------
__device__ float g_Q  [S * H];
__device__ float g_K  [S * H];
__device__ float g_V  [S * H];
__device__ float g_PK [LPOS * H];
__device__ float g_PQ [LPOS * H];
__device__ float g_CK [(size_t)NH * S * LPOS];   // q . posK   (unscaled)
__device__ float g_CQ [(size_t)NH * S * LPOS];   // k . posQ   (unscaled)
__device__ float g_SC [(size_t)NH * S * S];      // scores / probs
__device__ float g_CTX[S * H];
__device__ float g_TMP[S * H];

// ---------------------------------------------------------------------------
// Generic tiled GEMM, C = A[M,K] @ B[K,N] (+bias[N]) (+res[M,N]),
// batched via blockIdx.z element strides. M,N,K assumed tile-divisible.
// ---------------------------------------------------------------------------
template<int BM, int BN, int BK, int TM, int TN>
__global__ void gemm_nn(int K,
                        const float* __restrict__ A, int lda, long sA,
                        const float* __restrict__ B, int ldb, long sB,
                        float* __restrict__ C, int ldc, long sC,
                        const float* __restrict__ bias,
                        const float* __restrict__ res, int ldres)
{
    constexpr int THREADS = (BM / TM) * (BN / TN);
    __shared__ float As[BK][BM + 4];
    __shared__ float Bs[BK][BN + 4];

    A += (long)blockIdx.z * sA;
    B += (long)blockIdx.z * sB;
    C += (long)blockIdx.z * sC;

    const int bm  = blockIdx.y * BM;
    const int bn  = blockIdx.x * BN;
    const int tid = threadIdx.x;
    const int tc  = tid % (BN / TN);
    const int tr  = tid / (BN / TN);

    float acc[TM][TN] = {};

    for (int k0 = 0; k0 < K; k0 += BK) {
        #pragma unroll
        for (int i = tid; i < BM * BK; i += THREADS) {
            int r = i / BK, c = i % BK;
            As[c][r] = A[(long)(bm + r) * lda + (k0 + c)];
        }
        #pragma unroll
        for (int i = tid; i < BK * BN; i += THREADS) {
            int r = i / BN, c = i % BN;
            Bs[r][c] = B[(long)(k0 + r) * ldb + (bn + c)];
        }
        __syncthreads();
        #pragma unroll
        for (int kk = 0; kk < BK; kk++) {
            float ra[TM], rb[TN];
            #pragma unroll
            for (int i = 0; i < TM; i++) ra[i] = As[kk][tr * TM + i];
            #pragma unroll
            for (int j = 0; j < TN; j++) rb[j] = Bs[kk][tc * TN + j];
            #pragma unroll
            for (int i = 0; i < TM; i++)
                #pragma unroll
                for (int j = 0; j < TN; j++)
                    acc[i][j] = fmaf(ra[i], rb[j], acc[i][j]);
        }
        __syncthreads();
    }

    #pragma unroll
    for (int i = 0; i < TM; i++) {
        int r = bm + tr * TM + i;
        #pragma unroll
        for (int j = 0; j < TN; j++) {
            int c = bn + tc * TN + j;
            float v = acc[i][j];
            if (bias) v += bias[c];
            if (res)  v += res[(long)r * ldres + c];
            C[(long)r * ldc + c] = v;
        }
    }
}

// ---------------------------------------------------------------------------
// Tiled GEMM, C = A[M,K] @ B[N,K]^T, batched via blockIdx.z strides.
// ---------------------------------------------------------------------------
template<int BM, int BN, int BK, int TM, int TN>
__global__ void gemm_nt(int K,
                        const float* __restrict__ A, int lda, long sA,
                        const float* __restrict__ B, int ldb, long sB,
                        float* __restrict__ C, int ldc, long sC)
{
    constexpr int THREADS = (BM / TM) * (BN / TN);
    __shared__ float As[BK][BM + 4];
    __shared__ float Bs[BK][BN + 4];

    A += (long)blockIdx.z * sA;
    B += (long)blockIdx.z * sB;
    C += (long)blockIdx.z * sC;

    const int bm  = blockIdx.y * BM;
    const int bn  = blockIdx.x * BN;
    const int tid = threadIdx.x;
    const int tc  = tid % (BN / TN);
    const int tr  = tid / (BN / TN);

    float acc[TM][TN] = {};

    for (int k0 = 0; k0 < K; k0 += BK) {
        #pragma unroll
        for (int i = tid; i < BM * BK; i += THREADS) {
            int r = i / BK, c = i % BK;
            As[c][r] = A[(long)(bm + r) * lda + (k0 + c)];
        }
        #pragma unroll
        for (int i = tid; i < BK * BN; i += THREADS) {
            int c = i / BK, r = i % BK;   // contiguous along K
            Bs[r][c] = B[(long)(bn + c) * ldb + (k0 + r)];
        }
        __syncthreads();
        #pragma unroll
        for (int kk = 0; kk < BK; kk++) {
            float ra[TM], rb[TN];
            #pragma unroll
            for (int i = 0; i < TM; i++) ra[i] = As[kk][tr * TM + i];
            #pragma unroll
            for (int j = 0; j < TN; j++) rb[j] = Bs[kk][tc * TN + j];
            #pragma unroll
            for (int i = 0; i < TM; i++)
                #pragma unroll
                for (int j = 0; j < TN; j++)
                    acc[i][j] = fmaf(ra[i], rb[j], acc[i][j]);
        }
        __syncthreads();
    }

    #pragma unroll
    for (int i = 0; i < TM; i++) {
        int r = bm + tr * TM + i;
        #pragma unroll
        for (int j = 0; j < TN; j++) {
            int c = bn + tc * TN + j;
            C[(long)r * ldc + c] = acc[i][j];
        }
    }
}

// ---------------------------------------------------------------------------
// Scores: S[h,i,j] = scale*(q_i.k_j + ck[h,i,l] + cq[h,j,l]), l=clip(i-j+512),
// masked to -FLT_MAX where attention mask is 0.
// ---------------------------------------------------------------------------
__global__ void scores_kernel(const float* __restrict__ Qm,
                              const float* __restrict__ Km,
                              const int*   __restrict__ mask,
                              float* __restrict__ out)
{
    constexpr int BM = 128, BN = 128, BK = 16, TM = 8, TN = 8, THREADS = 256;
    __shared__ float As[BK][BM + 4];
    __shared__ float Bs[BK][BN + 4];

    const int h = blockIdx.z;
    const float* A   = Qm + h * D;
    const float* B   = Km + h * D;
    const float* ckh = g_CK + (size_t)h * S * LPOS;
    const float* cqh = g_CQ + (size_t)h * S * LPOS;
    float* C = out + (size_t)h * S * S;

    const int bm  = blockIdx.y * BM;
    const int bn  = blockIdx.x * BN;
    const int tid = threadIdx.x;
    const int tc  = tid % (BN / TN);
    const int tr  = tid / (BN / TN);

    float acc[TM][TN] = {};

    for (int k0 = 0; k0 < D; k0 += BK) {
        #pragma unroll
        for (int i = tid; i < BM * BK; i += THREADS) {
            int r = i / BK, c = i % BK;
            As[c][r] = A[(long)(bm + r) * H + (k0 + c)];
        }
        #pragma unroll
        for (int i = tid; i < BK * BN; i += THREADS) {
            int c = i / BK, r = i % BK;
            Bs[r][c] = B[(long)(bn + c) * H + (k0 + r)];
        }
        __syncthreads();
        #pragma unroll
        for (int kk = 0; kk < BK; kk++) {
            float ra[TM], rb[TN];
            #pragma unroll
            for (int i = 0; i < TM; i++) ra[i] = As[kk][tr * TM + i];
            #pragma unroll
            for (int j = 0; j < TN; j++) rb[j] = Bs[kk][tc * TN + j];
            #pragma unroll
            for (int i = 0; i < TM; i++)
                #pragma unroll
                for (int j = 0; j < TN; j++)
                    acc[i][j] = fmaf(ra[i], rb[j], acc[i][j]);
        }
        __syncthreads();
    }

    #pragma unroll
    for (int i = 0; i < TM; i++) {
        int r = bm + tr * TM + i;
        int mi = mask[r];
        #pragma unroll
        for (int j = 0; j < TN; j++) {
            int c = bn + tc * TN + j;
            int l = r - c + 512;
            l = min(max(l, 0), LPOS - 1);
            float v = (acc[i][j] + ckh[(long)r * LPOS + l]
                                 + cqh[(long)c * LPOS + l]) * SCALE;
            if (!(mi && mask[c])) v = NEGMAX;
            C[(long)r * S + c] = v;
        }
    }
}

// ---------------------------------------------------------------------------
// Row softmax over 2048 elements, one block (256 threads) per row.
// ---------------------------------------------------------------------------
__global__ void softmax_kernel(float* __restrict__ p)
{
    __shared__ float red[8];
    float* x = p + (size_t)blockIdx.x * S;
    const int tid = threadIdx.x;

    float v[8];
    float mx = NEGMAX;
    #pragma unroll
    for (int j = 0; j < 8; j++) { v[j] = x[tid + 256 * j]; mx = fmaxf(mx, v[j]); }
    #pragma unroll
    for (int o = 16; o > 0; o >>= 1) mx = fmaxf(mx, __shfl_xor_sync(0xffffffffu, mx, o));
    if ((tid & 31) == 0) red[tid >> 5] = mx;
    __syncthreads();
    #pragma unroll
    for (int w = 0; w < 8; w++) mx = fmaxf(mx, red[w]);

    float sum = 0.f;
    #pragma unroll
    for (int j = 0; j < 8; j++) { v[j] = __expf(v[j] - mx); sum += v[j]; }
    #pragma unroll
    for (int o = 16; o > 0; o >>= 1) sum += __shfl_xor_sync(0xffffffffu, sum, o);
    __syncthreads();
    if ((tid & 31) == 0) red[tid >> 5] = sum;
    __syncthreads();
    float ts = 0.f;
    #pragma unroll
    for (int w = 0; w < 8; w++) ts += red[w];

    float inv = 1.0f / ts;
    #pragma unroll
    for (int j = 0; j < 8; j++) x[tid + 256 * j] = v[j] * inv;
}

// ---------------------------------------------------------------------------
// LayerNorm over H=768, one block (256 threads) per row.
// ---------------------------------------------------------------------------
__global__ void ln_kernel(const float* __restrict__ x,
                          const float* __restrict__ gamma,
                          const float* __restrict__ beta,
                          float* __restrict__ out)
{
    __shared__ float rs[8], rq[8];
    const int s = blockIdx.x, tid = threadIdx.x;
    const float* row = x + (long)s * H;
    float a0 = row[tid], a1 = row[tid + 256], a2 = row[tid + 512];
    float sum = a0 + a1 + a2;
    float sq  = a0 * a0 + a1 * a1 + a2 * a2;
    #pragma unroll
    for (int o = 16; o > 0; o >>= 1) {
        sum += __shfl_xor_sync(0xffffffffu, sum, o);
        sq  += __shfl_xor_sync(0xffffffffu, sq,  o);
    }
    if ((tid & 31) == 0) { rs[tid >> 5] = sum; rq[tid >> 5] = sq; }
    __syncthreads();
    float ts = 0.f, tq = 0.f;
    #pragma unroll
    for (int w = 0; w < 8; w++) { ts += rs[w]; tq += rq[w]; }
    float mean = ts * (1.0f / H);
    float var  = tq * (1.0f / H) - mean * mean;
    float inv  = rsqrtf(var + 1e-7f);
    float* o = out + (long)s * H;
    o[tid]       = (a0 - mean) * inv * gamma[tid]       + beta[tid];
    o[tid + 256] = (a1 - mean) * inv * gamma[tid + 256] + beta[tid + 256];
    o[tid + 512] = (a2 - mean) * inv * gamma[tid + 512] + beta[tid + 512];
}

// ---------------------------------------------------------------------------
extern "C" void kernel_launch(void* const* d_in, const int* in_sizes, int n_in,
                              void* d_out, int out_size)
{
    const float* hidden = (const float*)d_in[0];
    const int*   mask   = (const int*)  d_in[1];
    const float* Wq     = (const float*)d_in[2];
    const float* bq     = (const float*)d_in[3];
    const float* Wk     = (const float*)d_in[4];
    const float* bk     = (const float*)d_in[5];
    const float* Wv     = (const float*)d_in[6];
    const float* bv     = (const float*)d_in[7];
    const float* rel    = (const float*)d_in[8];
    const float* Wpk    = (const float*)d_in[9];
    const float* Wpq    = (const float*)d_in[10];
    const float* bpq    = (const float*)d_in[11];
    const float* Wo     = (const float*)d_in[12];
    const float* bo     = (const float*)d_in[13];
    const float* gamma  = (const float*)d_in[14];
    const float* beta   = (const float*)d_in[15];
    float* out = (float*)d_out;

    float *Q, *Kb, *V, *PK, *PQ, *CK, *CQ, *SC, *CTX, *TMP;
    cudaGetSymbolAddress((void**)&Q,   g_Q);
    cudaGetSymbolAddress((void**)&Kb,  g_K);
    cudaGetSymbolAddress((void**)&V,   g_V);
    cudaGetSymbolAddress((void**)&PK,  g_PK);
    cudaGetSymbolAddress((void**)&PQ,  g_PQ);
    cudaGetSymbolAddress((void**)&CK,  g_CK);
    cudaGetSymbolAddress((void**)&CQ,  g_CQ);
    cudaGetSymbolAddress((void**)&SC,  g_SC);
    cudaGetSymbolAddress((void**)&CTX, g_CTX);
    cudaGetSymbolAddress((void**)&TMP, g_TMP);

    // --- projections ---
    gemm_nn<128,128,16,8,8><<<dim3(H/128, S/128, 1), 256>>>(
        H, hidden, H, 0, Wq, H, 0, Q,  H, 0, bq, nullptr, 0);
    gemm_nn<128,128,16,8,8><<<dim3(H/128, S/128, 1), 256>>>(
        H, hidden, H, 0, Wk, H, 0, Kb, H, 0, bk, nullptr, 0);
    gemm_nn<128,128,16,8,8><<<dim3(H/128, S/128, 1), 256>>>(
        H, hidden, H, 0, Wv, H, 0, V,  H, 0, bv, nullptr, 0);
    gemm_nn<128,128,16,8,8><<<dim3(H/128, LPOS/128, 1), 256>>>(
        H, rel, H, 0, Wpk, H, 0, PK, H, 0, nullptr, nullptr, 0);
    gemm_nn<128,128,16,8,8><<<dim3(H/128, LPOS/128, 1), 256>>>(
        H, rel, H, 0, Wpq, H, 0, PQ, H, 0, bpq, nullptr, 0);

    // --- relative-position dot tables (batched over heads) ---
    gemm_nt<128,128,16,8,8><<<dim3(LPOS/128, S/128, NH), 256>>>(
        D, Q,  H, D, PK, H, D, CK, LPOS, (long)S * LPOS);
    gemm_nt<128,128,16,8,8><<<dim3(LPOS/128, S/128, NH), 256>>>(
        D, Kb, H, D, PQ, H, D, CQ, LPOS, (long)S * LPOS);

    // --- scores (QK^T + gathered rel-pos bias + mask) ---
    scores_kernel<<<dim3(S/128, S/128, NH), 256>>>(Q, Kb, mask, SC);

    // --- softmax ---
    softmax_kernel<<<NH * S, 256>>>(SC);

    // --- probs @ V (batched over heads) ---
    gemm_nn<128,64,16,8,8><<<dim3(1, S/128, NH), 128>>>(
        S, SC, S, (long)S * S, V, H, D, CTX, H, D, nullptr, nullptr, 0);

    // --- output projection + bias + residual ---
    gemm_nn<128,128,16,8,8><<<dim3(H/128, S/128, 1), 256>>>(
        H, CTX, H, 0, Wo, H, 0, TMP, H, 0, bo, hidden, H);

    // --- layernorm ---
    ln_kernel<<<S, 256>>>(TMP, gamma, beta, out);
}

// round 3
// speedup vs baseline: 6.6299x; 6.6299x over previous
#include <cuda_runtime.h>
#include <cuda_bf16.h>
#include <cstdint>

// ---------------------------------------------------------------------------
// BertAttention (DeBERTa) — round 3: mma.sync bf16 tensor-core GEMMs
// (tcgen05 PTX rejected: harness ptxas targets bare sm_103).
// B=1, S=2048, H=768, NH=12, D=64, SPAN=512
// ---------------------------------------------------------------------------

constexpr int S    = 2048;
constexpr int H    = 768;
constexpr int NH   = 12;
constexpr int D    = 64;
constexpr int LPOS = 1024;  // 2*SPAN
constexpr float SCALE  = 0.07216878364870322f;  // 1/sqrt(64*3)
constexpr float NEGMAX = -3.402823466e38f;

using bf16 = __nv_bfloat16;

// ---------------------------- scratch (device globals) ---------------------
__device__ bf16  g_hbf  [S * H];
__device__ bf16  g_relbf[LPOS * H];
__device__ bf16  g_Wt   [6 * H * H];     // transposed bf16 weights [N,K]
__device__ bf16  g_Qbf  [S * H];
__device__ bf16  g_Kbf  [S * H];
__device__ bf16  g_Vt   [H * S];         // V transposed: [h*D+d][token]
__device__ bf16  g_PKbf [LPOS * H];
__device__ bf16  g_PQbf [LPOS * H];
__device__ float g_CK   [(size_t)NH * S * LPOS];
__device__ float g_CQ   [(size_t)NH * S * LPOS];
__device__ float g_SC   [(size_t)NH * S * S];
__device__ bf16  g_Pbf  [(size_t)NH * S * S];
__device__ bf16  g_CTXbf[S * H];
__device__ float g_TMP  [S * H];

// ---------------------------- PTX helpers ----------------------------------
__device__ __forceinline__ uint32_t smem_u32(const void* p) {
    uint32_t a;
    asm("{ .reg .u64 t; cvta.to.shared.u64 t, %1; cvt.u32.u64 %0, t; }"
        : "=r"(a) : "l"(p));
    return a;
}
__device__ __forceinline__ void cpasync16(uint32_t dst, const void* src) {
    asm volatile("cp.async.cg.shared.global [%0], [%1], 16;" :: "r"(dst), "l"(src));
}
#define CP_COMMIT() asm volatile("cp.async.commit_group;" ::: "memory")
#define CP_WAIT1()  asm volatile("cp.async.wait_group 1;" ::: "memory")
#define CP_WAIT0()  asm volatile("cp.async.wait_group 0;" ::: "memory")

__device__ __forceinline__ void ldsm4(uint32_t* r, uint32_t addr) {
    asm volatile("ldmatrix.sync.aligned.m8n8.x4.shared.b16 {%0,%1,%2,%3}, [%4];"
                 : "=r"(r[0]), "=r"(r[1]), "=r"(r[2]), "=r"(r[3]) : "r"(addr));
}
__device__ __forceinline__ void mma16816(float* c, const uint32_t* a, const uint32_t* b) {
    asm volatile(
        "mma.sync.aligned.m16n8k16.row.col.f32.bf16.bf16.f32 "
        "{%0,%1,%2,%3}, {%4,%5,%6,%7}, {%8,%9}, {%0,%1,%2,%3};"
        : "+f"(c[0]), "+f"(c[1]), "+f"(c[2]), "+f"(c[3])
        : "r"(a[0]), "r"(a[1]), "r"(a[2]), "r"(a[3]), "r"(b[0]), "r"(b[1]));
}

// 64-byte rows (32 bf16), 4 chunks of 16B; XOR swizzle conflict-free for
// both cp.async stores and ldmatrix reads.
__device__ __forceinline__ uint32_t swz(int row, int chunk) {
    return (uint32_t)(row * 64 + ((chunk ^ ((row >> 1) & 3)) << 4));
}

// ---------------------------- epilogue modes --------------------------------
enum { M_BIAS_BF16 = 0, M_VT = 1, M_F32 = 2, M_SCORES = 3, M_CTX = 4, M_OUT = 5 };

// ---------------------------------------------------------------------------
// Tensor-core GEMM: C[128, BN] = A[128,K] @ B[BN,K]^T (K-major bf16 inputs),
// batched over blockIdx.z. K multiple of 32. 2-stage cp.async pipeline.
// ---------------------------------------------------------------------------
template<int BN, int MODE>
__global__ void __launch_bounds__(BN == 128 ? 256 : 128) gemm_mma(
    const bf16* __restrict__ A, int lda, long sA,
    const bf16* __restrict__ B, int ldb, long sB,
    int K,
    float* __restrict__ Cf, bf16* __restrict__ Cb, int ldc, long sC,
    const float* __restrict__ bias,
    const float* __restrict__ res,
    const float* __restrict__ ckt, const float* __restrict__ cqt,
    const int* __restrict__ mask)
{
    constexpr int BM = 128, BK = 32;
    constexpr int WN = BN / 32;
    constexpr int THREADS = 2 * WN * 32;
    constexpr int ABYTES = BM * BK * 2;   // 8 KB
    constexpr int BBYTES = BN * BK * 2;

    __shared__ __align__(1024) char sm[2 * (ABYTES + BBYTES)];
    const uint32_t uA = smem_u32(sm);
    const uint32_t uB = uA + 2 * ABYTES;

    const int tid = threadIdx.x, lane = tid & 31, wid = tid >> 5;
    const int wm = wid & 1, wn = wid >> 1;
    const int h  = blockIdx.z;
    const int bm = blockIdx.y * BM, bn = blockIdx.x * BN;
    A += (long)h * sA;
    B += (long)h * sB;
    const long cOff = (long)h * sC;

    const bf16* Arow = A + (long)bm * lda;
    const bf16* Brow = B + (long)bn * ldb;

    auto load_tiles = [&](int ch, int st) {
        const bf16* Ak = Arow + ch * BK;
        #pragma unroll
        for (int i = tid; i < BM * 4; i += THREADS) {
            int r = i >> 2, c = i & 3;
            cpasync16(uA + st * ABYTES + swz(r, c), Ak + (long)r * lda + c * 8);
        }
        const bf16* Bk = Brow + ch * BK;
        #pragma unroll
        for (int i = tid; i < BN * 4; i += THREADS) {
            int r = i >> 2, c = i & 3;
            cpasync16(uB + st * BBYTES + swz(r, c), Bk + (long)r * ldb + c * 8);
        }
    };

    float acc[4][4][4] = {};

    const int nch = K >> 5;
    load_tiles(0, 0);
    CP_COMMIT();

    for (int ch = 0; ch < nch; ch++) {
        const int st = ch & 1;
        if (ch + 1 < nch) { load_tiles(ch + 1, st ^ 1); CP_COMMIT(); CP_WAIT1(); }
        else              { CP_WAIT0(); }
        __syncthreads();

        const uint32_t bA = uA + st * ABYTES;
        const uint32_t bB = uB + st * BBYTES;
        #pragma unroll
        for (int kk = 0; kk < 2; kk++) {
            uint32_t afr[4][4];
            #pragma unroll
            for (int i = 0; i < 4; i++) {
                int row = wm * 64 + i * 16 + (lane & 15);
                int chk = kk * 2 + (lane >> 4);
                ldsm4(afr[i], bA + swz(row, chk));
            }
            uint32_t bfr[4][2];
            #pragma unroll
            for (int p = 0; p < 2; p++) {
                uint32_t r4[4];
                int n   = wn * 32 + p * 16 + ((lane >> 4) << 3) + (lane & 7);
                int chk = kk * 2 + ((lane >> 3) & 1);
                ldsm4(r4, bB + swz(n, chk));
                bfr[2 * p][0] = r4[0]; bfr[2 * p][1] = r4[1];
                bfr[2 * p + 1][0] = r4[2]; bfr[2 * p + 1][1] = r4[3];
            }
            #pragma unroll
            for (int i = 0; i < 4; i++)
                #pragma unroll
                for (int j = 0; j < 4; j++)
                    mma16816(acc[i][j], afr[i], bfr[j]);
        }
        __syncthreads();
    }

    // ---------------- epilogue (fragment space) ----------------
    #pragma unroll
    for (int i = 0; i < 4; i++) {
        #pragma unroll
        for (int j = 0; j < 4; j++) {
            #pragma unroll
            for (int half = 0; half < 2; half++) {
                const int r  = bm + wm * 64 + i * 16 + (lane >> 2) + half * 8;
                const int c  = bn + wn * 32 + j * 8 + (lane & 3) * 2;
                const float v0 = acc[i][j][half * 2];
                const float v1 = acc[i][j][half * 2 + 1];

                if (MODE == M_BIAS_BF16) {
                    float b0 = bias ? bias[c] : 0.f, b1 = bias ? bias[c + 1] : 0.f;
                    *(__nv_bfloat162*)(Cb + cOff + (long)r * ldc + c) =
                        __float22bfloat162_rn(make_float2(v0 + b0, v1 + b1));
                } else if (MODE == M_VT) {
                    Cb[(long)c * S + r]       = __float2bfloat16(v0 + bias[c]);
                    Cb[(long)(c + 1) * S + r] = __float2bfloat16(v1 + bias[c + 1]);
                } else if (MODE == M_F32) {
                    *(float2*)(Cf + cOff + (long)r * ldc + c) = make_float2(v0, v1);
                } else if (MODE == M_SCORES) {
                    const float* ckh = ckt + (size_t)h * S * LPOS + (size_t)r * LPOS;
                    const float* cqh = cqt + (size_t)h * S * LPOS;
                    const int mr = mask[r];
                    int l0 = min(max(r - c + 512, 0), LPOS - 1);
                    int l1 = min(max(r - c + 511, 0), LPOS - 1);
                    float o0 = (v0 + ckh[l0] + cqh[(size_t)c * LPOS + l0]) * SCALE;
                    float o1 = (v1 + ckh[l1] + cqh[(size_t)(c + 1) * LPOS + l1]) * SCALE;
                    if (!(mr && mask[c]))     o0 = NEGMAX;
                    if (!(mr && mask[c + 1])) o1 = NEGMAX;
                    *(float2*)(Cf + cOff + (long)r * ldc + c) = make_float2(o0, o1);
                } else if (MODE == M_CTX) {
                    *(__nv_bfloat162*)(Cb + cOff + (long)r * ldc + c) =
                        __float22bfloat162_rn(make_float2(v0, v1));
                } else if (MODE == M_OUT) {
                    const float* rr = res + (long)r * H;
                    *(float2*)(Cf + (long)r * ldc + c) =
                        make_float2(v0 + bias[c] + rr[c], v1 + bias[c + 1] + rr[c + 1]);
                }
            }
        }
    }
}

// ---------------------------------------------------------------------------
// fp32 -> bf16 elementwise
__global__ void cvt_bf16(const float* __restrict__ x, bf16* __restrict__ y, int n)
{
    int i = blockIdx.x * 256 + threadIdx.x;
    if (i < n) y[i] = __float2bfloat16(x[i]);
}

// Weight transpose + convert: Wt[n*H + k] = W[k*H + n]
__global__ void wtrans(const float* __restrict__ W, bf16* __restrict__ Wt)
{
    __shared__ float t[32][33];
    const int bx = blockIdx.x * 32, by = blockIdx.y * 32;
    #pragma unroll
    for (int i = threadIdx.y; i < 32; i += 8)
        t[i][threadIdx.x] = W[(long)(by + i) * H + bx + threadIdx.x];
    __syncthreads();
    #pragma unroll
    for (int i = threadIdx.y; i < 32; i += 8)
        Wt[(long)(bx + i) * H + by + threadIdx.x] = __float2bfloat16(t[threadIdx.x][i]);
}

// ---------------------------------------------------------------------------
// Row softmax over 2048 fp32 -> bf16 probs. One block (256 thr) per row.
__global__ void softmax_kernel(const float* __restrict__ sc, bf16* __restrict__ pb)
{
    __shared__ float red[8];
    const size_t base = (size_t)blockIdx.x * S;
    const int tid = threadIdx.x;

    float v[8];
    float mx = NEGMAX;
    #pragma unroll
    for (int j = 0; j < 8; j++) { v[j] = sc[base + tid + 256 * j]; mx = fmaxf(mx, v[j]); }
    #pragma unroll
    for (int o = 16; o > 0; o >>= 1) mx = fmaxf(mx, __shfl_xor_sync(0xffffffffu, mx, o));
    if ((tid & 31) == 0) red[tid >> 5] = mx;
    __syncthreads();
    #pragma unroll
    for (int w = 0; w < 8; w++) mx = fmaxf(mx, red[w]);

    float sum = 0.f;
    #pragma unroll
    for (int j = 0; j < 8; j++) { v[j] = __expf(v[j] - mx); sum += v[j]; }
    #pragma unroll
    for (int o = 16; o > 0; o >>= 1) sum += __shfl_xor_sync(0xffffffffu, sum, o);
    __syncthreads();
    if ((tid & 31) == 0) red[tid >> 5] = sum;
    __syncthreads();
    float ts = 0.f;
    #pragma unroll
    for (int w = 0; w < 8; w++) ts += red[w];

    const float inv = 1.0f / ts;
    #pragma unroll
    for (int j = 0; j < 8; j++)
        pb[base + tid + 256 * j] = __float2bfloat16(v[j] * inv);
}

// ---------------------------------------------------------------------------
// LayerNorm over H=768, one block (256 threads) per row.
__global__ void ln_kernel(const float* __restrict__ x,
                          const float* __restrict__ gamma,
                          const float* __restrict__ beta,
                          float* __restrict__ out)
{
    __shared__ float rs[8], rq[8];
    const int s = blockIdx.x, tid = threadIdx.x;
    const float* row = x + (long)s * H;
    float a0 = row[tid], a1 = row[tid + 256], a2 = row[tid + 512];
    float sum = a0 + a1 + a2;
    float sq  = a0 * a0 + a1 * a1 + a2 * a2;
    #pragma unroll
    for (int o = 16; o > 0; o >>= 1) {
        sum += __shfl_xor_sync(0xffffffffu, sum, o);
        sq  += __shfl_xor_sync(0xffffffffu, sq,  o);
    }
    if ((tid & 31) == 0) { rs[tid >> 5] = sum; rq[tid >> 5] = sq; }
    __syncthreads();
    float ts = 0.f, tq = 0.f;
    #pragma unroll
    for (int w = 0; w < 8; w++) { ts += rs[w]; tq += rq[w]; }
    float mean = ts * (1.0f / H);
    float var  = tq * (1.0f / H) - mean * mean;
    float inv  = rsqrtf(var + 1e-7f);
    float* o = out + (long)s * H;
    o[tid]       = (a0 - mean) * inv * gamma[tid]       + beta[tid];
    o[tid + 256] = (a1 - mean) * inv * gamma[tid + 256] + beta[tid + 256];
    o[tid + 512] = (a2 - mean) * inv * gamma[tid + 512] + beta[tid + 512];
}

// ---------------------------------------------------------------------------
extern "C" void kernel_launch(void* const* d_in, const int* in_sizes, int n_in,
                              void* d_out, int out_size)
{
    const float* hidden = (const float*)d_in[0];
    const int*   mask   = (const int*)  d_in[1];
    const float* Wq     = (const float*)d_in[2];
    const float* bq     = (const float*)d_in[3];
    const float* Wk     = (const float*)d_in[4];
    const float* bk     = (const float*)d_in[5];
    const float* Wv     = (const float*)d_in[6];
    const float* bv     = (const float*)d_in[7];
    const float* rel    = (const float*)d_in[8];
    const float* Wpk    = (const float*)d_in[9];
    const float* Wpq    = (const float*)d_in[10];
    const float* bpq    = (const float*)d_in[11];
    const float* Wo     = (const float*)d_in[12];
    const float* bo     = (const float*)d_in[13];
    const float* gamma  = (const float*)d_in[14];
    const float* beta   = (const float*)d_in[15];
    float* out = (float*)d_out;

    bf16 *hbf, *relbf, *Wt, *Qbf, *Kbf, *Vt, *PKbf, *PQbf, *Pbf, *CTXbf;
    float *CK, *CQ, *SC, *TMP;
    cudaGetSymbolAddress((void**)&hbf,   g_hbf);
    cudaGetSymbolAddress((void**)&relbf, g_relbf);
    cudaGetSymbolAddress((void**)&Wt,    g_Wt);
    cudaGetSymbolAddress((void**)&Qbf,   g_Qbf);
    cudaGetSymbolAddress((void**)&Kbf,   g_Kbf);
    cudaGetSymbolAddress((void**)&Vt,    g_Vt);
    cudaGetSymbolAddress((void**)&PKbf,  g_PKbf);
    cudaGetSymbolAddress((void**)&PQbf,  g_PQbf);
    cudaGetSymbolAddress((void**)&CK,    g_CK);
    cudaGetSymbolAddress((void**)&CQ,    g_CQ);
    cudaGetSymbolAddress((void**)&SC,    g_SC);
    cudaGetSymbolAddress((void**)&Pbf,   g_Pbf);
    cudaGetSymbolAddress((void**)&CTXbf, g_CTXbf);
    cudaGetSymbolAddress((void**)&TMP,   g_TMP);

    // --- conversions / transposes ---
    cvt_bf16<<<(S * H + 255) / 256, 256>>>(hidden, hbf, S * H);
    cvt_bf16<<<(LPOS * H + 255) / 256, 256>>>(rel, relbf, LPOS * H);
    wtrans<<<dim3(H/32, H/32), dim3(32, 8)>>>(Wq,  Wt + 0 * H * H);
    wtrans<<<dim3(H/32, H/32), dim3(32, 8)>>>(Wk,  Wt + 1 * H * H);
    wtrans<<<dim3(H/32, H/32), dim3(32, 8)>>>(Wv,  Wt + 2 * H * H);
    wtrans<<<dim3(H/32, H/32), dim3(32, 8)>>>(Wpk, Wt + 3 * H * H);
    wtrans<<<dim3(H/32, H/32), dim3(32, 8)>>>(Wpq, Wt + 4 * H * H);
    wtrans<<<dim3(H/32, H/32), dim3(32, 8)>>>(Wo,  Wt + 5 * H * H);

    // --- projections (C = A @ Wt^T) ---
    gemm_mma<128, M_BIAS_BF16><<<dim3(6, 16, 1), 256>>>(
        hbf, H, 0, Wt + 0 * H * H, H, 0, H,
        nullptr, Qbf, H, 0, bq, nullptr, nullptr, nullptr, nullptr);
    gemm_mma<128, M_BIAS_BF16><<<dim3(6, 16, 1), 256>>>(
        hbf, H, 0, Wt + 1 * H * H, H, 0, H,
        nullptr, Kbf, H, 0, bk, nullptr, nullptr, nullptr, nullptr);
    gemm_mma<128, M_VT><<<dim3(6, 16, 1), 256>>>(
        hbf, H, 0, Wt + 2 * H * H, H, 0, H,
        nullptr, Vt, 0, 0, bv, nullptr, nullptr, nullptr, nullptr);
    gemm_mma<128, M_BIAS_BF16><<<dim3(6, 8, 1), 256>>>(
        relbf, H, 0, Wt + 3 * H * H, H, 0, H,
        nullptr, PKbf, H, 0, nullptr, nullptr, nullptr, nullptr, nullptr);
    gemm_mma<128, M_BIAS_BF16><<<dim3(6, 8, 1), 256>>>(
        relbf, H, 0, Wt + 4 * H * H, H, 0, H,
        nullptr, PQbf, H, 0, bpq, nullptr, nullptr, nullptr, nullptr);

    // --- rel-position dot tables: CK = Q_h @ PK_h^T, CQ = K_h @ PQ_h^T ---
    gemm_mma<128, M_F32><<<dim3(LPOS/128, S/128, NH), 256>>>(
        Qbf, H, D, PKbf, H, D, D,
        CK, nullptr, LPOS, (long)S * LPOS, nullptr, nullptr, nullptr, nullptr, nullptr);
    gemm_mma<128, M_F32><<<dim3(LPOS/128, S/128, NH), 256>>>(
        Kbf, H, D, PQbf, H, D, D,
        CQ, nullptr, LPOS, (long)S * LPOS, nullptr, nullptr, nullptr, nullptr, nullptr);

    // --- scores: QK^T + gathered rel bias + mask ---
    gemm_mma<128, M_SCORES><<<dim3(S/128, S/128, NH), 256>>>(
        Qbf, H, D, Kbf, H, D, D,
        SC, nullptr, S, (long)S * S, nullptr, nullptr, CK, CQ, mask);

    // --- softmax -> bf16 probs ---
    softmax_kernel<<<NH * S, 256>>>(SC, Pbf);

    // --- ctx = P @ V (V pre-transposed to [D,S] K-major) ---
    gemm_mma<64, M_CTX><<<dim3(1, S/128, NH), 128>>>(
        Pbf, S, (long)S * S, Vt, S, (long)D * S, S,
        nullptr, CTXbf, H, D, nullptr, nullptr, nullptr, nullptr, nullptr);

    // --- output projection + bias + residual ---
    gemm_mma<128, M_OUT><<<dim3(6, 16, 1), 256>>>(
        CTXbf, H, 0, Wt + 5 * H * H, H, 0, H,
        TMP, nullptr, H, 0, bo, hidden, nullptr, nullptr, nullptr);

    // --- layernorm ---
    ln_kernel<<<S, 256>>>(TMP, gamma, beta, out);
}

// round 4
// speedup vs baseline: 7.3734x; 1.1121x over previous
#include <cuda_runtime.h>
#include <cuda_bf16.h>
#include <cstdint>

// ---------------------------------------------------------------------------
// BertAttention (DeBERTa) — round 4: flash-fused attention + bf16 bias tables.
// B=1, S=2048, H=768, NH=12, D=64, SPAN=512
// ---------------------------------------------------------------------------

constexpr int S    = 2048;
constexpr int H    = 768;
constexpr int NH   = 12;
constexpr int D    = 64;
constexpr int LPOS = 1024;  // 2*SPAN
constexpr float SCALE  = 0.07216878364870322f;  // 1/sqrt(64*3)
constexpr float NEGMAX = -3.402823466e38f;

using bf16 = __nv_bfloat16;

// ---------------------------- scratch (device globals) ---------------------
__device__ bf16  g_hbf  [S * H];
__device__ bf16  g_relbf[LPOS * H];
__device__ bf16  g_Wt   [6 * H * H];     // transposed bf16 weights [N,K]
__device__ bf16  g_Qbf  [S * H];
__device__ bf16  g_Kbf  [S * H];
__device__ bf16  g_Vt   [H * S];         // V transposed: [h*D+d][token]
__device__ bf16  g_PKbf [LPOS * H];
__device__ bf16  g_PQbf [LPOS * H];
__device__ bf16  g_CKb  [(size_t)NH * S * LPOS];   // bf16 c2p table
__device__ bf16  g_CQb  [(size_t)NH * S * LPOS];   // bf16 p2c table
__device__ bf16  g_CTXbf[S * H];
__device__ float g_TMP  [S * H];

// ---------------------------- PTX helpers ----------------------------------
__device__ __forceinline__ uint32_t smem_u32(const void* p) {
    uint32_t a;
    asm("{ .reg .u64 t; cvta.to.shared.u64 t, %1; cvt.u32.u64 %0, t; }"
        : "=r"(a) : "l"(p));
    return a;
}
__device__ __forceinline__ void cpasync16(uint32_t dst, const void* src) {
    asm volatile("cp.async.cg.shared.global [%0], [%1], 16;" :: "r"(dst), "l"(src));
}
#define CP_COMMIT() asm volatile("cp.async.commit_group;" ::: "memory")
#define CP_WAIT1()  asm volatile("cp.async.wait_group 1;" ::: "memory")
#define CP_WAIT0()  asm volatile("cp.async.wait_group 0;" ::: "memory")

__device__ __forceinline__ void ldsm4(uint32_t* r, uint32_t addr) {
    asm volatile("ldmatrix.sync.aligned.m8n8.x4.shared.b16 {%0,%1,%2,%3}, [%4];"
                 : "=r"(r[0]), "=r"(r[1]), "=r"(r[2]), "=r"(r[3]) : "r"(addr));
}
__device__ __forceinline__ void mma16816(float* c, const uint32_t* a, const uint32_t* b) {
    asm volatile(
        "mma.sync.aligned.m16n8k16.row.col.f32.bf16.bf16.f32 "
        "{%0,%1,%2,%3}, {%4,%5,%6,%7}, {%8,%9}, {%0,%1,%2,%3};"
        : "+f"(c[0]), "+f"(c[1]), "+f"(c[2]), "+f"(c[3])
        : "r"(a[0]), "r"(a[1]), "r"(a[2]), "r"(a[3]), "r"(b[0]), "r"(b[1]));
}
__device__ __forceinline__ uint32_t packbf2(float a, float b) {
    __nv_bfloat162 t = __float22bfloat162_rn(make_float2(a, b));
    return *(uint32_t*)&t;
}

// 64-byte rows (32 bf16): generic GEMM tiles
__device__ __forceinline__ uint32_t swz(int row, int chunk) {
    return (uint32_t)(row * 64 + ((chunk ^ ((row >> 1) & 3)) << 4));
}
// 128-byte rows (64 bf16): flash tiles
__device__ __forceinline__ uint32_t swz128(int row, int c16) {
    return (uint32_t)(row * 128 + ((c16 ^ (row & 7)) << 4));
}

// ---------------------------- epilogue modes --------------------------------
enum { M_BIAS_BF16 = 0, M_VT = 1, M_BF16 = 2, M_OUT = 3 };

// ---------------------------------------------------------------------------
// Tensor-core GEMM: C[128, 128] = A[128,K] @ B[128,K]^T (K-major bf16),
// batched over blockIdx.z. K multiple of 32. 2-stage cp.async pipeline.
// ---------------------------------------------------------------------------
template<int MODE>
__global__ void __launch_bounds__(256) gemm_mma(
    const bf16* __restrict__ A, int lda, long sA,
    const bf16* __restrict__ B, int ldb, long sB,
    int K,
    float* __restrict__ Cf, bf16* __restrict__ Cb, int ldc, long sC,
    const float* __restrict__ bias,
    const float* __restrict__ res)
{
    constexpr int BM = 128, BN = 128, BK = 32;
    constexpr int THREADS = 256;
    constexpr int ABYTES = BM * BK * 2;   // 8 KB
    constexpr int BBYTES = BN * BK * 2;

    __shared__ __align__(1024) char sm[2 * (ABYTES + BBYTES)];
    const uint32_t uA = smem_u32(sm);
    const uint32_t uB = uA + 2 * ABYTES;

    const int tid = threadIdx.x, lane = tid & 31, wid = tid >> 5;
    const int wm = wid & 1, wn = wid >> 1;
    const int h  = blockIdx.z;
    const int bm = blockIdx.y * BM, bn = blockIdx.x * BN;
    A += (long)h * sA;
    B += (long)h * sB;
    const long cOff = (long)h * sC;

    const bf16* Arow = A + (long)bm * lda;
    const bf16* Brow = B + (long)bn * ldb;

    auto load_tiles = [&](int ch, int st) {
        const bf16* Ak = Arow + ch * BK;
        #pragma unroll
        for (int i = tid; i < BM * 4; i += THREADS) {
            int r = i >> 2, c = i & 3;
            cpasync16(uA + st * ABYTES + swz(r, c), Ak + (long)r * lda + c * 8);
        }
        const bf16* Bk = Brow + ch * BK;
        #pragma unroll
        for (int i = tid; i < BN * 4; i += THREADS) {
            int r = i >> 2, c = i & 3;
            cpasync16(uB + st * BBYTES + swz(r, c), Bk + (long)r * ldb + c * 8);
        }
    };

    float acc[4][4][4] = {};

    const int nch = K >> 5;
    load_tiles(0, 0);
    CP_COMMIT();

    for (int ch = 0; ch < nch; ch++) {
        const int st = ch & 1;
        if (ch + 1 < nch) { load_tiles(ch + 1, st ^ 1); CP_COMMIT(); CP_WAIT1(); }
        else              { CP_WAIT0(); }
        __syncthreads();

        const uint32_t bA = uA + st * ABYTES;
        const uint32_t bB = uB + st * BBYTES;
        #pragma unroll
        for (int kk = 0; kk < 2; kk++) {
            uint32_t afr[4][4];
            #pragma unroll
            for (int i = 0; i < 4; i++) {
                int row = wm * 64 + i * 16 + (lane & 15);
                int chk = kk * 2 + (lane >> 4);
                ldsm4(afr[i], bA + swz(row, chk));
            }
            uint32_t bfr[4][2];
            #pragma unroll
            for (int p = 0; p < 2; p++) {
                uint32_t r4[4];
                int n   = wn * 32 + p * 16 + ((lane >> 4) << 3) + (lane & 7);
                int chk = kk * 2 + ((lane >> 3) & 1);
                ldsm4(r4, bB + swz(n, chk));
                bfr[2 * p][0] = r4[0]; bfr[2 * p][1] = r4[1];
                bfr[2 * p + 1][0] = r4[2]; bfr[2 * p + 1][1] = r4[3];
            }
            #pragma unroll
            for (int i = 0; i < 4; i++)
                #pragma unroll
                for (int j = 0; j < 4; j++)
                    mma16816(acc[i][j], afr[i], bfr[j]);
        }
        __syncthreads();
    }

    // ---------------- epilogue (fragment space) ----------------
    #pragma unroll
    for (int i = 0; i < 4; i++) {
        #pragma unroll
        for (int j = 0; j < 4; j++) {
            #pragma unroll
            for (int half = 0; half < 2; half++) {
                const int r  = bm + wm * 64 + i * 16 + (lane >> 2) + half * 8;
                const int c  = bn + wn * 32 + j * 8 + (lane & 3) * 2;
                const float v0 = acc[i][j][half * 2];
                const float v1 = acc[i][j][half * 2 + 1];

                if (MODE == M_BIAS_BF16) {
                    float b0 = bias ? bias[c] : 0.f, b1 = bias ? bias[c + 1] : 0.f;
                    *(__nv_bfloat162*)(Cb + cOff + (long)r * ldc + c) =
                        __float22bfloat162_rn(make_float2(v0 + b0, v1 + b1));
                } else if (MODE == M_VT) {
                    Cb[(long)c * S + r]       = __float2bfloat16(v0 + bias[c]);
                    Cb[(long)(c + 1) * S + r] = __float2bfloat16(v1 + bias[c + 1]);
                } else if (MODE == M_BF16) {
                    *(__nv_bfloat162*)(Cb + cOff + (long)r * ldc + c) =
                        __float22bfloat162_rn(make_float2(v0, v1));
                } else if (MODE == M_OUT) {
                    const float* rr = res + (long)r * H;
                    *(float2*)(Cf + (long)r * ldc + c) =
                        make_float2(v0 + bias[c] + rr[c], v1 + bias[c + 1] + rr[c + 1]);
                }
            }
        }
    }
}

// ---------------------------------------------------------------------------
// Flash-fused attention: per (row-tile of 128, head): scores + rel-pos bias +
// mask + online softmax + P@V, streaming 32 key tiles of 64 tokens.
// ---------------------------------------------------------------------------
__global__ void __launch_bounds__(256) flash_attn(
    const bf16* __restrict__ Q, const bf16* __restrict__ K,
    const bf16* __restrict__ Vt,
    const bf16* __restrict__ CKb, const bf16* __restrict__ CQb,
    const int* __restrict__ mask, bf16* __restrict__ CTX)
{
    constexpr int NTILE = S / 64;                    // 32
    __shared__ __align__(1024) char sQm[128 * 128];  // 16 KB
    __shared__ __align__(1024) char sKm[2][64 * 128];
    __shared__ __align__(1024) char sVm[2][64 * 128];

    const int tid = threadIdx.x, lane = tid & 31, wid = tid >> 5;
    const int h = blockIdx.y, bm = blockIdx.x * 128;
    const uint32_t uQ = smem_u32(sQm);
    const uint32_t uK0 = smem_u32(sKm[0]), uK1 = smem_u32(sKm[1]);
    const uint32_t uV0 = smem_u32(sVm[0]), uV1 = smem_u32(sVm[1]);

    // Q tile: 128 rows x 64 bf16
    {
        const bf16* Qg = Q + (long)bm * H + h * D;
        #pragma unroll
        for (int i = tid; i < 1024; i += 256) {
            int r = i >> 3, c = i & 7;
            cpasync16(uQ + swz128(r, c), Qg + (long)r * H + c * 8);
        }
    }
    CP_COMMIT();

    auto load_kv = [&](int ct, int st) {
        const int c0 = ct * 64;
        const uint32_t uk = st ? uK1 : uK0;
        const uint32_t uv = st ? uV1 : uV0;
        const bf16* Kg = K + (long)c0 * H + h * D;
        #pragma unroll
        for (int i = tid; i < 512; i += 256) {
            int r = i >> 3, c = i & 7;
            cpasync16(uk + swz128(r, c), Kg + (long)r * H + c * 8);
        }
        const bf16* Vg = Vt + (long)(h * D) * S + c0;
        #pragma unroll
        for (int i = tid; i < 512; i += 256) {
            int d = i >> 3, c = i & 7;
            cpasync16(uv + swz128(d, c), Vg + (long)d * S + c * 8);
        }
    };
    load_kv(0, 0);
    CP_COMMIT();
    CP_WAIT1();          // Q arrived
    __syncthreads();

    // Q fragments (warp owns 16 rows)
    uint32_t qf[4][4];
    #pragma unroll
    for (int kk = 0; kk < 4; kk++) {
        int row = wid * 16 + (lane & 15);
        int c16 = kk * 2 + (lane >> 4);
        ldsm4(qf[kk], uQ + swz128(row, c16));
    }

    const int r0 = bm + wid * 16 + (lane >> 2);
    const int r1 = r0 + 8;
    const int m0v = mask[r0], m1v = mask[r1];
    const bf16* ck0 = CKb + ((size_t)h * S + r0) * LPOS;
    const bf16* ck1 = CKb + ((size_t)h * S + r1) * LPOS;
    const bf16* cqh = CQb + (size_t)h * S * LPOS;

    float m0 = NEGMAX, m1 = NEGMAX, l0 = 0.f, l1 = 0.f;
    float O[8][4] = {};

    for (int ct = 0; ct < NTILE; ct++) {
        const int st = ct & 1;
        if (ct + 1 < NTILE) { load_kv(ct + 1, st ^ 1); CP_COMMIT(); CP_WAIT1(); }
        else                { CP_WAIT0(); }
        __syncthreads();

        const uint32_t uk = st ? uK1 : uK0;
        const uint32_t uv = st ? uV1 : uV0;

        // ---- S = Q K^T (16 x 64 per warp) ----
        float sfr[8][4] = {};
        #pragma unroll
        for (int g = 0; g < 4; g++) {
            #pragma unroll
            for (int kk = 0; kk < 4; kk++) {
                uint32_t r4[4];
                int n   = g * 16 + ((lane >> 4) << 3) + (lane & 7);
                int c16 = kk * 2 + ((lane >> 3) & 1);
                ldsm4(r4, uk + swz128(n, c16));
                mma16816(sfr[2 * g],     qf[kk], r4);
                mma16816(sfr[2 * g + 1], qf[kk], r4 + 2);
            }
        }

        // ---- rel-pos bias + scale + mask, tile row max ----
        const int c0 = ct * 64;
        float tmx0 = NEGMAX, tmx1 = NEGMAX;
        #pragma unroll
        for (int nb = 0; nb < 8; nb++) {
            const int c = c0 + nb * 8 + (lane & 3) * 2;
            const int mc0 = mask[c], mc1 = mask[c + 1];
            {
                int la = min(max(r0 - c + 512, 0), LPOS - 1);
                int lb = min(max(r0 - c + 511, 0), LPOS - 1);
                float v0 = (sfr[nb][0] + __bfloat162float(ck0[la])
                            + __bfloat162float(cqh[(size_t)c * LPOS + la])) * SCALE;
                float v1 = (sfr[nb][1] + __bfloat162float(ck0[lb])
                            + __bfloat162float(cqh[(size_t)(c + 1) * LPOS + lb])) * SCALE;
                if (!(m0v && mc0)) v0 = NEGMAX;
                if (!(m0v && mc1)) v1 = NEGMAX;
                sfr[nb][0] = v0; sfr[nb][1] = v1;
                tmx0 = fmaxf(tmx0, fmaxf(v0, v1));
            }
            {
                int la = min(max(r1 - c + 512, 0), LPOS - 1);
                int lb = min(max(r1 - c + 511, 0), LPOS - 1);
                float v2 = (sfr[nb][2] + __bfloat162float(ck1[la])
                            + __bfloat162float(cqh[(size_t)c * LPOS + la])) * SCALE;
                float v3 = (sfr[nb][3] + __bfloat162float(ck1[lb])
                            + __bfloat162float(cqh[(size_t)(c + 1) * LPOS + lb])) * SCALE;
                if (!(m1v && mc0)) v2 = NEGMAX;
                if (!(m1v && mc1)) v3 = NEGMAX;
                sfr[nb][2] = v2; sfr[nb][3] = v3;
                tmx1 = fmaxf(tmx1, fmaxf(v2, v3));
            }
        }
        tmx0 = fmaxf(tmx0, __shfl_xor_sync(0xffffffffu, tmx0, 1));
        tmx0 = fmaxf(tmx0, __shfl_xor_sync(0xffffffffu, tmx0, 2));
        tmx1 = fmaxf(tmx1, __shfl_xor_sync(0xffffffffu, tmx1, 1));
        tmx1 = fmaxf(tmx1, __shfl_xor_sync(0xffffffffu, tmx1, 2));

        // ---- online softmax update ----
        const float mn0 = fmaxf(m0, tmx0), mn1 = fmaxf(m1, tmx1);
        const float sc0 = __expf(m0 - mn0), sc1 = __expf(m1 - mn1);
        m0 = mn0; m1 = mn1;
        float rs0 = 0.f, rs1 = 0.f;
        #pragma unroll
        for (int nb = 0; nb < 8; nb++) {
            sfr[nb][0] = __expf(sfr[nb][0] - mn0);
            sfr[nb][1] = __expf(sfr[nb][1] - mn0);
            sfr[nb][2] = __expf(sfr[nb][2] - mn1);
            sfr[nb][3] = __expf(sfr[nb][3] - mn1);
            rs0 += sfr[nb][0] + sfr[nb][1];
            rs1 += sfr[nb][2] + sfr[nb][3];
        }
        rs0 += __shfl_xor_sync(0xffffffffu, rs0, 1);
        rs0 += __shfl_xor_sync(0xffffffffu, rs0, 2);
        rs1 += __shfl_xor_sync(0xffffffffu, rs1, 1);
        rs1 += __shfl_xor_sync(0xffffffffu, rs1, 2);
        l0 = l0 * sc0 + rs0;
        l1 = l1 * sc1 + rs1;
        #pragma unroll
        for (int df = 0; df < 8; df++) {
            O[df][0] *= sc0; O[df][1] *= sc0;
            O[df][2] *= sc1; O[df][3] *= sc1;
        }

        // ---- P (bf16 A-frags) @ V ----
        #pragma unroll
        for (int kk2 = 0; kk2 < 4; kk2++) {
            uint32_t pf[4];
            pf[0] = packbf2(sfr[2 * kk2][0],     sfr[2 * kk2][1]);
            pf[1] = packbf2(sfr[2 * kk2][2],     sfr[2 * kk2][3]);
            pf[2] = packbf2(sfr[2 * kk2 + 1][0], sfr[2 * kk2 + 1][1]);
            pf[3] = packbf2(sfr[2 * kk2 + 1][2], sfr[2 * kk2 + 1][3]);
            #pragma unroll
            for (int dg = 0; dg < 4; dg++) {
                uint32_t r4[4];
                int n   = dg * 16 + ((lane >> 4) << 3) + (lane & 7);
                int c16 = kk2 * 2 + ((lane >> 3) & 1);
                ldsm4(r4, uv + swz128(n, c16));
                mma16816(O[2 * dg],     pf, r4);
                mma16816(O[2 * dg + 1], pf, r4 + 2);
            }
        }
        __syncthreads();
    }

    // ---- normalize + write ctx (bf16) ----
    const float inv0 = 1.0f / l0, inv1 = 1.0f / l1;
    bf16* o0 = CTX + (long)r0 * H + h * D + (lane & 3) * 2;
    bf16* o1 = CTX + (long)r1 * H + h * D + (lane & 3) * 2;
    #pragma unroll
    for (int df = 0; df < 8; df++) {
        *(__nv_bfloat162*)(o0 + df * 8) =
            __float22bfloat162_rn(make_float2(O[df][0] * inv0, O[df][1] * inv0));
        *(__nv_bfloat162*)(o1 + df * 8) =
            __float22bfloat162_rn(make_float2(O[df][2] * inv1, O[df][3] * inv1));
    }
}

// ---------------------------------------------------------------------------
// fp32 -> bf16 elementwise
__global__ void cvt_bf16(const float* __restrict__ x, bf16* __restrict__ y, int n)
{
    int i = blockIdx.x * 256 + threadIdx.x;
    if (i < n) y[i] = __float2bfloat16(x[i]);
}

// Weight transpose + convert: Wt[n*H + k] = W[k*H + n]
__global__ void wtrans(const float* __restrict__ W, bf16* __restrict__ Wt)
{
    __shared__ float t[32][33];
    const int bx = blockIdx.x * 32, by = blockIdx.y * 32;
    #pragma unroll
    for (int i = threadIdx.y; i < 32; i += 8)
        t[i][threadIdx.x] = W[(long)(by + i) * H + bx + threadIdx.x];
    __syncthreads();
    #pragma unroll
    for (int i = threadIdx.y; i < 32; i += 8)
        Wt[(long)(bx + i) * H + by + threadIdx.x] = __float2bfloat16(t[threadIdx.x][i]);
}

// ---------------------------------------------------------------------------
// LayerNorm over H=768, one block (256 threads) per row.
__global__ void ln_kernel(const float* __restrict__ x,
                          const float* __restrict__ gamma,
                          const float* __restrict__ beta,
                          float* __restrict__ out)
{
    __shared__ float rs[8], rq[8];
    const int s = blockIdx.x, tid = threadIdx.x;
    const float* row = x + (long)s * H;
    float a0 = row[tid], a1 = row[tid + 256], a2 = row[tid + 512];
    float sum = a0 + a1 + a2;
    float sq  = a0 * a0 + a1 * a1 + a2 * a2;
    #pragma unroll
    for (int o = 16; o > 0; o >>= 1) {
        sum += __shfl_xor_sync(0xffffffffu, sum, o);
        sq  += __shfl_xor_sync(0xffffffffu, sq,  o);
    }
    if ((tid & 31) == 0) { rs[tid >> 5] = sum; rq[tid >> 5] = sq; }
    __syncthreads();
    float ts = 0.f, tq = 0.f;
    #pragma unroll
    for (int w = 0; w < 8; w++) { ts += rs[w]; tq += rq[w]; }
    float mean = ts * (1.0f / H);
    float var  = tq * (1.0f / H) - mean * mean;
    float inv  = rsqrtf(var + 1e-7f);
    float* o = out + (long)s * H;
    o[tid]       = (a0 - mean) * inv * gamma[tid]       + beta[tid];
    o[tid + 256] = (a1 - mean) * inv * gamma[tid + 256] + beta[tid + 256];
    o[tid + 512] = (a2 - mean) * inv * gamma[tid + 512] + beta[tid + 512];
}

// ---------------------------------------------------------------------------
extern "C" void kernel_launch(void* const* d_in, const int* in_sizes, int n_in,
                              void* d_out, int out_size)
{
    const float* hidden = (const float*)d_in[0];
    const int*   mask   = (const int*)  d_in[1];
    const float* Wq     = (const float*)d_in[2];
    const float* bq     = (const float*)d_in[3];
    const float* Wk     = (const float*)d_in[4];
    const float* bk     = (const float*)d_in[5];
    const float* Wv     = (const float*)d_in[6];
    const float* bv     = (const float*)d_in[7];
    const float* rel    = (const float*)d_in[8];
    const float* Wpk    = (const float*)d_in[9];
    const float* Wpq    = (const float*)d_in[10];
    const float* bpq    = (const float*)d_in[11];
    const float* Wo     = (const float*)d_in[12];
    const float* bo     = (const float*)d_in[13];
    const float* gamma  = (const float*)d_in[14];
    const float* beta   = (const float*)d_in[15];
    float* out = (float*)d_out;

    bf16 *hbf, *relbf, *Wt, *Qbf, *Kbf, *Vt, *PKbf, *PQbf, *CKb, *CQb, *CTXbf;
    float *TMP;
    cudaGetSymbolAddress((void**)&hbf,   g_hbf);
    cudaGetSymbolAddress((void**)&relbf, g_relbf);
    cudaGetSymbolAddress((void**)&Wt,    g_Wt);
    cudaGetSymbolAddress((void**)&Qbf,   g_Qbf);
    cudaGetSymbolAddress((void**)&Kbf,   g_Kbf);
    cudaGetSymbolAddress((void**)&Vt,    g_Vt);
    cudaGetSymbolAddress((void**)&PKbf,  g_PKbf);
    cudaGetSymbolAddress((void**)&PQbf,  g_PQbf);
    cudaGetSymbolAddress((void**)&CKb,   g_CKb);
    cudaGetSymbolAddress((void**)&CQb,   g_CQb);
    cudaGetSymbolAddress((void**)&CTXbf, g_CTXbf);
    cudaGetSymbolAddress((void**)&TMP,   g_TMP);

    // --- conversions / transposes ---
    cvt_bf16<<<(S * H + 255) / 256, 256>>>(hidden, hbf, S * H);
    cvt_bf16<<<(LPOS * H + 255) / 256, 256>>>(rel, relbf, LPOS * H);
    wtrans<<<dim3(H/32, H/32), dim3(32, 8)>>>(Wq,  Wt + 0 * H * H);
    wtrans<<<dim3(H/32, H/32), dim3(32, 8)>>>(Wk,  Wt + 1 * H * H);
    wtrans<<<dim3(H/32, H/32), dim3(32, 8)>>>(Wv,  Wt + 2 * H * H);
    wtrans<<<dim3(H/32, H/32), dim3(32, 8)>>>(Wpk, Wt + 3 * H * H);
    wtrans<<<dim3(H/32, H/32), dim3(32, 8)>>>(Wpq, Wt + 4 * H * H);
    wtrans<<<dim3(H/32, H/32), dim3(32, 8)>>>(Wo,  Wt + 5 * H * H);

    // --- projections (C = A @ Wt^T) ---
    gemm_mma<M_BIAS_BF16><<<dim3(6, 16, 1), 256>>>(
        hbf, H, 0, Wt + 0 * H * H, H, 0, H,
        nullptr, Qbf, H, 0, bq, nullptr);
    gemm_mma<M_BIAS_BF16><<<dim3(6, 16, 1), 256>>>(
        hbf, H, 0, Wt + 1 * H * H, H, 0, H,
        nullptr, Kbf, H, 0, bk, nullptr);
    gemm_mma<M_VT><<<dim3(6, 16, 1), 256>>>(
        hbf, H, 0, Wt + 2 * H * H, H, 0, H,
        nullptr, Vt, 0, 0, bv, nullptr);
    gemm_mma<M_BIAS_BF16><<<dim3(6, 8, 1), 256>>>(
        relbf, H, 0, Wt + 3 * H * H, H, 0, H,
        nullptr, PKbf, H, 0, nullptr, nullptr);
    gemm_mma<M_BIAS_BF16><<<dim3(6, 8, 1), 256>>>(
        relbf, H, 0, Wt + 4 * H * H, H, 0, H,
        nullptr, PQbf, H, 0, bpq, nullptr);

    // --- rel-position tables (bf16): CK = Q_h @ PK_h^T, CQ = K_h @ PQ_h^T ---
    gemm_mma<M_BF16><<<dim3(LPOS/128, S/128, NH), 256>>>(
        Qbf, H, D, PKbf, H, D, D,
        nullptr, CKb, LPOS, (long)S * LPOS, nullptr, nullptr);
    gemm_mma<M_BF16><<<dim3(LPOS/128, S/128, NH), 256>>>(
        Kbf, H, D, PQbf, H, D, D,
        nullptr, CQb, LPOS, (long)S * LPOS, nullptr, nullptr);

    // --- fused attention: scores + bias + mask + softmax + P@V ---
    flash_attn<<<dim3(S/128, NH), 256>>>(Qbf, Kbf, Vt, CKb, CQb, mask, CTXbf);

    // --- output projection + bias + residual ---
    gemm_mma<M_OUT><<<dim3(6, 16, 1), 256>>>(
        CTXbf, H, 0, Wt + 5 * H * H, H, 0, H,
        TMP, nullptr, H, 0, bo, hidden);

    // --- layernorm ---
    ln_kernel<<<S, 256>>>(TMP, gamma, beta, out);
}

// round 5
// speedup vs baseline: 7.8361x; 1.0628x over previous
#include <cuda_runtime.h>
#include <cuda_bf16.h>
#include <cstdint>

// ---------------------------------------------------------------------------
// BertAttention (DeBERTa) — round 5: smem-staged cq gather + batched wtrans.
// B=1, S=2048, H=768, NH=12, D=64, SPAN=512
// ---------------------------------------------------------------------------

constexpr int S    = 2048;
constexpr int H    = 768;
constexpr int NH   = 12;
constexpr int D    = 64;
constexpr int LPOS = 1024;  // 2*SPAN
constexpr float SCALE  = 0.07216878364870322f;  // 1/sqrt(64*3)
constexpr float NEGMAX = -3.402823466e38f;

using bf16 = __nv_bfloat16;

// ---------------------------- scratch (device globals) ---------------------
__device__ bf16  g_hbf  [S * H];
__device__ bf16  g_relbf[LPOS * H];
__device__ bf16  g_Wt   [6 * H * H];     // transposed bf16 weights [N,K]
__device__ bf16  g_Qbf  [S * H];
__device__ bf16  g_Kbf  [S * H];
__device__ bf16  g_Vt   [H * S];         // V transposed: [h*D+d][token]
__device__ bf16  g_PKbf [LPOS * H];
__device__ bf16  g_PQbf [LPOS * H];
__device__ bf16  g_CKb  [(size_t)NH * S * LPOS];        // bf16 c2p table
__device__ bf16  g_CQb  [(size_t)NH * S * LPOS + 256];  // bf16 p2c table (+pad)
__device__ bf16  g_CTXbf[S * H];
__device__ float g_TMP  [S * H];

// ---------------------------- PTX helpers ----------------------------------
__device__ __forceinline__ uint32_t smem_u32(const void* p) {
    uint32_t a;
    asm("{ .reg .u64 t; cvta.to.shared.u64 t, %1; cvt.u32.u64 %0, t; }"
        : "=r"(a) : "l"(p));
    return a;
}
__device__ __forceinline__ void cpasync16(uint32_t dst, const void* src) {
    asm volatile("cp.async.cg.shared.global [%0], [%1], 16;" :: "r"(dst), "l"(src));
}
#define CP_COMMIT() asm volatile("cp.async.commit_group;" ::: "memory")
#define CP_WAIT1()  asm volatile("cp.async.wait_group 1;" ::: "memory")
#define CP_WAIT0()  asm volatile("cp.async.wait_group 0;" ::: "memory")

__device__ __forceinline__ void ldsm4(uint32_t* r, uint32_t addr) {
    asm volatile("ldmatrix.sync.aligned.m8n8.x4.shared.b16 {%0,%1,%2,%3}, [%4];"
                 : "=r"(r[0]), "=r"(r[1]), "=r"(r[2]), "=r"(r[3]) : "r"(addr));
}
__device__ __forceinline__ void mma16816(float* c, const uint32_t* a, const uint32_t* b) {
    asm volatile(
        "mma.sync.aligned.m16n8k16.row.col.f32.bf16.bf16.f32 "
        "{%0,%1,%2,%3}, {%4,%5,%6,%7}, {%8,%9}, {%0,%1,%2,%3};"
        : "+f"(c[0]), "+f"(c[1]), "+f"(c[2]), "+f"(c[3])
        : "r"(a[0]), "r"(a[1]), "r"(a[2]), "r"(a[3]), "r"(b[0]), "r"(b[1]));
}
__device__ __forceinline__ uint32_t packbf2(float a, float b) {
    __nv_bfloat162 t = __float22bfloat162_rn(make_float2(a, b));
    return *(uint32_t*)&t;
}

// 64-byte rows (32 bf16): generic GEMM tiles
__device__ __forceinline__ uint32_t swz(int row, int chunk) {
    return (uint32_t)(row * 64 + ((chunk ^ ((row >> 1) & 3)) << 4));
}
// 128-byte rows (64 bf16): flash tiles
__device__ __forceinline__ uint32_t swz128(int row, int c16) {
    return (uint32_t)(row * 128 + ((c16 ^ (row & 7)) << 4));
}

// ---------------------------- epilogue modes --------------------------------
enum { M_BIAS_BF16 = 0, M_VT = 1, M_BF16 = 2, M_OUT = 3 };

// ---------------------------------------------------------------------------
// Tensor-core GEMM: C[128, 128] = A[128,K] @ B[128,K]^T (K-major bf16),
// batched over blockIdx.z. K multiple of 32. 2-stage cp.async pipeline.
// ---------------------------------------------------------------------------
template<int MODE>
__global__ void __launch_bounds__(256) gemm_mma(
    const bf16* __restrict__ A, int lda, long sA,
    const bf16* __restrict__ B, int ldb, long sB,
    int K,
    float* __restrict__ Cf, bf16* __restrict__ Cb, int ldc, long sC,
    const float* __restrict__ bias,
    const float* __restrict__ res)
{
    constexpr int BM = 128, BN = 128, BK = 32;
    constexpr int THREADS = 256;
    constexpr int ABYTES = BM * BK * 2;   // 8 KB
    constexpr int BBYTES = BN * BK * 2;

    __shared__ __align__(1024) char sm[2 * (ABYTES + BBYTES)];
    const uint32_t uA = smem_u32(sm);
    const uint32_t uB = uA + 2 * ABYTES;

    const int tid = threadIdx.x, lane = tid & 31, wid = tid >> 5;
    const int wm = wid & 1, wn = wid >> 1;
    const int h  = blockIdx.z;
    const int bm = blockIdx.y * BM, bn = blockIdx.x * BN;
    A += (long)h * sA;
    B += (long)h * sB;
    const long cOff = (long)h * sC;

    const bf16* Arow = A + (long)bm * lda;
    const bf16* Brow = B + (long)bn * ldb;

    auto load_tiles = [&](int ch, int st) {
        const bf16* Ak = Arow + ch * BK;
        #pragma unroll
        for (int i = tid; i < BM * 4; i += THREADS) {
            int r = i >> 2, c = i & 3;
            cpasync16(uA + st * ABYTES + swz(r, c), Ak + (long)r * lda + c * 8);
        }
        const bf16* Bk = Brow + ch * BK;
        #pragma unroll
        for (int i = tid; i < BN * 4; i += THREADS) {
            int r = i >> 2, c = i & 3;
            cpasync16(uB + st * BBYTES + swz(r, c), Bk + (long)r * ldb + c * 8);
        }
    };

    float acc[4][4][4] = {};

    const int nch = K >> 5;
    load_tiles(0, 0);
    CP_COMMIT();

    for (int ch = 0; ch < nch; ch++) {
        const int st = ch & 1;
        if (ch + 1 < nch) { load_tiles(ch + 1, st ^ 1); CP_COMMIT(); CP_WAIT1(); }
        else              { CP_WAIT0(); }
        __syncthreads();

        const uint32_t bA = uA + st * ABYTES;
        const uint32_t bB = uB + st * BBYTES;
        #pragma unroll
        for (int kk = 0; kk < 2; kk++) {
            uint32_t afr[4][4];
            #pragma unroll
            for (int i = 0; i < 4; i++) {
                int row = wm * 64 + i * 16 + (lane & 15);
                int chk = kk * 2 + (lane >> 4);
                ldsm4(afr[i], bA + swz(row, chk));
            }
            uint32_t bfr[4][2];
            #pragma unroll
            for (int p = 0; p < 2; p++) {
                uint32_t r4[4];
                int n   = wn * 32 + p * 16 + ((lane >> 4) << 3) + (lane & 7);
                int chk = kk * 2 + ((lane >> 3) & 1);
                ldsm4(r4, bB + swz(n, chk));
                bfr[2 * p][0] = r4[0]; bfr[2 * p][1] = r4[1];
                bfr[2 * p + 1][0] = r4[2]; bfr[2 * p + 1][1] = r4[3];
            }
            #pragma unroll
            for (int i = 0; i < 4; i++)
                #pragma unroll
                for (int j = 0; j < 4; j++)
                    mma16816(acc[i][j], afr[i], bfr[j]);
        }
        __syncthreads();
    }

    // ---------------- epilogue (fragment space) ----------------
    #pragma unroll
    for (int i = 0; i < 4; i++) {
        #pragma unroll
        for (int j = 0; j < 4; j++) {
            #pragma unroll
            for (int half = 0; half < 2; half++) {
                const int r  = bm + wm * 64 + i * 16 + (lane >> 2) + half * 8;
                const int c  = bn + wn * 32 + j * 8 + (lane & 3) * 2;
                const float v0 = acc[i][j][half * 2];
                const float v1 = acc[i][j][half * 2 + 1];

                if (MODE == M_BIAS_BF16) {
                    float b0 = bias ? bias[c] : 0.f, b1 = bias ? bias[c + 1] : 0.f;
                    *(__nv_bfloat162*)(Cb + cOff + (long)r * ldc + c) =
                        __float22bfloat162_rn(make_float2(v0 + b0, v1 + b1));
                } else if (MODE == M_VT) {
                    Cb[(long)c * S + r]       = __float2bfloat16(v0 + bias[c]);
                    Cb[(long)(c + 1) * S + r] = __float2bfloat16(v1 + bias[c + 1]);
                } else if (MODE == M_BF16) {
                    *(__nv_bfloat162*)(Cb + cOff + (long)r * ldc + c) =
                        __float22bfloat162_rn(make_float2(v0, v1));
                } else if (MODE == M_OUT) {
                    const float* rr = res + (long)r * H;
                    *(float2*)(Cf + (long)r * ldc + c) =
                        make_float2(v0 + bias[c] + rr[c], v1 + bias[c + 1] + rr[c + 1]);
                }
            }
        }
    }
}

// ---------------------------------------------------------------------------
// Flash-fused attention with smem-staged cq band.
// Per tile pair (bm, c0=ct*64): needed l = clip(r-c+512) all lie in
// [Lbase, Lbase+207], Lbase = clamp(bm-c0+449, 0, 816) & ~7.
// ---------------------------------------------------------------------------
constexpr int CQ_W     = 208;                 // staged l-values per column
constexpr int CQ_ROWB  = CQ_W * 2;            // 416 B per column row
constexpr int CQ_BYTES = 64 * CQ_ROWB;        // 26624 B per buffer
constexpr int FL_SMEM  = 16384 + 2 * 8192 + 2 * 8192 + 2 * CQ_BYTES;  // 102400

__global__ void __launch_bounds__(256) flash_attn(
    const bf16* __restrict__ Q, const bf16* __restrict__ K,
    const bf16* __restrict__ Vt,
    const bf16* __restrict__ CKb, const bf16* __restrict__ CQb,
    const int* __restrict__ mask, bf16* __restrict__ CTX)
{
    constexpr int NTILE = S / 64;  // 32
    extern __shared__ __align__(1024) char dyn[];
    const uint32_t uQ  = smem_u32(dyn);          // 16 KB
    const uint32_t uK  = uQ + 16384;             // 2 x 8 KB
    const uint32_t uV  = uK + 16384;             // 2 x 8 KB
    const uint32_t uCQ = uV + 16384;             // 2 x 26 KB

    const int tid = threadIdx.x, lane = tid & 31, wid = tid >> 5;
    const int h = blockIdx.y, bm = blockIdx.x * 128;

    auto lbase_of = [&](int ct) {
        int lo = bm - ct * 64 + 449;
        return min(max(lo, 0), 816) & ~7;
    };

    // Q tile: 128 rows x 64 bf16
    {
        const bf16* Qg = Q + (long)bm * H + h * D;
        #pragma unroll
        for (int i = tid; i < 1024; i += 256) {
            int r = i >> 3, c = i & 7;
            cpasync16(uQ + swz128(r, c), Qg + (long)r * H + c * 8);
        }
    }
    CP_COMMIT();

    auto load_kv = [&](int ct, int st) {
        const int c0 = ct * 64;
        const uint32_t uk = uK + st * 8192;
        const uint32_t uv = uV + st * 8192;
        const bf16* Kg = K + (long)c0 * H + h * D;
        #pragma unroll
        for (int i = tid; i < 512; i += 256) {
            int r = i >> 3, c = i & 7;
            cpasync16(uk + swz128(r, c), Kg + (long)r * H + c * 8);
        }
        const bf16* Vg = Vt + (long)(h * D) * S + c0;
        #pragma unroll
        for (int i = tid; i < 512; i += 256) {
            int d = i >> 3, c = i & 7;
            cpasync16(uv + swz128(d, c), Vg + (long)d * S + c * 8);
        }
        // cq band stage: 64 columns x 208 l-values, coalesced
        const int Lb = lbase_of(ct);
        const uint32_t ucq = uCQ + st * CQ_BYTES;
        const bf16* CQg = CQb + ((size_t)h * S + c0) * LPOS + Lb;
        #pragma unroll
        for (int i = tid; i < 64 * 26; i += 256) {
            int r = i / 26, ch = i % 26;
            cpasync16(ucq + r * CQ_ROWB + ch * 16, CQg + (size_t)r * LPOS + ch * 8);
        }
    };
    load_kv(0, 0);
    CP_COMMIT();
    CP_WAIT1();          // Q arrived
    __syncthreads();

    // Q fragments (warp owns 16 rows)
    uint32_t qf[4][4];
    #pragma unroll
    for (int kk = 0; kk < 4; kk++) {
        int row = wid * 16 + (lane & 15);
        int c16 = kk * 2 + (lane >> 4);
        ldsm4(qf[kk], uQ + swz128(row, c16));
    }

    const int r0 = bm + wid * 16 + (lane >> 2);
    const int r1 = r0 + 8;
    const int m0v = mask[r0], m1v = mask[r1];
    const bf16* ck0 = CKb + ((size_t)h * S + r0) * LPOS;
    const bf16* ck1 = CKb + ((size_t)h * S + r1) * LPOS;

    float m0 = NEGMAX, m1 = NEGMAX, l0 = 0.f, l1 = 0.f;
    float O[8][4] = {};

    for (int ct = 0; ct < NTILE; ct++) {
        const int st = ct & 1;
        if (ct + 1 < NTILE) { load_kv(ct + 1, st ^ 1); CP_COMMIT(); CP_WAIT1(); }
        else                { CP_WAIT0(); }
        __syncthreads();

        const uint32_t uk = uK + st * 8192;
        const uint32_t uv = uV + st * 8192;
        const bf16* sCQ = (const bf16*)(dyn + (uCQ - uQ) + st * CQ_BYTES);
        const int Lb = lbase_of(ct);

        // ---- S = Q K^T (16 x 64 per warp) ----
        float sfr[8][4] = {};
        #pragma unroll
        for (int g = 0; g < 4; g++) {
            #pragma unroll
            for (int kk = 0; kk < 4; kk++) {
                uint32_t r4[4];
                int n   = g * 16 + ((lane >> 4) << 3) + (lane & 7);
                int c16 = kk * 2 + ((lane >> 3) & 1);
                ldsm4(r4, uk + swz128(n, c16));
                mma16816(sfr[2 * g],     qf[kk], r4);
                mma16816(sfr[2 * g + 1], qf[kk], r4 + 2);
            }
        }

        // ---- rel-pos bias + scale + mask, tile row max ----
        const int c0 = ct * 64;
        float tmx0 = NEGMAX, tmx1 = NEGMAX;
        #pragma unroll
        for (int nb = 0; nb < 8; nb++) {
            const int cl = nb * 8 + (lane & 3) * 2;   // column within tile
            const int c  = c0 + cl;
            const int mc0 = mask[c], mc1 = mask[c + 1];
            {
                int la = min(max(r0 - c + 512, 0), LPOS - 1);
                int lb = min(max(r0 - c + 511, 0), LPOS - 1);
                float v0 = (sfr[nb][0] + __bfloat162float(ck0[la])
                            + __bfloat162float(sCQ[cl * CQ_W + (la - Lb)])) * SCALE;
                float v1 = (sfr[nb][1] + __bfloat162float(ck0[lb])
                            + __bfloat162float(sCQ[(cl + 1) * CQ_W + (lb - Lb)])) * SCALE;
                if (!(m0v && mc0)) v0 = NEGMAX;
                if (!(m0v && mc1)) v1 = NEGMAX;
                sfr[nb][0] = v0; sfr[nb][1] = v1;
                tmx0 = fmaxf(tmx0, fmaxf(v0, v1));
            }
            {
                int la = min(max(r1 - c + 512, 0), LPOS - 1);
                int lb = min(max(r1 - c + 511, 0), LPOS - 1);
                float v2 = (sfr[nb][2] + __bfloat162float(ck1[la])
                            + __bfloat162float(sCQ[cl * CQ_W + (la - Lb)])) * SCALE;
                float v3 = (sfr[nb][3] + __bfloat162float(ck1[lb])
                            + __bfloat162float(sCQ[(cl + 1) * CQ_W + (lb - Lb)])) * SCALE;
                if (!(m1v && mc0)) v2 = NEGMAX;
                if (!(m1v && mc1)) v3 = NEGMAX;
                sfr[nb][2] = v2; sfr[nb][3] = v3;
                tmx1 = fmaxf(tmx1, fmaxf(v2, v3));
            }
        }
        tmx0 = fmaxf(tmx0, __shfl_xor_sync(0xffffffffu, tmx0, 1));
        tmx0 = fmaxf(tmx0, __shfl_xor_sync(0xffffffffu, tmx0, 2));
        tmx1 = fmaxf(tmx1, __shfl_xor_sync(0xffffffffu, tmx1, 1));
        tmx1 = fmaxf(tmx1, __shfl_xor_sync(0xffffffffu, tmx1, 2));

        // ---- online softmax update ----
        const float mn0 = fmaxf(m0, tmx0), mn1 = fmaxf(m1, tmx1);
        const float sc0 = __expf(m0 - mn0), sc1 = __expf(m1 - mn1);
        m0 = mn0; m1 = mn1;
        float rs0 = 0.f, rs1 = 0.f;
        #pragma unroll
        for (int nb = 0; nb < 8; nb++) {
            sfr[nb][0] = __expf(sfr[nb][0] - mn0);
            sfr[nb][1] = __expf(sfr[nb][1] - mn0);
            sfr[nb][2] = __expf(sfr[nb][2] - mn1);
            sfr[nb][3] = __expf(sfr[nb][3] - mn1);
            rs0 += sfr[nb][0] + sfr[nb][1];
            rs1 += sfr[nb][2] + sfr[nb][3];
        }
        rs0 += __shfl_xor_sync(0xffffffffu, rs0, 1);
        rs0 += __shfl_xor_sync(0xffffffffu, rs0, 2);
        rs1 += __shfl_xor_sync(0xffffffffu, rs1, 1);
        rs1 += __shfl_xor_sync(0xffffffffu, rs1, 2);
        l0 = l0 * sc0 + rs0;
        l1 = l1 * sc1 + rs1;
        #pragma unroll
        for (int df = 0; df < 8; df++) {
            O[df][0] *= sc0; O[df][1] *= sc0;
            O[df][2] *= sc1; O[df][3] *= sc1;
        }

        // ---- P (bf16 A-frags) @ V ----
        #pragma unroll
        for (int kk2 = 0; kk2 < 4; kk2++) {
            uint32_t pf[4];
            pf[0] = packbf2(sfr[2 * kk2][0],     sfr[2 * kk2][1]);
            pf[1] = packbf2(sfr[2 * kk2][2],     sfr[2 * kk2][3]);
            pf[2] = packbf2(sfr[2 * kk2 + 1][0], sfr[2 * kk2 + 1][1]);
            pf[3] = packbf2(sfr[2 * kk2 + 1][2], sfr[2 * kk2 + 1][3]);
            #pragma unroll
            for (int dg = 0; dg < 4; dg++) {
                uint32_t r4[4];
                int n   = dg * 16 + ((lane >> 4) << 3) + (lane & 7);
                int c16 = kk2 * 2 + ((lane >> 3) & 1);
                ldsm4(r4, uv + swz128(n, c16));
                mma16816(O[2 * dg],     pf, r4);
                mma16816(O[2 * dg + 1], pf, r4 + 2);
            }
        }
        __syncthreads();
    }

    // ---- normalize + write ctx (bf16) ----
    const float inv0 = 1.0f / l0, inv1 = 1.0f / l1;
    bf16* o0 = CTX + (long)r0 * H + h * D + (lane & 3) * 2;
    bf16* o1 = CTX + (long)r1 * H + h * D + (lane & 3) * 2;
    #pragma unroll
    for (int df = 0; df < 8; df++) {
        *(__nv_bfloat162*)(o0 + df * 8) =
            __float22bfloat162_rn(make_float2(O[df][0] * inv0, O[df][1] * inv0));
        *(__nv_bfloat162*)(o1 + df * 8) =
            __float22bfloat162_rn(make_float2(O[df][2] * inv1, O[df][3] * inv1));
    }
}

// ---------------------------------------------------------------------------
// fp32 -> bf16 elementwise
__global__ void cvt_bf16(const float* __restrict__ x, bf16* __restrict__ y, int n)
{
    int i = blockIdx.x * 256 + threadIdx.x;
    if (i < n) y[i] = __float2bfloat16(x[i]);
}

// All six weight transposes in one launch: Wt[z][n*H + k] = W[z][k*H + n]
struct P6 { const float* p[6]; };
__global__ void wtrans6(P6 srcs, bf16* __restrict__ Wt)
{
    __shared__ float t[32][33];
    const float* W = srcs.p[blockIdx.z];
    bf16* dst = Wt + (size_t)blockIdx.z * H * H;
    const int bx = blockIdx.x * 32, by = blockIdx.y * 32;
    #pragma unroll
    for (int i = threadIdx.y; i < 32; i += 8)
        t[i][threadIdx.x] = W[(long)(by + i) * H + bx + threadIdx.x];
    __syncthreads();
    #pragma unroll
    for (int i = threadIdx.y; i < 32; i += 8)
        dst[(long)(bx + i) * H + by + threadIdx.x] = __float2bfloat16(t[threadIdx.x][i]);
}

// ---------------------------------------------------------------------------
// LayerNorm over H=768, one block (256 threads) per row.
__global__ void ln_kernel(const float* __restrict__ x,
                          const float* __restrict__ gamma,
                          const float* __restrict__ beta,
                          float* __restrict__ out)
{
    __shared__ float rs[8], rq[8];
    const int s = blockIdx.x, tid = threadIdx.x;
    const float* row = x + (long)s * H;
    float a0 = row[tid], a1 = row[tid + 256], a2 = row[tid + 512];
    float sum = a0 + a1 + a2;
    float sq  = a0 * a0 + a1 * a1 + a2 * a2;
    #pragma unroll
    for (int o = 16; o > 0; o >>= 1) {
        sum += __shfl_xor_sync(0xffffffffu, sum, o);
        sq  += __shfl_xor_sync(0xffffffffu, sq,  o);
    }
    if ((tid & 31) == 0) { rs[tid >> 5] = sum; rq[tid >> 5] = sq; }
    __syncthreads();
    float ts = 0.f, tq = 0.f;
    #pragma unroll
    for (int w = 0; w < 8; w++) { ts += rs[w]; tq += rq[w]; }
    float mean = ts * (1.0f / H);
    float var  = tq * (1.0f / H) - mean * mean;
    float inv  = rsqrtf(var + 1e-7f);
    float* o = out + (long)s * H;
    o[tid]       = (a0 - mean) * inv * gamma[tid]       + beta[tid];
    o[tid + 256] = (a1 - mean) * inv * gamma[tid + 256] + beta[tid + 256];
    o[tid + 512] = (a2 - mean) * inv * gamma[tid + 512] + beta[tid + 512];
}

// ---------------------------------------------------------------------------
extern "C" void kernel_launch(void* const* d_in, const int* in_sizes, int n_in,
                              void* d_out, int out_size)
{
    const float* hidden = (const float*)d_in[0];
    const int*   mask   = (const int*)  d_in[1];
    const float* Wq     = (const float*)d_in[2];
    const float* bq     = (const float*)d_in[3];
    const float* Wk     = (const float*)d_in[4];
    const float* bk     = (const float*)d_in[5];
    const float* Wv     = (const float*)d_in[6];
    const float* bv     = (const float*)d_in[7];
    const float* rel    = (const float*)d_in[8];
    const float* Wpk    = (const float*)d_in[9];
    const float* Wpq    = (const float*)d_in[10];
    const float* bpq    = (const float*)d_in[11];
    const float* Wo     = (const float*)d_in[12];
    const float* bo     = (const float*)d_in[13];
    const float* gamma  = (const float*)d_in[14];
    const float* beta   = (const float*)d_in[15];
    float* out = (float*)d_out;

    bf16 *hbf, *relbf, *Wt, *Qbf, *Kbf, *Vt, *PKbf, *PQbf, *CKb, *CQb, *CTXbf;
    float *TMP;
    cudaGetSymbolAddress((void**)&hbf,   g_hbf);
    cudaGetSymbolAddress((void**)&relbf, g_relbf);
    cudaGetSymbolAddress((void**)&Wt,    g_Wt);
    cudaGetSymbolAddress((void**)&Qbf,   g_Qbf);
    cudaGetSymbolAddress((void**)&Kbf,   g_Kbf);
    cudaGetSymbolAddress((void**)&Vt,    g_Vt);
    cudaGetSymbolAddress((void**)&PKbf,  g_PKbf);
    cudaGetSymbolAddress((void**)&PQbf,  g_PQbf);
    cudaGetSymbolAddress((void**)&CKb,   g_CKb);
    cudaGetSymbolAddress((void**)&CQb,   g_CQb);
    cudaGetSymbolAddress((void**)&CTXbf, g_CTXbf);
    cudaGetSymbolAddress((void**)&TMP,   g_TMP);

    static bool attr_done = false;
    if (!attr_done) {
        cudaFuncSetAttribute(flash_attn,
                             cudaFuncAttributeMaxDynamicSharedMemorySize, FL_SMEM);
        attr_done = true;
    }

    // --- conversions / transposes ---
    cvt_bf16<<<(S * H + 255) / 256, 256>>>(hidden, hbf, S * H);
    cvt_bf16<<<(LPOS * H + 255) / 256, 256>>>(rel, relbf, LPOS * H);
    P6 w6; w6.p[0] = Wq; w6.p[1] = Wk; w6.p[2] = Wv;
    w6.p[3] = Wpk; w6.p[4] = Wpq; w6.p[5] = Wo;
    wtrans6<<<dim3(H/32, H/32, 6), dim3(32, 8)>>>(w6, Wt);

    // --- projections (C = A @ Wt^T) ---
    gemm_mma<M_BIAS_BF16><<<dim3(6, 16, 1), 256>>>(
        hbf, H, 0, Wt + 0 * H * H, H, 0, H,
        nullptr, Qbf, H, 0, bq, nullptr);
    gemm_mma<M_BIAS_BF16><<<dim3(6, 16, 1), 256>>>(
        hbf, H, 0, Wt + 1 * H * H, H, 0, H,
        nullptr, Kbf, H, 0, bk, nullptr);
    gemm_mma<M_VT><<<dim3(6, 16, 1), 256>>>(
        hbf, H, 0, Wt + 2 * H * H, H, 0, H,
        nullptr, Vt, 0, 0, bv, nullptr);
    gemm_mma<M_BIAS_BF16><<<dim3(6, 8, 1), 256>>>(
        relbf, H, 0, Wt + 3 * H * H, H, 0, H,
        nullptr, PKbf, H, 0, nullptr, nullptr);
    gemm_mma<M_BIAS_BF16><<<dim3(6, 8, 1), 256>>>(
        relbf, H, 0, Wt + 4 * H * H, H, 0, H,
        nullptr, PQbf, H, 0, bpq, nullptr);

    // --- rel-position tables (bf16): CK = Q_h @ PK_h^T, CQ = K_h @ PQ_h^T ---
    gemm_mma<M_BF16><<<dim3(LPOS/128, S/128, NH), 256>>>(
        Qbf, H, D, PKbf, H, D, D,
        nullptr, CKb, LPOS, (long)S * LPOS, nullptr, nullptr);
    gemm_mma<M_BF16><<<dim3(LPOS/128, S/128, NH), 256>>>(
        Kbf, H, D, PQbf, H, D, D,
        nullptr, CQb, LPOS, (long)S * LPOS, nullptr, nullptr);

    // --- fused attention: scores + bias + mask + softmax + P@V ---
    flash_attn<<<dim3(S/128, NH), 256, FL_SMEM>>>(
        Qbf, Kbf, Vt, CKb, CQb, mask, CTXbf);

    // --- output projection + bias + residual ---
    gemm_mma<M_OUT><<<dim3(6, 16, 1), 256>>>(
        CTXbf, H, 0, Wt + 5 * H * H, H, 0, H,
        TMP, nullptr, H, 0, bo, hidden);

    // --- layernorm ---
    ln_kernel<<<S, 256>>>(TMP, gamma, beta, out);
}

// round 6
// speedup vs baseline: 8.9113x; 1.1372x over previous
#include <cuda_runtime.h>
#include <cuda_bf16.h>
#include <cstdint>

// ---------------------------------------------------------------------------
// BertAttention (DeBERTa) — round 6: consolidated launches (1 proj, 1 tables).
// B=1, S=2048, H=768, NH=12, D=64, SPAN=512
// ---------------------------------------------------------------------------

constexpr int S    = 2048;
constexpr int H    = 768;
constexpr int NH   = 12;
constexpr int D    = 64;
constexpr int LPOS = 1024;  // 2*SPAN
constexpr float SCALE  = 0.07216878364870322f;  // 1/sqrt(64*3)
constexpr float NEGMAX = -3.402823466e38f;

using bf16 = __nv_bfloat16;

// ---------------------------- scratch (device globals) ---------------------
__device__ bf16  g_hbf  [S * H];
__device__ bf16  g_relbf[LPOS * H];
__device__ bf16  g_Wt   [6 * H * H];     // transposed bf16 weights [N,K]
__device__ bf16  g_Qbf  [S * H];
__device__ bf16  g_Kbf  [S * H];
__device__ bf16  g_Vt   [H * S];         // V transposed: [h*D+d][token]
__device__ bf16  g_PKbf [LPOS * H];
__device__ bf16  g_PQbf [LPOS * H];
__device__ bf16  g_CKb  [(size_t)NH * S * LPOS];        // bf16 c2p table
__device__ bf16  g_CQb  [(size_t)NH * S * LPOS + 256];  // bf16 p2c table (+pad)
__device__ bf16  g_CTXbf[S * H];
__device__ float g_TMP  [S * H];

// ---------------------------- PTX helpers ----------------------------------
__device__ __forceinline__ uint32_t smem_u32(const void* p) {
    uint32_t a;
    asm("{ .reg .u64 t; cvta.to.shared.u64 t, %1; cvt.u32.u64 %0, t; }"
        : "=r"(a) : "l"(p));
    return a;
}
__device__ __forceinline__ void cpasync16(uint32_t dst, const void* src) {
    asm volatile("cp.async.cg.shared.global [%0], [%1], 16;" :: "r"(dst), "l"(src));
}
#define CP_COMMIT() asm volatile("cp.async.commit_group;" ::: "memory")
#define CP_WAIT1()  asm volatile("cp.async.wait_group 1;" ::: "memory")
#define CP_WAIT0()  asm volatile("cp.async.wait_group 0;" ::: "memory")

__device__ __forceinline__ void ldsm4(uint32_t* r, uint32_t addr) {
    asm volatile("ldmatrix.sync.aligned.m8n8.x4.shared.b16 {%0,%1,%2,%3}, [%4];"
                 : "=r"(r[0]), "=r"(r[1]), "=r"(r[2]), "=r"(r[3]) : "r"(addr));
}
__device__ __forceinline__ void mma16816(float* c, const uint32_t* a, const uint32_t* b) {
    asm volatile(
        "mma.sync.aligned.m16n8k16.row.col.f32.bf16.bf16.f32 "
        "{%0,%1,%2,%3}, {%4,%5,%6,%7}, {%8,%9}, {%0,%1,%2,%3};"
        : "+f"(c[0]), "+f"(c[1]), "+f"(c[2]), "+f"(c[3])
        : "r"(a[0]), "r"(a[1]), "r"(a[2]), "r"(a[3]), "r"(b[0]), "r"(b[1]));
}
__device__ __forceinline__ uint32_t packbf2(float a, float b) {
    __nv_bfloat162 t = __float22bfloat162_rn(make_float2(a, b));
    return *(uint32_t*)&t;
}

// 64-byte rows (32 bf16): generic GEMM tiles
__device__ __forceinline__ uint32_t swz(int row, int chunk) {
    return (uint32_t)(row * 64 + ((chunk ^ ((row >> 1) & 3)) << 4));
}
// 128-byte rows (64 bf16): flash tiles
__device__ __forceinline__ uint32_t swz128(int row, int c16) {
    return (uint32_t)(row * 128 + ((c16 ^ (row & 7)) << 4));
}

// ---------------------------------------------------------------------------
// Shared GEMM mainloop (128x128 tile, K-major bf16, NT): accumulates into acc.
// ---------------------------------------------------------------------------
struct SmemPtrs { uint32_t uA, uB; };

template<typename LoadFn>
__device__ __forceinline__ void gemm_core(
    int nch, SmemPtrs sp, int tid, int lane, int wm, int wn,
    float (&acc)[4][4][4], LoadFn load_tiles)
{
    constexpr int ABYTES = 128 * 32 * 2;
    constexpr int BBYTES = 128 * 32 * 2;
    load_tiles(0, 0);
    CP_COMMIT();
    for (int ch = 0; ch < nch; ch++) {
        const int st = ch & 1;
        if (ch + 1 < nch) { load_tiles(ch + 1, st ^ 1); CP_COMMIT(); CP_WAIT1(); }
        else              { CP_WAIT0(); }
        __syncthreads();
        const uint32_t bA = sp.uA + st * ABYTES;
        const uint32_t bB = sp.uB + st * BBYTES;
        #pragma unroll
        for (int kk = 0; kk < 2; kk++) {
            uint32_t afr[4][4];
            #pragma unroll
            for (int i = 0; i < 4; i++) {
                int row = wm * 64 + i * 16 + (lane & 15);
                int chk = kk * 2 + (lane >> 4);
                ldsm4(afr[i], bA + swz(row, chk));
            }
            uint32_t bfr[4][2];
            #pragma unroll
            for (int p = 0; p < 2; p++) {
                uint32_t r4[4];
                int n   = wn * 32 + p * 16 + ((lane >> 4) << 3) + (lane & 7);
                int chk = kk * 2 + ((lane >> 3) & 1);
                ldsm4(r4, bB + swz(n, chk));
                bfr[2 * p][0] = r4[0]; bfr[2 * p][1] = r4[1];
                bfr[2 * p + 1][0] = r4[2]; bfr[2 * p + 1][1] = r4[3];
            }
            #pragma unroll
            for (int i = 0; i < 4; i++)
                #pragma unroll
                for (int j = 0; j < 4; j++)
                    mma16816(acc[i][j], afr[i], bfr[j]);
        }
        __syncthreads();
    }
}

// ---------------------------------------------------------------------------
// Fused projection kernel: 5 jobs (Q, K, V->Vt, PK, PQ) in one 1-D grid.
// ---------------------------------------------------------------------------
struct ProjJobs {
    const bf16* A[5];
    const bf16* Bw[5];
    bf16*       C[5];
    const float* bias[5];
    int mode[5];     // 0 = bias+bf16 row-major (ldc=H), 1 = VT transposed store
    int start[6];    // prefix CTA offsets
};

__global__ void __launch_bounds__(256) gemm_proj(ProjJobs J)
{
    constexpr int ABYTES = 128 * 32 * 2, BBYTES = 128 * 32 * 2;
    __shared__ __align__(1024) char sm[2 * (ABYTES + BBYTES)];
    SmemPtrs sp { smem_u32(sm), smem_u32(sm) + 2 * ABYTES };

    int bx = blockIdx.x;
    int j = 0;
    while (bx >= J.start[j + 1]) j++;
    const int local = bx - J.start[j];
    const int bm = (local / 6) * 128, bn = (local % 6) * 128;

    const int tid = threadIdx.x, lane = tid & 31, wid = tid >> 5;
    const int wm = wid & 1, wn = wid >> 1;

    const bf16* Arow = J.A[j] + (long)bm * H;
    const bf16* Brow = J.Bw[j] + (long)bn * H;

    auto load_tiles = [&](int ch, int st) {
        const bf16* Ak = Arow + ch * 32;
        #pragma unroll
        for (int i = tid; i < 512; i += 256) {
            int r = i >> 2, c = i & 3;
            cpasync16(sp.uA + st * ABYTES + swz(r, c), Ak + (long)r * H + c * 8);
        }
        const bf16* Bk = Brow + ch * 32;
        #pragma unroll
        for (int i = tid; i < 512; i += 256) {
            int r = i >> 2, c = i & 3;
            cpasync16(sp.uB + st * BBYTES + swz(r, c), Bk + (long)r * H + c * 8);
        }
    };

    float acc[4][4][4] = {};
    gemm_core(H / 32, sp, tid, lane, wm, wn, acc, load_tiles);

    bf16* C = J.C[j];
    const float* bias = J.bias[j];
    const int mode = J.mode[j];

    #pragma unroll
    for (int i = 0; i < 4; i++)
        #pragma unroll
        for (int jj = 0; jj < 4; jj++)
            #pragma unroll
            for (int half = 0; half < 2; half++) {
                const int r = bm + wm * 64 + i * 16 + (lane >> 2) + half * 8;
                const int c = bn + wn * 32 + jj * 8 + (lane & 3) * 2;
                const float v0 = acc[i][jj][half * 2];
                const float v1 = acc[i][jj][half * 2 + 1];
                float b0 = bias ? bias[c] : 0.f, b1 = bias ? bias[c + 1] : 0.f;
                if (mode == 0) {
                    *(__nv_bfloat162*)(C + (long)r * H + c) =
                        __float22bfloat162_rn(make_float2(v0 + b0, v1 + b1));
                } else {
                    C[(long)c * S + r]       = __float2bfloat16(v0 + b0);
                    C[(long)(c + 1) * S + r] = __float2bfloat16(v1 + b1);
                }
            }
}

// ---------------------------------------------------------------------------
// Fused tables kernel: z<NH -> CK = Q_h @ PK_h^T ; else CQ = K_h @ PQ_h^T.
// ---------------------------------------------------------------------------
__global__ void __launch_bounds__(256) gemm_tables(
    const bf16* __restrict__ Qb, const bf16* __restrict__ Kb,
    const bf16* __restrict__ PK, const bf16* __restrict__ PQ,
    bf16* __restrict__ CK, bf16* __restrict__ CQ)
{
    constexpr int ABYTES = 128 * 32 * 2, BBYTES = 128 * 32 * 2;
    __shared__ __align__(1024) char sm[2 * (ABYTES + BBYTES)];
    SmemPtrs sp { smem_u32(sm), smem_u32(sm) + 2 * ABYTES };

    const int z = blockIdx.z;
    const bool isCK = z < NH;
    const int h = isCK ? z : z - NH;
    const bf16* A = (isCK ? Qb : Kb) + h * D;
    const bf16* B = (isCK ? PK : PQ) + h * D;
    bf16* C = (isCK ? CK : CQ) + (size_t)h * S * LPOS;

    const int tid = threadIdx.x, lane = tid & 31, wid = tid >> 5;
    const int wm = wid & 1, wn = wid >> 1;
    const int bm = blockIdx.y * 128, bn = blockIdx.x * 128;

    const bf16* Arow = A + (long)bm * H;
    const bf16* Brow = B + (long)bn * H;

    auto load_tiles = [&](int ch, int st) {
        const bf16* Ak = Arow + ch * 32;
        #pragma unroll
        for (int i = tid; i < 512; i += 256) {
            int r = i >> 2, c = i & 3;
            cpasync16(sp.uA + st * ABYTES + swz(r, c), Ak + (long)r * H + c * 8);
        }
        const bf16* Bk = Brow + ch * 32;
        #pragma unroll
        for (int i = tid; i < 512; i += 256) {
            int r = i >> 2, c = i & 3;
            cpasync16(sp.uB + st * BBYTES + swz(r, c), Bk + (long)r * H + c * 8);
        }
    };

    float acc[4][4][4] = {};
    gemm_core(D / 32, sp, tid, lane, wm, wn, acc, load_tiles);

    #pragma unroll
    for (int i = 0; i < 4; i++)
        #pragma unroll
        for (int jj = 0; jj < 4; jj++)
            #pragma unroll
            for (int half = 0; half < 2; half++) {
                const int r = bm + wm * 64 + i * 16 + (lane >> 2) + half * 8;
                const int c = bn + wn * 32 + jj * 8 + (lane & 3) * 2;
                *(__nv_bfloat162*)(C + (long)r * LPOS + c) =
                    __float22bfloat162_rn(make_float2(acc[i][jj][half * 2],
                                                      acc[i][jj][half * 2 + 1]));
            }
}

// ---------------------------------------------------------------------------
// Output projection + bias + residual (single job, fp32 out).
// ---------------------------------------------------------------------------
__global__ void __launch_bounds__(256) gemm_out(
    const bf16* __restrict__ A, const bf16* __restrict__ Bw,
    float* __restrict__ C, const float* __restrict__ bias,
    const float* __restrict__ res)
{
    constexpr int ABYTES = 128 * 32 * 2, BBYTES = 128 * 32 * 2;
    __shared__ __align__(1024) char sm[2 * (ABYTES + BBYTES)];
    SmemPtrs sp { smem_u32(sm), smem_u32(sm) + 2 * ABYTES };

    const int tid = threadIdx.x, lane = tid & 31, wid = tid >> 5;
    const int wm = wid & 1, wn = wid >> 1;
    const int bm = blockIdx.y * 128, bn = blockIdx.x * 128;

    const bf16* Arow = A + (long)bm * H;
    const bf16* Brow = Bw + (long)bn * H;

    auto load_tiles = [&](int ch, int st) {
        const bf16* Ak = Arow + ch * 32;
        #pragma unroll
        for (int i = tid; i < 512; i += 256) {
            int r = i >> 2, c = i & 3;
            cpasync16(sp.uA + st * ABYTES + swz(r, c), Ak + (long)r * H + c * 8);
        }
        const bf16* Bk = Brow + ch * 32;
        #pragma unroll
        for (int i = tid; i < 512; i += 256) {
            int r = i >> 2, c = i & 3;
            cpasync16(sp.uB + st * BBYTES + swz(r, c), Bk + (long)r * H + c * 8);
        }
    };

    float acc[4][4][4] = {};
    gemm_core(H / 32, sp, tid, lane, wm, wn, acc, load_tiles);

    #pragma unroll
    for (int i = 0; i < 4; i++)
        #pragma unroll
        for (int jj = 0; jj < 4; jj++)
            #pragma unroll
            for (int half = 0; half < 2; half++) {
                const int r = bm + wm * 64 + i * 16 + (lane >> 2) + half * 8;
                const int c = bn + wn * 32 + jj * 8 + (lane & 3) * 2;
                const float* rr = res + (long)r * H;
                *(float2*)(C + (long)r * H + c) =
                    make_float2(acc[i][jj][half * 2] + bias[c] + rr[c],
                                acc[i][jj][half * 2 + 1] + bias[c + 1] + rr[c + 1]);
            }
}

// ---------------------------------------------------------------------------
// Flash-fused attention with smem-staged cq band (unchanged from R5).
// ---------------------------------------------------------------------------
constexpr int CQ_W     = 208;
constexpr int CQ_ROWB  = CQ_W * 2;
constexpr int CQ_BYTES = 64 * CQ_ROWB;
constexpr int FL_SMEM  = 16384 + 2 * 8192 + 2 * 8192 + 2 * CQ_BYTES;  // 102400

__global__ void __launch_bounds__(256) flash_attn(
    const bf16* __restrict__ Q, const bf16* __restrict__ K,
    const bf16* __restrict__ Vt,
    const bf16* __restrict__ CKb, const bf16* __restrict__ CQb,
    const int* __restrict__ mask, bf16* __restrict__ CTX)
{
    constexpr int NTILE = S / 64;  // 32
    extern __shared__ __align__(1024) char dyn[];
    const uint32_t uQ  = smem_u32(dyn);
    const uint32_t uK  = uQ + 16384;
    const uint32_t uV  = uK + 16384;
    const uint32_t uCQ = uV + 16384;

    const int tid = threadIdx.x, lane = tid & 31, wid = tid >> 5;
    const int h = blockIdx.y, bm = blockIdx.x * 128;

    auto lbase_of = [&](int ct) {
        int lo = bm - ct * 64 + 449;
        return min(max(lo, 0), 816) & ~7;
    };

    {
        const bf16* Qg = Q + (long)bm * H + h * D;
        #pragma unroll
        for (int i = tid; i < 1024; i += 256) {
            int r = i >> 3, c = i & 7;
            cpasync16(uQ + swz128(r, c), Qg + (long)r * H + c * 8);
        }
    }
    CP_COMMIT();

    auto load_kv = [&](int ct, int st) {
        const int c0 = ct * 64;
        const uint32_t uk = uK + st * 8192;
        const uint32_t uv = uV + st * 8192;
        const bf16* Kg = K + (long)c0 * H + h * D;
        #pragma unroll
        for (int i = tid; i < 512; i += 256) {
            int r = i >> 3, c = i & 7;
            cpasync16(uk + swz128(r, c), Kg + (long)r * H + c * 8);
        }
        const bf16* Vg = Vt + (long)(h * D) * S + c0;
        #pragma unroll
        for (int i = tid; i < 512; i += 256) {
            int d = i >> 3, c = i & 7;
            cpasync16(uv + swz128(d, c), Vg + (long)d * S + c * 8);
        }
        const int Lb = lbase_of(ct);
        const uint32_t ucq = uCQ + st * CQ_BYTES;
        const bf16* CQg = CQb + ((size_t)h * S + c0) * LPOS + Lb;
        #pragma unroll
        for (int i = tid; i < 64 * 26; i += 256) {
            int r = i / 26, ch = i % 26;
            cpasync16(ucq + r * CQ_ROWB + ch * 16, CQg + (size_t)r * LPOS + ch * 8);
        }
    };
    load_kv(0, 0);
    CP_COMMIT();
    CP_WAIT1();
    __syncthreads();

    uint32_t qf[4][4];
    #pragma unroll
    for (int kk = 0; kk < 4; kk++) {
        int row = wid * 16 + (lane & 15);
        int c16 = kk * 2 + (lane >> 4);
        ldsm4(qf[kk], uQ + swz128(row, c16));
    }

    const int r0 = bm + wid * 16 + (lane >> 2);
    const int r1 = r0 + 8;
    const int m0v = mask[r0], m1v = mask[r1];
    const bf16* ck0 = CKb + ((size_t)h * S + r0) * LPOS;
    const bf16* ck1 = CKb + ((size_t)h * S + r1) * LPOS;

    float m0 = NEGMAX, m1 = NEGMAX, l0 = 0.f, l1 = 0.f;
    float O[8][4] = {};

    for (int ct = 0; ct < NTILE; ct++) {
        const int st = ct & 1;
        if (ct + 1 < NTILE) { load_kv(ct + 1, st ^ 1); CP_COMMIT(); CP_WAIT1(); }
        else                { CP_WAIT0(); }
        __syncthreads();

        const uint32_t uk = uK + st * 8192;
        const uint32_t uv = uV + st * 8192;
        const bf16* sCQ = (const bf16*)(dyn + (uCQ - uQ) + st * CQ_BYTES);
        const int Lb = lbase_of(ct);

        float sfr[8][4] = {};
        #pragma unroll
        for (int g = 0; g < 4; g++) {
            #pragma unroll
            for (int kk = 0; kk < 4; kk++) {
                uint32_t r4[4];
                int n   = g * 16 + ((lane >> 4) << 3) + (lane & 7);
                int c16 = kk * 2 + ((lane >> 3) & 1);
                ldsm4(r4, uk + swz128(n, c16));
                mma16816(sfr[2 * g],     qf[kk], r4);
                mma16816(sfr[2 * g + 1], qf[kk], r4 + 2);
            }
        }

        const int c0 = ct * 64;
        float tmx0 = NEGMAX, tmx1 = NEGMAX;
        #pragma unroll
        for (int nb = 0; nb < 8; nb++) {
            const int cl = nb * 8 + (lane & 3) * 2;
            const int c  = c0 + cl;
            const int mc0 = mask[c], mc1 = mask[c + 1];
            {
                int la = min(max(r0 - c + 512, 0), LPOS - 1);
                int lb = min(max(r0 - c + 511, 0), LPOS - 1);
                float v0 = (sfr[nb][0] + __bfloat162float(ck0[la])
                            + __bfloat162float(sCQ[cl * CQ_W + (la - Lb)])) * SCALE;
                float v1 = (sfr[nb][1] + __bfloat162float(ck0[lb])
                            + __bfloat162float(sCQ[(cl + 1) * CQ_W + (lb - Lb)])) * SCALE;
                if (!(m0v && mc0)) v0 = NEGMAX;
                if (!(m0v && mc1)) v1 = NEGMAX;
                sfr[nb][0] = v0; sfr[nb][1] = v1;
                tmx0 = fmaxf(tmx0, fmaxf(v0, v1));
            }
            {
                int la = min(max(r1 - c + 512, 0), LPOS - 1);
                int lb = min(max(r1 - c + 511, 0), LPOS - 1);
                float v2 = (sfr[nb][2] + __bfloat162float(ck1[la])
                            + __bfloat162float(sCQ[cl * CQ_W + (la - Lb)])) * SCALE;
                float v3 = (sfr[nb][3] + __bfloat162float(ck1[lb])
                            + __bfloat162float(sCQ[(cl + 1) * CQ_W + (lb - Lb)])) * SCALE;
                if (!(m1v && mc0)) v2 = NEGMAX;
                if (!(m1v && mc1)) v3 = NEGMAX;
                sfr[nb][2] = v2; sfr[nb][3] = v3;
                tmx1 = fmaxf(tmx1, fmaxf(v2, v3));
            }
        }
        tmx0 = fmaxf(tmx0, __shfl_xor_sync(0xffffffffu, tmx0, 1));
        tmx0 = fmaxf(tmx0, __shfl_xor_sync(0xffffffffu, tmx0, 2));
        tmx1 = fmaxf(tmx1, __shfl_xor_sync(0xffffffffu, tmx1, 1));
        tmx1 = fmaxf(tmx1, __shfl_xor_sync(0xffffffffu, tmx1, 2));

        const float mn0 = fmaxf(m0, tmx0), mn1 = fmaxf(m1, tmx1);
        const float sc0 = __expf(m0 - mn0), sc1 = __expf(m1 - mn1);
        m0 = mn0; m1 = mn1;
        float rs0 = 0.f, rs1 = 0.f;
        #pragma unroll
        for (int nb = 0; nb < 8; nb++) {
            sfr[nb][0] = __expf(sfr[nb][0] - mn0);
            sfr[nb][1] = __expf(sfr[nb][1] - mn0);
            sfr[nb][2] = __expf(sfr[nb][2] - mn1);
            sfr[nb][3] = __expf(sfr[nb][3] - mn1);
            rs0 += sfr[nb][0] + sfr[nb][1];
            rs1 += sfr[nb][2] + sfr[nb][3];
        }
        rs0 += __shfl_xor_sync(0xffffffffu, rs0, 1);
        rs0 += __shfl_xor_sync(0xffffffffu, rs0, 2);
        rs1 += __shfl_xor_sync(0xffffffffu, rs1, 1);
        rs1 += __shfl_xor_sync(0xffffffffu, rs1, 2);
        l0 = l0 * sc0 + rs0;
        l1 = l1 * sc1 + rs1;
        #pragma unroll
        for (int df = 0; df < 8; df++) {
            O[df][0] *= sc0; O[df][1] *= sc0;
            O[df][2] *= sc1; O[df][3] *= sc1;
        }

        #pragma unroll
        for (int kk2 = 0; kk2 < 4; kk2++) {
            uint32_t pf[4];
            pf[0] = packbf2(sfr[2 * kk2][0],     sfr[2 * kk2][1]);
            pf[1] = packbf2(sfr[2 * kk2][2],     sfr[2 * kk2][3]);
            pf[2] = packbf2(sfr[2 * kk2 + 1][0], sfr[2 * kk2 + 1][1]);
            pf[3] = packbf2(sfr[2 * kk2 + 1][2], sfr[2 * kk2 + 1][3]);
            #pragma unroll
            for (int dg = 0; dg < 4; dg++) {
                uint32_t r4[4];
                int n   = dg * 16 + ((lane >> 4) << 3) + (lane & 7);
                int c16 = kk2 * 2 + ((lane >> 3) & 1);
                ldsm4(r4, uv + swz128(n, c16));
                mma16816(O[2 * dg],     pf, r4);
                mma16816(O[2 * dg + 1], pf, r4 + 2);
            }
        }
        __syncthreads();
    }

    const float inv0 = 1.0f / l0, inv1 = 1.0f / l1;
    bf16* o0 = CTX + (long)r0 * H + h * D + (lane & 3) * 2;
    bf16* o1 = CTX + (long)r1 * H + h * D + (lane & 3) * 2;
    #pragma unroll
    for (int df = 0; df < 8; df++) {
        *(__nv_bfloat162*)(o0 + df * 8) =
            __float22bfloat162_rn(make_float2(O[df][0] * inv0, O[df][1] * inv0));
        *(__nv_bfloat162*)(o1 + df * 8) =
            __float22bfloat162_rn(make_float2(O[df][2] * inv1, O[df][3] * inv1));
    }
}

// ---------------------------------------------------------------------------
// fp32 -> bf16, both input tensors in one launch.
__global__ void cvt_bf16_2(const float* __restrict__ x0, bf16* __restrict__ y0, int n0,
                           const float* __restrict__ x1, bf16* __restrict__ y1, int n1)
{
    int i = blockIdx.x * 256 + threadIdx.x;
    if (i < n0) y0[i] = __float2bfloat16(x0[i]);
    else if (i < n0 + n1) y1[i - n0] = __float2bfloat16(x1[i - n0]);
}

// All six weight transposes in one launch.
struct P6 { const float* p[6]; };
__global__ void wtrans6(P6 srcs, bf16* __restrict__ Wt)
{
    __shared__ float t[32][33];
    const float* W = srcs.p[blockIdx.z];
    bf16* dst = Wt + (size_t)blockIdx.z * H * H;
    const int bx = blockIdx.x * 32, by = blockIdx.y * 32;
    #pragma unroll
    for (int i = threadIdx.y; i < 32; i += 8)
        t[i][threadIdx.x] = W[(long)(by + i) * H + bx + threadIdx.x];
    __syncthreads();
    #pragma unroll
    for (int i = threadIdx.y; i < 32; i += 8)
        dst[(long)(bx + i) * H + by + threadIdx.x] = __float2bfloat16(t[threadIdx.x][i]);
}

// ---------------------------------------------------------------------------
// LayerNorm over H=768, one block (256 threads) per row.
__global__ void ln_kernel(const float* __restrict__ x,
                          const float* __restrict__ gamma,
                          const float* __restrict__ beta,
                          float* __restrict__ out)
{
    __shared__ float rs[8], rq[8];
    const int s = blockIdx.x, tid = threadIdx.x;
    const float* row = x + (long)s * H;
    float a0 = row[tid], a1 = row[tid + 256], a2 = row[tid + 512];
    float sum = a0 + a1 + a2;
    float sq  = a0 * a0 + a1 * a1 + a2 * a2;
    #pragma unroll
    for (int o = 16; o > 0; o >>= 1) {
        sum += __shfl_xor_sync(0xffffffffu, sum, o);
        sq  += __shfl_xor_sync(0xffffffffu, sq,  o);
    }
    if ((tid & 31) == 0) { rs[tid >> 5] = sum; rq[tid >> 5] = sq; }
    __syncthreads();
    float ts = 0.f, tq = 0.f;
    #pragma unroll
    for (int w = 0; w < 8; w++) { ts += rs[w]; tq += rq[w]; }
    float mean = ts * (1.0f / H);
    float var  = tq * (1.0f / H) - mean * mean;
    float inv  = rsqrtf(var + 1e-7f);
    float* o = out + (long)s * H;
    o[tid]       = (a0 - mean) * inv * gamma[tid]       + beta[tid];
    o[tid + 256] = (a1 - mean) * inv * gamma[tid + 256] + beta[tid + 256];
    o[tid + 512] = (a2 - mean) * inv * gamma[tid + 512] + beta[tid + 512];
}

// ---------------------------------------------------------------------------
extern "C" void kernel_launch(void* const* d_in, const int* in_sizes, int n_in,
                              void* d_out, int out_size)
{
    const float* hidden = (const float*)d_in[0];
    const int*   mask   = (const int*)  d_in[1];
    const float* Wq     = (const float*)d_in[2];
    const float* bq     = (const float*)d_in[3];
    const float* Wk     = (const float*)d_in[4];
    const float* bk     = (const float*)d_in[5];
    const float* Wv     = (const float*)d_in[6];
    const float* bv     = (const float*)d_in[7];
    const float* rel    = (const float*)d_in[8];
    const float* Wpk    = (const float*)d_in[9];
    const float* Wpq    = (const float*)d_in[10];
    const float* bpq    = (const float*)d_in[11];
    const float* Wo     = (const float*)d_in[12];
    const float* bo     = (const float*)d_in[13];
    const float* gamma  = (const float*)d_in[14];
    const float* beta   = (const float*)d_in[15];
    float* out = (float*)d_out;

    bf16 *hbf, *relbf, *Wt, *Qbf, *Kbf, *Vt, *PKbf, *PQbf, *CKb, *CQb, *CTXbf;
    float *TMP;
    cudaGetSymbolAddress((void**)&hbf,   g_hbf);
    cudaGetSymbolAddress((void**)&relbf, g_relbf);
    cudaGetSymbolAddress((void**)&Wt,    g_Wt);
    cudaGetSymbolAddress((void**)&Qbf,   g_Qbf);
    cudaGetSymbolAddress((void**)&Kbf,   g_Kbf);
    cudaGetSymbolAddress((void**)&Vt,    g_Vt);
    cudaGetSymbolAddress((void**)&PKbf,  g_PKbf);
    cudaGetSymbolAddress((void**)&PQbf,  g_PQbf);
    cudaGetSymbolAddress((void**)&CKb,   g_CKb);
    cudaGetSymbolAddress((void**)&CQb,   g_CQb);
    cudaGetSymbolAddress((void**)&CTXbf, g_CTXbf);
    cudaGetSymbolAddress((void**)&TMP,   g_TMP);

    static bool attr_done = false;
    if (!attr_done) {
        cudaFuncSetAttribute(flash_attn,
                             cudaFuncAttributeMaxDynamicSharedMemorySize, FL_SMEM);
        attr_done = true;
    }

    // --- conversions / transposes ---
    cvt_bf16_2<<<(S * H + LPOS * H + 255) / 256, 256>>>(
        hidden, hbf, S * H, rel, relbf, LPOS * H);
    P6 w6; w6.p[0] = Wq; w6.p[1] = Wk; w6.p[2] = Wv;
    w6.p[3] = Wpk; w6.p[4] = Wpq; w6.p[5] = Wo;
    wtrans6<<<dim3(H/32, H/32, 6), dim3(32, 8)>>>(w6, Wt);

    // --- all five projections in one launch ---
    ProjJobs J;
    J.A[0] = hbf;   J.Bw[0] = Wt + 0 * H * H; J.C[0] = Qbf;  J.bias[0] = bq;      J.mode[0] = 0;
    J.A[1] = hbf;   J.Bw[1] = Wt + 1 * H * H; J.C[1] = Kbf;  J.bias[1] = bk;      J.mode[1] = 0;
    J.A[2] = hbf;   J.Bw[2] = Wt + 2 * H * H; J.C[2] = Vt;   J.bias[2] = bv;      J.mode[2] = 1;
    J.A[3] = relbf; J.Bw[3] = Wt + 3 * H * H; J.C[3] = PKbf; J.bias[3] = nullptr; J.mode[3] = 0;
    J.A[4] = relbf; J.Bw[4] = Wt + 4 * H * H; J.C[4] = PQbf; J.bias[4] = bpq;     J.mode[4] = 0;
    J.start[0] = 0;   J.start[1] = 96;  J.start[2] = 192;
    J.start[3] = 288; J.start[4] = 336; J.start[5] = 384;
    gemm_proj<<<384, 256>>>(J);

    // --- both rel-position tables in one launch ---
    gemm_tables<<<dim3(LPOS/128, S/128, 2 * NH), 256>>>(
        Qbf, Kbf, PKbf, PQbf, CKb, CQb);

    // --- fused attention ---
    flash_attn<<<dim3(S/128, NH), 256, FL_SMEM>>>(
        Qbf, Kbf, Vt, CKb, CQb, mask, CTXbf);

    // --- output projection + bias + residual ---
    gemm_out<<<dim3(6, 16), 256>>>(CTXbf, Wt + 5 * H * H, TMP, bo, hidden);

    // --- layernorm ---
    ln_kernel<<<S, 256>>>(TMP, gamma, beta, out);
}

// round 7
// speedup vs baseline: 10.3546x; 1.1620x over previous
#include <cuda_runtime.h>
#include <cuda_bf16.h>
#include <cstdint>

// ---------------------------------------------------------------------------
// BertAttention (DeBERTa) — round 7: split-K flash + staged table stores.
// B=1, S=2048, H=768, NH=12, D=64, SPAN=512
// ---------------------------------------------------------------------------

constexpr int S    = 2048;
constexpr int H    = 768;
constexpr int NH   = 12;
constexpr int D    = 64;
constexpr int LPOS = 1024;  // 2*SPAN
constexpr float SCALE  = 0.07216878364870322f;  // 1/sqrt(64*3)
constexpr float NEGMAX = -3.402823466e38f;

using bf16 = __nv_bfloat16;

// ---------------------------- scratch (device globals) ---------------------
__device__ bf16   g_hbf  [S * H];
__device__ bf16   g_relbf[LPOS * H];
__device__ bf16   g_Wt   [6 * H * H];
__device__ bf16   g_Qbf  [S * H];
__device__ bf16   g_Kbf  [S * H];
__device__ bf16   g_Vt   [H * S];
__device__ bf16   g_PKbf [LPOS * H];
__device__ bf16   g_PQbf [LPOS * H];
__device__ bf16   g_CKb  [(size_t)NH * S * LPOS];
__device__ bf16   g_CQb  [(size_t)NH * S * LPOS + 256];
__device__ float  g_Opart[(size_t)2 * NH * S * D];   // unnormalized partial O
__device__ float2 g_ML   [2 * NH * S];               // (m, l) per half
__device__ bf16   g_CTXbf[S * H];
__device__ float  g_TMP  [S * H];

// ---------------------------- PTX helpers ----------------------------------
__device__ __forceinline__ uint32_t smem_u32(const void* p) {
    uint32_t a;
    asm("{ .reg .u64 t; cvta.to.shared.u64 t, %1; cvt.u32.u64 %0, t; }"
        : "=r"(a) : "l"(p));
    return a;
}
__device__ __forceinline__ void cpasync16(uint32_t dst, const void* src) {
    asm volatile("cp.async.cg.shared.global [%0], [%1], 16;" :: "r"(dst), "l"(src));
}
#define CP_COMMIT() asm volatile("cp.async.commit_group;" ::: "memory")
#define CP_WAIT1()  asm volatile("cp.async.wait_group 1;" ::: "memory")
#define CP_WAIT0()  asm volatile("cp.async.wait_group 0;" ::: "memory")

__device__ __forceinline__ void ldsm4(uint32_t* r, uint32_t addr) {
    asm volatile("ldmatrix.sync.aligned.m8n8.x4.shared.b16 {%0,%1,%2,%3}, [%4];"
                 : "=r"(r[0]), "=r"(r[1]), "=r"(r[2]), "=r"(r[3]) : "r"(addr));
}
__device__ __forceinline__ void mma16816(float* c, const uint32_t* a, const uint32_t* b) {
    asm volatile(
        "mma.sync.aligned.m16n8k16.row.col.f32.bf16.bf16.f32 "
        "{%0,%1,%2,%3}, {%4,%5,%6,%7}, {%8,%9}, {%0,%1,%2,%3};"
        : "+f"(c[0]), "+f"(c[1]), "+f"(c[2]), "+f"(c[3])
        : "r"(a[0]), "r"(a[1]), "r"(a[2]), "r"(a[3]), "r"(b[0]), "r"(b[1]));
}
__device__ __forceinline__ uint32_t packbf2(float a, float b) {
    __nv_bfloat162 t = __float22bfloat162_rn(make_float2(a, b));
    return *(uint32_t*)&t;
}

__device__ __forceinline__ uint32_t swz(int row, int chunk) {
    return (uint32_t)(row * 64 + ((chunk ^ ((row >> 1) & 3)) << 4));
}
__device__ __forceinline__ uint32_t swz128(int row, int c16) {
    return (uint32_t)(row * 128 + ((c16 ^ (row & 7)) << 4));
}

// ---------------------------------------------------------------------------
// Shared GEMM mainloop (128x128 tile, K-major bf16, NT).
// ---------------------------------------------------------------------------
struct SmemPtrs { uint32_t uA, uB; };

template<typename LoadFn>
__device__ __forceinline__ void gemm_core(
    int nch, SmemPtrs sp, int tid, int lane, int wm, int wn,
    float (&acc)[4][4][4], LoadFn load_tiles)
{
    constexpr int ABYTES = 128 * 32 * 2;
    constexpr int BBYTES = 128 * 32 * 2;
    load_tiles(0, 0);
    CP_COMMIT();
    for (int ch = 0; ch < nch; ch++) {
        const int st = ch & 1;
        if (ch + 1 < nch) { load_tiles(ch + 1, st ^ 1); CP_COMMIT(); CP_WAIT1(); }
        else              { CP_WAIT0(); }
        __syncthreads();
        const uint32_t bA = sp.uA + st * ABYTES;
        const uint32_t bB = sp.uB + st * BBYTES;
        #pragma unroll
        for (int kk = 0; kk < 2; kk++) {
            uint32_t afr[4][4];
            #pragma unroll
            for (int i = 0; i < 4; i++) {
                int row = wm * 64 + i * 16 + (lane & 15);
                int chk = kk * 2 + (lane >> 4);
                ldsm4(afr[i], bA + swz(row, chk));
            }
            uint32_t bfr[4][2];
            #pragma unroll
            for (int p = 0; p < 2; p++) {
                uint32_t r4[4];
                int n   = wn * 32 + p * 16 + ((lane >> 4) << 3) + (lane & 7);
                int chk = kk * 2 + ((lane >> 3) & 1);
                ldsm4(r4, bB + swz(n, chk));
                bfr[2 * p][0] = r4[0]; bfr[2 * p][1] = r4[1];
                bfr[2 * p + 1][0] = r4[2]; bfr[2 * p + 1][1] = r4[3];
            }
            #pragma unroll
            for (int i = 0; i < 4; i++)
                #pragma unroll
                for (int j = 0; j < 4; j++)
                    mma16816(acc[i][j], afr[i], bfr[j]);
        }
        __syncthreads();
    }
}

// ---------------------------------------------------------------------------
// Fused projection kernel: 5 jobs (Q, K, V->Vt, PK, PQ) in one 1-D grid.
// ---------------------------------------------------------------------------
struct ProjJobs {
    const bf16* A[5];
    const bf16* Bw[5];
    bf16*       C[5];
    const float* bias[5];
    int mode[5];
    int start[6];
};

__global__ void __launch_bounds__(256) gemm_proj(ProjJobs J)
{
    constexpr int ABYTES = 128 * 32 * 2, BBYTES = 128 * 32 * 2;
    __shared__ __align__(1024) char sm[2 * (ABYTES + BBYTES)];
    SmemPtrs sp { smem_u32(sm), smem_u32(sm) + 2 * ABYTES };

    int bx = blockIdx.x;
    int j = 0;
    while (bx >= J.start[j + 1]) j++;
    const int local = bx - J.start[j];
    const int bm = (local / 6) * 128, bn = (local % 6) * 128;

    const int tid = threadIdx.x, lane = tid & 31, wid = tid >> 5;
    const int wm = wid & 1, wn = wid >> 1;

    const bf16* Arow = J.A[j] + (long)bm * H;
    const bf16* Brow = J.Bw[j] + (long)bn * H;

    auto load_tiles = [&](int ch, int st) {
        const bf16* Ak = Arow + ch * 32;
        #pragma unroll
        for (int i = tid; i < 512; i += 256) {
            int r = i >> 2, c = i & 3;
            cpasync16(sp.uA + st * ABYTES + swz(r, c), Ak + (long)r * H + c * 8);
        }
        const bf16* Bk = Brow + ch * 32;
        #pragma unroll
        for (int i = tid; i < 512; i += 256) {
            int r = i >> 2, c = i & 3;
            cpasync16(sp.uB + st * BBYTES + swz(r, c), Bk + (long)r * H + c * 8);
        }
    };

    float acc[4][4][4] = {};
    gemm_core(H / 32, sp, tid, lane, wm, wn, acc, load_tiles);

    bf16* C = J.C[j];
    const float* bias = J.bias[j];
    const int mode = J.mode[j];

    #pragma unroll
    for (int i = 0; i < 4; i++)
        #pragma unroll
        for (int jj = 0; jj < 4; jj++)
            #pragma unroll
            for (int half = 0; half < 2; half++) {
                const int r = bm + wm * 64 + i * 16 + (lane >> 2) + half * 8;
                const int c = bn + wn * 32 + jj * 8 + (lane & 3) * 2;
                const float v0 = acc[i][jj][half * 2];
                const float v1 = acc[i][jj][half * 2 + 1];
                float b0 = bias ? bias[c] : 0.f, b1 = bias ? bias[c + 1] : 0.f;
                if (mode == 0) {
                    *(__nv_bfloat162*)(C + (long)r * H + c) =
                        __float22bfloat162_rn(make_float2(v0 + b0, v1 + b1));
                } else {
                    C[(long)c * S + r]       = __float2bfloat16(v0 + b0);
                    C[(long)(c + 1) * S + r] = __float2bfloat16(v1 + b1);
                }
            }
}

// ---------------------------------------------------------------------------
// Fused tables kernel with smem-staged coalesced output stores.
// z<NH -> CK = Q_h @ PK_h^T ; else CQ = K_h @ PQ_h^T.
// ---------------------------------------------------------------------------
constexpr int TB_STRIDE = 272;   // staging row stride (16B-aligned, conflict-free)

__global__ void __launch_bounds__(256) gemm_tables(
    const bf16* __restrict__ Qb, const bf16* __restrict__ Kb,
    const bf16* __restrict__ PK, const bf16* __restrict__ PQ,
    bf16* __restrict__ CK, bf16* __restrict__ CQ)
{
    constexpr int ABYTES = 128 * 32 * 2, BBYTES = 128 * 32 * 2;
    __shared__ __align__(1024) char sm[128 * TB_STRIDE];  // 34816 >= 32768 mainloop
    SmemPtrs sp { smem_u32(sm), smem_u32(sm) + 2 * ABYTES };

    const int z = blockIdx.z;
    const bool isCK = z < NH;
    const int h = isCK ? z : z - NH;
    const bf16* A = (isCK ? Qb : Kb) + h * D;
    const bf16* B = (isCK ? PK : PQ) + h * D;
    bf16* C = (isCK ? CK : CQ) + (size_t)h * S * LPOS;

    const int tid = threadIdx.x, lane = tid & 31, wid = tid >> 5;
    const int wm = wid & 1, wn = wid >> 1;
    const int bm = blockIdx.y * 128, bn = blockIdx.x * 128;

    const bf16* Arow = A + (long)bm * H;
    const bf16* Brow = B + (long)bn * H;

    auto load_tiles = [&](int ch, int st) {
        const bf16* Ak = Arow + ch * 32;
        #pragma unroll
        for (int i = tid; i < 512; i += 256) {
            int r = i >> 2, c = i & 3;
            cpasync16(sp.uA + st * ABYTES + swz(r, c), Ak + (long)r * H + c * 8);
        }
        const bf16* Bk = Brow + ch * 32;
        #pragma unroll
        for (int i = tid; i < 512; i += 256) {
            int r = i >> 2, c = i & 3;
            cpasync16(sp.uB + st * BBYTES + swz(r, c), Bk + (long)r * H + c * 8);
        }
    };

    float acc[4][4][4] = {};
    gemm_core(D / 32, sp, tid, lane, wm, wn, acc, load_tiles);
    // gemm_core ends with __syncthreads(): smem reusable as output staging.

    #pragma unroll
    for (int i = 0; i < 4; i++)
        #pragma unroll
        for (int jj = 0; jj < 4; jj++)
            #pragma unroll
            for (int half = 0; half < 2; half++) {
                const int rl = wm * 64 + i * 16 + (lane >> 2) + half * 8;
                const int cl = wn * 32 + jj * 8 + (lane & 3) * 2;
                *(uint32_t*)(sm + rl * TB_STRIDE + cl * 2) =
                    packbf2(acc[i][jj][half * 2], acc[i][jj][half * 2 + 1]);
            }
    __syncthreads();

    // coalesced copy-out: 128 rows x 256B, 16B per thread-chunk
    #pragma unroll
    for (int i = tid; i < 2048; i += 256) {
        int r = i >> 4, ch = i & 15;
        uint4 v = *(uint4*)(sm + r * TB_STRIDE + ch * 16);
        *(uint4*)(C + (long)(bm + r) * LPOS + bn + ch * 8) = v;
    }
}

// ---------------------------------------------------------------------------
// Output projection + bias + residual (fp32 out).
// ---------------------------------------------------------------------------
__global__ void __launch_bounds__(256) gemm_out(
    const bf16* __restrict__ A, const bf16* __restrict__ Bw,
    float* __restrict__ C, const float* __restrict__ bias,
    const float* __restrict__ res)
{
    constexpr int ABYTES = 128 * 32 * 2, BBYTES = 128 * 32 * 2;
    __shared__ __align__(1024) char sm[2 * (ABYTES + BBYTES)];
    SmemPtrs sp { smem_u32(sm), smem_u32(sm) + 2 * ABYTES };

    const int tid = threadIdx.x, lane = tid & 31, wid = tid >> 5;
    const int wm = wid & 1, wn = wid >> 1;
    const int bm = blockIdx.y * 128, bn = blockIdx.x * 128;

    const bf16* Arow = A + (long)bm * H;
    const bf16* Brow = Bw + (long)bn * H;

    auto load_tiles = [&](int ch, int st) {
        const bf16* Ak = Arow + ch * 32;
        #pragma unroll
        for (int i = tid; i < 512; i += 256) {
            int r = i >> 2, c = i & 3;
            cpasync16(sp.uA + st * ABYTES + swz(r, c), Ak + (long)r * H + c * 8);
        }
        const bf16* Bk = Brow + ch * 32;
        #pragma unroll
        for (int i = tid; i < 512; i += 256) {
            int r = i >> 2, c = i & 3;
            cpasync16(sp.uB + st * BBYTES + swz(r, c), Bk + (long)r * H + c * 8);
        }
    };

    float acc[4][4][4] = {};
    gemm_core(H / 32, sp, tid, lane, wm, wn, acc, load_tiles);

    #pragma unroll
    for (int i = 0; i < 4; i++)
        #pragma unroll
        for (int jj = 0; jj < 4; jj++)
            #pragma unroll
            for (int half = 0; half < 2; half++) {
                const int r = bm + wm * 64 + i * 16 + (lane >> 2) + half * 8;
                const int c = bn + wn * 32 + jj * 8 + (lane & 3) * 2;
                const float* rr = res + (long)r * H;
                *(float2*)(C + (long)r * H + c) =
                    make_float2(acc[i][jj][half * 2] + bias[c] + rr[c],
                                acc[i][jj][half * 2 + 1] + bias[c + 1] + rr[c + 1]);
            }
}

// ---------------------------------------------------------------------------
// Flash-fused attention, split-K over 2 halves of the key sequence.
// Each CTA: 128 rows x 1024 keys; writes unnormalized O + (m,l) partials.
// ---------------------------------------------------------------------------
constexpr int CQ_W     = 208;
constexpr int CQ_ROWB  = CQ_W * 2;
constexpr int CQ_BYTES = 64 * CQ_ROWB;
constexpr int FL_SMEM  = 16384 + 2 * 8192 + 2 * 8192 + 2 * CQ_BYTES;  // 102400
constexpr int HTILES   = 16;   // key tiles per half

__global__ void __launch_bounds__(256) flash_attn(
    const bf16* __restrict__ Q, const bf16* __restrict__ K,
    const bf16* __restrict__ Vt,
    const bf16* __restrict__ CKb, const bf16* __restrict__ CQb,
    const int* __restrict__ mask,
    float* __restrict__ Opart, float2* __restrict__ ML)
{
    extern __shared__ __align__(1024) char dyn[];
    const uint32_t uQ  = smem_u32(dyn);
    const uint32_t uK  = uQ + 16384;
    const uint32_t uV  = uK + 16384;
    const uint32_t uCQ = uV + 16384;

    const int tid = threadIdx.x, lane = tid & 31, wid = tid >> 5;
    const int h = blockIdx.y, bm = blockIdx.x * 128;
    const int z = blockIdx.z;
    const int ct0 = z * HTILES;

    auto lbase_of = [&](int ct) {
        int lo = bm - ct * 64 + 449;
        return min(max(lo, 0), 816) & ~7;
    };

    {
        const bf16* Qg = Q + (long)bm * H + h * D;
        #pragma unroll
        for (int i = tid; i < 1024; i += 256) {
            int r = i >> 3, c = i & 7;
            cpasync16(uQ + swz128(r, c), Qg + (long)r * H + c * 8);
        }
    }
    CP_COMMIT();

    auto load_kv = [&](int ct, int st) {
        const int c0 = ct * 64;
        const uint32_t uk = uK + st * 8192;
        const uint32_t uv = uV + st * 8192;
        const bf16* Kg = K + (long)c0 * H + h * D;
        #pragma unroll
        for (int i = tid; i < 512; i += 256) {
            int r = i >> 3, c = i & 7;
            cpasync16(uk + swz128(r, c), Kg + (long)r * H + c * 8);
        }
        const bf16* Vg = Vt + (long)(h * D) * S + c0;
        #pragma unroll
        for (int i = tid; i < 512; i += 256) {
            int d = i >> 3, c = i & 7;
            cpasync16(uv + swz128(d, c), Vg + (long)d * S + c * 8);
        }
        const int Lb = lbase_of(ct);
        const uint32_t ucq = uCQ + st * CQ_BYTES;
        const bf16* CQg = CQb + ((size_t)h * S + c0) * LPOS + Lb;
        #pragma unroll
        for (int i = tid; i < 64 * 26; i += 256) {
            int r = i / 26, ch = i % 26;
            cpasync16(ucq + r * CQ_ROWB + ch * 16, CQg + (size_t)r * LPOS + ch * 8);
        }
    };
    load_kv(ct0, 0);
    CP_COMMIT();
    CP_WAIT1();
    __syncthreads();

    uint32_t qf[4][4];
    #pragma unroll
    for (int kk = 0; kk < 4; kk++) {
        int row = wid * 16 + (lane & 15);
        int c16 = kk * 2 + (lane >> 4);
        ldsm4(qf[kk], uQ + swz128(row, c16));
    }

    const int r0 = bm + wid * 16 + (lane >> 2);
    const int r1 = r0 + 8;
    const int m0v = mask[r0], m1v = mask[r1];
    const bf16* ck0 = CKb + ((size_t)h * S + r0) * LPOS;
    const bf16* ck1 = CKb + ((size_t)h * S + r1) * LPOS;

    float m0 = NEGMAX, m1 = NEGMAX, l0 = 0.f, l1 = 0.f;
    float O[8][4] = {};

    for (int it = 0; it < HTILES; it++) {
        const int ct = ct0 + it;
        const int st = it & 1;
        if (it + 1 < HTILES) { load_kv(ct + 1, st ^ 1); CP_COMMIT(); CP_WAIT1(); }
        else                 { CP_WAIT0(); }
        __syncthreads();

        const uint32_t uk = uK + st * 8192;
        const uint32_t uv = uV + st * 8192;
        const bf16* sCQ = (const bf16*)(dyn + (uCQ - uQ) + st * CQ_BYTES);
        const int Lb = lbase_of(ct);

        float sfr[8][4] = {};
        #pragma unroll
        for (int g = 0; g < 4; g++) {
            #pragma unroll
            for (int kk = 0; kk < 4; kk++) {
                uint32_t r4[4];
                int n   = g * 16 + ((lane >> 4) << 3) + (lane & 7);
                int c16 = kk * 2 + ((lane >> 3) & 1);
                ldsm4(r4, uk + swz128(n, c16));
                mma16816(sfr[2 * g],     qf[kk], r4);
                mma16816(sfr[2 * g + 1], qf[kk], r4 + 2);
            }
        }

        const int c0 = ct * 64;
        float tmx0 = NEGMAX, tmx1 = NEGMAX;
        #pragma unroll
        for (int nb = 0; nb < 8; nb++) {
            const int cl = nb * 8 + (lane & 3) * 2;
            const int c  = c0 + cl;
            const int mc0 = mask[c], mc1 = mask[c + 1];
            {
                int la = min(max(r0 - c + 512, 0), LPOS - 1);
                int lb = min(max(r0 - c + 511, 0), LPOS - 1);
                float v0 = (sfr[nb][0] + __bfloat162float(ck0[la])
                            + __bfloat162float(sCQ[cl * CQ_W + (la - Lb)])) * SCALE;
                float v1 = (sfr[nb][1] + __bfloat162float(ck0[lb])
                            + __bfloat162float(sCQ[(cl + 1) * CQ_W + (lb - Lb)])) * SCALE;
                if (!(m0v && mc0)) v0 = NEGMAX;
                if (!(m0v && mc1)) v1 = NEGMAX;
                sfr[nb][0] = v0; sfr[nb][1] = v1;
                tmx0 = fmaxf(tmx0, fmaxf(v0, v1));
            }
            {
                int la = min(max(r1 - c + 512, 0), LPOS - 1);
                int lb = min(max(r1 - c + 511, 0), LPOS - 1);
                float v2 = (sfr[nb][2] + __bfloat162float(ck1[la])
                            + __bfloat162float(sCQ[cl * CQ_W + (la - Lb)])) * SCALE;
                float v3 = (sfr[nb][3] + __bfloat162float(ck1[lb])
                            + __bfloat162float(sCQ[(cl + 1) * CQ_W + (lb - Lb)])) * SCALE;
                if (!(m1v && mc0)) v2 = NEGMAX;
                if (!(m1v && mc1)) v3 = NEGMAX;
                sfr[nb][2] = v2; sfr[nb][3] = v3;
                tmx1 = fmaxf(tmx1, fmaxf(v2, v3));
            }
        }
        tmx0 = fmaxf(tmx0, __shfl_xor_sync(0xffffffffu, tmx0, 1));
        tmx0 = fmaxf(tmx0, __shfl_xor_sync(0xffffffffu, tmx0, 2));
        tmx1 = fmaxf(tmx1, __shfl_xor_sync(0xffffffffu, tmx1, 1));
        tmx1 = fmaxf(tmx1, __shfl_xor_sync(0xffffffffu, tmx1, 2));

        const float mn0 = fmaxf(m0, tmx0), mn1 = fmaxf(m1, tmx1);
        const float sc0 = __expf(m0 - mn0), sc1 = __expf(m1 - mn1);
        m0 = mn0; m1 = mn1;
        float rs0 = 0.f, rs1 = 0.f;
        #pragma unroll
        for (int nb = 0; nb < 8; nb++) {
            sfr[nb][0] = __expf(sfr[nb][0] - mn0);
            sfr[nb][1] = __expf(sfr[nb][1] - mn0);
            sfr[nb][2] = __expf(sfr[nb][2] - mn1);
            sfr[nb][3] = __expf(sfr[nb][3] - mn1);
            rs0 += sfr[nb][0] + sfr[nb][1];
            rs1 += sfr[nb][2] + sfr[nb][3];
        }
        rs0 += __shfl_xor_sync(0xffffffffu, rs0, 1);
        rs0 += __shfl_xor_sync(0xffffffffu, rs0, 2);
        rs1 += __shfl_xor_sync(0xffffffffu, rs1, 1);
        rs1 += __shfl_xor_sync(0xffffffffu, rs1, 2);
        l0 = l0 * sc0 + rs0;
        l1 = l1 * sc1 + rs1;
        #pragma unroll
        for (int df = 0; df < 8; df++) {
            O[df][0] *= sc0; O[df][1] *= sc0;
            O[df][2] *= sc1; O[df][3] *= sc1;
        }

        #pragma unroll
        for (int kk2 = 0; kk2 < 4; kk2++) {
            uint32_t pf[4];
            pf[0] = packbf2(sfr[2 * kk2][0],     sfr[2 * kk2][1]);
            pf[1] = packbf2(sfr[2 * kk2][2],     sfr[2 * kk2][3]);
            pf[2] = packbf2(sfr[2 * kk2 + 1][0], sfr[2 * kk2 + 1][1]);
            pf[3] = packbf2(sfr[2 * kk2 + 1][2], sfr[2 * kk2 + 1][3]);
            #pragma unroll
            for (int dg = 0; dg < 4; dg++) {
                uint32_t r4[4];
                int n   = dg * 16 + ((lane >> 4) << 3) + (lane & 7);
                int c16 = kk2 * 2 + ((lane >> 3) & 1);
                ldsm4(r4, uv + swz128(n, c16));
                mma16816(O[2 * dg],     pf, r4);
                mma16816(O[2 * dg + 1], pf, r4 + 2);
            }
        }
        __syncthreads();
    }

    // ---- write unnormalized partials ----
    const size_t base = ((size_t)z * NH + h) * S;
    if ((lane & 3) == 0) {
        ML[base + r0] = make_float2(m0, l0);
        ML[base + r1] = make_float2(m1, l1);
    }
    float* o0 = Opart + (base + r0) * D + (lane & 3) * 2;
    float* o1 = Opart + (base + r1) * D + (lane & 3) * 2;
    #pragma unroll
    for (int df = 0; df < 8; df++) {
        *(float2*)(o0 + df * 8) = make_float2(O[df][0], O[df][1]);
        *(float2*)(o1 + df * 8) = make_float2(O[df][2], O[df][3]);
    }
}

// ---------------------------------------------------------------------------
// Merge the two split-K halves -> normalized bf16 context.
// One warp per (h,row); 8 rows per 256-thread block.
// ---------------------------------------------------------------------------
__global__ void __launch_bounds__(256) merge_attn(
    const float* __restrict__ Opart, const float2* __restrict__ ML,
    bf16* __restrict__ CTX)
{
    const int p = blockIdx.x * 8 + (threadIdx.x >> 5);   // (h,row) pair
    const int lane = threadIdx.x & 31;
    const int h = p / S, row = p % S;

    const float2 ml0 = ML[p];
    const float2 ml1 = ML[NH * S + p];
    const float M  = fmaxf(ml0.x, ml1.x);
    const float w0 = __expf(ml0.x - M);
    const float w1 = __expf(ml1.x - M);
    const float inv = 1.0f / (w0 * ml0.y + w1 * ml1.y);

    const int d = lane * 2;
    const float2 a = *(const float2*)(Opart + (size_t)p * D + d);
    const float2 b = *(const float2*)(Opart + ((size_t)NH * S + p) * D + d);
    *(__nv_bfloat162*)(CTX + (long)row * H + h * D + d) =
        __float22bfloat162_rn(make_float2((w0 * a.x + w1 * b.x) * inv,
                                          (w0 * a.y + w1 * b.y) * inv));
}

// ---------------------------------------------------------------------------
__global__ void cvt_bf16_2(const float* __restrict__ x0, bf16* __restrict__ y0, int n0,
                           const float* __restrict__ x1, bf16* __restrict__ y1, int n1)
{
    int i = blockIdx.x * 256 + threadIdx.x;
    if (i < n0) y0[i] = __float2bfloat16(x0[i]);
    else if (i < n0 + n1) y1[i - n0] = __float2bfloat16(x1[i - n0]);
}

struct P6 { const float* p[6]; };
__global__ void wtrans6(P6 srcs, bf16* __restrict__ Wt)
{
    __shared__ float t[32][33];
    const float* W = srcs.p[blockIdx.z];
    bf16* dst = Wt + (size_t)blockIdx.z * H * H;
    const int bx = blockIdx.x * 32, by = blockIdx.y * 32;
    #pragma unroll
    for (int i = threadIdx.y; i < 32; i += 8)
        t[i][threadIdx.x] = W[(long)(by + i) * H + bx + threadIdx.x];
    __syncthreads();
    #pragma unroll
    for (int i = threadIdx.y; i < 32; i += 8)
        dst[(long)(bx + i) * H + by + threadIdx.x] = __float2bfloat16(t[threadIdx.x][i]);
}

__global__ void ln_kernel(const float* __restrict__ x,
                          const float* __restrict__ gamma,
                          const float* __restrict__ beta,
                          float* __restrict__ out)
{
    __shared__ float rs[8], rq[8];
    const int s = blockIdx.x, tid = threadIdx.x;
    const float* row = x + (long)s * H;
    float a0 = row[tid], a1 = row[tid + 256], a2 = row[tid + 512];
    float sum = a0 + a1 + a2;
    float sq  = a0 * a0 + a1 * a1 + a2 * a2;
    #pragma unroll
    for (int o = 16; o > 0; o >>= 1) {
        sum += __shfl_xor_sync(0xffffffffu, sum, o);
        sq  += __shfl_xor_sync(0xffffffffu, sq,  o);
    }
    if ((tid & 31) == 0) { rs[tid >> 5] = sum; rq[tid >> 5] = sq; }
    __syncthreads();
    float ts = 0.f, tq = 0.f;
    #pragma unroll
    for (int w = 0; w < 8; w++) { ts += rs[w]; tq += rq[w]; }
    float mean = ts * (1.0f / H);
    float var  = tq * (1.0f / H) - mean * mean;
    float inv  = rsqrtf(var + 1e-7f);
    float* o = out + (long)s * H;
    o[tid]       = (a0 - mean) * inv * gamma[tid]       + beta[tid];
    o[tid + 256] = (a1 - mean) * inv * gamma[tid + 256] + beta[tid + 256];
    o[tid + 512] = (a2 - mean) * inv * gamma[tid + 512] + beta[tid + 512];
}

// ---------------------------------------------------------------------------
extern "C" void kernel_launch(void* const* d_in, const int* in_sizes, int n_in,
                              void* d_out, int out_size)
{
    const float* hidden = (const float*)d_in[0];
    const int*   mask   = (const int*)  d_in[1];
    const float* Wq     = (const float*)d_in[2];
    const float* bq     = (const float*)d_in[3];
    const float* Wk     = (const float*)d_in[4];
    const float* bk     = (const float*)d_in[5];
    const float* Wv     = (const float*)d_in[6];
    const float* bv     = (const float*)d_in[7];
    const float* rel    = (const float*)d_in[8];
    const float* Wpk    = (const float*)d_in[9];
    const float* Wpq    = (const float*)d_in[10];
    const float* bpq    = (const float*)d_in[11];
    const float* Wo     = (const float*)d_in[12];
    const float* bo     = (const float*)d_in[13];
    const float* gamma  = (const float*)d_in[14];
    const float* beta   = (const float*)d_in[15];
    float* out = (float*)d_out;

    bf16 *hbf, *relbf, *Wt, *Qbf, *Kbf, *Vt, *PKbf, *PQbf, *CKb, *CQb, *CTXbf;
    float *TMP, *Opart;
    float2* ML;
    cudaGetSymbolAddress((void**)&hbf,   g_hbf);
    cudaGetSymbolAddress((void**)&relbf, g_relbf);
    cudaGetSymbolAddress((void**)&Wt,    g_Wt);
    cudaGetSymbolAddress((void**)&Qbf,   g_Qbf);
    cudaGetSymbolAddress((void**)&Kbf,   g_Kbf);
    cudaGetSymbolAddress((void**)&Vt,    g_Vt);
    cudaGetSymbolAddress((void**)&PKbf,  g_PKbf);
    cudaGetSymbolAddress((void**)&PQbf,  g_PQbf);
    cudaGetSymbolAddress((void**)&CKb,   g_CKb);
    cudaGetSymbolAddress((void**)&CQb,   g_CQb);
    cudaGetSymbolAddress((void**)&Opart, g_Opart);
    cudaGetSymbolAddress((void**)&ML,    g_ML);
    cudaGetSymbolAddress((void**)&CTXbf, g_CTXbf);
    cudaGetSymbolAddress((void**)&TMP,   g_TMP);

    static bool attr_done = false;
    if (!attr_done) {
        cudaFuncSetAttribute(flash_attn,
                             cudaFuncAttributeMaxDynamicSharedMemorySize, FL_SMEM);
        attr_done = true;
    }

    // --- conversions / transposes ---
    cvt_bf16_2<<<(S * H + LPOS * H + 255) / 256, 256>>>(
        hidden, hbf, S * H, rel, relbf, LPOS * H);
    P6 w6; w6.p[0] = Wq; w6.p[1] = Wk; w6.p[2] = Wv;
    w6.p[3] = Wpk; w6.p[4] = Wpq; w6.p[5] = Wo;
    wtrans6<<<dim3(H/32, H/32, 6), dim3(32, 8)>>>(w6, Wt);

    // --- all five projections in one launch ---
    ProjJobs J;
    J.A[0] = hbf;   J.Bw[0] = Wt + 0 * H * H; J.C[0] = Qbf;  J.bias[0] = bq;      J.mode[0] = 0;
    J.A[1] = hbf;   J.Bw[1] = Wt + 1 * H * H; J.C[1] = Kbf;  J.bias[1] = bk;      J.mode[1] = 0;
    J.A[2] = hbf;   J.Bw[2] = Wt + 2 * H * H; J.C[2] = Vt;   J.bias[2] = bv;      J.mode[2] = 1;
    J.A[3] = relbf; J.Bw[3] = Wt + 3 * H * H; J.C[3] = PKbf; J.bias[3] = nullptr; J.mode[3] = 0;
    J.A[4] = relbf; J.Bw[4] = Wt + 4 * H * H; J.C[4] = PQbf; J.bias[4] = bpq;     J.mode[4] = 0;
    J.start[0] = 0;   J.start[1] = 96;  J.start[2] = 192;
    J.start[3] = 288; J.start[4] = 336; J.start[5] = 384;
    gemm_proj<<<384, 256>>>(J);

    // --- both rel-position tables in one launch ---
    gemm_tables<<<dim3(LPOS/128, S/128, 2 * NH), 256>>>(
        Qbf, Kbf, PKbf, PQbf, CKb, CQb);

    // --- fused attention, split-K over 2 halves ---
    flash_attn<<<dim3(S/128, NH, 2), 256, FL_SMEM>>>(
        Qbf, Kbf, Vt, CKb, CQb, mask, Opart, ML);
    merge_attn<<<NH * S / 8, 256>>>(Opart, ML, CTXbf);

    // --- output projection + bias + residual ---
    gemm_out<<<dim3(6, 16), 256>>>(CTXbf, Wt + 5 * H * H, TMP, bo, hidden);

    // --- layernorm ---
    ln_kernel<<<S, 256>>>(TMP, gamma, beta, out);
}

// round 8
// speedup vs baseline: 11.0002x; 1.0624x over previous
#include <cuda_runtime.h>
#include <cuda_bf16.h>
#include <cstdint>

// ---------------------------------------------------------------------------
// BertAttention (DeBERTa) — round 8: z=4 split flash + per-column cq bands.
// B=1, S=2048, H=768, NH=12, D=64, SPAN=512
// ---------------------------------------------------------------------------

constexpr int S    = 2048;
constexpr int H    = 768;
constexpr int NH   = 12;
constexpr int D    = 64;
constexpr int LPOS = 1024;  // 2*SPAN
constexpr int ZSPL = 4;     // split-K factor over key sequence
constexpr float SCALE  = 0.07216878364870322f;  // 1/sqrt(64*3)
constexpr float NEGMAX = -3.402823466e38f;

using bf16 = __nv_bfloat16;

// ---------------------------- scratch (device globals) ---------------------
__device__ bf16   g_hbf  [S * H];
__device__ bf16   g_relbf[LPOS * H];
__device__ bf16   g_Wt   [6 * H * H];
__device__ bf16   g_Qbf  [S * H];
__device__ bf16   g_Kbf  [S * H];
__device__ bf16   g_Vt   [H * S];
__device__ bf16   g_PKbf [LPOS * H];
__device__ bf16   g_PQbf [LPOS * H];
__device__ bf16   g_CKb  [(size_t)NH * S * LPOS];
__device__ bf16   g_CQb  [(size_t)NH * S * LPOS + 256];
__device__ float  g_Opart[(size_t)ZSPL * NH * S * D];
__device__ float2 g_ML   [ZSPL * NH * S];
__device__ bf16   g_CTXbf[S * H];
__device__ float  g_TMP  [S * H];

// ---------------------------- PTX helpers ----------------------------------
__device__ __forceinline__ uint32_t smem_u32(const void* p) {
    uint32_t a;
    asm("{ .reg .u64 t; cvta.to.shared.u64 t, %1; cvt.u32.u64 %0, t; }"
        : "=r"(a) : "l"(p));
    return a;
}
__device__ __forceinline__ void cpasync16(uint32_t dst, const void* src) {
    asm volatile("cp.async.cg.shared.global [%0], [%1], 16;" :: "r"(dst), "l"(src));
}
#define CP_COMMIT() asm volatile("cp.async.commit_group;" ::: "memory")
#define CP_WAIT1()  asm volatile("cp.async.wait_group 1;" ::: "memory")
#define CP_WAIT0()  asm volatile("cp.async.wait_group 0;" ::: "memory")

__device__ __forceinline__ void ldsm4(uint32_t* r, uint32_t addr) {
    asm volatile("ldmatrix.sync.aligned.m8n8.x4.shared.b16 {%0,%1,%2,%3}, [%4];"
                 : "=r"(r[0]), "=r"(r[1]), "=r"(r[2]), "=r"(r[3]) : "r"(addr));
}
__device__ __forceinline__ void mma16816(float* c, const uint32_t* a, const uint32_t* b) {
    asm volatile(
        "mma.sync.aligned.m16n8k16.row.col.f32.bf16.bf16.f32 "
        "{%0,%1,%2,%3}, {%4,%5,%6,%7}, {%8,%9}, {%0,%1,%2,%3};"
        : "+f"(c[0]), "+f"(c[1]), "+f"(c[2]), "+f"(c[3])
        : "r"(a[0]), "r"(a[1]), "r"(a[2]), "r"(a[3]), "r"(b[0]), "r"(b[1]));
}
__device__ __forceinline__ uint32_t packbf2(float a, float b) {
    __nv_bfloat162 t = __float22bfloat162_rn(make_float2(a, b));
    return *(uint32_t*)&t;
}

__device__ __forceinline__ uint32_t swz(int row, int chunk) {
    return (uint32_t)(row * 64 + ((chunk ^ ((row >> 1) & 3)) << 4));
}
__device__ __forceinline__ uint32_t swz128(int row, int c16) {
    return (uint32_t)(row * 128 + ((c16 ^ (row & 7)) << 4));
}

// ---------------------------------------------------------------------------
// Shared GEMM mainloop (128x128 tile, K-major bf16, NT).
// ---------------------------------------------------------------------------
struct SmemPtrs { uint32_t uA, uB; };

template<typename LoadFn>
__device__ __forceinline__ void gemm_core(
    int nch, SmemPtrs sp, int tid, int lane, int wm, int wn,
    float (&acc)[4][4][4], LoadFn load_tiles)
{
    constexpr int ABYTES = 128 * 32 * 2;
    constexpr int BBYTES = 128 * 32 * 2;
    load_tiles(0, 0);
    CP_COMMIT();
    for (int ch = 0; ch < nch; ch++) {
        const int st = ch & 1;
        if (ch + 1 < nch) { load_tiles(ch + 1, st ^ 1); CP_COMMIT(); CP_WAIT1(); }
        else              { CP_WAIT0(); }
        __syncthreads();
        const uint32_t bA = sp.uA + st * ABYTES;
        const uint32_t bB = sp.uB + st * BBYTES;
        #pragma unroll
        for (int kk = 0; kk < 2; kk++) {
            uint32_t afr[4][4];
            #pragma unroll
            for (int i = 0; i < 4; i++) {
                int row = wm * 64 + i * 16 + (lane & 15);
                int chk = kk * 2 + (lane >> 4);
                ldsm4(afr[i], bA + swz(row, chk));
            }
            uint32_t bfr[4][2];
            #pragma unroll
            for (int p = 0; p < 2; p++) {
                uint32_t r4[4];
                int n   = wn * 32 + p * 16 + ((lane >> 4) << 3) + (lane & 7);
                int chk = kk * 2 + ((lane >> 3) & 1);
                ldsm4(r4, bB + swz(n, chk));
                bfr[2 * p][0] = r4[0]; bfr[2 * p][1] = r4[1];
                bfr[2 * p + 1][0] = r4[2]; bfr[2 * p + 1][1] = r4[3];
            }
            #pragma unroll
            for (int i = 0; i < 4; i++)
                #pragma unroll
                for (int j = 0; j < 4; j++)
                    mma16816(acc[i][j], afr[i], bfr[j]);
        }
        __syncthreads();
    }
}

// ---------------------------------------------------------------------------
// Fused projection kernel: 5 jobs (Q, K, V->Vt, PK, PQ) in one 1-D grid.
// ---------------------------------------------------------------------------
struct ProjJobs {
    const bf16* A[5];
    const bf16* Bw[5];
    bf16*       C[5];
    const float* bias[5];
    int mode[5];
    int start[6];
};

__global__ void __launch_bounds__(256) gemm_proj(ProjJobs J)
{
    constexpr int ABYTES = 128 * 32 * 2, BBYTES = 128 * 32 * 2;
    __shared__ __align__(1024) char sm[2 * (ABYTES + BBYTES)];
    SmemPtrs sp { smem_u32(sm), smem_u32(sm) + 2 * ABYTES };

    int bx = blockIdx.x;
    int j = 0;
    while (bx >= J.start[j + 1]) j++;
    const int local = bx - J.start[j];
    const int bm = (local / 6) * 128, bn = (local % 6) * 128;

    const int tid = threadIdx.x, lane = tid & 31, wid = tid >> 5;
    const int wm = wid & 1, wn = wid >> 1;

    const bf16* Arow = J.A[j] + (long)bm * H;
    const bf16* Brow = J.Bw[j] + (long)bn * H;

    auto load_tiles = [&](int ch, int st) {
        const bf16* Ak = Arow + ch * 32;
        #pragma unroll
        for (int i = tid; i < 512; i += 256) {
            int r = i >> 2, c = i & 3;
            cpasync16(sp.uA + st * ABYTES + swz(r, c), Ak + (long)r * H + c * 8);
        }
        const bf16* Bk = Brow + ch * 32;
        #pragma unroll
        for (int i = tid; i < 512; i += 256) {
            int r = i >> 2, c = i & 3;
            cpasync16(sp.uB + st * BBYTES + swz(r, c), Bk + (long)r * H + c * 8);
        }
    };

    float acc[4][4][4] = {};
    gemm_core(H / 32, sp, tid, lane, wm, wn, acc, load_tiles);

    bf16* C = J.C[j];
    const float* bias = J.bias[j];
    const int mode = J.mode[j];

    #pragma unroll
    for (int i = 0; i < 4; i++)
        #pragma unroll
        for (int jj = 0; jj < 4; jj++)
            #pragma unroll
            for (int half = 0; half < 2; half++) {
                const int r = bm + wm * 64 + i * 16 + (lane >> 2) + half * 8;
                const int c = bn + wn * 32 + jj * 8 + (lane & 3) * 2;
                const float v0 = acc[i][jj][half * 2];
                const float v1 = acc[i][jj][half * 2 + 1];
                float b0 = bias ? bias[c] : 0.f, b1 = bias ? bias[c + 1] : 0.f;
                if (mode == 0) {
                    *(__nv_bfloat162*)(C + (long)r * H + c) =
                        __float22bfloat162_rn(make_float2(v0 + b0, v1 + b1));
                } else {
                    C[(long)c * S + r]       = __float2bfloat16(v0 + b0);
                    C[(long)(c + 1) * S + r] = __float2bfloat16(v1 + b1);
                }
            }
}

// ---------------------------------------------------------------------------
// Fused tables kernel with smem-staged coalesced output stores.
// ---------------------------------------------------------------------------
constexpr int TB_STRIDE = 272;

__global__ void __launch_bounds__(256) gemm_tables(
    const bf16* __restrict__ Qb, const bf16* __restrict__ Kb,
    const bf16* __restrict__ PK, const bf16* __restrict__ PQ,
    bf16* __restrict__ CK, bf16* __restrict__ CQ)
{
    constexpr int ABYTES = 128 * 32 * 2, BBYTES = 128 * 32 * 2;
    __shared__ __align__(1024) char sm[128 * TB_STRIDE];
    SmemPtrs sp { smem_u32(sm), smem_u32(sm) + 2 * ABYTES };

    const int z = blockIdx.z;
    const bool isCK = z < NH;
    const int h = isCK ? z : z - NH;
    const bf16* A = (isCK ? Qb : Kb) + h * D;
    const bf16* B = (isCK ? PK : PQ) + h * D;
    bf16* C = (isCK ? CK : CQ) + (size_t)h * S * LPOS;

    const int tid = threadIdx.x, lane = tid & 31, wid = tid >> 5;
    const int wm = wid & 1, wn = wid >> 1;
    const int bm = blockIdx.y * 128, bn = blockIdx.x * 128;

    const bf16* Arow = A + (long)bm * H;
    const bf16* Brow = B + (long)bn * H;

    auto load_tiles = [&](int ch, int st) {
        const bf16* Ak = Arow + ch * 32;
        #pragma unroll
        for (int i = tid; i < 512; i += 256) {
            int r = i >> 2, c = i & 3;
            cpasync16(sp.uA + st * ABYTES + swz(r, c), Ak + (long)r * H + c * 8);
        }
        const bf16* Bk = Brow + ch * 32;
        #pragma unroll
        for (int i = tid; i < 512; i += 256) {
            int r = i >> 2, c = i & 3;
            cpasync16(sp.uB + st * BBYTES + swz(r, c), Bk + (long)r * H + c * 8);
        }
    };

    float acc[4][4][4] = {};
    gemm_core(D / 32, sp, tid, lane, wm, wn, acc, load_tiles);

    #pragma unroll
    for (int i = 0; i < 4; i++)
        #pragma unroll
        for (int jj = 0; jj < 4; jj++)
            #pragma unroll
            for (int half = 0; half < 2; half++) {
                const int rl = wm * 64 + i * 16 + (lane >> 2) + half * 8;
                const int cl = wn * 32 + jj * 8 + (lane & 3) * 2;
                *(uint32_t*)(sm + rl * TB_STRIDE + cl * 2) =
                    packbf2(acc[i][jj][half * 2], acc[i][jj][half * 2 + 1]);
            }
    __syncthreads();

    #pragma unroll
    for (int i = tid; i < 2048; i += 256) {
        int r = i >> 4, ch = i & 15;
        uint4 v = *(uint4*)(sm + r * TB_STRIDE + ch * 16);
        *(uint4*)(C + (long)(bm + r) * LPOS + bn + ch * 8) = v;
    }
}

// ---------------------------------------------------------------------------
// Output projection + bias + residual (fp32 out).
// ---------------------------------------------------------------------------
__global__ void __launch_bounds__(256) gemm_out(
    const bf16* __restrict__ A, const bf16* __restrict__ Bw,
    float* __restrict__ C, const float* __restrict__ bias,
    const float* __restrict__ res)
{
    constexpr int ABYTES = 128 * 32 * 2, BBYTES = 128 * 32 * 2;
    __shared__ __align__(1024) char sm[2 * (ABYTES + BBYTES)];
    SmemPtrs sp { smem_u32(sm), smem_u32(sm) + 2 * ABYTES };

    const int tid = threadIdx.x, lane = tid & 31, wid = tid >> 5;
    const int wm = wid & 1, wn = wid >> 1;
    const int bm = blockIdx.y * 128, bn = blockIdx.x * 128;

    const bf16* Arow = A + (long)bm * H;
    const bf16* Brow = Bw + (long)bn * H;

    auto load_tiles = [&](int ch, int st) {
        const bf16* Ak = Arow + ch * 32;
        #pragma unroll
        for (int i = tid; i < 512; i += 256) {
            int r = i >> 2, c = i & 3;
            cpasync16(sp.uA + st * ABYTES + swz(r, c), Ak + (long)r * H + c * 8);
        }
        const bf16* Bk = Brow + ch * 32;
        #pragma unroll
        for (int i = tid; i < 512; i += 256) {
            int r = i >> 2, c = i & 3;
            cpasync16(sp.uB + st * BBYTES + swz(r, c), Bk + (long)r * H + c * 8);
        }
    };

    float acc[4][4][4] = {};
    gemm_core(H / 32, sp, tid, lane, wm, wn, acc, load_tiles);

    #pragma unroll
    for (int i = 0; i < 4; i++)
        #pragma unroll
        for (int jj = 0; jj < 4; jj++)
            #pragma unroll
            for (int half = 0; half < 2; half++) {
                const int r = bm + wm * 64 + i * 16 + (lane >> 2) + half * 8;
                const int c = bn + wn * 32 + jj * 8 + (lane & 3) * 2;
                const float* rr = res + (long)r * H;
                *(float2*)(C + (long)r * H + c) =
                    make_float2(acc[i][jj][half * 2] + bias[c] + rr[c],
                                acc[i][jj][half * 2 + 1] + bias[c + 1] + rr[c + 1]);
            }
}

// ---------------------------------------------------------------------------
// Flash-fused attention, split-K over ZSPL slices of the key sequence.
// cq band staged per-column: Lb(c) = clamp(bm - c + 512, 0, 888) & ~7,
// guaranteeing la - Lb(c) in [0, 136) for all r in the 128-row tile.
// ---------------------------------------------------------------------------
constexpr int CQ_W     = 144;
constexpr int CQ_ROWB  = CQ_W * 2;            // 288 B per column
constexpr int CQ_BYTES = 64 * CQ_ROWB;        // 18432 per buffer
constexpr int FL_SMEM  = 16384 + 2 * 8192 + 2 * 8192 + 2 * CQ_BYTES;  // 86016
constexpr int HTILES   = (S / 64) / ZSPL;     // 8 key tiles per slice

__global__ void __launch_bounds__(256) flash_attn(
    const bf16* __restrict__ Q, const bf16* __restrict__ K,
    const bf16* __restrict__ Vt,
    const bf16* __restrict__ CKb, const bf16* __restrict__ CQb,
    const int* __restrict__ mask,
    float* __restrict__ Opart, float2* __restrict__ ML)
{
    extern __shared__ __align__(1024) char dyn[];
    const uint32_t uQ  = smem_u32(dyn);
    const uint32_t uK  = uQ + 16384;
    const uint32_t uV  = uK + 16384;
    const uint32_t uCQ = uV + 16384;

    const int tid = threadIdx.x, lane = tid & 31, wid = tid >> 5;
    const int h = blockIdx.y, bm = blockIdx.x * 128;
    const int z = blockIdx.z;
    const int ct0 = z * HTILES;
    const int bmc = bm + 512;

    // per-column band base
    auto lbc = [&](int c) { return min(max(bmc - c, 0), 888) & ~7; };

    {
        const bf16* Qg = Q + (long)bm * H + h * D;
        #pragma unroll
        for (int i = tid; i < 1024; i += 256) {
            int r = i >> 3, c = i & 7;
            cpasync16(uQ + swz128(r, c), Qg + (long)r * H + c * 8);
        }
    }
    CP_COMMIT();

    auto load_kv = [&](int ct, int st) {
        const int c0 = ct * 64;
        const uint32_t uk = uK + st * 8192;
        const uint32_t uv = uV + st * 8192;
        const bf16* Kg = K + (long)c0 * H + h * D;
        #pragma unroll
        for (int i = tid; i < 512; i += 256) {
            int r = i >> 3, c = i & 7;
            cpasync16(uk + swz128(r, c), Kg + (long)r * H + c * 8);
        }
        const bf16* Vg = Vt + (long)(h * D) * S + c0;
        #pragma unroll
        for (int i = tid; i < 512; i += 256) {
            int d = i >> 3, c = i & 7;
            cpasync16(uv + swz128(d, c), Vg + (long)d * S + c * 8);
        }
        // per-column cq band: 64 cols x 144 l-values (18 chunks of 16B)
        const uint32_t ucq = uCQ + st * CQ_BYTES;
        const bf16* CQg = CQb + ((size_t)h * S + c0) * LPOS;
        for (int i = tid; i < 64 * 18; i += 256) {
            int j = i / 18, ch = i % 18;
            int Lb = lbc(c0 + j);
            cpasync16(ucq + j * CQ_ROWB + ch * 16,
                      CQg + (size_t)j * LPOS + Lb + ch * 8);
        }
    };
    load_kv(ct0, 0);
    CP_COMMIT();
    CP_WAIT1();
    __syncthreads();

    uint32_t qf[4][4];
    #pragma unroll
    for (int kk = 0; kk < 4; kk++) {
        int row = wid * 16 + (lane & 15);
        int c16 = kk * 2 + (lane >> 4);
        ldsm4(qf[kk], uQ + swz128(row, c16));
    }

    const int r0 = bm + wid * 16 + (lane >> 2);
    const int r1 = r0 + 8;
    const int m0v = mask[r0], m1v = mask[r1];
    const bf16* ck0 = CKb + ((size_t)h * S + r0) * LPOS;
    const bf16* ck1 = CKb + ((size_t)h * S + r1) * LPOS;

    float m0 = NEGMAX, m1 = NEGMAX, l0 = 0.f, l1 = 0.f;
    float O[8][4] = {};

    for (int it = 0; it < HTILES; it++) {
        const int ct = ct0 + it;
        const int st = it & 1;
        if (it + 1 < HTILES) { load_kv(ct + 1, st ^ 1); CP_COMMIT(); CP_WAIT1(); }
        else                 { CP_WAIT0(); }
        __syncthreads();

        const uint32_t uk = uK + st * 8192;
        const uint32_t uv = uV + st * 8192;
        const bf16* sCQ = (const bf16*)(dyn + (uCQ - uQ) + st * CQ_BYTES);

        float sfr[8][4] = {};
        #pragma unroll
        for (int g = 0; g < 4; g++) {
            #pragma unroll
            for (int kk = 0; kk < 4; kk++) {
                uint32_t r4[4];
                int n   = g * 16 + ((lane >> 4) << 3) + (lane & 7);
                int c16 = kk * 2 + ((lane >> 3) & 1);
                ldsm4(r4, uk + swz128(n, c16));
                mma16816(sfr[2 * g],     qf[kk], r4);
                mma16816(sfr[2 * g + 1], qf[kk], r4 + 2);
            }
        }

        const int c0 = ct * 64;
        float tmx0 = NEGMAX, tmx1 = NEGMAX;
        #pragma unroll
        for (int nb = 0; nb < 8; nb++) {
            const int cl = nb * 8 + (lane & 3) * 2;
            const int c  = c0 + cl;
            const int Lb0 = lbc(c);
            const int Lb1 = lbc(c + 1);
            const int mc0 = mask[c], mc1 = mask[c + 1];
            {
                int la = min(max(r0 - c + 512, 0), LPOS - 1);
                int lb = min(max(r0 - c + 511, 0), LPOS - 1);
                float v0 = (sfr[nb][0] + __bfloat162float(ck0[la])
                            + __bfloat162float(sCQ[cl * CQ_W + (la - Lb0)])) * SCALE;
                float v1 = (sfr[nb][1] + __bfloat162float(ck0[lb])
                            + __bfloat162float(sCQ[(cl + 1) * CQ_W + (lb - Lb1)])) * SCALE;
                if (!(m0v && mc0)) v0 = NEGMAX;
                if (!(m0v && mc1)) v1 = NEGMAX;
                sfr[nb][0] = v0; sfr[nb][1] = v1;
                tmx0 = fmaxf(tmx0, fmaxf(v0, v1));
            }
            {
                int la = min(max(r1 - c + 512, 0), LPOS - 1);
                int lb = min(max(r1 - c + 511, 0), LPOS - 1);
                float v2 = (sfr[nb][2] + __bfloat162float(ck1[la])
                            + __bfloat162float(sCQ[cl * CQ_W + (la - Lb0)])) * SCALE;
                float v3 = (sfr[nb][3] + __bfloat162float(ck1[lb])
                            + __bfloat162float(sCQ[(cl + 1) * CQ_W + (lb - Lb1)])) * SCALE;
                if (!(m1v && mc0)) v2 = NEGMAX;
                if (!(m1v && mc1)) v3 = NEGMAX;
                sfr[nb][2] = v2; sfr[nb][3] = v3;
                tmx1 = fmaxf(tmx1, fmaxf(v2, v3));
            }
        }
        tmx0 = fmaxf(tmx0, __shfl_xor_sync(0xffffffffu, tmx0, 1));
        tmx0 = fmaxf(tmx0, __shfl_xor_sync(0xffffffffu, tmx0, 2));
        tmx1 = fmaxf(tmx1, __shfl_xor_sync(0xffffffffu, tmx1, 1));
        tmx1 = fmaxf(tmx1, __shfl_xor_sync(0xffffffffu, tmx1, 2));

        const float mn0 = fmaxf(m0, tmx0), mn1 = fmaxf(m1, tmx1);
        const float sc0 = __expf(m0 - mn0), sc1 = __expf(m1 - mn1);
        m0 = mn0; m1 = mn1;
        float rs0 = 0.f, rs1 = 0.f;
        #pragma unroll
        for (int nb = 0; nb < 8; nb++) {
            sfr[nb][0] = __expf(sfr[nb][0] - mn0);
            sfr[nb][1] = __expf(sfr[nb][1] - mn0);
            sfr[nb][2] = __expf(sfr[nb][2] - mn1);
            sfr[nb][3] = __expf(sfr[nb][3] - mn1);
            rs0 += sfr[nb][0] + sfr[nb][1];
            rs1 += sfr[nb][2] + sfr[nb][3];
        }
        rs0 += __shfl_xor_sync(0xffffffffu, rs0, 1);
        rs0 += __shfl_xor_sync(0xffffffffu, rs0, 2);
        rs1 += __shfl_xor_sync(0xffffffffu, rs1, 1);
        rs1 += __shfl_xor_sync(0xffffffffu, rs1, 2);
        l0 = l0 * sc0 + rs0;
        l1 = l1 * sc1 + rs1;
        #pragma unroll
        for (int df = 0; df < 8; df++) {
            O[df][0] *= sc0; O[df][1] *= sc0;
            O[df][2] *= sc1; O[df][3] *= sc1;
        }

        #pragma unroll
        for (int kk2 = 0; kk2 < 4; kk2++) {
            uint32_t pf[4];
            pf[0] = packbf2(sfr[2 * kk2][0],     sfr[2 * kk2][1]);
            pf[1] = packbf2(sfr[2 * kk2][2],     sfr[2 * kk2][3]);
            pf[2] = packbf2(sfr[2 * kk2 + 1][0], sfr[2 * kk2 + 1][1]);
            pf[3] = packbf2(sfr[2 * kk2 + 1][2], sfr[2 * kk2 + 1][3]);
            #pragma unroll
            for (int dg = 0; dg < 4; dg++) {
                uint32_t r4[4];
                int n   = dg * 16 + ((lane >> 4) << 3) + (lane & 7);
                int c16 = kk2 * 2 + ((lane >> 3) & 1);
                ldsm4(r4, uv + swz128(n, c16));
                mma16816(O[2 * dg],     pf, r4);
                mma16816(O[2 * dg + 1], pf, r4 + 2);
            }
        }
        __syncthreads();
    }

    const size_t base = ((size_t)z * NH + h) * S;
    if ((lane & 3) == 0) {
        ML[base + r0] = make_float2(m0, l0);
        ML[base + r1] = make_float2(m1, l1);
    }
    float* o0 = Opart + (base + r0) * D + (lane & 3) * 2;
    float* o1 = Opart + (base + r1) * D + (lane & 3) * 2;
    #pragma unroll
    for (int df = 0; df < 8; df++) {
        *(float2*)(o0 + df * 8) = make_float2(O[df][0], O[df][1]);
        *(float2*)(o1 + df * 8) = make_float2(O[df][2], O[df][3]);
    }
}

// ---------------------------------------------------------------------------
// Merge the ZSPL split-K slices -> normalized bf16 context.
// ---------------------------------------------------------------------------
__global__ void __launch_bounds__(256) merge_attn(
    const float* __restrict__ Opart, const float2* __restrict__ ML,
    bf16* __restrict__ CTX)
{
    const int p = blockIdx.x * 8 + (threadIdx.x >> 5);
    const int lane = threadIdx.x & 31;
    const int h = p / S, row = p % S;

    float2 ml[ZSPL];
    float M = NEGMAX;
    #pragma unroll
    for (int zz = 0; zz < ZSPL; zz++) {
        ml[zz] = ML[zz * NH * S + p];
        M = fmaxf(M, ml[zz].x);
    }
    float w[ZSPL], denom = 0.f;
    #pragma unroll
    for (int zz = 0; zz < ZSPL; zz++) {
        w[zz] = __expf(ml[zz].x - M);
        denom += w[zz] * ml[zz].y;
    }
    const float inv = 1.0f / denom;

    const int d = lane * 2;
    float ax = 0.f, ay = 0.f;
    #pragma unroll
    for (int zz = 0; zz < ZSPL; zz++) {
        const float2 v = *(const float2*)(Opart + ((size_t)zz * NH * S + p) * D + d);
        ax += w[zz] * v.x;
        ay += w[zz] * v.y;
    }
    *(__nv_bfloat162*)(CTX + (long)row * H + h * D + d) =
        __float22bfloat162_rn(make_float2(ax * inv, ay * inv));
}

// ---------------------------------------------------------------------------
__global__ void cvt_bf16_2(const float* __restrict__ x0, bf16* __restrict__ y0, int n0,
                           const float* __restrict__ x1, bf16* __restrict__ y1, int n1)
{
    int i = blockIdx.x * 256 + threadIdx.x;
    if (i < n0) y0[i] = __float2bfloat16(x0[i]);
    else if (i < n0 + n1) y1[i - n0] = __float2bfloat16(x1[i - n0]);
}

struct P6 { const float* p[6]; };
__global__ void wtrans6(P6 srcs, bf16* __restrict__ Wt)
{
    __shared__ float t[32][33];
    const float* W = srcs.p[blockIdx.z];
    bf16* dst = Wt + (size_t)blockIdx.z * H * H;
    const int bx = blockIdx.x * 32, by = blockIdx.y * 32;
    #pragma unroll
    for (int i = threadIdx.y; i < 32; i += 8)
        t[i][threadIdx.x] = W[(long)(by + i) * H + bx + threadIdx.x];
    __syncthreads();
    #pragma unroll
    for (int i = threadIdx.y; i < 32; i += 8)
        dst[(long)(bx + i) * H + by + threadIdx.x] = __float2bfloat16(t[threadIdx.x][i]);
}

__global__ void ln_kernel(const float* __restrict__ x,
                          const float* __restrict__ gamma,
                          const float* __restrict__ beta,
                          float* __restrict__ out)
{
    __shared__ float rs[8], rq[8];
    const int s = blockIdx.x, tid = threadIdx.x;
    const float* row = x + (long)s * H;
    float a0 = row[tid], a1 = row[tid + 256], a2 = row[tid + 512];
    float sum = a0 + a1 + a2;
    float sq  = a0 * a0 + a1 * a1 + a2 * a2;
    #pragma unroll
    for (int o = 16; o > 0; o >>= 1) {
        sum += __shfl_xor_sync(0xffffffffu, sum, o);
        sq  += __shfl_xor_sync(0xffffffffu, sq,  o);
    }
    if ((tid & 31) == 0) { rs[tid >> 5] = sum; rq[tid >> 5] = sq; }
    __syncthreads();
    float ts = 0.f, tq = 0.f;
    #pragma unroll
    for (int w = 0; w < 8; w++) { ts += rs[w]; tq += rq[w]; }
    float mean = ts * (1.0f / H);
    float var  = tq * (1.0f / H) - mean * mean;
    float inv  = rsqrtf(var + 1e-7f);
    float* o = out + (long)s * H;
    o[tid]       = (a0 - mean) * inv * gamma[tid]       + beta[tid];
    o[tid + 256] = (a1 - mean) * inv * gamma[tid + 256] + beta[tid + 256];
    o[tid + 512] = (a2 - mean) * inv * gamma[tid + 512] + beta[tid + 512];
}

// ---------------------------------------------------------------------------
extern "C" void kernel_launch(void* const* d_in, const int* in_sizes, int n_in,
                              void* d_out, int out_size)
{
    const float* hidden = (const float*)d_in[0];
    const int*   mask   = (const int*)  d_in[1];
    const float* Wq     = (const float*)d_in[2];
    const float* bq     = (const float*)d_in[3];
    const float* Wk     = (const float*)d_in[4];
    const float* bk     = (const float*)d_in[5];
    const float* Wv     = (const float*)d_in[6];
    const float* bv     = (const float*)d_in[7];
    const float* rel    = (const float*)d_in[8];
    const float* Wpk    = (const float*)d_in[9];
    const float* Wpq    = (const float*)d_in[10];
    const float* bpq    = (const float*)d_in[11];
    const float* Wo     = (const float*)d_in[12];
    const float* bo     = (const float*)d_in[13];
    const float* gamma  = (const float*)d_in[14];
    const float* beta   = (const float*)d_in[15];
    float* out = (float*)d_out;

    bf16 *hbf, *relbf, *Wt, *Qbf, *Kbf, *Vt, *PKbf, *PQbf, *CKb, *CQb, *CTXbf;
    float *TMP, *Opart;
    float2* ML;
    cudaGetSymbolAddress((void**)&hbf,   g_hbf);
    cudaGetSymbolAddress((void**)&relbf, g_relbf);
    cudaGetSymbolAddress((void**)&Wt,    g_Wt);
    cudaGetSymbolAddress((void**)&Qbf,   g_Qbf);
    cudaGetSymbolAddress((void**)&Kbf,   g_Kbf);
    cudaGetSymbolAddress((void**)&Vt,    g_Vt);
    cudaGetSymbolAddress((void**)&PKbf,  g_PKbf);
    cudaGetSymbolAddress((void**)&PQbf,  g_PQbf);
    cudaGetSymbolAddress((void**)&CKb,   g_CKb);
    cudaGetSymbolAddress((void**)&CQb,   g_CQb);
    cudaGetSymbolAddress((void**)&Opart, g_Opart);
    cudaGetSymbolAddress((void**)&ML,    g_ML);
    cudaGetSymbolAddress((void**)&CTXbf, g_CTXbf);
    cudaGetSymbolAddress((void**)&TMP,   g_TMP);

    static bool attr_done = false;
    if (!attr_done) {
        cudaFuncSetAttribute(flash_attn,
                             cudaFuncAttributeMaxDynamicSharedMemorySize, FL_SMEM);
        attr_done = true;
    }

    // --- conversions / transposes ---
    cvt_bf16_2<<<(S * H + LPOS * H + 255) / 256, 256>>>(
        hidden, hbf, S * H, rel, relbf, LPOS * H);
    P6 w6; w6.p[0] = Wq; w6.p[1] = Wk; w6.p[2] = Wv;
    w6.p[3] = Wpk; w6.p[4] = Wpq; w6.p[5] = Wo;
    wtrans6<<<dim3(H/32, H/32, 6), dim3(32, 8)>>>(w6, Wt);

    // --- all five projections in one launch ---
    ProjJobs J;
    J.A[0] = hbf;   J.Bw[0] = Wt + 0 * H * H; J.C[0] = Qbf;  J.bias[0] = bq;      J.mode[0] = 0;
    J.A[1] = hbf;   J.Bw[1] = Wt + 1 * H * H; J.C[1] = Kbf;  J.bias[1] = bk;      J.mode[1] = 0;
    J.A[2] = hbf;   J.Bw[2] = Wt + 2 * H * H; J.C[2] = Vt;   J.bias[2] = bv;      J.mode[2] = 1;
    J.A[3] = relbf; J.Bw[3] = Wt + 3 * H * H; J.C[3] = PKbf; J.bias[3] = nullptr; J.mode[3] = 0;
    J.A[4] = relbf; J.Bw[4] = Wt + 4 * H * H; J.C[4] = PQbf; J.bias[4] = bpq;     J.mode[4] = 0;
    J.start[0] = 0;   J.start[1] = 96;  J.start[2] = 192;
    J.start[3] = 288; J.start[4] = 336; J.start[5] = 384;
    gemm_proj<<<384, 256>>>(J);

    // --- both rel-position tables in one launch ---
    gemm_tables<<<dim3(LPOS/128, S/128, 2 * NH), 256>>>(
        Qbf, Kbf, PKbf, PQbf, CKb, CQb);

    // --- fused attention, split-K over ZSPL slices ---
    flash_attn<<<dim3(S/128, NH, ZSPL), 256, FL_SMEM>>>(
        Qbf, Kbf, Vt, CKb, CQb, mask, Opart, ML);
    merge_attn<<<NH * S / 8, 256>>>(Opart, ML, CTXbf);

    // --- output projection + bias + residual ---
    gemm_out<<<dim3(6, 16), 256>>>(CTXbf, Wt + 5 * H * H, TMP, bo, hidden);

    // --- layernorm ---
    ln_kernel<<<S, 256>>>(TMP, gamma, beta, out);
}

// round 9
// speedup vs baseline: 11.3293x; 1.0299x over previous
#include <cuda_runtime.h>
#include <cuda_bf16.h>
#include <cstdint>

// ---------------------------------------------------------------------------
// BertAttention (DeBERTa) — round 9: 2-stream overlap + fast-path epilogue.
// B=1, S=2048, H=768, NH=12, D=64, SPAN=512
// ---------------------------------------------------------------------------

constexpr int S    = 2048;
constexpr int H    = 768;
constexpr int NH   = 12;
constexpr int D    = 64;
constexpr int LPOS = 1024;  // 2*SPAN
constexpr int ZSPL = 4;     // split-K factor over key sequence
// scores scaled by 1/sqrt(192) * log2(e): softmax done in exp2 domain.
constexpr float SCALE2 = 0.07216878364870322f * 1.4426950408889634f;
constexpr float NEGMAX = -3.402823466e38f;

using bf16 = __nv_bfloat16;

// ---------------------------- scratch (device globals) ---------------------
__device__ bf16   g_hbf  [S * H];
__device__ bf16   g_relbf[LPOS * H];
__device__ bf16   g_Wt   [6 * H * H];
__device__ bf16   g_Qbf  [S * H];
__device__ bf16   g_Kbf  [S * H];
__device__ bf16   g_Vt   [H * S];
__device__ bf16   g_PKbf [LPOS * H];
__device__ bf16   g_PQbf [LPOS * H];
__device__ bf16   g_CKb  [(size_t)NH * S * LPOS];
__device__ bf16   g_CQb  [(size_t)NH * S * LPOS + 256];
__device__ float  g_Opart[(size_t)ZSPL * NH * S * D];
__device__ float2 g_ML   [ZSPL * NH * S];
__device__ bf16   g_CTXbf[S * H];
__device__ float  g_TMP  [S * H];

// ---------------------------- PTX helpers ----------------------------------
__device__ __forceinline__ uint32_t smem_u32(const void* p) {
    uint32_t a;
    asm("{ .reg .u64 t; cvta.to.shared.u64 t, %1; cvt.u32.u64 %0, t; }"
        : "=r"(a) : "l"(p));
    return a;
}
__device__ __forceinline__ void cpasync16(uint32_t dst, const void* src) {
    asm volatile("cp.async.cg.shared.global [%0], [%1], 16;" :: "r"(dst), "l"(src));
}
#define CP_COMMIT() asm volatile("cp.async.commit_group;" ::: "memory")
#define CP_WAIT1()  asm volatile("cp.async.wait_group 1;" ::: "memory")
#define CP_WAIT0()  asm volatile("cp.async.wait_group 0;" ::: "memory")

__device__ __forceinline__ void ldsm4(uint32_t* r, uint32_t addr) {
    asm volatile("ldmatrix.sync.aligned.m8n8.x4.shared.b16 {%0,%1,%2,%3}, [%4];"
                 : "=r"(r[0]), "=r"(r[1]), "=r"(r[2]), "=r"(r[3]) : "r"(addr));
}
__device__ __forceinline__ void mma16816(float* c, const uint32_t* a, const uint32_t* b) {
    asm volatile(
        "mma.sync.aligned.m16n8k16.row.col.f32.bf16.bf16.f32 "
        "{%0,%1,%2,%3}, {%4,%5,%6,%7}, {%8,%9}, {%0,%1,%2,%3};"
        : "+f"(c[0]), "+f"(c[1]), "+f"(c[2]), "+f"(c[3])
        : "r"(a[0]), "r"(a[1]), "r"(a[2]), "r"(a[3]), "r"(b[0]), "r"(b[1]));
}
__device__ __forceinline__ uint32_t packbf2(float a, float b) {
    __nv_bfloat162 t = __float22bfloat162_rn(make_float2(a, b));
    return *(uint32_t*)&t;
}

__device__ __forceinline__ uint32_t swz(int row, int chunk) {
    return (uint32_t)(row * 64 + ((chunk ^ ((row >> 1) & 3)) << 4));
}
__device__ __forceinline__ uint32_t swz128(int row, int c16) {
    return (uint32_t)(row * 128 + ((c16 ^ (row & 7)) << 4));
}

// ---------------------------------------------------------------------------
// Shared GEMM mainloop (128x128 tile, K-major bf16, NT).
// ---------------------------------------------------------------------------
struct SmemPtrs { uint32_t uA, uB; };

template<typename LoadFn>
__device__ __forceinline__ void gemm_core(
    int nch, SmemPtrs sp, int tid, int lane, int wm, int wn,
    float (&acc)[4][4][4], LoadFn load_tiles)
{
    constexpr int ABYTES = 128 * 32 * 2;
    constexpr int BBYTES = 128 * 32 * 2;
    load_tiles(0, 0);
    CP_COMMIT();
    for (int ch = 0; ch < nch; ch++) {
        const int st = ch & 1;
        if (ch + 1 < nch) { load_tiles(ch + 1, st ^ 1); CP_COMMIT(); CP_WAIT1(); }
        else              { CP_WAIT0(); }
        __syncthreads();
        const uint32_t bA = sp.uA + st * ABYTES;
        const uint32_t bB = sp.uB + st * BBYTES;
        #pragma unroll
        for (int kk = 0; kk < 2; kk++) {
            uint32_t afr[4][4];
            #pragma unroll
            for (int i = 0; i < 4; i++) {
                int row = wm * 64 + i * 16 + (lane & 15);
                int chk = kk * 2 + (lane >> 4);
                ldsm4(afr[i], bA + swz(row, chk));
            }
            uint32_t bfr[4][2];
            #pragma unroll
            for (int p = 0; p < 2; p++) {
                uint32_t r4[4];
                int n   = wn * 32 + p * 16 + ((lane >> 4) << 3) + (lane & 7);
                int chk = kk * 2 + ((lane >> 3) & 1);
                ldsm4(r4, bB + swz(n, chk));
                bfr[2 * p][0] = r4[0]; bfr[2 * p][1] = r4[1];
                bfr[2 * p + 1][0] = r4[2]; bfr[2 * p + 1][1] = r4[3];
            }
            #pragma unroll
            for (int i = 0; i < 4; i++)
                #pragma unroll
                for (int j = 0; j < 4; j++)
                    mma16816(acc[i][j], afr[i], bfr[j]);
        }
        __syncthreads();
    }
}

// ---------------------------------------------------------------------------
// Fused projection kernel: 5 jobs (Q, K, V->Vt, PK, PQ) in one 1-D grid.
// ---------------------------------------------------------------------------
struct ProjJobs {
    const bf16* A[5];
    const bf16* Bw[5];
    bf16*       C[5];
    const float* bias[5];
    int mode[5];
    int start[6];
};

__global__ void __launch_bounds__(256) gemm_proj(ProjJobs J)
{
    constexpr int ABYTES = 128 * 32 * 2, BBYTES = 128 * 32 * 2;
    __shared__ __align__(1024) char sm[2 * (ABYTES + BBYTES)];
    SmemPtrs sp { smem_u32(sm), smem_u32(sm) + 2 * ABYTES };

    int bx = blockIdx.x;
    int j = 0;
    while (bx >= J.start[j + 1]) j++;
    const int local = bx - J.start[j];
    const int bm = (local / 6) * 128, bn = (local % 6) * 128;

    const int tid = threadIdx.x, lane = tid & 31, wid = tid >> 5;
    const int wm = wid & 1, wn = wid >> 1;

    const bf16* Arow = J.A[j] + (long)bm * H;
    const bf16* Brow = J.Bw[j] + (long)bn * H;

    auto load_tiles = [&](int ch, int st) {
        const bf16* Ak = Arow + ch * 32;
        #pragma unroll
        for (int i = tid; i < 512; i += 256) {
            int r = i >> 2, c = i & 3;
            cpasync16(sp.uA + st * ABYTES + swz(r, c), Ak + (long)r * H + c * 8);
        }
        const bf16* Bk = Brow + ch * 32;
        #pragma unroll
        for (int i = tid; i < 512; i += 256) {
            int r = i >> 2, c = i & 3;
            cpasync16(sp.uB + st * BBYTES + swz(r, c), Bk + (long)r * H + c * 8);
        }
    };

    float acc[4][4][4] = {};
    gemm_core(H / 32, sp, tid, lane, wm, wn, acc, load_tiles);

    bf16* C = J.C[j];
    const float* bias = J.bias[j];
    const int mode = J.mode[j];

    #pragma unroll
    for (int i = 0; i < 4; i++)
        #pragma unroll
        for (int jj = 0; jj < 4; jj++)
            #pragma unroll
            for (int half = 0; half < 2; half++) {
                const int r = bm + wm * 64 + i * 16 + (lane >> 2) + half * 8;
                const int c = bn + wn * 32 + jj * 8 + (lane & 3) * 2;
                const float v0 = acc[i][jj][half * 2];
                const float v1 = acc[i][jj][half * 2 + 1];
                float b0 = bias ? bias[c] : 0.f, b1 = bias ? bias[c + 1] : 0.f;
                if (mode == 0) {
                    *(__nv_bfloat162*)(C + (long)r * H + c) =
                        __float22bfloat162_rn(make_float2(v0 + b0, v1 + b1));
                } else {
                    C[(long)c * S + r]       = __float2bfloat16(v0 + b0);
                    C[(long)(c + 1) * S + r] = __float2bfloat16(v1 + b1);
                }
            }
}

// ---------------------------------------------------------------------------
// Fused tables kernel (head range via hbase): z<6 -> CK head hbase+z ;
// z>=6 -> CQ head hbase+z-6. Smem-staged coalesced output stores.
// ---------------------------------------------------------------------------
constexpr int TB_STRIDE = 272;

__global__ void __launch_bounds__(256) gemm_tables(
    const bf16* __restrict__ Qb, const bf16* __restrict__ Kb,
    const bf16* __restrict__ PK, const bf16* __restrict__ PQ,
    bf16* __restrict__ CK, bf16* __restrict__ CQ, int hbase)
{
    constexpr int ABYTES = 128 * 32 * 2, BBYTES = 128 * 32 * 2;
    __shared__ __align__(1024) char sm[128 * TB_STRIDE];
    SmemPtrs sp { smem_u32(sm), smem_u32(sm) + 2 * ABYTES };

    const int z = blockIdx.z;
    const bool isCK = z < 6;
    const int h = hbase + (isCK ? z : z - 6);
    const bf16* A = (isCK ? Qb : Kb) + h * D;
    const bf16* B = (isCK ? PK : PQ) + h * D;
    bf16* C = (isCK ? CK : CQ) + (size_t)h * S * LPOS;

    const int tid = threadIdx.x, lane = tid & 31, wid = tid >> 5;
    const int wm = wid & 1, wn = wid >> 1;
    const int bm = blockIdx.y * 128, bn = blockIdx.x * 128;

    const bf16* Arow = A + (long)bm * H;
    const bf16* Brow = B + (long)bn * H;

    auto load_tiles = [&](int ch, int st) {
        const bf16* Ak = Arow + ch * 32;
        #pragma unroll
        for (int i = tid; i < 512; i += 256) {
            int r = i >> 2, c = i & 3;
            cpasync16(sp.uA + st * ABYTES + swz(r, c), Ak + (long)r * H + c * 8);
        }
        const bf16* Bk = Brow + ch * 32;
        #pragma unroll
        for (int i = tid; i < 512; i += 256) {
            int r = i >> 2, c = i & 3;
            cpasync16(sp.uB + st * BBYTES + swz(r, c), Bk + (long)r * H + c * 8);
        }
    };

    float acc[4][4][4] = {};
    gemm_core(D / 32, sp, tid, lane, wm, wn, acc, load_tiles);

    #pragma unroll
    for (int i = 0; i < 4; i++)
        #pragma unroll
        for (int jj = 0; jj < 4; jj++)
            #pragma unroll
            for (int half = 0; half < 2; half++) {
                const int rl = wm * 64 + i * 16 + (lane >> 2) + half * 8;
                const int cl = wn * 32 + jj * 8 + (lane & 3) * 2;
                *(uint32_t*)(sm + rl * TB_STRIDE + cl * 2) =
                    packbf2(acc[i][jj][half * 2], acc[i][jj][half * 2 + 1]);
            }
    __syncthreads();

    #pragma unroll
    for (int i = tid; i < 2048; i += 256) {
        int r = i >> 4, ch = i & 15;
        uint4 v = *(uint4*)(sm + r * TB_STRIDE + ch * 16);
        *(uint4*)(C + (long)(bm + r) * LPOS + bn + ch * 8) = v;
    }
}

// ---------------------------------------------------------------------------
// Output projection + bias + residual (fp32 out).
// ---------------------------------------------------------------------------
__global__ void __launch_bounds__(256) gemm_out(
    const bf16* __restrict__ A, const bf16* __restrict__ Bw,
    float* __restrict__ C, const float* __restrict__ bias,
    const float* __restrict__ res)
{
    constexpr int ABYTES = 128 * 32 * 2, BBYTES = 128 * 32 * 2;
    __shared__ __align__(1024) char sm[2 * (ABYTES + BBYTES)];
    SmemPtrs sp { smem_u32(sm), smem_u32(sm) + 2 * ABYTES };

    const int tid = threadIdx.x, lane = tid & 31, wid = tid >> 5;
    const int wm = wid & 1, wn = wid >> 1;
    const int bm = blockIdx.y * 128, bn = blockIdx.x * 128;

    const bf16* Arow = A + (long)bm * H;
    const bf16* Brow = Bw + (long)bn * H;

    auto load_tiles = [&](int ch, int st) {
        const bf16* Ak = Arow + ch * 32;
        #pragma unroll
        for (int i = tid; i < 512; i += 256) {
            int r = i >> 2, c = i & 3;
            cpasync16(sp.uA + st * ABYTES + swz(r, c), Ak + (long)r * H + c * 8);
        }
        const bf16* Bk = Brow + ch * 32;
        #pragma unroll
        for (int i = tid; i < 512; i += 256) {
            int r = i >> 2, c = i & 3;
            cpasync16(sp.uB + st * BBYTES + swz(r, c), Bk + (long)r * H + c * 8);
        }
    };

    float acc[4][4][4] = {};
    gemm_core(H / 32, sp, tid, lane, wm, wn, acc, load_tiles);

    #pragma unroll
    for (int i = 0; i < 4; i++)
        #pragma unroll
        for (int jj = 0; jj < 4; jj++)
            #pragma unroll
            for (int half = 0; half < 2; half++) {
                const int r = bm + wm * 64 + i * 16 + (lane >> 2) + half * 8;
                const int c = bn + wn * 32 + jj * 8 + (lane & 3) * 2;
                const float* rr = res + (long)r * H;
                *(float2*)(C + (long)r * H + c) =
                    make_float2(acc[i][jj][half * 2] + bias[c] + rr[c],
                                acc[i][jj][half * 2 + 1] + bias[c + 1] + rr[c + 1]);
            }
}

// ---------------------------------------------------------------------------
// Flash-fused attention (head range via hbase), split-K over ZSPL slices.
// exp2-domain softmax; per-tile no-clip fast path for rel-pos indices.
// ---------------------------------------------------------------------------
constexpr int CQ_W     = 144;
constexpr int CQ_ROWB  = CQ_W * 2;
constexpr int CQ_BYTES = 64 * CQ_ROWB;
constexpr int FL_SMEM  = 16384 + 2 * 8192 + 2 * 8192 + 2 * CQ_BYTES;  // 86016
constexpr int HTILES   = (S / 64) / ZSPL;

__global__ void __launch_bounds__(256) flash_attn(
    const bf16* __restrict__ Q, const bf16* __restrict__ K,
    const bf16* __restrict__ Vt,
    const bf16* __restrict__ CKb, const bf16* __restrict__ CQb,
    const int* __restrict__ mask,
    float* __restrict__ Opart, float2* __restrict__ ML, int hbase)
{
    extern __shared__ __align__(1024) char dyn[];
    const uint32_t uQ  = smem_u32(dyn);
    const uint32_t uK  = uQ + 16384;
    const uint32_t uV  = uK + 16384;
    const uint32_t uCQ = uV + 16384;

    const int tid = threadIdx.x, lane = tid & 31, wid = tid >> 5;
    const int h = hbase + blockIdx.y, bm = blockIdx.x * 128;
    const int z = blockIdx.z;
    const int ct0 = z * HTILES;
    const int bmc = bm + 512;

    auto lbc = [&](int c) { return min(max(bmc - c, 0), 888) & ~7; };

    {
        const bf16* Qg = Q + (long)bm * H + h * D;
        #pragma unroll
        for (int i = tid; i < 1024; i += 256) {
            int r = i >> 3, c = i & 7;
            cpasync16(uQ + swz128(r, c), Qg + (long)r * H + c * 8);
        }
    }
    CP_COMMIT();

    auto load_kv = [&](int ct, int st) {
        const int c0 = ct * 64;
        const uint32_t uk = uK + st * 8192;
        const uint32_t uv = uV + st * 8192;
        const bf16* Kg = K + (long)c0 * H + h * D;
        #pragma unroll
        for (int i = tid; i < 512; i += 256) {
            int r = i >> 3, c = i & 7;
            cpasync16(uk + swz128(r, c), Kg + (long)r * H + c * 8);
        }
        const bf16* Vg = Vt + (long)(h * D) * S + c0;
        #pragma unroll
        for (int i = tid; i < 512; i += 256) {
            int d = i >> 3, c = i & 7;
            cpasync16(uv + swz128(d, c), Vg + (long)d * S + c * 8);
        }
        const uint32_t ucq = uCQ + st * CQ_BYTES;
        const bf16* CQg = CQb + ((size_t)h * S + c0) * LPOS;
        for (int i = tid; i < 64 * 18; i += 256) {
            int j = i / 18, ch = i % 18;
            int Lb = lbc(c0 + j);
            cpasync16(ucq + j * CQ_ROWB + ch * 16,
                      CQg + (size_t)j * LPOS + Lb + ch * 8);
        }
    };
    load_kv(ct0, 0);
    CP_COMMIT();
    CP_WAIT1();
    __syncthreads();

    uint32_t qf[4][4];
    #pragma unroll
    for (int kk = 0; kk < 4; kk++) {
        int row = wid * 16 + (lane & 15);
        int c16 = kk * 2 + (lane >> 4);
        ldsm4(qf[kk], uQ + swz128(row, c16));
    }

    const int r0 = bm + wid * 16 + (lane >> 2);
    const int r1 = r0 + 8;
    const int m0v = mask[r0], m1v = mask[r1];
    const bf16* ck0 = CKb + ((size_t)h * S + r0) * LPOS;
    const bf16* ck1 = CKb + ((size_t)h * S + r1) * LPOS;

    float m0 = NEGMAX, m1 = NEGMAX, l0 = 0.f, l1 = 0.f;
    float O[8][4] = {};

    for (int it = 0; it < HTILES; it++) {
        const int ct = ct0 + it;
        const int st = it & 1;
        if (it + 1 < HTILES) { load_kv(ct + 1, st ^ 1); CP_COMMIT(); CP_WAIT1(); }
        else                 { CP_WAIT0(); }
        __syncthreads();

        const uint32_t uk = uK + st * 8192;
        const uint32_t uv = uV + st * 8192;
        const bf16* sCQ = (const bf16*)(dyn + (uCQ - uQ) + st * CQ_BYTES);

        float sfr[8][4] = {};
        #pragma unroll
        for (int g = 0; g < 4; g++) {
            #pragma unroll
            for (int kk = 0; kk < 4; kk++) {
                uint32_t r4[4];
                int n   = g * 16 + ((lane >> 4) << 3) + (lane & 7);
                int c16 = kk * 2 + ((lane >> 3) & 1);
                ldsm4(r4, uk + swz128(n, c16));
                mma16816(sfr[2 * g],     qf[kk], r4);
                mma16816(sfr[2 * g + 1], qf[kk], r4 + 2);
            }
        }

        const int c0 = ct * 64;
        const int dRC = bm - c0;
        const bool noclip = (dRC >= -449) && (dRC <= 384);
        float tmx0 = NEGMAX, tmx1 = NEGMAX;

        if (noclip) {
            #pragma unroll
            for (int nb = 0; nb < 8; nb++) {
                const int cl = nb * 8 + (lane & 3) * 2;
                const int c  = c0 + cl;
                const int Lb0 = lbc(c);
                const int Lb1 = lbc(c + 1);
                const int mc0 = mask[c], mc1 = mask[c + 1];
                {
                    int la = r0 - c + 512, lb = la - 1;
                    float v0 = (sfr[nb][0] + __bfloat162float(ck0[la])
                                + __bfloat162float(sCQ[cl * CQ_W + (la - Lb0)])) * SCALE2;
                    float v1 = (sfr[nb][1] + __bfloat162float(ck0[lb])
                                + __bfloat162float(sCQ[(cl + 1) * CQ_W + (lb - Lb1)])) * SCALE2;
                    if (!(m0v && mc0)) v0 = NEGMAX;
                    if (!(m0v && mc1)) v1 = NEGMAX;
                    sfr[nb][0] = v0; sfr[nb][1] = v1;
                    tmx0 = fmaxf(tmx0, fmaxf(v0, v1));
                }
                {
                    int la = r1 - c + 512, lb = la - 1;
                    float v2 = (sfr[nb][2] + __bfloat162float(ck1[la])
                                + __bfloat162float(sCQ[cl * CQ_W + (la - Lb0)])) * SCALE2;
                    float v3 = (sfr[nb][3] + __bfloat162float(ck1[lb])
                                + __bfloat162float(sCQ[(cl + 1) * CQ_W + (lb - Lb1)])) * SCALE2;
                    if (!(m1v && mc0)) v2 = NEGMAX;
                    if (!(m1v && mc1)) v3 = NEGMAX;
                    sfr[nb][2] = v2; sfr[nb][3] = v3;
                    tmx1 = fmaxf(tmx1, fmaxf(v2, v3));
                }
            }
        } else {
            #pragma unroll
            for (int nb = 0; nb < 8; nb++) {
                const int cl = nb * 8 + (lane & 3) * 2;
                const int c  = c0 + cl;
                const int Lb0 = lbc(c);
                const int Lb1 = lbc(c + 1);
                const int mc0 = mask[c], mc1 = mask[c + 1];
                {
                    int la = min(max(r0 - c + 512, 0), LPOS - 1);
                    int lb = min(max(r0 - c + 511, 0), LPOS - 1);
                    float v0 = (sfr[nb][0] + __bfloat162float(ck0[la])
                                + __bfloat162float(sCQ[cl * CQ_W + (la - Lb0)])) * SCALE2;
                    float v1 = (sfr[nb][1] + __bfloat162float(ck0[lb])
                                + __bfloat162float(sCQ[(cl + 1) * CQ_W + (lb - Lb1)])) * SCALE2;
                    if (!(m0v && mc0)) v0 = NEGMAX;
                    if (!(m0v && mc1)) v1 = NEGMAX;
                    sfr[nb][0] = v0; sfr[nb][1] = v1;
                    tmx0 = fmaxf(tmx0, fmaxf(v0, v1));
                }
                {
                    int la = min(max(r1 - c + 512, 0), LPOS - 1);
                    int lb = min(max(r1 - c + 511, 0), LPOS - 1);
                    float v2 = (sfr[nb][2] + __bfloat162float(ck1[la])
                                + __bfloat162float(sCQ[cl * CQ_W + (la - Lb0)])) * SCALE2;
                    float v3 = (sfr[nb][3] + __bfloat162float(ck1[lb])
                                + __bfloat162float(sCQ[(cl + 1) * CQ_W + (lb - Lb1)])) * SCALE2;
                    if (!(m1v && mc0)) v2 = NEGMAX;
                    if (!(m1v && mc1)) v3 = NEGMAX;
                    sfr[nb][2] = v2; sfr[nb][3] = v3;
                    tmx1 = fmaxf(tmx1, fmaxf(v2, v3));
                }
            }
        }
        tmx0 = fmaxf(tmx0, __shfl_xor_sync(0xffffffffu, tmx0, 1));
        tmx0 = fmaxf(tmx0, __shfl_xor_sync(0xffffffffu, tmx0, 2));
        tmx1 = fmaxf(tmx1, __shfl_xor_sync(0xffffffffu, tmx1, 1));
        tmx1 = fmaxf(tmx1, __shfl_xor_sync(0xffffffffu, tmx1, 2));

        const float mn0 = fmaxf(m0, tmx0), mn1 = fmaxf(m1, tmx1);
        const float sc0 = exp2f(m0 - mn0), sc1 = exp2f(m1 - mn1);
        m0 = mn0; m1 = mn1;
        float rs0 = 0.f, rs1 = 0.f;
        #pragma unroll
        for (int nb = 0; nb < 8; nb++) {
            sfr[nb][0] = exp2f(sfr[nb][0] - mn0);
            sfr[nb][1] = exp2f(sfr[nb][1] - mn0);
            sfr[nb][2] = exp2f(sfr[nb][2] - mn1);
            sfr[nb][3] = exp2f(sfr[nb][3] - mn1);
            rs0 += sfr[nb][0] + sfr[nb][1];
            rs1 += sfr[nb][2] + sfr[nb][3];
        }
        rs0 += __shfl_xor_sync(0xffffffffu, rs0, 1);
        rs0 += __shfl_xor_sync(0xffffffffu, rs0, 2);
        rs1 += __shfl_xor_sync(0xffffffffu, rs1, 1);
        rs1 += __shfl_xor_sync(0xffffffffu, rs1, 2);
        l0 = l0 * sc0 + rs0;
        l1 = l1 * sc1 + rs1;
        #pragma unroll
        for (int df = 0; df < 8; df++) {
            O[df][0] *= sc0; O[df][1] *= sc0;
            O[df][2] *= sc1; O[df][3] *= sc1;
        }

        #pragma unroll
        for (int kk2 = 0; kk2 < 4; kk2++) {
            uint32_t pf[4];
            pf[0] = packbf2(sfr[2 * kk2][0],     sfr[2 * kk2][1]);
            pf[1] = packbf2(sfr[2 * kk2][2],     sfr[2 * kk2][3]);
            pf[2] = packbf2(sfr[2 * kk2 + 1][0], sfr[2 * kk2 + 1][1]);
            pf[3] = packbf2(sfr[2 * kk2 + 1][2], sfr[2 * kk2 + 1][3]);
            #pragma unroll
            for (int dg = 0; dg < 4; dg++) {
                uint32_t r4[4];
                int n   = dg * 16 + ((lane >> 4) << 3) + (lane & 7);
                int c16 = kk2 * 2 + ((lane >> 3) & 1);
                ldsm4(r4, uv + swz128(n, c16));
                mma16816(O[2 * dg],     pf, r4);
                mma16816(O[2 * dg + 1], pf, r4 + 2);
            }
        }
        __syncthreads();
    }

    const size_t base = ((size_t)z * NH + h) * S;
    if ((lane & 3) == 0) {
        ML[base + r0] = make_float2(m0, l0);
        ML[base + r1] = make_float2(m1, l1);
    }
    float* o0 = Opart + (base + r0) * D + (lane & 3) * 2;
    float* o1 = Opart + (base + r1) * D + (lane & 3) * 2;
    #pragma unroll
    for (int df = 0; df < 8; df++) {
        *(float2*)(o0 + df * 8) = make_float2(O[df][0], O[df][1]);
        *(float2*)(o1 + df * 8) = make_float2(O[df][2], O[df][3]);
    }
}

// ---------------------------------------------------------------------------
// Merge the ZSPL split-K slices (exp2 domain) -> normalized bf16 context.
// ---------------------------------------------------------------------------
__global__ void __launch_bounds__(256) merge_attn(
    const float* __restrict__ Opart, const float2* __restrict__ ML,
    bf16* __restrict__ CTX)
{
    const int p = blockIdx.x * 8 + (threadIdx.x >> 5);
    const int lane = threadIdx.x & 31;
    const int h = p / S, row = p % S;

    float2 ml[ZSPL];
    float M = NEGMAX;
    #pragma unroll
    for (int zz = 0; zz < ZSPL; zz++) {
        ml[zz] = ML[zz * NH * S + p];
        M = fmaxf(M, ml[zz].x);
    }
    float w[ZSPL], denom = 0.f;
    #pragma unroll
    for (int zz = 0; zz < ZSPL; zz++) {
        w[zz] = exp2f(ml[zz].x - M);
        denom += w[zz] * ml[zz].y;
    }
    const float inv = 1.0f / denom;

    const int d = lane * 2;
    float ax = 0.f, ay = 0.f;
    #pragma unroll
    for (int zz = 0; zz < ZSPL; zz++) {
        const float2 v = *(const float2*)(Opart + ((size_t)zz * NH * S + p) * D + d);
        ax += w[zz] * v.x;
        ay += w[zz] * v.y;
    }
    *(__nv_bfloat162*)(CTX + (long)row * H + h * D + d) =
        __float22bfloat162_rn(make_float2(ax * inv, ay * inv));
}

// ---------------------------------------------------------------------------
__global__ void cvt_bf16_2(const float* __restrict__ x0, bf16* __restrict__ y0, int n0,
                           const float* __restrict__ x1, bf16* __restrict__ y1, int n1)
{
    int i = blockIdx.x * 256 + threadIdx.x;
    if (i < n0) y0[i] = __float2bfloat16(x0[i]);
    else if (i < n0 + n1) y1[i - n0] = __float2bfloat16(x1[i - n0]);
}

struct P6 { const float* p[6]; };
__global__ void wtrans6(P6 srcs, bf16* __restrict__ Wt)
{
    __shared__ float t[32][33];
    const float* W = srcs.p[blockIdx.z];
    bf16* dst = Wt + (size_t)blockIdx.z * H * H;
    const int bx = blockIdx.x * 32, by = blockIdx.y * 32;
    #pragma unroll
    for (int i = threadIdx.y; i < 32; i += 8)
        t[i][threadIdx.x] = W[(long)(by + i) * H + bx + threadIdx.x];
    __syncthreads();
    #pragma unroll
    for (int i = threadIdx.y; i < 32; i += 8)
        dst[(long)(bx + i) * H + by + threadIdx.x] = __float2bfloat16(t[threadIdx.x][i]);
}

__global__ void ln_kernel(const float* __restrict__ x,
                          const float* __restrict__ gamma,
                          const float* __restrict__ beta,
                          float* __restrict__ out)
{
    __shared__ float rs[8], rq[8];
    const int s = blockIdx.x, tid = threadIdx.x;
    const float* row = x + (long)s * H;
    float a0 = row[tid], a1 = row[tid + 256], a2 = row[tid + 512];
    float sum = a0 + a1 + a2;
    float sq  = a0 * a0 + a1 * a1 + a2 * a2;
    #pragma unroll
    for (int o = 16; o > 0; o >>= 1) {
        sum += __shfl_xor_sync(0xffffffffu, sum, o);
        sq  += __shfl_xor_sync(0xffffffffu, sq,  o);
    }
    if ((tid & 31) == 0) { rs[tid >> 5] = sum; rq[tid >> 5] = sq; }
    __syncthreads();
    float ts = 0.f, tq = 0.f;
    #pragma unroll
    for (int w = 0; w < 8; w++) { ts += rs[w]; tq += rq[w]; }
    float mean = ts * (1.0f / H);
    float var  = tq * (1.0f / H) - mean * mean;
    float inv  = rsqrtf(var + 1e-7f);
    float* o = out + (long)s * H;
    o[tid]       = (a0 - mean) * inv * gamma[tid]       + beta[tid];
    o[tid + 256] = (a1 - mean) * inv * gamma[tid + 256] + beta[tid + 256];
    o[tid + 512] = (a2 - mean) * inv * gamma[tid + 512] + beta[tid + 512];
}

// ---------------------------------------------------------------------------
extern "C" void kernel_launch(void* const* d_in, const int* in_sizes, int n_in,
                              void* d_out, int out_size)
{
    const float* hidden = (const float*)d_in[0];
    const int*   mask   = (const int*)  d_in[1];
    const float* Wq     = (const float*)d_in[2];
    const float* bq     = (const float*)d_in[3];
    const float* Wk     = (const float*)d_in[4];
    const float* bk     = (const float*)d_in[5];
    const float* Wv     = (const float*)d_in[6];
    const float* bv     = (const float*)d_in[7];
    const float* rel    = (const float*)d_in[8];
    const float* Wpk    = (const float*)d_in[9];
    const float* Wpq    = (const float*)d_in[10];
    const float* bpq    = (const float*)d_in[11];
    const float* Wo     = (const float*)d_in[12];
    const float* bo     = (const float*)d_in[13];
    const float* gamma  = (const float*)d_in[14];
    const float* beta   = (const float*)d_in[15];
    float* out = (float*)d_out;

    bf16 *hbf, *relbf, *Wt, *Qbf, *Kbf, *Vt, *PKbf, *PQbf, *CKb, *CQb, *CTXbf;
    float *TMP, *Opart;
    float2* ML;
    cudaGetSymbolAddress((void**)&hbf,   g_hbf);
    cudaGetSymbolAddress((void**)&relbf, g_relbf);
    cudaGetSymbolAddress((void**)&Wt,    g_Wt);
    cudaGetSymbolAddress((void**)&Qbf,   g_Qbf);
    cudaGetSymbolAddress((void**)&Kbf,   g_Kbf);
    cudaGetSymbolAddress((void**)&Vt,    g_Vt);
    cudaGetSymbolAddress((void**)&PKbf,  g_PKbf);
    cudaGetSymbolAddress((void**)&PQbf,  g_PQbf);
    cudaGetSymbolAddress((void**)&CKb,   g_CKb);
    cudaGetSymbolAddress((void**)&CQb,   g_CQb);
    cudaGetSymbolAddress((void**)&Opart, g_Opart);
    cudaGetSymbolAddress((void**)&ML,    g_ML);
    cudaGetSymbolAddress((void**)&CTXbf, g_CTXbf);
    cudaGetSymbolAddress((void**)&TMP,   g_TMP);

    static cudaStream_t s1 = nullptr, s2 = nullptr;
    static cudaEvent_t evP = nullptr, evF1 = nullptr, evF2 = nullptr;
    static bool init_done = false;
    if (!init_done) {
        cudaFuncSetAttribute(flash_attn,
                             cudaFuncAttributeMaxDynamicSharedMemorySize, FL_SMEM);
        cudaStreamCreateWithFlags(&s1, cudaStreamNonBlocking);
        cudaStreamCreateWithFlags(&s2, cudaStreamNonBlocking);
        cudaEventCreateWithFlags(&evP,  cudaEventDisableTiming);
        cudaEventCreateWithFlags(&evF1, cudaEventDisableTiming);
        cudaEventCreateWithFlags(&evF2, cudaEventDisableTiming);
        init_done = true;
    }

    // --- conversions / transposes (default stream) ---
    cvt_bf16_2<<<(S * H + LPOS * H + 255) / 256, 256>>>(
        hidden, hbf, S * H, rel, relbf, LPOS * H);
    P6 w6; w6.p[0] = Wq; w6.p[1] = Wk; w6.p[2] = Wv;
    w6.p[3] = Wpk; w6.p[4] = Wpq; w6.p[5] = Wo;
    wtrans6<<<dim3(H/32, H/32, 6), dim3(32, 8)>>>(w6, Wt);

    // --- all five projections in one launch (default stream) ---
    ProjJobs J;
    J.A[0] = hbf;   J.Bw[0] = Wt + 0 * H * H; J.C[0] = Qbf;  J.bias[0] = bq;      J.mode[0] = 0;
    J.A[1] = hbf;   J.Bw[1] = Wt + 1 * H * H; J.C[1] = Kbf;  J.bias[1] = bk;      J.mode[1] = 0;
    J.A[2] = hbf;   J.Bw[2] = Wt + 2 * H * H; J.C[2] = Vt;   J.bias[2] = bv;      J.mode[2] = 1;
    J.A[3] = relbf; J.Bw[3] = Wt + 3 * H * H; J.C[3] = PKbf; J.bias[3] = nullptr; J.mode[3] = 0;
    J.A[4] = relbf; J.Bw[4] = Wt + 4 * H * H; J.C[4] = PQbf; J.bias[4] = bpq;     J.mode[4] = 0;
    J.start[0] = 0;   J.start[1] = 96;  J.start[2] = 192;
    J.start[3] = 288; J.start[4] = 336; J.start[5] = 384;
    gemm_proj<<<384, 256>>>(J);
    cudaEventRecord(evP, 0);

    // --- fork: per-head-half tables -> flash on two streams ---
    cudaStreamWaitEvent(s1, evP, 0);
    gemm_tables<<<dim3(LPOS/128, S/128, 12), 256, 0, s1>>>(
        Qbf, Kbf, PKbf, PQbf, CKb, CQb, 0);
    flash_attn<<<dim3(S/128, NH/2, ZSPL), 256, FL_SMEM, s1>>>(
        Qbf, Kbf, Vt, CKb, CQb, mask, Opart, ML, 0);
    cudaEventRecord(evF1, s1);

    cudaStreamWaitEvent(s2, evP, 0);
    gemm_tables<<<dim3(LPOS/128, S/128, 12), 256, 0, s2>>>(
        Qbf, Kbf, PKbf, PQbf, CKb, CQb, 6);
    flash_attn<<<dim3(S/128, NH/2, ZSPL), 256, FL_SMEM, s2>>>(
        Qbf, Kbf, Vt, CKb, CQb, mask, Opart, ML, 6);
    cudaEventRecord(evF2, s2);

    // --- join back to default stream ---
    cudaStreamWaitEvent(0, evF1, 0);
    cudaStreamWaitEvent(0, evF2, 0);

    merge_attn<<<NH * S / 8, 256>>>(Opart, ML, CTXbf);

    // --- output projection + bias + residual ---
    gemm_out<<<dim3(6, 16), 256>>>(CTXbf, Wt + 5 * H * H, TMP, bo, hidden);

    // --- layernorm ---
    ln_kernel<<<S, 256>>>(TMP, gamma, beta, out);
}

// round 10
// speedup vs baseline: 11.3364x; 1.0006x over previous
#include <cuda_runtime.h>
#include <cuda_bf16.h>
#include <cstdint>

// ---------------------------------------------------------------------------
// BertAttention (DeBERTa) — round 10: force flash occupancy to 2 CTAs/SM.
// B=1, S=2048, H=768, NH=12, D=64, SPAN=512
// ---------------------------------------------------------------------------

constexpr int S    = 2048;
constexpr int H    = 768;
constexpr int NH   = 12;
constexpr int D    = 64;
constexpr int LPOS = 1024;  // 2*SPAN
constexpr int ZSPL = 4;     // split-K factor over key sequence
// scores scaled by 1/sqrt(192) * log2(e): softmax done in exp2 domain.
constexpr float SCALE2 = 0.07216878364870322f * 1.4426950408889634f;
constexpr float NEGMAX = -3.402823466e38f;

using bf16 = __nv_bfloat16;

// ---------------------------- scratch (device globals) ---------------------
__device__ bf16   g_hbf  [S * H];
__device__ bf16   g_relbf[LPOS * H];
__device__ bf16   g_Wt   [6 * H * H];
__device__ bf16   g_Qbf  [S * H];
__device__ bf16   g_Kbf  [S * H];
__device__ bf16   g_Vt   [H * S];
__device__ bf16   g_PKbf [LPOS * H];
__device__ bf16   g_PQbf [LPOS * H];
__device__ bf16   g_CKb  [(size_t)NH * S * LPOS];
__device__ bf16   g_CQb  [(size_t)NH * S * LPOS + 256];
__device__ float  g_Opart[(size_t)ZSPL * NH * S * D];
__device__ float2 g_ML   [ZSPL * NH * S];
__device__ bf16   g_CTXbf[S * H];
__device__ float  g_TMP  [S * H];

// ---------------------------- PTX helpers ----------------------------------
__device__ __forceinline__ uint32_t smem_u32(const void* p) {
    uint32_t a;
    asm("{ .reg .u64 t; cvta.to.shared.u64 t, %1; cvt.u32.u64 %0, t; }"
        : "=r"(a) : "l"(p));
    return a;
}
__device__ __forceinline__ void cpasync16(uint32_t dst, const void* src) {
    asm volatile("cp.async.cg.shared.global [%0], [%1], 16;" :: "r"(dst), "l"(src));
}
#define CP_COMMIT() asm volatile("cp.async.commit_group;" ::: "memory")
#define CP_WAIT1()  asm volatile("cp.async.wait_group 1;" ::: "memory")
#define CP_WAIT0()  asm volatile("cp.async.wait_group 0;" ::: "memory")

__device__ __forceinline__ void ldsm4(uint32_t* r, uint32_t addr) {
    asm volatile("ldmatrix.sync.aligned.m8n8.x4.shared.b16 {%0,%1,%2,%3}, [%4];"
                 : "=r"(r[0]), "=r"(r[1]), "=r"(r[2]), "=r"(r[3]) : "r"(addr));
}
__device__ __forceinline__ void mma16816(float* c, const uint32_t* a, const uint32_t* b) {
    asm volatile(
        "mma.sync.aligned.m16n8k16.row.col.f32.bf16.bf16.f32 "
        "{%0,%1,%2,%3}, {%4,%5,%6,%7}, {%8,%9}, {%0,%1,%2,%3};"
        : "+f"(c[0]), "+f"(c[1]), "+f"(c[2]), "+f"(c[3])
        : "r"(a[0]), "r"(a[1]), "r"(a[2]), "r"(a[3]), "r"(b[0]), "r"(b[1]));
}
__device__ __forceinline__ uint32_t packbf2(float a, float b) {
    __nv_bfloat162 t = __float22bfloat162_rn(make_float2(a, b));
    return *(uint32_t*)&t;
}

__device__ __forceinline__ uint32_t swz(int row, int chunk) {
    return (uint32_t)(row * 64 + ((chunk ^ ((row >> 1) & 3)) << 4));
}
__device__ __forceinline__ uint32_t swz128(int row, int c16) {
    return (uint32_t)(row * 128 + ((c16 ^ (row & 7)) << 4));
}

// ---------------------------------------------------------------------------
// Shared GEMM mainloop (128x128 tile, K-major bf16, NT).
// ---------------------------------------------------------------------------
struct SmemPtrs { uint32_t uA, uB; };

template<typename LoadFn>
__device__ __forceinline__ void gemm_core(
    int nch, SmemPtrs sp, int tid, int lane, int wm, int wn,
    float (&acc)[4][4][4], LoadFn load_tiles)
{
    constexpr int ABYTES = 128 * 32 * 2;
    constexpr int BBYTES = 128 * 32 * 2;
    load_tiles(0, 0);
    CP_COMMIT();
    for (int ch = 0; ch < nch; ch++) {
        const int st = ch & 1;
        if (ch + 1 < nch) { load_tiles(ch + 1, st ^ 1); CP_COMMIT(); CP_WAIT1(); }
        else              { CP_WAIT0(); }
        __syncthreads();
        const uint32_t bA = sp.uA + st * ABYTES;
        const uint32_t bB = sp.uB + st * BBYTES;
        #pragma unroll
        for (int kk = 0; kk < 2; kk++) {
            uint32_t afr[4][4];
            #pragma unroll
            for (int i = 0; i < 4; i++) {
                int row = wm * 64 + i * 16 + (lane & 15);
                int chk = kk * 2 + (lane >> 4);
                ldsm4(afr[i], bA + swz(row, chk));
            }
            uint32_t bfr[4][2];
            #pragma unroll
            for (int p = 0; p < 2; p++) {
                uint32_t r4[4];
                int n   = wn * 32 + p * 16 + ((lane >> 4) << 3) + (lane & 7);
                int chk = kk * 2 + ((lane >> 3) & 1);
                ldsm4(r4, bB + swz(n, chk));
                bfr[2 * p][0] = r4[0]; bfr[2 * p][1] = r4[1];
                bfr[2 * p + 1][0] = r4[2]; bfr[2 * p + 1][1] = r4[3];
            }
            #pragma unroll
            for (int i = 0; i < 4; i++)
                #pragma unroll
                for (int j = 0; j < 4; j++)
                    mma16816(acc[i][j], afr[i], bfr[j]);
        }
        __syncthreads();
    }
}

// ---------------------------------------------------------------------------
// Fused projection kernel: 5 jobs (Q, K, V->Vt, PK, PQ) in one 1-D grid.
// ---------------------------------------------------------------------------
struct ProjJobs {
    const bf16* A[5];
    const bf16* Bw[5];
    bf16*       C[5];
    const float* bias[5];
    int mode[5];
    int start[6];
};

__global__ void __launch_bounds__(256) gemm_proj(ProjJobs J)
{
    constexpr int ABYTES = 128 * 32 * 2, BBYTES = 128 * 32 * 2;
    __shared__ __align__(1024) char sm[2 * (ABYTES + BBYTES)];
    SmemPtrs sp { smem_u32(sm), smem_u32(sm) + 2 * ABYTES };

    int bx = blockIdx.x;
    int j = 0;
    while (bx >= J.start[j + 1]) j++;
    const int local = bx - J.start[j];
    const int bm = (local / 6) * 128, bn = (local % 6) * 128;

    const int tid = threadIdx.x, lane = tid & 31, wid = tid >> 5;
    const int wm = wid & 1, wn = wid >> 1;

    const bf16* Arow = J.A[j] + (long)bm * H;
    const bf16* Brow = J.Bw[j] + (long)bn * H;

    auto load_tiles = [&](int ch, int st) {
        const bf16* Ak = Arow + ch * 32;
        #pragma unroll
        for (int i = tid; i < 512; i += 256) {
            int r = i >> 2, c = i & 3;
            cpasync16(sp.uA + st * ABYTES + swz(r, c), Ak + (long)r * H + c * 8);
        }
        const bf16* Bk = Brow + ch * 32;
        #pragma unroll
        for (int i = tid; i < 512; i += 256) {
            int r = i >> 2, c = i & 3;
            cpasync16(sp.uB + st * BBYTES + swz(r, c), Bk + (long)r * H + c * 8);
        }
    };

    float acc[4][4][4] = {};
    gemm_core(H / 32, sp, tid, lane, wm, wn, acc, load_tiles);

    bf16* C = J.C[j];
    const float* bias = J.bias[j];
    const int mode = J.mode[j];

    #pragma unroll
    for (int i = 0; i < 4; i++)
        #pragma unroll
        for (int jj = 0; jj < 4; jj++)
            #pragma unroll
            for (int half = 0; half < 2; half++) {
                const int r = bm + wm * 64 + i * 16 + (lane >> 2) + half * 8;
                const int c = bn + wn * 32 + jj * 8 + (lane & 3) * 2;
                const float v0 = acc[i][jj][half * 2];
                const float v1 = acc[i][jj][half * 2 + 1];
                float b0 = bias ? bias[c] : 0.f, b1 = bias ? bias[c + 1] : 0.f;
                if (mode == 0) {
                    *(__nv_bfloat162*)(C + (long)r * H + c) =
                        __float22bfloat162_rn(make_float2(v0 + b0, v1 + b1));
                } else {
                    C[(long)c * S + r]       = __float2bfloat16(v0 + b0);
                    C[(long)(c + 1) * S + r] = __float2bfloat16(v1 + b1);
                }
            }
}

// ---------------------------------------------------------------------------
// Fused tables kernel (head range via hbase): z<6 -> CK head hbase+z ;
// z>=6 -> CQ head hbase+z-6. Smem-staged coalesced output stores.
// ---------------------------------------------------------------------------
constexpr int TB_STRIDE = 272;

__global__ void __launch_bounds__(256) gemm_tables(
    const bf16* __restrict__ Qb, const bf16* __restrict__ Kb,
    const bf16* __restrict__ PK, const bf16* __restrict__ PQ,
    bf16* __restrict__ CK, bf16* __restrict__ CQ, int hbase)
{
    constexpr int ABYTES = 128 * 32 * 2, BBYTES = 128 * 32 * 2;
    __shared__ __align__(1024) char sm[128 * TB_STRIDE];
    SmemPtrs sp { smem_u32(sm), smem_u32(sm) + 2 * ABYTES };

    const int z = blockIdx.z;
    const bool isCK = z < 6;
    const int h = hbase + (isCK ? z : z - 6);
    const bf16* A = (isCK ? Qb : Kb) + h * D;
    const bf16* B = (isCK ? PK : PQ) + h * D;
    bf16* C = (isCK ? CK : CQ) + (size_t)h * S * LPOS;

    const int tid = threadIdx.x, lane = tid & 31, wid = tid >> 5;
    const int wm = wid & 1, wn = wid >> 1;
    const int bm = blockIdx.y * 128, bn = blockIdx.x * 128;

    const bf16* Arow = A + (long)bm * H;
    const bf16* Brow = B + (long)bn * H;

    auto load_tiles = [&](int ch, int st) {
        const bf16* Ak = Arow + ch * 32;
        #pragma unroll
        for (int i = tid; i < 512; i += 256) {
            int r = i >> 2, c = i & 3;
            cpasync16(sp.uA + st * ABYTES + swz(r, c), Ak + (long)r * H + c * 8);
        }
        const bf16* Bk = Brow + ch * 32;
        #pragma unroll
        for (int i = tid; i < 512; i += 256) {
            int r = i >> 2, c = i & 3;
            cpasync16(sp.uB + st * BBYTES + swz(r, c), Bk + (long)r * H + c * 8);
        }
    };

    float acc[4][4][4] = {};
    gemm_core(D / 32, sp, tid, lane, wm, wn, acc, load_tiles);

    #pragma unroll
    for (int i = 0; i < 4; i++)
        #pragma unroll
        for (int jj = 0; jj < 4; jj++)
            #pragma unroll
            for (int half = 0; half < 2; half++) {
                const int rl = wm * 64 + i * 16 + (lane >> 2) + half * 8;
                const int cl = wn * 32 + jj * 8 + (lane & 3) * 2;
                *(uint32_t*)(sm + rl * TB_STRIDE + cl * 2) =
                    packbf2(acc[i][jj][half * 2], acc[i][jj][half * 2 + 1]);
            }
    __syncthreads();

    #pragma unroll
    for (int i = tid; i < 2048; i += 256) {
        int r = i >> 4, ch = i & 15;
        uint4 v = *(uint4*)(sm + r * TB_STRIDE + ch * 16);
        *(uint4*)(C + (long)(bm + r) * LPOS + bn + ch * 8) = v;
    }
}

// ---------------------------------------------------------------------------
// Output projection + bias + residual (fp32 out).
// ---------------------------------------------------------------------------
__global__ void __launch_bounds__(256) gemm_out(
    const bf16* __restrict__ A, const bf16* __restrict__ Bw,
    float* __restrict__ C, const float* __restrict__ bias,
    const float* __restrict__ res)
{
    constexpr int ABYTES = 128 * 32 * 2, BBYTES = 128 * 32 * 2;
    __shared__ __align__(1024) char sm[2 * (ABYTES + BBYTES)];
    SmemPtrs sp { smem_u32(sm), smem_u32(sm) + 2 * ABYTES };

    const int tid = threadIdx.x, lane = tid & 31, wid = tid >> 5;
    const int wm = wid & 1, wn = wid >> 1;
    const int bm = blockIdx.y * 128, bn = blockIdx.x * 128;

    const bf16* Arow = A + (long)bm * H;
    const bf16* Brow = Bw + (long)bn * H;

    auto load_tiles = [&](int ch, int st) {
        const bf16* Ak = Arow + ch * 32;
        #pragma unroll
        for (int i = tid; i < 512; i += 256) {
            int r = i >> 2, c = i & 3;
            cpasync16(sp.uA + st * ABYTES + swz(r, c), Ak + (long)r * H + c * 8);
        }
        const bf16* Bk = Brow + ch * 32;
        #pragma unroll
        for (int i = tid; i < 512; i += 256) {
            int r = i >> 2, c = i & 3;
            cpasync16(sp.uB + st * BBYTES + swz(r, c), Bk + (long)r * H + c * 8);
        }
    };

    float acc[4][4][4] = {};
    gemm_core(H / 32, sp, tid, lane, wm, wn, acc, load_tiles);

    #pragma unroll
    for (int i = 0; i < 4; i++)
        #pragma unroll
        for (int jj = 0; jj < 4; jj++)
            #pragma unroll
            for (int half = 0; half < 2; half++) {
                const int r = bm + wm * 64 + i * 16 + (lane >> 2) + half * 8;
                const int c = bn + wn * 32 + jj * 8 + (lane & 3) * 2;
                const float* rr = res + (long)r * H;
                *(float2*)(C + (long)r * H + c) =
                    make_float2(acc[i][jj][half * 2] + bias[c] + rr[c],
                                acc[i][jj][half * 2 + 1] + bias[c + 1] + rr[c + 1]);
            }
}

// ---------------------------------------------------------------------------
// Flash-fused attention (head range via hbase), split-K over ZSPL slices.
// exp2-domain softmax; per-tile no-clip fast path; forced 2 CTAs/SM.
// ---------------------------------------------------------------------------
constexpr int CQ_W     = 144;
constexpr int CQ_ROWB  = CQ_W * 2;
constexpr int CQ_BYTES = 64 * CQ_ROWB;
constexpr int FL_SMEM  = 16384 + 2 * 8192 + 2 * 8192 + 2 * CQ_BYTES;  // 86016
constexpr int HTILES   = (S / 64) / ZSPL;

__global__ void __launch_bounds__(256, 2) flash_attn(
    const bf16* __restrict__ Q, const bf16* __restrict__ K,
    const bf16* __restrict__ Vt,
    const bf16* __restrict__ CKb, const bf16* __restrict__ CQb,
    const int* __restrict__ mask,
    float* __restrict__ Opart, float2* __restrict__ ML, int hbase)
{
    extern __shared__ __align__(1024) char dyn[];
    const uint32_t uQ  = smem_u32(dyn);
    const uint32_t uK  = uQ + 16384;
    const uint32_t uV  = uK + 16384;
    const uint32_t uCQ = uV + 16384;

    const int tid = threadIdx.x, lane = tid & 31, wid = tid >> 5;
    const int h = hbase + blockIdx.y, bm = blockIdx.x * 128;
    const int z = blockIdx.z;
    const int ct0 = z * HTILES;
    const int bmc = bm + 512;

    auto lbc = [&](int c) { return min(max(bmc - c, 0), 888) & ~7; };

    {
        const bf16* Qg = Q + (long)bm * H + h * D;
        #pragma unroll
        for (int i = tid; i < 1024; i += 256) {
            int r = i >> 3, c = i & 7;
            cpasync16(uQ + swz128(r, c), Qg + (long)r * H + c * 8);
        }
    }
    CP_COMMIT();

    auto load_kv = [&](int ct, int st) {
        const int c0 = ct * 64;
        const uint32_t uk = uK + st * 8192;
        const uint32_t uv = uV + st * 8192;
        const bf16* Kg = K + (long)c0 * H + h * D;
        #pragma unroll
        for (int i = tid; i < 512; i += 256) {
            int r = i >> 3, c = i & 7;
            cpasync16(uk + swz128(r, c), Kg + (long)r * H + c * 8);
        }
        const bf16* Vg = Vt + (long)(h * D) * S + c0;
        #pragma unroll
        for (int i = tid; i < 512; i += 256) {
            int d = i >> 3, c = i & 7;
            cpasync16(uv + swz128(d, c), Vg + (long)d * S + c * 8);
        }
        const uint32_t ucq = uCQ + st * CQ_BYTES;
        const bf16* CQg = CQb + ((size_t)h * S + c0) * LPOS;
        for (int i = tid; i < 64 * 18; i += 256) {
            int j = i / 18, ch = i % 18;
            int Lb = lbc(c0 + j);
            cpasync16(ucq + j * CQ_ROWB + ch * 16,
                      CQg + (size_t)j * LPOS + Lb + ch * 8);
        }
    };
    load_kv(ct0, 0);
    CP_COMMIT();
    CP_WAIT1();
    __syncthreads();

    uint32_t qf[4][4];
    #pragma unroll
    for (int kk = 0; kk < 4; kk++) {
        int row = wid * 16 + (lane & 15);
        int c16 = kk * 2 + (lane >> 4);
        ldsm4(qf[kk], uQ + swz128(row, c16));
    }

    const int r0 = bm + wid * 16 + (lane >> 2);
    const int r1 = r0 + 8;
    const int m0v = mask[r0], m1v = mask[r1];
    const bf16* ck0 = CKb + ((size_t)h * S + r0) * LPOS;
    const bf16* ck1 = CKb + ((size_t)h * S + r1) * LPOS;

    float m0 = NEGMAX, m1 = NEGMAX, l0 = 0.f, l1 = 0.f;
    float O[8][4] = {};

    for (int it = 0; it < HTILES; it++) {
        const int ct = ct0 + it;
        const int st = it & 1;
        if (it + 1 < HTILES) { load_kv(ct + 1, st ^ 1); CP_COMMIT(); CP_WAIT1(); }
        else                 { CP_WAIT0(); }
        __syncthreads();

        const uint32_t uk = uK + st * 8192;
        const uint32_t uv = uV + st * 8192;
        const bf16* sCQ = (const bf16*)(dyn + (uCQ - uQ) + st * CQ_BYTES);

        float sfr[8][4] = {};
        #pragma unroll
        for (int g = 0; g < 4; g++) {
            #pragma unroll
            for (int kk = 0; kk < 4; kk++) {
                uint32_t r4[4];
                int n   = g * 16 + ((lane >> 4) << 3) + (lane & 7);
                int c16 = kk * 2 + ((lane >> 3) & 1);
                ldsm4(r4, uk + swz128(n, c16));
                mma16816(sfr[2 * g],     qf[kk], r4);
                mma16816(sfr[2 * g + 1], qf[kk], r4 + 2);
            }
        }

        const int c0 = ct * 64;
        const int dRC = bm - c0;
        const bool noclip = (dRC >= -449) && (dRC <= 384);
        float tmx0 = NEGMAX, tmx1 = NEGMAX;

        if (noclip) {
            #pragma unroll
            for (int nb = 0; nb < 8; nb++) {
                const int cl = nb * 8 + (lane & 3) * 2;
                const int c  = c0 + cl;
                const int Lb0 = lbc(c);
                const int Lb1 = lbc(c + 1);
                const int mc0 = mask[c], mc1 = mask[c + 1];
                {
                    int la = r0 - c + 512, lb = la - 1;
                    float v0 = (sfr[nb][0] + __bfloat162float(ck0[la])
                                + __bfloat162float(sCQ[cl * CQ_W + (la - Lb0)])) * SCALE2;
                    float v1 = (sfr[nb][1] + __bfloat162float(ck0[lb])
                                + __bfloat162float(sCQ[(cl + 1) * CQ_W + (lb - Lb1)])) * SCALE2;
                    if (!(m0v && mc0)) v0 = NEGMAX;
                    if (!(m0v && mc1)) v1 = NEGMAX;
                    sfr[nb][0] = v0; sfr[nb][1] = v1;
                    tmx0 = fmaxf(tmx0, fmaxf(v0, v1));
                }
                {
                    int la = r1 - c + 512, lb = la - 1;
                    float v2 = (sfr[nb][2] + __bfloat162float(ck1[la])
                                + __bfloat162float(sCQ[cl * CQ_W + (la - Lb0)])) * SCALE2;
                    float v3 = (sfr[nb][3] + __bfloat162float(ck1[lb])
                                + __bfloat162float(sCQ[(cl + 1) * CQ_W + (lb - Lb1)])) * SCALE2;
                    if (!(m1v && mc0)) v2 = NEGMAX;
                    if (!(m1v && mc1)) v3 = NEGMAX;
                    sfr[nb][2] = v2; sfr[nb][3] = v3;
                    tmx1 = fmaxf(tmx1, fmaxf(v2, v3));
                }
            }
        } else {
            #pragma unroll
            for (int nb = 0; nb < 8; nb++) {
                const int cl = nb * 8 + (lane & 3) * 2;
                const int c  = c0 + cl;
                const int Lb0 = lbc(c);
                const int Lb1 = lbc(c + 1);
                const int mc0 = mask[c], mc1 = mask[c + 1];
                {
                    int la = min(max(r0 - c + 512, 0), LPOS - 1);
                    int lb = min(max(r0 - c + 511, 0), LPOS - 1);
                    float v0 = (sfr[nb][0] + __bfloat162float(ck0[la])
                                + __bfloat162float(sCQ[cl * CQ_W + (la - Lb0)])) * SCALE2;
                    float v1 = (sfr[nb][1] + __bfloat162float(ck0[lb])
                                + __bfloat162float(sCQ[(cl + 1) * CQ_W + (lb - Lb1)])) * SCALE2;
                    if (!(m0v && mc0)) v0 = NEGMAX;
                    if (!(m0v && mc1)) v1 = NEGMAX;
                    sfr[nb][0] = v0; sfr[nb][1] = v1;
                    tmx0 = fmaxf(tmx0, fmaxf(v0, v1));
                }
                {
                    int la = min(max(r1 - c + 512, 0), LPOS - 1);
                    int lb = min(max(r1 - c + 511, 0), LPOS - 1);
                    float v2 = (sfr[nb][2] + __bfloat162float(ck1[la])
                                + __bfloat162float(sCQ[cl * CQ_W + (la - Lb0)])) * SCALE2;
                    float v3 = (sfr[nb][3] + __bfloat162float(ck1[lb])
                                + __bfloat162float(sCQ[(cl + 1) * CQ_W + (lb - Lb1)])) * SCALE2;
                    if (!(m1v && mc0)) v2 = NEGMAX;
                    if (!(m1v && mc1)) v3 = NEGMAX;
                    sfr[nb][2] = v2; sfr[nb][3] = v3;
                    tmx1 = fmaxf(tmx1, fmaxf(v2, v3));
                }
            }
        }
        tmx0 = fmaxf(tmx0, __shfl_xor_sync(0xffffffffu, tmx0, 1));
        tmx0 = fmaxf(tmx0, __shfl_xor_sync(0xffffffffu, tmx0, 2));
        tmx1 = fmaxf(tmx1, __shfl_xor_sync(0xffffffffu, tmx1, 1));
        tmx1 = fmaxf(tmx1, __shfl_xor_sync(0xffffffffu, tmx1, 2));

        const float mn0 = fmaxf(m0, tmx0), mn1 = fmaxf(m1, tmx1);
        const float sc0 = exp2f(m0 - mn0), sc1 = exp2f(m1 - mn1);
        m0 = mn0; m1 = mn1;
        float rs0 = 0.f, rs1 = 0.f;
        #pragma unroll
        for (int nb = 0; nb < 8; nb++) {
            sfr[nb][0] = exp2f(sfr[nb][0] - mn0);
            sfr[nb][1] = exp2f(sfr[nb][1] - mn0);
            sfr[nb][2] = exp2f(sfr[nb][2] - mn1);
            sfr[nb][3] = exp2f(sfr[nb][3] - mn1);
            rs0 += sfr[nb][0] + sfr[nb][1];
            rs1 += sfr[nb][2] + sfr[nb][3];
        }
        rs0 += __shfl_xor_sync(0xffffffffu, rs0, 1);
        rs0 += __shfl_xor_sync(0xffffffffu, rs0, 2);
        rs1 += __shfl_xor_sync(0xffffffffu, rs1, 1);
        rs1 += __shfl_xor_sync(0xffffffffu, rs1, 2);
        l0 = l0 * sc0 + rs0;
        l1 = l1 * sc1 + rs1;
        #pragma unroll
        for (int df = 0; df < 8; df++) {
            O[df][0] *= sc0; O[df][1] *= sc0;
            O[df][2] *= sc1; O[df][3] *= sc1;
        }

        #pragma unroll
        for (int kk2 = 0; kk2 < 4; kk2++) {
            uint32_t pf[4];
            pf[0] = packbf2(sfr[2 * kk2][0],     sfr[2 * kk2][1]);
            pf[1] = packbf2(sfr[2 * kk2][2],     sfr[2 * kk2][3]);
            pf[2] = packbf2(sfr[2 * kk2 + 1][0], sfr[2 * kk2 + 1][1]);
            pf[3] = packbf2(sfr[2 * kk2 + 1][2], sfr[2 * kk2 + 1][3]);
            #pragma unroll
            for (int dg = 0; dg < 4; dg++) {
                uint32_t r4[4];
                int n   = dg * 16 + ((lane >> 4) << 3) + (lane & 7);
                int c16 = kk2 * 2 + ((lane >> 3) & 1);
                ldsm4(r4, uv + swz128(n, c16));
                mma16816(O[2 * dg],     pf, r4);
                mma16816(O[2 * dg + 1], pf, r4 + 2);
            }
        }
        __syncthreads();
    }

    const size_t base = ((size_t)z * NH + h) * S;
    if ((lane & 3) == 0) {
        ML[base + r0] = make_float2(m0, l0);
        ML[base + r1] = make_float2(m1, l1);
    }
    float* o0 = Opart + (base + r0) * D + (lane & 3) * 2;
    float* o1 = Opart + (base + r1) * D + (lane & 3) * 2;
    #pragma unroll
    for (int df = 0; df < 8; df++) {
        *(float2*)(o0 + df * 8) = make_float2(O[df][0], O[df][1]);
        *(float2*)(o1 + df * 8) = make_float2(O[df][2], O[df][3]);
    }
}

// ---------------------------------------------------------------------------
// Merge the ZSPL split-K slices (exp2 domain) -> normalized bf16 context.
// ---------------------------------------------------------------------------
__global__ void __launch_bounds__(256) merge_attn(
    const float* __restrict__ Opart, const float2* __restrict__ ML,
    bf16* __restrict__ CTX)
{
    const int p = blockIdx.x * 8 + (threadIdx.x >> 5);
    const int lane = threadIdx.x & 31;
    const int h = p / S, row = p % S;

    float2 ml[ZSPL];
    float M = NEGMAX;
    #pragma unroll
    for (int zz = 0; zz < ZSPL; zz++) {
        ml[zz] = ML[zz * NH * S + p];
        M = fmaxf(M, ml[zz].x);
    }
    float w[ZSPL], denom = 0.f;
    #pragma unroll
    for (int zz = 0; zz < ZSPL; zz++) {
        w[zz] = exp2f(ml[zz].x - M);
        denom += w[zz] * ml[zz].y;
    }
    const float inv = 1.0f / denom;

    const int d = lane * 2;
    float ax = 0.f, ay = 0.f;
    #pragma unroll
    for (int zz = 0; zz < ZSPL; zz++) {
        const float2 v = *(const float2*)(Opart + ((size_t)zz * NH * S + p) * D + d);
        ax += w[zz] * v.x;
        ay += w[zz] * v.y;
    }
    *(__nv_bfloat162*)(CTX + (long)row * H + h * D + d) =
        __float22bfloat162_rn(make_float2(ax * inv, ay * inv));
}

// ---------------------------------------------------------------------------
__global__ void cvt_bf16_2(const float* __restrict__ x0, bf16* __restrict__ y0, int n0,
                           const float* __restrict__ x1, bf16* __restrict__ y1, int n1)
{
    int i = blockIdx.x * 256 + threadIdx.x;
    if (i < n0) y0[i] = __float2bfloat16(x0[i]);
    else if (i < n0 + n1) y1[i - n0] = __float2bfloat16(x1[i - n0]);
}

struct P6 { const float* p[6]; };
__global__ void wtrans6(P6 srcs, bf16* __restrict__ Wt)
{
    __shared__ float t[32][33];
    const float* W = srcs.p[blockIdx.z];
    bf16* dst = Wt + (size_t)blockIdx.z * H * H;
    const int bx = blockIdx.x * 32, by = blockIdx.y * 32;
    #pragma unroll
    for (int i = threadIdx.y; i < 32; i += 8)
        t[i][threadIdx.x] = W[(long)(by + i) * H + bx + threadIdx.x];
    __syncthreads();
    #pragma unroll
    for (int i = threadIdx.y; i < 32; i += 8)
        dst[(long)(bx + i) * H + by + threadIdx.x] = __float2bfloat16(t[threadIdx.x][i]);
}

__global__ void ln_kernel(const float* __restrict__ x,
                          const float* __restrict__ gamma,
                          const float* __restrict__ beta,
                          float* __restrict__ out)
{
    __shared__ float rs[8], rq[8];
    const int s = blockIdx.x, tid = threadIdx.x;
    const float* row = x + (long)s * H;
    float a0 = row[tid], a1 = row[tid + 256], a2 = row[tid + 512];
    float sum = a0 + a1 + a2;
    float sq  = a0 * a0 + a1 * a1 + a2 * a2;
    #pragma unroll
    for (int o = 16; o > 0; o >>= 1) {
        sum += __shfl_xor_sync(0xffffffffu, sum, o);
        sq  += __shfl_xor_sync(0xffffffffu, sq,  o);
    }
    if ((tid & 31) == 0) { rs[tid >> 5] = sum; rq[tid >> 5] = sq; }
    __syncthreads();
    float ts = 0.f, tq = 0.f;
    #pragma unroll
    for (int w = 0; w < 8; w++) { ts += rs[w]; tq += rq[w]; }
    float mean = ts * (1.0f / H);
    float var  = tq * (1.0f / H) - mean * mean;
    float inv  = rsqrtf(var + 1e-7f);
    float* o = out + (long)s * H;
    o[tid]       = (a0 - mean) * inv * gamma[tid]       + beta[tid];
    o[tid + 256] = (a1 - mean) * inv * gamma[tid + 256] + beta[tid + 256];
    o[tid + 512] = (a2 - mean) * inv * gamma[tid + 512] + beta[tid + 512];
}

// ---------------------------------------------------------------------------
extern "C" void kernel_launch(void* const* d_in, const int* in_sizes, int n_in,
                              void* d_out, int out_size)
{
    const float* hidden = (const float*)d_in[0];
    const int*   mask   = (const int*)  d_in[1];
    const float* Wq     = (const float*)d_in[2];
    const float* bq     = (const float*)d_in[3];
    const float* Wk     = (const float*)d_in[4];
    const float* bk     = (const float*)d_in[5];
    const float* Wv     = (const float*)d_in[6];
    const float* bv     = (const float*)d_in[7];
    const float* rel    = (const float*)d_in[8];
    const float* Wpk    = (const float*)d_in[9];
    const float* Wpq    = (const float*)d_in[10];
    const float* bpq    = (const float*)d_in[11];
    const float* Wo     = (const float*)d_in[12];
    const float* bo     = (const float*)d_in[13];
    const float* gamma  = (const float*)d_in[14];
    const float* beta   = (const float*)d_in[15];
    float* out = (float*)d_out;

    bf16 *hbf, *relbf, *Wt, *Qbf, *Kbf, *Vt, *PKbf, *PQbf, *CKb, *CQb, *CTXbf;
    float *TMP, *Opart;
    float2* ML;
    cudaGetSymbolAddress((void**)&hbf,   g_hbf);
    cudaGetSymbolAddress((void**)&relbf, g_relbf);
    cudaGetSymbolAddress((void**)&Wt,    g_Wt);
    cudaGetSymbolAddress((void**)&Qbf,   g_Qbf);
    cudaGetSymbolAddress((void**)&Kbf,   g_Kbf);
    cudaGetSymbolAddress((void**)&Vt,    g_Vt);
    cudaGetSymbolAddress((void**)&PKbf,  g_PKbf);
    cudaGetSymbolAddress((void**)&PQbf,  g_PQbf);
    cudaGetSymbolAddress((void**)&CKb,   g_CKb);
    cudaGetSymbolAddress((void**)&CQb,   g_CQb);
    cudaGetSymbolAddress((void**)&Opart, g_Opart);
    cudaGetSymbolAddress((void**)&ML,    g_ML);
    cudaGetSymbolAddress((void**)&CTXbf, g_CTXbf);
    cudaGetSymbolAddress((void**)&TMP,   g_TMP);

    static cudaStream_t s1 = nullptr, s2 = nullptr;
    static cudaEvent_t evP = nullptr, evF1 = nullptr, evF2 = nullptr;
    static bool init_done = false;
    if (!init_done) {
        cudaFuncSetAttribute(flash_attn,
                             cudaFuncAttributeMaxDynamicSharedMemorySize, FL_SMEM);
        cudaStreamCreateWithFlags(&s1, cudaStreamNonBlocking);
        cudaStreamCreateWithFlags(&s2, cudaStreamNonBlocking);
        cudaEventCreateWithFlags(&evP,  cudaEventDisableTiming);
        cudaEventCreateWithFlags(&evF1, cudaEventDisableTiming);
        cudaEventCreateWithFlags(&evF2, cudaEventDisableTiming);
        init_done = true;
    }

    // --- conversions / transposes (default stream) ---
    cvt_bf16_2<<<(S * H + LPOS * H + 255) / 256, 256>>>(
        hidden, hbf, S * H, rel, relbf, LPOS * H);
    P6 w6; w6.p[0] = Wq; w6.p[1] = Wk; w6.p[2] = Wv;
    w6.p[3] = Wpk; w6.p[4] = Wpq; w6.p[5] = Wo;
    wtrans6<<<dim3(H/32, H/32, 6), dim3(32, 8)>>>(w6, Wt);

    // --- all five projections in one launch (default stream) ---
    ProjJobs J;
    J.A[0] = hbf;   J.Bw[0] = Wt + 0 * H * H; J.C[0] = Qbf;  J.bias[0] = bq;      J.mode[0] = 0;
    J.A[1] = hbf;   J.Bw[1] = Wt + 1 * H * H; J.C[1] = Kbf;  J.bias[1] = bk;      J.mode[1] = 0;
    J.A[2] = hbf;   J.Bw[2] = Wt + 2 * H * H; J.C[2] = Vt;   J.bias[2] = bv;      J.mode[2] = 1;
    J.A[3] = relbf; J.Bw[3] = Wt + 3 * H * H; J.C[3] = PKbf; J.bias[3] = nullptr; J.mode[3] = 0;
    J.A[4] = relbf; J.Bw[4] = Wt + 4 * H * H; J.C[4] = PQbf; J.bias[4] = bpq;     J.mode[4] = 0;
    J.start[0] = 0;   J.start[1] = 96;  J.start[2] = 192;
    J.start[3] = 288; J.start[4] = 336; J.start[5] = 384;
    gemm_proj<<<384, 256>>>(J);
    cudaEventRecord(evP, 0);

    // --- fork: per-head-half tables -> flash on two streams ---
    cudaStreamWaitEvent(s1, evP, 0);
    gemm_tables<<<dim3(LPOS/128, S/128, 12), 256, 0, s1>>>(
        Qbf, Kbf, PKbf, PQbf, CKb, CQb, 0);
    flash_attn<<<dim3(S/128, NH/2, ZSPL), 256, FL_SMEM, s1>>>(
        Qbf, Kbf, Vt, CKb, CQb, mask, Opart, ML, 0);
    cudaEventRecord(evF1, s1);

    cudaStreamWaitEvent(s2, evP, 0);
    gemm_tables<<<dim3(LPOS/128, S/128, 12), 256, 0, s2>>>(
        Qbf, Kbf, PKbf, PQbf, CKb, CQb, 6);
    flash_attn<<<dim3(S/128, NH/2, ZSPL), 256, FL_SMEM, s2>>>(
        Qbf, Kbf, Vt, CKb, CQb, mask, Opart, ML, 6);
    cudaEventRecord(evF2, s2);

    // --- join back to default stream ---
    cudaStreamWaitEvent(0, evF1, 0);
    cudaStreamWaitEvent(0, evF2, 0);

    merge_attn<<<NH * S / 8, 256>>>(Opart, ML, CTXbf);

    // --- output projection + bias + residual ---
    gemm_out<<<dim3(6, 16), 256>>>(CTXbf, Wt + 5 * H * H, TMP, bo, hidden);

    // --- layernorm ---
    ln_kernel<<<S, 256>>>(TMP, gamma, beta, out);
}

// round 11
// speedup vs baseline: 11.4429x; 1.0094x over previous
#include <cuda_runtime.h>
#include <cuda_bf16.h>
#include <cstdint>

// ---------------------------------------------------------------------------
// BertAttention (DeBERTa) — round 11: closed-form band index fast path +
// launch reorder so ncu captures flash.
// B=1, S=2048, H=768, NH=12, D=64, SPAN=512
// ---------------------------------------------------------------------------

constexpr int S    = 2048;
constexpr int H    = 768;
constexpr int NH   = 12;
constexpr int D    = 64;
constexpr int LPOS = 1024;  // 2*SPAN
constexpr int ZSPL = 4;     // split-K factor over key sequence
constexpr float SCALE2 = 0.07216878364870322f * 1.4426950408889634f;
constexpr float NEGMAX = -3.402823466e38f;

using bf16 = __nv_bfloat16;

// ---------------------------- scratch (device globals) ---------------------
__device__ bf16   g_hbf  [S * H];
__device__ bf16   g_relbf[LPOS * H];
__device__ bf16   g_Wt   [6 * H * H];
__device__ bf16   g_Qbf  [S * H];
__device__ bf16   g_Kbf  [S * H];
__device__ bf16   g_Vt   [H * S];
__device__ bf16   g_PKbf [LPOS * H];
__device__ bf16   g_PQbf [LPOS * H];
__device__ bf16   g_CKb  [(size_t)NH * S * LPOS];
__device__ bf16   g_CQb  [(size_t)NH * S * LPOS + 256];
__device__ float  g_Opart[(size_t)ZSPL * NH * S * D];
__device__ float2 g_ML   [ZSPL * NH * S];
__device__ bf16   g_CTXbf[S * H];
__device__ float  g_TMP  [S * H];

// ---------------------------- PTX helpers ----------------------------------
__device__ __forceinline__ uint32_t smem_u32(const void* p) {
    uint32_t a;
    asm("{ .reg .u64 t; cvta.to.shared.u64 t, %1; cvt.u32.u64 %0, t; }"
        : "=r"(a) : "l"(p));
    return a;
}
__device__ __forceinline__ void cpasync16(uint32_t dst, const void* src) {
    asm volatile("cp.async.cg.shared.global [%0], [%1], 16;" :: "r"(dst), "l"(src));
}
#define CP_COMMIT() asm volatile("cp.async.commit_group;" ::: "memory")
#define CP_WAIT1()  asm volatile("cp.async.wait_group 1;" ::: "memory")
#define CP_WAIT0()  asm volatile("cp.async.wait_group 0;" ::: "memory")

__device__ __forceinline__ void ldsm4(uint32_t* r, uint32_t addr) {
    asm volatile("ldmatrix.sync.aligned.m8n8.x4.shared.b16 {%0,%1,%2,%3}, [%4];"
                 : "=r"(r[0]), "=r"(r[1]), "=r"(r[2]), "=r"(r[3]) : "r"(addr));
}
__device__ __forceinline__ void mma16816(float* c, const uint32_t* a, const uint32_t* b) {
    asm volatile(
        "mma.sync.aligned.m16n8k16.row.col.f32.bf16.bf16.f32 "
        "{%0,%1,%2,%3}, {%4,%5,%6,%7}, {%8,%9}, {%0,%1,%2,%3};"
        : "+f"(c[0]), "+f"(c[1]), "+f"(c[2]), "+f"(c[3])
        : "r"(a[0]), "r"(a[1]), "r"(a[2]), "r"(a[3]), "r"(b[0]), "r"(b[1]));
}
__device__ __forceinline__ uint32_t packbf2(float a, float b) {
    __nv_bfloat162 t = __float22bfloat162_rn(make_float2(a, b));
    return *(uint32_t*)&t;
}

__device__ __forceinline__ uint32_t swz(int row, int chunk) {
    return (uint32_t)(row * 64 + ((chunk ^ ((row >> 1) & 3)) << 4));
}
__device__ __forceinline__ uint32_t swz128(int row, int c16) {
    return (uint32_t)(row * 128 + ((c16 ^ (row & 7)) << 4));
}

// ---------------------------------------------------------------------------
// Shared GEMM mainloop (128x128 tile, K-major bf16, NT).
// ---------------------------------------------------------------------------
struct SmemPtrs { uint32_t uA, uB; };

template<typename LoadFn>
__device__ __forceinline__ void gemm_core(
    int nch, SmemPtrs sp, int tid, int lane, int wm, int wn,
    float (&acc)[4][4][4], LoadFn load_tiles)
{
    constexpr int ABYTES = 128 * 32 * 2;
    constexpr int BBYTES = 128 * 32 * 2;
    load_tiles(0, 0);
    CP_COMMIT();
    for (int ch = 0; ch < nch; ch++) {
        const int st = ch & 1;
        if (ch + 1 < nch) { load_tiles(ch + 1, st ^ 1); CP_COMMIT(); CP_WAIT1(); }
        else              { CP_WAIT0(); }
        __syncthreads();
        const uint32_t bA = sp.uA + st * ABYTES;
        const uint32_t bB = sp.uB + st * BBYTES;
        #pragma unroll
        for (int kk = 0; kk < 2; kk++) {
            uint32_t afr[4][4];
            #pragma unroll
            for (int i = 0; i < 4; i++) {
                int row = wm * 64 + i * 16 + (lane & 15);
                int chk = kk * 2 + (lane >> 4);
                ldsm4(afr[i], bA + swz(row, chk));
            }
            uint32_t bfr[4][2];
            #pragma unroll
            for (int p = 0; p < 2; p++) {
                uint32_t r4[4];
                int n   = wn * 32 + p * 16 + ((lane >> 4) << 3) + (lane & 7);
                int chk = kk * 2 + ((lane >> 3) & 1);
                ldsm4(r4, bB + swz(n, chk));
                bfr[2 * p][0] = r4[0]; bfr[2 * p][1] = r4[1];
                bfr[2 * p + 1][0] = r4[2]; bfr[2 * p + 1][1] = r4[3];
            }
            #pragma unroll
            for (int i = 0; i < 4; i++)
                #pragma unroll
                for (int j = 0; j < 4; j++)
                    mma16816(acc[i][j], afr[i], bfr[j]);
        }
        __syncthreads();
    }
}

// ---------------------------------------------------------------------------
// Fused projection kernel: 5 jobs (Q, K, V->Vt, PK, PQ) in one 1-D grid.
// ---------------------------------------------------------------------------
struct ProjJobs {
    const bf16* A[5];
    const bf16* Bw[5];
    bf16*       C[5];
    const float* bias[5];
    int mode[5];
    int start[6];
};

__global__ void __launch_bounds__(256) gemm_proj(ProjJobs J)
{
    constexpr int ABYTES = 128 * 32 * 2, BBYTES = 128 * 32 * 2;
    __shared__ __align__(1024) char sm[2 * (ABYTES + BBYTES)];
    SmemPtrs sp { smem_u32(sm), smem_u32(sm) + 2 * ABYTES };

    int bx = blockIdx.x;
    int j = 0;
    while (bx >= J.start[j + 1]) j++;
    const int local = bx - J.start[j];
    const int bm = (local / 6) * 128, bn = (local % 6) * 128;

    const int tid = threadIdx.x, lane = tid & 31, wid = tid >> 5;
    const int wm = wid & 1, wn = wid >> 1;

    const bf16* Arow = J.A[j] + (long)bm * H;
    const bf16* Brow = J.Bw[j] + (long)bn * H;

    auto load_tiles = [&](int ch, int st) {
        const bf16* Ak = Arow + ch * 32;
        #pragma unroll
        for (int i = tid; i < 512; i += 256) {
            int r = i >> 2, c = i & 3;
            cpasync16(sp.uA + st * ABYTES + swz(r, c), Ak + (long)r * H + c * 8);
        }
        const bf16* Bk = Brow + ch * 32;
        #pragma unroll
        for (int i = tid; i < 512; i += 256) {
            int r = i >> 2, c = i & 3;
            cpasync16(sp.uB + st * BBYTES + swz(r, c), Bk + (long)r * H + c * 8);
        }
    };

    float acc[4][4][4] = {};
    gemm_core(H / 32, sp, tid, lane, wm, wn, acc, load_tiles);

    bf16* C = J.C[j];
    const float* bias = J.bias[j];
    const int mode = J.mode[j];

    #pragma unroll
    for (int i = 0; i < 4; i++)
        #pragma unroll
        for (int jj = 0; jj < 4; jj++)
            #pragma unroll
            for (int half = 0; half < 2; half++) {
                const int r = bm + wm * 64 + i * 16 + (lane >> 2) + half * 8;
                const int c = bn + wn * 32 + jj * 8 + (lane & 3) * 2;
                const float v0 = acc[i][jj][half * 2];
                const float v1 = acc[i][jj][half * 2 + 1];
                float b0 = bias ? bias[c] : 0.f, b1 = bias ? bias[c + 1] : 0.f;
                if (mode == 0) {
                    *(__nv_bfloat162*)(C + (long)r * H + c) =
                        __float22bfloat162_rn(make_float2(v0 + b0, v1 + b1));
                } else {
                    C[(long)c * S + r]       = __float2bfloat16(v0 + b0);
                    C[(long)(c + 1) * S + r] = __float2bfloat16(v1 + b1);
                }
            }
}

// ---------------------------------------------------------------------------
// Fused tables kernel (head range via hbase).
// ---------------------------------------------------------------------------
constexpr int TB_STRIDE = 272;

__global__ void __launch_bounds__(256) gemm_tables(
    const bf16* __restrict__ Qb, const bf16* __restrict__ Kb,
    const bf16* __restrict__ PK, const bf16* __restrict__ PQ,
    bf16* __restrict__ CK, bf16* __restrict__ CQ, int hbase)
{
    constexpr int ABYTES = 128 * 32 * 2, BBYTES = 128 * 32 * 2;
    __shared__ __align__(1024) char sm[128 * TB_STRIDE];
    SmemPtrs sp { smem_u32(sm), smem_u32(sm) + 2 * ABYTES };

    const int z = blockIdx.z;
    const bool isCK = z < 6;
    const int h = hbase + (isCK ? z : z - 6);
    const bf16* A = (isCK ? Qb : Kb) + h * D;
    const bf16* B = (isCK ? PK : PQ) + h * D;
    bf16* C = (isCK ? CK : CQ) + (size_t)h * S * LPOS;

    const int tid = threadIdx.x, lane = tid & 31, wid = tid >> 5;
    const int wm = wid & 1, wn = wid >> 1;
    const int bm = blockIdx.y * 128, bn = blockIdx.x * 128;

    const bf16* Arow = A + (long)bm * H;
    const bf16* Brow = B + (long)bn * H;

    auto load_tiles = [&](int ch, int st) {
        const bf16* Ak = Arow + ch * 32;
        #pragma unroll
        for (int i = tid; i < 512; i += 256) {
            int r = i >> 2, c = i & 3;
            cpasync16(sp.uA + st * ABYTES + swz(r, c), Ak + (long)r * H + c * 8);
        }
        const bf16* Bk = Brow + ch * 32;
        #pragma unroll
        for (int i = tid; i < 512; i += 256) {
            int r = i >> 2, c = i & 3;
            cpasync16(sp.uB + st * BBYTES + swz(r, c), Bk + (long)r * H + c * 8);
        }
    };

    float acc[4][4][4] = {};
    gemm_core(D / 32, sp, tid, lane, wm, wn, acc, load_tiles);

    #pragma unroll
    for (int i = 0; i < 4; i++)
        #pragma unroll
        for (int jj = 0; jj < 4; jj++)
            #pragma unroll
            for (int half = 0; half < 2; half++) {
                const int rl = wm * 64 + i * 16 + (lane >> 2) + half * 8;
                const int cl = wn * 32 + jj * 8 + (lane & 3) * 2;
                *(uint32_t*)(sm + rl * TB_STRIDE + cl * 2) =
                    packbf2(acc[i][jj][half * 2], acc[i][jj][half * 2 + 1]);
            }
    __syncthreads();

    #pragma unroll
    for (int i = tid; i < 2048; i += 256) {
        int r = i >> 4, ch = i & 15;
        uint4 v = *(uint4*)(sm + r * TB_STRIDE + ch * 16);
        *(uint4*)(C + (long)(bm + r) * LPOS + bn + ch * 8) = v;
    }
}

// ---------------------------------------------------------------------------
// Output projection + bias + residual (fp32 out).
// ---------------------------------------------------------------------------
__global__ void __launch_bounds__(256) gemm_out(
    const bf16* __restrict__ A, const bf16* __restrict__ Bw,
    float* __restrict__ C, const float* __restrict__ bias,
    const float* __restrict__ res)
{
    constexpr int ABYTES = 128 * 32 * 2, BBYTES = 128 * 32 * 2;
    __shared__ __align__(1024) char sm[2 * (ABYTES + BBYTES)];
    SmemPtrs sp { smem_u32(sm), smem_u32(sm) + 2 * ABYTES };

    const int tid = threadIdx.x, lane = tid & 31, wid = tid >> 5;
    const int wm = wid & 1, wn = wid >> 1;
    const int bm = blockIdx.y * 128, bn = blockIdx.x * 128;

    const bf16* Arow = A + (long)bm * H;
    const bf16* Brow = Bw + (long)bn * H;

    auto load_tiles = [&](int ch, int st) {
        const bf16* Ak = Arow + ch * 32;
        #pragma unroll
        for (int i = tid; i < 512; i += 256) {
            int r = i >> 2, c = i & 3;
            cpasync16(sp.uA + st * ABYTES + swz(r, c), Ak + (long)r * H + c * 8);
        }
        const bf16* Bk = Brow + ch * 32;
        #pragma unroll
        for (int i = tid; i < 512; i += 256) {
            int r = i >> 2, c = i & 3;
            cpasync16(sp.uB + st * BBYTES + swz(r, c), Bk + (long)r * H + c * 8);
        }
    };

    float acc[4][4][4] = {};
    gemm_core(H / 32, sp, tid, lane, wm, wn, acc, load_tiles);

    #pragma unroll
    for (int i = 0; i < 4; i++)
        #pragma unroll
        for (int jj = 0; jj < 4; jj++)
            #pragma unroll
            for (int half = 0; half < 2; half++) {
                const int r = bm + wm * 64 + i * 16 + (lane >> 2) + half * 8;
                const int c = bn + wn * 32 + jj * 8 + (lane & 3) * 2;
                const float* rr = res + (long)r * H;
                *(float2*)(C + (long)r * H + c) =
                    make_float2(acc[i][jj][half * 2] + bias[c] + rr[c],
                                acc[i][jj][half * 2 + 1] + bias[c + 1] + rr[c + 1]);
            }
}

// ---------------------------------------------------------------------------
// Flash-fused attention (head range via hbase), split-K over ZSPL slices.
// Fast path: dRC in [-448, 320] -> band index = (r-bm) + ((dRC-cl)&7), no clamps.
// ---------------------------------------------------------------------------
constexpr int CQ_W     = 144;
constexpr int CQ_ROWB  = CQ_W * 2;
constexpr int CQ_BYTES = 64 * CQ_ROWB;
constexpr int FL_SMEM  = 16384 + 2 * 8192 + 2 * 8192 + 2 * CQ_BYTES;  // 86016
constexpr int HTILES   = (S / 64) / ZSPL;

__global__ void __launch_bounds__(256, 2) flash_attn(
    const bf16* __restrict__ Q, const bf16* __restrict__ K,
    const bf16* __restrict__ Vt,
    const bf16* __restrict__ CKb, const bf16* __restrict__ CQb,
    const int* __restrict__ mask,
    float* __restrict__ Opart, float2* __restrict__ ML, int hbase)
{
    extern __shared__ __align__(1024) char dyn[];
    const uint32_t uQ  = smem_u32(dyn);
    const uint32_t uK  = uQ + 16384;
    const uint32_t uV  = uK + 16384;
    const uint32_t uCQ = uV + 16384;

    const int tid = threadIdx.x, lane = tid & 31, wid = tid >> 5;
    const int h = hbase + blockIdx.y, bm = blockIdx.x * 128;
    const int z = blockIdx.z;
    const int ct0 = z * HTILES;
    const int bmc = bm + 512;

    auto lbc = [&](int c) { return min(max(bmc - c, 0), 888) & ~7; };

    {
        const bf16* Qg = Q + (long)bm * H + h * D;
        #pragma unroll
        for (int i = tid; i < 1024; i += 256) {
            int r = i >> 3, c = i & 7;
            cpasync16(uQ + swz128(r, c), Qg + (long)r * H + c * 8);
        }
    }
    CP_COMMIT();

    auto load_kv = [&](int ct, int st) {
        const int c0 = ct * 64;
        const uint32_t uk = uK + st * 8192;
        const uint32_t uv = uV + st * 8192;
        const bf16* Kg = K + (long)c0 * H + h * D;
        #pragma unroll
        for (int i = tid; i < 512; i += 256) {
            int r = i >> 3, c = i & 7;
            cpasync16(uk + swz128(r, c), Kg + (long)r * H + c * 8);
        }
        const bf16* Vg = Vt + (long)(h * D) * S + c0;
        #pragma unroll
        for (int i = tid; i < 512; i += 256) {
            int d = i >> 3, c = i & 7;
            cpasync16(uv + swz128(d, c), Vg + (long)d * S + c * 8);
        }
        const uint32_t ucq = uCQ + st * CQ_BYTES;
        const bf16* CQg = CQb + ((size_t)h * S + c0) * LPOS;
        for (int i = tid; i < 64 * 18; i += 256) {
            int j = i / 18, ch = i % 18;
            int Lb = lbc(c0 + j);
            cpasync16(ucq + j * CQ_ROWB + ch * 16,
                      CQg + (size_t)j * LPOS + Lb + ch * 8);
        }
    };
    load_kv(ct0, 0);
    CP_COMMIT();
    CP_WAIT1();
    __syncthreads();

    uint32_t qf[4][4];
    #pragma unroll
    for (int kk = 0; kk < 4; kk++) {
        int row = wid * 16 + (lane & 15);
        int c16 = kk * 2 + (lane >> 4);
        ldsm4(qf[kk], uQ + swz128(row, c16));
    }

    const int rb0 = wid * 16 + (lane >> 2);   // r0 - bm
    const int rb1 = rb0 + 8;                  // r1 - bm
    const int r0 = bm + rb0;
    const int r1 = bm + rb1;
    const int m0v = mask[r0], m1v = mask[r1];
    const bf16* ck0 = CKb + ((size_t)h * S + r0) * LPOS;
    const bf16* ck1 = CKb + ((size_t)h * S + r1) * LPOS;

    float m0 = NEGMAX, m1 = NEGMAX, l0 = 0.f, l1 = 0.f;
    float O[8][4] = {};

    for (int it = 0; it < HTILES; it++) {
        const int ct = ct0 + it;
        const int st = it & 1;
        if (it + 1 < HTILES) { load_kv(ct + 1, st ^ 1); CP_COMMIT(); CP_WAIT1(); }
        else                 { CP_WAIT0(); }
        __syncthreads();

        const uint32_t uk = uK + st * 8192;
        const uint32_t uv = uV + st * 8192;
        const bf16* sCQ = (const bf16*)(dyn + (uCQ - uQ) + st * CQ_BYTES);

        float sfr[8][4] = {};
        #pragma unroll
        for (int g = 0; g < 4; g++) {
            #pragma unroll
            for (int kk = 0; kk < 4; kk++) {
                uint32_t r4[4];
                int n   = g * 16 + ((lane >> 4) << 3) + (lane & 7);
                int c16 = kk * 2 + ((lane >> 3) & 1);
                ldsm4(r4, uk + swz128(n, c16));
                mma16816(sfr[2 * g],     qf[kk], r4);
                mma16816(sfr[2 * g + 1], qf[kk], r4 + 2);
            }
        }

        const int c0 = ct * 64;
        const int dRC = bm - c0;
        // closed-form band index valid: q = dRC+512-cl' in [1, 888] for cl' in [0,63]
        const bool noclip = (dRC >= -448) && (dRC <= 320);
        float tmx0 = NEGMAX, tmx1 = NEGMAX;

        if (noclip) {
            #pragma unroll
            for (int nb = 0; nb < 8; nb++) {
                const int cl  = nb * 8 + (lane & 3) * 2;
                const int c   = c0 + cl;
                const int q0  = dRC + 512 - cl;      // ck index base, col cl
                const int t0  = q0 & 7;              // band offset, col cl
                const int t1  = (q0 - 1) & 7;        // band offset, col cl+1
                const int mc0 = mask[c], mc1 = mask[c + 1];
                const bf16* sq0 = sCQ + cl * CQ_W;
                const bf16* sq1 = sCQ + (cl + 1) * CQ_W;
                {
                    float v0 = (sfr[nb][0] + __bfloat162float(ck0[rb0 + q0])
                                + __bfloat162float(sq0[rb0 + t0])) * SCALE2;
                    float v1 = (sfr[nb][1] + __bfloat162float(ck0[rb0 + q0 - 1])
                                + __bfloat162float(sq1[rb0 + t1])) * SCALE2;
                    if (!(m0v && mc0)) v0 = NEGMAX;
                    if (!(m0v && mc1)) v1 = NEGMAX;
                    sfr[nb][0] = v0; sfr[nb][1] = v1;
                    tmx0 = fmaxf(tmx0, fmaxf(v0, v1));
                }
                {
                    float v2 = (sfr[nb][2] + __bfloat162float(ck1[rb1 + q0])
                                + __bfloat162float(sq0[rb1 + t0])) * SCALE2;
                    float v3 = (sfr[nb][3] + __bfloat162float(ck1[rb1 + q0 - 1])
                                + __bfloat162float(sq1[rb1 + t1])) * SCALE2;
                    if (!(m1v && mc0)) v2 = NEGMAX;
                    if (!(m1v && mc1)) v3 = NEGMAX;
                    sfr[nb][2] = v2; sfr[nb][3] = v3;
                    tmx1 = fmaxf(tmx1, fmaxf(v2, v3));
                }
            }
        } else {
            #pragma unroll
            for (int nb = 0; nb < 8; nb++) {
                const int cl = nb * 8 + (lane & 3) * 2;
                const int c  = c0 + cl;
                const int Lb0 = lbc(c);
                const int Lb1 = lbc(c + 1);
                const int mc0 = mask[c], mc1 = mask[c + 1];
                {
                    int la = min(max(r0 - c + 512, 0), LPOS - 1);
                    int lb = min(max(r0 - c + 511, 0), LPOS - 1);
                    float v0 = (sfr[nb][0] + __bfloat162float(ck0[la])
                                + __bfloat162float(sCQ[cl * CQ_W + (la - Lb0)])) * SCALE2;
                    float v1 = (sfr[nb][1] + __bfloat162float(ck0[lb])
                                + __bfloat162float(sCQ[(cl + 1) * CQ_W + (lb - Lb1)])) * SCALE2;
                    if (!(m0v && mc0)) v0 = NEGMAX;
                    if (!(m0v && mc1)) v1 = NEGMAX;
                    sfr[nb][0] = v0; sfr[nb][1] = v1;
                    tmx0 = fmaxf(tmx0, fmaxf(v0, v1));
                }
                {
                    int la = min(max(r1 - c + 512, 0), LPOS - 1);
                    int lb = min(max(r1 - c + 511, 0), LPOS - 1);
                    float v2 = (sfr[nb][2] + __bfloat162float(ck1[la])
                                + __bfloat162float(sCQ[cl * CQ_W + (la - Lb0)])) * SCALE2;
                    float v3 = (sfr[nb][3] + __bfloat162float(ck1[lb])
                                + __bfloat162float(sCQ[(cl + 1) * CQ_W + (lb - Lb1)])) * SCALE2;
                    if (!(m1v && mc0)) v2 = NEGMAX;
                    if (!(m1v && mc1)) v3 = NEGMAX;
                    sfr[nb][2] = v2; sfr[nb][3] = v3;
                    tmx1 = fmaxf(tmx1, fmaxf(v2, v3));
                }
            }
        }
        tmx0 = fmaxf(tmx0, __shfl_xor_sync(0xffffffffu, tmx0, 1));
        tmx0 = fmaxf(tmx0, __shfl_xor_sync(0xffffffffu, tmx0, 2));
        tmx1 = fmaxf(tmx1, __shfl_xor_sync(0xffffffffu, tmx1, 1));
        tmx1 = fmaxf(tmx1, __shfl_xor_sync(0xffffffffu, tmx1, 2));

        const float mn0 = fmaxf(m0, tmx0), mn1 = fmaxf(m1, tmx1);
        const float sc0 = exp2f(m0 - mn0), sc1 = exp2f(m1 - mn1);
        m0 = mn0; m1 = mn1;
        float rs0 = 0.f, rs1 = 0.f;
        #pragma unroll
        for (int nb = 0; nb < 8; nb++) {
            sfr[nb][0] = exp2f(sfr[nb][0] - mn0);
            sfr[nb][1] = exp2f(sfr[nb][1] - mn0);
            sfr[nb][2] = exp2f(sfr[nb][2] - mn1);
            sfr[nb][3] = exp2f(sfr[nb][3] - mn1);
            rs0 += sfr[nb][0] + sfr[nb][1];
            rs1 += sfr[nb][2] + sfr[nb][3];
        }
        rs0 += __shfl_xor_sync(0xffffffffu, rs0, 1);
        rs0 += __shfl_xor_sync(0xffffffffu, rs0, 2);
        rs1 += __shfl_xor_sync(0xffffffffu, rs1, 1);
        rs1 += __shfl_xor_sync(0xffffffffu, rs1, 2);
        l0 = l0 * sc0 + rs0;
        l1 = l1 * sc1 + rs1;
        #pragma unroll
        for (int df = 0; df < 8; df++) {
            O[df][0] *= sc0; O[df][1] *= sc0;
            O[df][2] *= sc1; O[df][3] *= sc1;
        }

        #pragma unroll
        for (int kk2 = 0; kk2 < 4; kk2++) {
            uint32_t pf[4];
            pf[0] = packbf2(sfr[2 * kk2][0],     sfr[2 * kk2][1]);
            pf[1] = packbf2(sfr[2 * kk2][2],     sfr[2 * kk2][3]);
            pf[2] = packbf2(sfr[2 * kk2 + 1][0], sfr[2 * kk2 + 1][1]);
            pf[3] = packbf2(sfr[2 * kk2 + 1][2], sfr[2 * kk2 + 1][3]);
            #pragma unroll
            for (int dg = 0; dg < 4; dg++) {
                uint32_t r4[4];
                int n   = dg * 16 + ((lane >> 4) << 3) + (lane & 7);
                int c16 = kk2 * 2 + ((lane >> 3) & 1);
                ldsm4(r4, uv + swz128(n, c16));
                mma16816(O[2 * dg],     pf, r4);
                mma16816(O[2 * dg + 1], pf, r4 + 2);
            }
        }
        __syncthreads();
    }

    const size_t base = ((size_t)z * NH + h) * S;
    if ((lane & 3) == 0) {
        ML[base + r0] = make_float2(m0, l0);
        ML[base + r1] = make_float2(m1, l1);
    }
    float* o0 = Opart + (base + r0) * D + (lane & 3) * 2;
    float* o1 = Opart + (base + r1) * D + (lane & 3) * 2;
    #pragma unroll
    for (int df = 0; df < 8; df++) {
        *(float2*)(o0 + df * 8) = make_float2(O[df][0], O[df][1]);
        *(float2*)(o1 + df * 8) = make_float2(O[df][2], O[df][3]);
    }
}

// ---------------------------------------------------------------------------
// Merge the ZSPL split-K slices (exp2 domain) -> normalized bf16 context.
// ---------------------------------------------------------------------------
__global__ void __launch_bounds__(256) merge_attn(
    const float* __restrict__ Opart, const float2* __restrict__ ML,
    bf16* __restrict__ CTX)
{
    const int p = blockIdx.x * 8 + (threadIdx.x >> 5);
    const int lane = threadIdx.x & 31;
    const int h = p / S, row = p % S;

    float2 ml[ZSPL];
    float M = NEGMAX;
    #pragma unroll
    for (int zz = 0; zz < ZSPL; zz++) {
        ml[zz] = ML[zz * NH * S + p];
        M = fmaxf(M, ml[zz].x);
    }
    float w[ZSPL], denom = 0.f;
    #pragma unroll
    for (int zz = 0; zz < ZSPL; zz++) {
        w[zz] = exp2f(ml[zz].x - M);
        denom += w[zz] * ml[zz].y;
    }
    const float inv = 1.0f / denom;

    const int d = lane * 2;
    float ax = 0.f, ay = 0.f;
    #pragma unroll
    for (int zz = 0; zz < ZSPL; zz++) {
        const float2 v = *(const float2*)(Opart + ((size_t)zz * NH * S + p) * D + d);
        ax += w[zz] * v.x;
        ay += w[zz] * v.y;
    }
    *(__nv_bfloat162*)(CTX + (long)row * H + h * D + d) =
        __float22bfloat162_rn(make_float2(ax * inv, ay * inv));
}

// ---------------------------------------------------------------------------
__global__ void cvt_bf16_2(const float* __restrict__ x0, bf16* __restrict__ y0, int n0,
                           const float* __restrict__ x1, bf16* __restrict__ y1, int n1)
{
    int i = blockIdx.x * 256 + threadIdx.x;
    if (i < n0) y0[i] = __float2bfloat16(x0[i]);
    else if (i < n0 + n1) y1[i - n0] = __float2bfloat16(x1[i - n0]);
}

struct P6 { const float* p[6]; };
__global__ void wtrans6(P6 srcs, bf16* __restrict__ Wt)
{
    __shared__ float t[32][33];
    const float* W = srcs.p[blockIdx.z];
    bf16* dst = Wt + (size_t)blockIdx.z * H * H;
    const int bx = blockIdx.x * 32, by = blockIdx.y * 32;
    #pragma unroll
    for (int i = threadIdx.y; i < 32; i += 8)
        t[i][threadIdx.x] = W[(long)(by + i) * H + bx + threadIdx.x];
    __syncthreads();
    #pragma unroll
    for (int i = threadIdx.y; i < 32; i += 8)
        dst[(long)(bx + i) * H + by + threadIdx.x] = __float2bfloat16(t[threadIdx.x][i]);
}

__global__ void ln_kernel(const float* __restrict__ x,
                          const float* __restrict__ gamma,
                          const float* __restrict__ beta,
                          float* __restrict__ out)
{
    __shared__ float rs[8], rq[8];
    const int s = blockIdx.x, tid = threadIdx.x;
    const float* row = x + (long)s * H;
    float a0 = row[tid], a1 = row[tid + 256], a2 = row[tid + 512];
    float sum = a0 + a1 + a2;
    float sq  = a0 * a0 + a1 * a1 + a2 * a2;
    #pragma unroll
    for (int o = 16; o > 0; o >>= 1) {
        sum += __shfl_xor_sync(0xffffffffu, sum, o);
        sq  += __shfl_xor_sync(0xffffffffu, sq,  o);
    }
    if ((tid & 31) == 0) { rs[tid >> 5] = sum; rq[tid >> 5] = sq; }
    __syncthreads();
    float ts = 0.f, tq = 0.f;
    #pragma unroll
    for (int w = 0; w < 8; w++) { ts += rs[w]; tq += rq[w]; }
    float mean = ts * (1.0f / H);
    float var  = tq * (1.0f / H) - mean * mean;
    float inv  = rsqrtf(var + 1e-7f);
    float* o = out + (long)s * H;
    o[tid]       = (a0 - mean) * inv * gamma[tid]       + beta[tid];
    o[tid + 256] = (a1 - mean) * inv * gamma[tid + 256] + beta[tid + 256];
    o[tid + 512] = (a2 - mean) * inv * gamma[tid + 512] + beta[tid + 512];
}

// ---------------------------------------------------------------------------
extern "C" void kernel_launch(void* const* d_in, const int* in_sizes, int n_in,
                              void* d_out, int out_size)
{
    const float* hidden = (const float*)d_in[0];
    const int*   mask   = (const int*)  d_in[1];
    const float* Wq     = (const float*)d_in[2];
    const float* bq     = (const float*)d_in[3];
    const float* Wk     = (const float*)d_in[4];
    const float* bk     = (const float*)d_in[5];
    const float* Wv     = (const float*)d_in[6];
    const float* bv     = (const float*)d_in[7];
    const float* rel    = (const float*)d_in[8];
    const float* Wpk    = (const float*)d_in[9];
    const float* Wpq    = (const float*)d_in[10];
    const float* bpq    = (const float*)d_in[11];
    const float* Wo     = (const float*)d_in[12];
    const float* bo     = (const float*)d_in[13];
    const float* gamma  = (const float*)d_in[14];
    const float* beta   = (const float*)d_in[15];
    float* out = (float*)d_out;

    bf16 *hbf, *relbf, *Wt, *Qbf, *Kbf, *Vt, *PKbf, *PQbf, *CKb, *CQb, *CTXbf;
    float *TMP, *Opart;
    float2* ML;
    cudaGetSymbolAddress((void**)&hbf,   g_hbf);
    cudaGetSymbolAddress((void**)&relbf, g_relbf);
    cudaGetSymbolAddress((void**)&Wt,    g_Wt);
    cudaGetSymbolAddress((void**)&Qbf,   g_Qbf);
    cudaGetSymbolAddress((void**)&Kbf,   g_Kbf);
    cudaGetSymbolAddress((void**)&Vt,    g_Vt);
    cudaGetSymbolAddress((void**)&PKbf,  g_PKbf);
    cudaGetSymbolAddress((void**)&PQbf,  g_PQbf);
    cudaGetSymbolAddress((void**)&CKb,   g_CKb);
    cudaGetSymbolAddress((void**)&CQb,   g_CQb);
    cudaGetSymbolAddress((void**)&Opart, g_Opart);
    cudaGetSymbolAddress((void**)&ML,    g_ML);
    cudaGetSymbolAddress((void**)&CTXbf, g_CTXbf);
    cudaGetSymbolAddress((void**)&TMP,   g_TMP);

    static cudaStream_t s1 = nullptr, s2 = nullptr;
    static cudaEvent_t evP = nullptr, evF1 = nullptr, evF2 = nullptr;
    static bool init_done = false;
    if (!init_done) {
        cudaFuncSetAttribute(flash_attn,
                             cudaFuncAttributeMaxDynamicSharedMemorySize, FL_SMEM);
        cudaStreamCreateWithFlags(&s1, cudaStreamNonBlocking);
        cudaStreamCreateWithFlags(&s2, cudaStreamNonBlocking);
        cudaEventCreateWithFlags(&evP,  cudaEventDisableTiming);
        cudaEventCreateWithFlags(&evF1, cudaEventDisableTiming);
        cudaEventCreateWithFlags(&evF2, cudaEventDisableTiming);
        init_done = true;
    }

    // --- conversions / transposes (default stream) ---
    cvt_bf16_2<<<(S * H + LPOS * H + 255) / 256, 256>>>(
        hidden, hbf, S * H, rel, relbf, LPOS * H);
    P6 w6; w6.p[0] = Wq; w6.p[1] = Wk; w6.p[2] = Wv;
    w6.p[3] = Wpk; w6.p[4] = Wpq; w6.p[5] = Wo;
    wtrans6<<<dim3(H/32, H/32, 6), dim3(32, 8)>>>(w6, Wt);

    // --- all five projections in one launch (default stream) ---
    ProjJobs J;
    J.A[0] = hbf;   J.Bw[0] = Wt + 0 * H * H; J.C[0] = Qbf;  J.bias[0] = bq;      J.mode[0] = 0;
    J.A[1] = hbf;   J.Bw[1] = Wt + 1 * H * H; J.C[1] = Kbf;  J.bias[1] = bk;      J.mode[1] = 0;
    J.A[2] = hbf;   J.Bw[2] = Wt + 2 * H * H; J.C[2] = Vt;   J.bias[2] = bv;      J.mode[2] = 1;
    J.A[3] = relbf; J.Bw[3] = Wt + 3 * H * H; J.C[3] = PKbf; J.bias[3] = nullptr; J.mode[3] = 0;
    J.A[4] = relbf; J.Bw[4] = Wt + 4 * H * H; J.C[4] = PQbf; J.bias[4] = bpq;     J.mode[4] = 0;
    J.start[0] = 0;   J.start[1] = 96;  J.start[2] = 192;
    J.start[3] = 288; J.start[4] = 336; J.start[5] = 384;
    gemm_proj<<<384, 256>>>(J);
    cudaEventRecord(evP, 0);

    // --- fork: tables first on both streams, then flash (per-stream order
    //     unchanged; submission order makes launch #6 = flash_s1 for ncu) ---
    cudaStreamWaitEvent(s1, evP, 0);
    gemm_tables<<<dim3(LPOS/128, S/128, 12), 256, 0, s1>>>(
        Qbf, Kbf, PKbf, PQbf, CKb, CQb, 0);
    cudaStreamWaitEvent(s2, evP, 0);
    gemm_tables<<<dim3(LPOS/128, S/128, 12), 256, 0, s2>>>(
        Qbf, Kbf, PKbf, PQbf, CKb, CQb, 6);

    flash_attn<<<dim3(S/128, NH/2, ZSPL), 256, FL_SMEM, s1>>>(
        Qbf, Kbf, Vt, CKb, CQb, mask, Opart, ML, 0);
    cudaEventRecord(evF1, s1);
    flash_attn<<<dim3(S/128, NH/2, ZSPL), 256, FL_SMEM, s2>>>(
        Qbf, Kbf, Vt, CKb, CQb, mask, Opart, ML, 6);
    cudaEventRecord(evF2, s2);

    // --- join back to default stream ---
    cudaStreamWaitEvent(0, evF1, 0);
    cudaStreamWaitEvent(0, evF2, 0);

    merge_attn<<<NH * S / 8, 256>>>(Opart, ML, CTXbf);

    // --- output projection + bias + residual ---
    gemm_out<<<dim3(6, 16), 256>>>(CTXbf, Wt + 5 * H * H, TMP, bo, hidden);

    // --- layernorm ---
    ln_kernel<<<S, 256>>>(TMP, gamma, beta, out);
}

// round 12
// speedup vs baseline: 11.9006x; 1.0400x over previous
#include <cuda_runtime.h>
#include <cuda_bf16.h>
#include <cstdint>

// ---------------------------------------------------------------------------
// BertAttention (DeBERTa) — round 12: smem-staged ck band (kills scattered
// ck LDGs in the flash epilogue). B=1, S=2048, H=768, NH=12, D=64, SPAN=512
// ---------------------------------------------------------------------------

constexpr int S    = 2048;
constexpr int H    = 768;
constexpr int NH   = 12;
constexpr int D    = 64;
constexpr int LPOS = 1024;  // 2*SPAN
constexpr int ZSPL = 4;     // split-K factor over key sequence
constexpr float SCALE2 = 0.07216878364870322f * 1.4426950408889634f;
constexpr float NEGMAX = -3.402823466e38f;

using bf16 = __nv_bfloat16;

// ---------------------------- scratch (device globals) ---------------------
__device__ bf16   g_hbf  [S * H];
__device__ bf16   g_relbf[LPOS * H];
__device__ bf16   g_Wt   [6 * H * H];
__device__ bf16   g_Qbf  [S * H];
__device__ bf16   g_Kbf  [S * H];
__device__ bf16   g_Vt   [H * S];
__device__ bf16   g_PKbf [LPOS * H];
__device__ bf16   g_PQbf [LPOS * H];
__device__ bf16   g_CKb  [(size_t)NH * S * LPOS];
__device__ bf16   g_CQb  [(size_t)NH * S * LPOS + 256];
__device__ float  g_Opart[(size_t)ZSPL * NH * S * D];
__device__ float2 g_ML   [ZSPL * NH * S];
__device__ bf16   g_CTXbf[S * H];
__device__ float  g_TMP  [S * H];

// ---------------------------- PTX helpers ----------------------------------
__device__ __forceinline__ uint32_t smem_u32(const void* p) {
    uint32_t a;
    asm("{ .reg .u64 t; cvta.to.shared.u64 t, %1; cvt.u32.u64 %0, t; }"
        : "=r"(a) : "l"(p));
    return a;
}
__device__ __forceinline__ void cpasync16(uint32_t dst, const void* src) {
    asm volatile("cp.async.cg.shared.global [%0], [%1], 16;" :: "r"(dst), "l"(src));
}
#define CP_COMMIT() asm volatile("cp.async.commit_group;" ::: "memory")
#define CP_WAIT1()  asm volatile("cp.async.wait_group 1;" ::: "memory")
#define CP_WAIT0()  asm volatile("cp.async.wait_group 0;" ::: "memory")

__device__ __forceinline__ void ldsm4(uint32_t* r, uint32_t addr) {
    asm volatile("ldmatrix.sync.aligned.m8n8.x4.shared.b16 {%0,%1,%2,%3}, [%4];"
                 : "=r"(r[0]), "=r"(r[1]), "=r"(r[2]), "=r"(r[3]) : "r"(addr));
}
__device__ __forceinline__ void mma16816(float* c, const uint32_t* a, const uint32_t* b) {
    asm volatile(
        "mma.sync.aligned.m16n8k16.row.col.f32.bf16.bf16.f32 "
        "{%0,%1,%2,%3}, {%4,%5,%6,%7}, {%8,%9}, {%0,%1,%2,%3};"
        : "+f"(c[0]), "+f"(c[1]), "+f"(c[2]), "+f"(c[3])
        : "r"(a[0]), "r"(a[1]), "r"(a[2]), "r"(a[3]), "r"(b[0]), "r"(b[1]));
}
__device__ __forceinline__ uint32_t packbf2(float a, float b) {
    __nv_bfloat162 t = __float22bfloat162_rn(make_float2(a, b));
    return *(uint32_t*)&t;
}

__device__ __forceinline__ uint32_t swz(int row, int chunk) {
    return (uint32_t)(row * 64 + ((chunk ^ ((row >> 1) & 3)) << 4));
}
__device__ __forceinline__ uint32_t swz128(int row, int c16) {
    return (uint32_t)(row * 128 + ((c16 ^ (row & 7)) << 4));
}

// ---------------------------------------------------------------------------
// Shared GEMM mainloop (128x128 tile, K-major bf16, NT).
// ---------------------------------------------------------------------------
struct SmemPtrs { uint32_t uA, uB; };

template<typename LoadFn>
__device__ __forceinline__ void gemm_core(
    int nch, SmemPtrs sp, int tid, int lane, int wm, int wn,
    float (&acc)[4][4][4], LoadFn load_tiles)
{
    constexpr int ABYTES = 128 * 32 * 2;
    constexpr int BBYTES = 128 * 32 * 2;
    load_tiles(0, 0);
    CP_COMMIT();
    for (int ch = 0; ch < nch; ch++) {
        const int st = ch & 1;
        if (ch + 1 < nch) { load_tiles(ch + 1, st ^ 1); CP_COMMIT(); CP_WAIT1(); }
        else              { CP_WAIT0(); }
        __syncthreads();
        const uint32_t bA = sp.uA + st * ABYTES;
        const uint32_t bB = sp.uB + st * BBYTES;
        #pragma unroll
        for (int kk = 0; kk < 2; kk++) {
            uint32_t afr[4][4];
            #pragma unroll
            for (int i = 0; i < 4; i++) {
                int row = wm * 64 + i * 16 + (lane & 15);
                int chk = kk * 2 + (lane >> 4);
                ldsm4(afr[i], bA + swz(row, chk));
            }
            uint32_t bfr[4][2];
            #pragma unroll
            for (int p = 0; p < 2; p++) {
                uint32_t r4[4];
                int n   = wn * 32 + p * 16 + ((lane >> 4) << 3) + (lane & 7);
                int chk = kk * 2 + ((lane >> 3) & 1);
                ldsm4(r4, bB + swz(n, chk));
                bfr[2 * p][0] = r4[0]; bfr[2 * p][1] = r4[1];
                bfr[2 * p + 1][0] = r4[2]; bfr[2 * p + 1][1] = r4[3];
            }
            #pragma unroll
            for (int i = 0; i < 4; i++)
                #pragma unroll
                for (int j = 0; j < 4; j++)
                    mma16816(acc[i][j], afr[i], bfr[j]);
        }
        __syncthreads();
    }
}

// ---------------------------------------------------------------------------
// Fused projection kernel: 5 jobs (Q, K, V->Vt, PK, PQ) in one 1-D grid.
// ---------------------------------------------------------------------------
struct ProjJobs {
    const bf16* A[5];
    const bf16* Bw[5];
    bf16*       C[5];
    const float* bias[5];
    int mode[5];
    int start[6];
};

__global__ void __launch_bounds__(256) gemm_proj(ProjJobs J)
{
    constexpr int ABYTES = 128 * 32 * 2, BBYTES = 128 * 32 * 2;
    __shared__ __align__(1024) char sm[2 * (ABYTES + BBYTES)];
    SmemPtrs sp { smem_u32(sm), smem_u32(sm) + 2 * ABYTES };

    int bx = blockIdx.x;
    int j = 0;
    while (bx >= J.start[j + 1]) j++;
    const int local = bx - J.start[j];
    const int bm = (local / 6) * 128, bn = (local % 6) * 128;

    const int tid = threadIdx.x, lane = tid & 31, wid = tid >> 5;
    const int wm = wid & 1, wn = wid >> 1;

    const bf16* Arow = J.A[j] + (long)bm * H;
    const bf16* Brow = J.Bw[j] + (long)bn * H;

    auto load_tiles = [&](int ch, int st) {
        const bf16* Ak = Arow + ch * 32;
        #pragma unroll
        for (int i = tid; i < 512; i += 256) {
            int r = i >> 2, c = i & 3;
            cpasync16(sp.uA + st * ABYTES + swz(r, c), Ak + (long)r * H + c * 8);
        }
        const bf16* Bk = Brow + ch * 32;
        #pragma unroll
        for (int i = tid; i < 512; i += 256) {
            int r = i >> 2, c = i & 3;
            cpasync16(sp.uB + st * BBYTES + swz(r, c), Bk + (long)r * H + c * 8);
        }
    };

    float acc[4][4][4] = {};
    gemm_core(H / 32, sp, tid, lane, wm, wn, acc, load_tiles);

    bf16* C = J.C[j];
    const float* bias = J.bias[j];
    const int mode = J.mode[j];

    #pragma unroll
    for (int i = 0; i < 4; i++)
        #pragma unroll
        for (int jj = 0; jj < 4; jj++)
            #pragma unroll
            for (int half = 0; half < 2; half++) {
                const int r = bm + wm * 64 + i * 16 + (lane >> 2) + half * 8;
                const int c = bn + wn * 32 + jj * 8 + (lane & 3) * 2;
                const float v0 = acc[i][jj][half * 2];
                const float v1 = acc[i][jj][half * 2 + 1];
                float b0 = bias ? bias[c] : 0.f, b1 = bias ? bias[c + 1] : 0.f;
                if (mode == 0) {
                    *(__nv_bfloat162*)(C + (long)r * H + c) =
                        __float22bfloat162_rn(make_float2(v0 + b0, v1 + b1));
                } else {
                    C[(long)c * S + r]       = __float2bfloat16(v0 + b0);
                    C[(long)(c + 1) * S + r] = __float2bfloat16(v1 + b1);
                }
            }
}

// ---------------------------------------------------------------------------
// Fused tables kernel (head range via hbase).
// ---------------------------------------------------------------------------
constexpr int TB_STRIDE = 272;

__global__ void __launch_bounds__(256) gemm_tables(
    const bf16* __restrict__ Qb, const bf16* __restrict__ Kb,
    const bf16* __restrict__ PK, const bf16* __restrict__ PQ,
    bf16* __restrict__ CK, bf16* __restrict__ CQ, int hbase)
{
    constexpr int ABYTES = 128 * 32 * 2, BBYTES = 128 * 32 * 2;
    __shared__ __align__(1024) char sm[128 * TB_STRIDE];
    SmemPtrs sp { smem_u32(sm), smem_u32(sm) + 2 * ABYTES };

    const int z = blockIdx.z;
    const bool isCK = z < 6;
    const int h = hbase + (isCK ? z : z - 6);
    const bf16* A = (isCK ? Qb : Kb) + h * D;
    const bf16* B = (isCK ? PK : PQ) + h * D;
    bf16* C = (isCK ? CK : CQ) + (size_t)h * S * LPOS;

    const int tid = threadIdx.x, lane = tid & 31, wid = tid >> 5;
    const int wm = wid & 1, wn = wid >> 1;
    const int bm = blockIdx.y * 128, bn = blockIdx.x * 128;

    const bf16* Arow = A + (long)bm * H;
    const bf16* Brow = B + (long)bn * H;

    auto load_tiles = [&](int ch, int st) {
        const bf16* Ak = Arow + ch * 32;
        #pragma unroll
        for (int i = tid; i < 512; i += 256) {
            int r = i >> 2, c = i & 3;
            cpasync16(sp.uA + st * ABYTES + swz(r, c), Ak + (long)r * H + c * 8);
        }
        const bf16* Bk = Brow + ch * 32;
        #pragma unroll
        for (int i = tid; i < 512; i += 256) {
            int r = i >> 2, c = i & 3;
            cpasync16(sp.uB + st * BBYTES + swz(r, c), Bk + (long)r * H + c * 8);
        }
    };

    float acc[4][4][4] = {};
    gemm_core(D / 32, sp, tid, lane, wm, wn, acc, load_tiles);

    #pragma unroll
    for (int i = 0; i < 4; i++)
        #pragma unroll
        for (int jj = 0; jj < 4; jj++)
            #pragma unroll
            for (int half = 0; half < 2; half++) {
                const int rl = wm * 64 + i * 16 + (lane >> 2) + half * 8;
                const int cl = wn * 32 + jj * 8 + (lane & 3) * 2;
                *(uint32_t*)(sm + rl * TB_STRIDE + cl * 2) =
                    packbf2(acc[i][jj][half * 2], acc[i][jj][half * 2 + 1]);
            }
    __syncthreads();

    #pragma unroll
    for (int i = tid; i < 2048; i += 256) {
        int r = i >> 4, ch = i & 15;
        uint4 v = *(uint4*)(sm + r * TB_STRIDE + ch * 16);
        *(uint4*)(C + (long)(bm + r) * LPOS + bn + ch * 8) = v;
    }
}

// ---------------------------------------------------------------------------
// Output projection + bias + residual (fp32 out).
// ---------------------------------------------------------------------------
__global__ void __launch_bounds__(256) gemm_out(
    const bf16* __restrict__ A, const bf16* __restrict__ Bw,
    float* __restrict__ C, const float* __restrict__ bias,
    const float* __restrict__ res)
{
    constexpr int ABYTES = 128 * 32 * 2, BBYTES = 128 * 32 * 2;
    __shared__ __align__(1024) char sm[2 * (ABYTES + BBYTES)];
    SmemPtrs sp { smem_u32(sm), smem_u32(sm) + 2 * ABYTES };

    const int tid = threadIdx.x, lane = tid & 31, wid = tid >> 5;
    const int wm = wid & 1, wn = wid >> 1;
    const int bm = blockIdx.y * 128, bn = blockIdx.x * 128;

    const bf16* Arow = A + (long)bm * H;
    const bf16* Brow = Bw + (long)bn * H;

    auto load_tiles = [&](int ch, int st) {
        const bf16* Ak = Arow + ch * 32;
        #pragma unroll
        for (int i = tid; i < 512; i += 256) {
            int r = i >> 2, c = i & 3;
            cpasync16(sp.uA + st * ABYTES + swz(r, c), Ak + (long)r * H + c * 8);
        }
        const bf16* Bk = Brow + ch * 32;
        #pragma unroll
        for (int i = tid; i < 512; i += 256) {
            int r = i >> 2, c = i & 3;
            cpasync16(sp.uB + st * BBYTES + swz(r, c), Bk + (long)r * H + c * 8);
        }
    };

    float acc[4][4][4] = {};
    gemm_core(H / 32, sp, tid, lane, wm, wn, acc, load_tiles);

    #pragma unroll
    for (int i = 0; i < 4; i++)
        #pragma unroll
        for (int jj = 0; jj < 4; jj++)
            #pragma unroll
            for (int half = 0; half < 2; half++) {
                const int r = bm + wm * 64 + i * 16 + (lane >> 2) + half * 8;
                const int c = bn + wn * 32 + jj * 8 + (lane & 3) * 2;
                const float* rr = res + (long)r * H;
                *(float2*)(C + (long)r * H + c) =
                    make_float2(acc[i][jj][half * 2] + bias[c] + rr[c],
                                acc[i][jj][half * 2 + 1] + bias[c + 1] + rr[c + 1]);
            }
}

// ---------------------------------------------------------------------------
// Flash-fused attention: both rel-pos tables staged through SMEM.
// cq band: 64 cols x 144 (as before, single-buffered).
// ck band: 128 rows x 72 values, base (rb+dRC+448)&~7, fast-path tiles only.
// ---------------------------------------------------------------------------
constexpr int CQ_W     = 144;
constexpr int CQ_ROWB  = CQ_W * 2;            // 288
constexpr int CQ_BYTES = 64 * CQ_ROWB;        // 18432
constexpr int CK_W     = 80;                  // 72 used + pad
constexpr int CK_ROWB  = CK_W * 2;            // 160
constexpr int CK_BYTES = 128 * CK_ROWB;       // 20480
constexpr int OFF_K    = 16384;
constexpr int OFF_V    = OFF_K + 16384;
constexpr int OFF_CQ   = OFF_V + 16384;
constexpr int OFF_CK   = OFF_CQ + CQ_BYTES;
constexpr int FL_SMEM  = OFF_CK + CK_BYTES;   // 88064
constexpr int HTILES   = (S / 64) / ZSPL;

__global__ void __launch_bounds__(256, 2) flash_attn(
    const bf16* __restrict__ Q, const bf16* __restrict__ K,
    const bf16* __restrict__ Vt,
    const bf16* __restrict__ CKb, const bf16* __restrict__ CQb,
    const int* __restrict__ mask,
    float* __restrict__ Opart, float2* __restrict__ ML, int hbase)
{
    extern __shared__ __align__(1024) char dyn[];
    const uint32_t uQ  = smem_u32(dyn);
    const uint32_t uK  = uQ + OFF_K;
    const uint32_t uV  = uQ + OFF_V;
    const uint32_t uCQ = uQ + OFF_CQ;
    const uint32_t uCK = uQ + OFF_CK;

    const int tid = threadIdx.x, lane = tid & 31, wid = tid >> 5;
    const int h = hbase + blockIdx.y, bm = blockIdx.x * 128;
    const int z = blockIdx.z;
    const int ct0 = z * HTILES;
    const int bmc = bm + 512;

    auto lbc = [&](int c) { return min(max(bmc - c, 0), 888) & ~7; };
    auto is_fast = [&](int ct) {
        int dRC = bm - ct * 64;
        return (dRC >= -448) && (dRC <= 320);
    };

    {
        const bf16* Qg = Q + (long)bm * H + h * D;
        #pragma unroll
        for (int i = tid; i < 1024; i += 256) {
            int r = i >> 3, c = i & 7;
            cpasync16(uQ + swz128(r, c), Qg + (long)r * H + c * 8);
        }
    }
    CP_COMMIT();

    auto load_kv = [&](int ct, int st) {
        const int c0 = ct * 64;
        const uint32_t uk = uK + st * 8192;
        const uint32_t uv = uV + st * 8192;
        const bf16* Kg = K + (long)c0 * H + h * D;
        #pragma unroll
        for (int i = tid; i < 512; i += 256) {
            int r = i >> 3, c = i & 7;
            cpasync16(uk + swz128(r, c), Kg + (long)r * H + c * 8);
        }
        const bf16* Vg = Vt + (long)(h * D) * S + c0;
        #pragma unroll
        for (int i = tid; i < 512; i += 256) {
            int d = i >> 3, c = i & 7;
            cpasync16(uv + swz128(d, c), Vg + (long)d * S + c * 8);
        }
    };

    auto load_band = [&](int ct) {
        const int c0 = ct * 64;
        const int dRC = bm - c0;
        // cq band (always)
        const bf16* CQg = CQb + ((size_t)h * S + c0) * LPOS;
        for (int i = tid; i < 64 * 18; i += 256) {
            int j = i / 18, ch = i % 18;
            int Lb = lbc(c0 + j);
            cpasync16(uCQ + j * CQ_ROWB + ch * 16,
                      CQg + (size_t)j * LPOS + Lb + ch * 8);
        }
        // ck band (fast-path tiles only)
        if (is_fast(ct)) {
            const bf16* CKg = CKb + ((size_t)h * S + bm) * LPOS;
            for (int i = tid; i < 128 * 9; i += 256) {
                int rb = i / 9, ch = i % 9;
                int Bal = (rb + dRC + 448) & ~7;
                cpasync16(uCK + rb * CK_ROWB + ch * 16,
                          CKg + (size_t)rb * LPOS + Bal + ch * 8);
            }
        }
    };

    load_kv(ct0, 0);
    CP_COMMIT();
    CP_WAIT1();          // Q done (KV may still be pending)
    __syncthreads();

    uint32_t qf[4][4];
    #pragma unroll
    for (int kk = 0; kk < 4; kk++) {
        int row = wid * 16 + (lane & 15);
        int c16 = kk * 2 + (lane >> 4);
        ldsm4(qf[kk], uQ + swz128(row, c16));
    }

    const int rb0 = wid * 16 + (lane >> 2);
    const int rb1 = rb0 + 8;
    const int r0 = bm + rb0;
    const int r1 = bm + rb1;
    const int m0v = mask[r0], m1v = mask[r1];
    const bf16* ck0 = CKb + ((size_t)h * S + r0) * LPOS;
    const bf16* ck1 = CKb + ((size_t)h * S + r1) * LPOS;

    float m0 = NEGMAX, m1 = NEGMAX, l0 = 0.f, l1 = 0.f;
    float O[8][4] = {};

    for (int it = 0; it < HTILES; it++) {
        const int ct = ct0 + it;
        const int st = it & 1;

        load_band(ct);
        CP_COMMIT();
        if (it + 1 < HTILES) { load_kv(ct + 1, st ^ 1); CP_COMMIT(); CP_WAIT1(); }
        else                 { CP_WAIT0(); }
        __syncthreads();

        const uint32_t uk = uK + st * 8192;
        const uint32_t uv = uV + st * 8192;
        const bf16* sCQ = (const bf16*)(dyn + OFF_CQ);
        const bf16* sCK = (const bf16*)(dyn + OFF_CK);

        float sfr[8][4] = {};
        #pragma unroll
        for (int g = 0; g < 4; g++) {
            #pragma unroll
            for (int kk = 0; kk < 4; kk++) {
                uint32_t r4[4];
                int n   = g * 16 + ((lane >> 4) << 3) + (lane & 7);
                int c16 = kk * 2 + ((lane >> 3) & 1);
                ldsm4(r4, uk + swz128(n, c16));
                mma16816(sfr[2 * g],     qf[kk], r4);
                mma16816(sfr[2 * g + 1], qf[kk], r4 + 2);
            }
        }

        const int c0 = ct * 64;
        const int dRC = bm - c0;
        const bool noclip = (dRC >= -448) && (dRC <= 320);
        float tmx0 = NEGMAX, tmx1 = NEGMAX;

        if (noclip) {
            const int ph = (rb0 + dRC + 448) & 7;     // same for rb1 (rb1=rb0+8)
            const bf16* sk0 = sCK + rb0 * CK_W;
            const bf16* sk1 = sCK + rb1 * CK_W;
            #pragma unroll
            for (int nb = 0; nb < 8; nb++) {
                const int cl  = nb * 8 + (lane & 3) * 2;
                const int c   = c0 + cl;
                const int off = 64 - cl + ph;          // idx for col cl; col cl+1 -> off-1
                const int mc0 = mask[c], mc1 = mask[c + 1];
                const bf16* sq0 = sCQ + cl * CQ_W;
                const bf16* sq1 = sCQ + (cl + 1) * CQ_W;
                const int q0 = dRC + 512 - cl;
                const int t0 = q0 & 7, t1 = (q0 - 1) & 7;
                {
                    float v0 = (sfr[nb][0] + __bfloat162float(sk0[off])
                                + __bfloat162float(sq0[rb0 + t0])) * SCALE2;
                    float v1 = (sfr[nb][1] + __bfloat162float(sk0[off - 1])
                                + __bfloat162float(sq1[rb0 + t1])) * SCALE2;
                    if (!(m0v && mc0)) v0 = NEGMAX;
                    if (!(m0v && mc1)) v1 = NEGMAX;
                    sfr[nb][0] = v0; sfr[nb][1] = v1;
                    tmx0 = fmaxf(tmx0, fmaxf(v0, v1));
                }
                {
                    float v2 = (sfr[nb][2] + __bfloat162float(sk1[off])
                                + __bfloat162float(sq0[rb1 + t0])) * SCALE2;
                    float v3 = (sfr[nb][3] + __bfloat162float(sk1[off - 1])
                                + __bfloat162float(sq1[rb1 + t1])) * SCALE2;
                    if (!(m1v && mc0)) v2 = NEGMAX;
                    if (!(m1v && mc1)) v3 = NEGMAX;
                    sfr[nb][2] = v2; sfr[nb][3] = v3;
                    tmx1 = fmaxf(tmx1, fmaxf(v2, v3));
                }
            }
        } else {
            #pragma unroll
            for (int nb = 0; nb < 8; nb++) {
                const int cl = nb * 8 + (lane & 3) * 2;
                const int c  = c0 + cl;
                const int Lb0 = lbc(c);
                const int Lb1 = lbc(c + 1);
                const int mc0 = mask[c], mc1 = mask[c + 1];
                {
                    int la = min(max(r0 - c + 512, 0), LPOS - 1);
                    int lb = min(max(r0 - c + 511, 0), LPOS - 1);
                    float v0 = (sfr[nb][0] + __bfloat162float(ck0[la])
                                + __bfloat162float(sCQ[cl * CQ_W + (la - Lb0)])) * SCALE2;
                    float v1 = (sfr[nb][1] + __bfloat162float(ck0[lb])
                                + __bfloat162float(sCQ[(cl + 1) * CQ_W + (lb - Lb1)])) * SCALE2;
                    if (!(m0v && mc0)) v0 = NEGMAX;
                    if (!(m0v && mc1)) v1 = NEGMAX;
                    sfr[nb][0] = v0; sfr[nb][1] = v1;
                    tmx0 = fmaxf(tmx0, fmaxf(v0, v1));
                }
                {
                    int la = min(max(r1 - c + 512, 0), LPOS - 1);
                    int lb = min(max(r1 - c + 511, 0), LPOS - 1);
                    float v2 = (sfr[nb][2] + __bfloat162float(ck1[la])
                                + __bfloat162float(sCQ[cl * CQ_W + (la - Lb0)])) * SCALE2;
                    float v3 = (sfr[nb][3] + __bfloat162float(ck1[lb])
                                + __bfloat162float(sCQ[(cl + 1) * CQ_W + (lb - Lb1)])) * SCALE2;
                    if (!(m1v && mc0)) v2 = NEGMAX;
                    if (!(m1v && mc1)) v3 = NEGMAX;
                    sfr[nb][2] = v2; sfr[nb][3] = v3;
                    tmx1 = fmaxf(tmx1, fmaxf(v2, v3));
                }
            }
        }
        tmx0 = fmaxf(tmx0, __shfl_xor_sync(0xffffffffu, tmx0, 1));
        tmx0 = fmaxf(tmx0, __shfl_xor_sync(0xffffffffu, tmx0, 2));
        tmx1 = fmaxf(tmx1, __shfl_xor_sync(0xffffffffu, tmx1, 1));
        tmx1 = fmaxf(tmx1, __shfl_xor_sync(0xffffffffu, tmx1, 2));

        const float mn0 = fmaxf(m0, tmx0), mn1 = fmaxf(m1, tmx1);
        const float sc0 = exp2f(m0 - mn0), sc1 = exp2f(m1 - mn1);
        m0 = mn0; m1 = mn1;
        float rs0 = 0.f, rs1 = 0.f;
        #pragma unroll
        for (int nb = 0; nb < 8; nb++) {
            sfr[nb][0] = exp2f(sfr[nb][0] - mn0);
            sfr[nb][1] = exp2f(sfr[nb][1] - mn0);
            sfr[nb][2] = exp2f(sfr[nb][2] - mn1);
            sfr[nb][3] = exp2f(sfr[nb][3] - mn1);
            rs0 += sfr[nb][0] + sfr[nb][1];
            rs1 += sfr[nb][2] + sfr[nb][3];
        }
        rs0 += __shfl_xor_sync(0xffffffffu, rs0, 1);
        rs0 += __shfl_xor_sync(0xffffffffu, rs0, 2);
        rs1 += __shfl_xor_sync(0xffffffffu, rs1, 1);
        rs1 += __shfl_xor_sync(0xffffffffu, rs1, 2);
        l0 = l0 * sc0 + rs0;
        l1 = l1 * sc1 + rs1;
        #pragma unroll
        for (int df = 0; df < 8; df++) {
            O[df][0] *= sc0; O[df][1] *= sc0;
            O[df][2] *= sc1; O[df][3] *= sc1;
        }

        #pragma unroll
        for (int kk2 = 0; kk2 < 4; kk2++) {
            uint32_t pf[4];
            pf[0] = packbf2(sfr[2 * kk2][0],     sfr[2 * kk2][1]);
            pf[1] = packbf2(sfr[2 * kk2][2],     sfr[2 * kk2][3]);
            pf[2] = packbf2(sfr[2 * kk2 + 1][0], sfr[2 * kk2 + 1][1]);
            pf[3] = packbf2(sfr[2 * kk2 + 1][2], sfr[2 * kk2 + 1][3]);
            #pragma unroll
            for (int dg = 0; dg < 4; dg++) {
                uint32_t r4[4];
                int n   = dg * 16 + ((lane >> 4) << 3) + (lane & 7);
                int c16 = kk2 * 2 + ((lane >> 3) & 1);
                ldsm4(r4, uv + swz128(n, c16));
                mma16816(O[2 * dg],     pf, r4);
                mma16816(O[2 * dg + 1], pf, r4 + 2);
            }
        }
        __syncthreads();   // protect cq/ck/KV buffers before next iteration
    }

    const size_t base = ((size_t)z * NH + h) * S;
    if ((lane & 3) == 0) {
        ML[base + r0] = make_float2(m0, l0);
        ML[base + r1] = make_float2(m1, l1);
    }
    float* o0 = Opart + (base + r0) * D + (lane & 3) * 2;
    float* o1 = Opart + (base + r1) * D + (lane & 3) * 2;
    #pragma unroll
    for (int df = 0; df < 8; df++) {
        *(float2*)(o0 + df * 8) = make_float2(O[df][0], O[df][1]);
        *(float2*)(o1 + df * 8) = make_float2(O[df][2], O[df][3]);
    }
}

// ---------------------------------------------------------------------------
// Merge the ZSPL split-K slices (exp2 domain) -> normalized bf16 context.
// ---------------------------------------------------------------------------
__global__ void __launch_bounds__(256) merge_attn(
    const float* __restrict__ Opart, const float2* __restrict__ ML,
    bf16* __restrict__ CTX)
{
    const int p = blockIdx.x * 8 + (threadIdx.x >> 5);
    const int lane = threadIdx.x & 31;
    const int h = p / S, row = p % S;

    float2 ml[ZSPL];
    float M = NEGMAX;
    #pragma unroll
    for (int zz = 0; zz < ZSPL; zz++) {
        ml[zz] = ML[zz * NH * S + p];
        M = fmaxf(M, ml[zz].x);
    }
    float w[ZSPL], denom = 0.f;
    #pragma unroll
    for (int zz = 0; zz < ZSPL; zz++) {
        w[zz] = exp2f(ml[zz].x - M);
        denom += w[zz] * ml[zz].y;
    }
    const float inv = 1.0f / denom;

    const int d = lane * 2;
    float ax = 0.f, ay = 0.f;
    #pragma unroll
    for (int zz = 0; zz < ZSPL; zz++) {
        const float2 v = *(const float2*)(Opart + ((size_t)zz * NH * S + p) * D + d);
        ax += w[zz] * v.x;
        ay += w[zz] * v.y;
    }
    *(__nv_bfloat162*)(CTX + (long)row * H + h * D + d) =
        __float22bfloat162_rn(make_float2(ax * inv, ay * inv));
}

// ---------------------------------------------------------------------------
__global__ void cvt_bf16_2(const float* __restrict__ x0, bf16* __restrict__ y0, int n0,
                           const float* __restrict__ x1, bf16* __restrict__ y1, int n1)
{
    int i = blockIdx.x * 256 + threadIdx.x;
    if (i < n0) y0[i] = __float2bfloat16(x0[i]);
    else if (i < n0 + n1) y1[i - n0] = __float2bfloat16(x1[i - n0]);
}

struct P6 { const float* p[6]; };
__global__ void wtrans6(P6 srcs, bf16* __restrict__ Wt)
{
    __shared__ float t[32][33];
    const float* W = srcs.p[blockIdx.z];
    bf16* dst = Wt + (size_t)blockIdx.z * H * H;
    const int bx = blockIdx.x * 32, by = blockIdx.y * 32;
    #pragma unroll
    for (int i = threadIdx.y; i < 32; i += 8)
        t[i][threadIdx.x] = W[(long)(by + i) * H + bx + threadIdx.x];
    __syncthreads();
    #pragma unroll
    for (int i = threadIdx.y; i < 32; i += 8)
        dst[(long)(bx + i) * H + by + threadIdx.x] = __float2bfloat16(t[threadIdx.x][i]);
}

__global__ void ln_kernel(const float* __restrict__ x,
                          const float* __restrict__ gamma,
                          const float* __restrict__ beta,
                          float* __restrict__ out)
{
    __shared__ float rs[8], rq[8];
    const int s = blockIdx.x, tid = threadIdx.x;
    const float* row = x + (long)s * H;
    float a0 = row[tid], a1 = row[tid + 256], a2 = row[tid + 512];
    float sum = a0 + a1 + a2;
    float sq  = a0 * a0 + a1 * a1 + a2 * a2;
    #pragma unroll
    for (int o = 16; o > 0; o >>= 1) {
        sum += __shfl_xor_sync(0xffffffffu, sum, o);
        sq  += __shfl_xor_sync(0xffffffffu, sq,  o);
    }
    if ((tid & 31) == 0) { rs[tid >> 5] = sum; rq[tid >> 5] = sq; }
    __syncthreads();
    float ts = 0.f, tq = 0.f;
    #pragma unroll
    for (int w = 0; w < 8; w++) { ts += rs[w]; tq += rq[w]; }
    float mean = ts * (1.0f / H);
    float var  = tq * (1.0f / H) - mean * mean;
    float inv  = rsqrtf(var + 1e-7f);
    float* o = out + (long)s * H;
    o[tid]       = (a0 - mean) * inv * gamma[tid]       + beta[tid];
    o[tid + 256] = (a1 - mean) * inv * gamma[tid + 256] + beta[tid + 256];
    o[tid + 512] = (a2 - mean) * inv * gamma[tid + 512] + beta[tid + 512];
}

// ---------------------------------------------------------------------------
extern "C" void kernel_launch(void* const* d_in, const int* in_sizes, int n_in,
                              void* d_out, int out_size)
{
    const float* hidden = (const float*)d_in[0];
    const int*   mask   = (const int*)  d_in[1];
    const float* Wq     = (const float*)d_in[2];
    const float* bq     = (const float*)d_in[3];
    const float* Wk     = (const float*)d_in[4];
    const float* bk     = (const float*)d_in[5];
    const float* Wv     = (const float*)d_in[6];
    const float* bv     = (const float*)d_in[7];
    const float* rel    = (const float*)d_in[8];
    const float* Wpk    = (const float*)d_in[9];
    const float* Wpq    = (const float*)d_in[10];
    const float* bpq    = (const float*)d_in[11];
    const float* Wo     = (const float*)d_in[12];
    const float* bo     = (const float*)d_in[13];
    const float* gamma  = (const float*)d_in[14];
    const float* beta   = (const float*)d_in[15];
    float* out = (float*)d_out;

    bf16 *hbf, *relbf, *Wt, *Qbf, *Kbf, *Vt, *PKbf, *PQbf, *CKb, *CQb, *CTXbf;
    float *TMP, *Opart;
    float2* ML;
    cudaGetSymbolAddress((void**)&hbf,   g_hbf);
    cudaGetSymbolAddress((void**)&relbf, g_relbf);
    cudaGetSymbolAddress((void**)&Wt,    g_Wt);
    cudaGetSymbolAddress((void**)&Qbf,   g_Qbf);
    cudaGetSymbolAddress((void**)&Kbf,   g_Kbf);
    cudaGetSymbolAddress((void**)&Vt,    g_Vt);
    cudaGetSymbolAddress((void**)&PKbf,  g_PKbf);
    cudaGetSymbolAddress((void**)&PQbf,  g_PQbf);
    cudaGetSymbolAddress((void**)&CKb,   g_CKb);
    cudaGetSymbolAddress((void**)&CQb,   g_CQb);
    cudaGetSymbolAddress((void**)&Opart, g_Opart);
    cudaGetSymbolAddress((void**)&ML,    g_ML);
    cudaGetSymbolAddress((void**)&CTXbf, g_CTXbf);
    cudaGetSymbolAddress((void**)&TMP,   g_TMP);

    static cudaStream_t s1 = nullptr, s2 = nullptr;
    static cudaEvent_t evP = nullptr, evF1 = nullptr, evF2 = nullptr;
    static bool init_done = false;
    if (!init_done) {
        cudaFuncSetAttribute(flash_attn,
                             cudaFuncAttributeMaxDynamicSharedMemorySize, FL_SMEM);
        cudaStreamCreateWithFlags(&s1, cudaStreamNonBlocking);
        cudaStreamCreateWithFlags(&s2, cudaStreamNonBlocking);
        cudaEventCreateWithFlags(&evP,  cudaEventDisableTiming);
        cudaEventCreateWithFlags(&evF1, cudaEventDisableTiming);
        cudaEventCreateWithFlags(&evF2, cudaEventDisableTiming);
        init_done = true;
    }

    // --- conversions / transposes (default stream) ---
    cvt_bf16_2<<<(S * H + LPOS * H + 255) / 256, 256>>>(
        hidden, hbf, S * H, rel, relbf, LPOS * H);
    P6 w6; w6.p[0] = Wq; w6.p[1] = Wk; w6.p[2] = Wv;
    w6.p[3] = Wpk; w6.p[4] = Wpq; w6.p[5] = Wo;
    wtrans6<<<dim3(H/32, H/32, 6), dim3(32, 8)>>>(w6, Wt);

    // --- all five projections in one launch (default stream) ---
    ProjJobs J;
    J.A[0] = hbf;   J.Bw[0] = Wt + 0 * H * H; J.C[0] = Qbf;  J.bias[0] = bq;      J.mode[0] = 0;
    J.A[1] = hbf;   J.Bw[1] = Wt + 1 * H * H; J.C[1] = Kbf;  J.bias[1] = bk;      J.mode[1] = 0;
    J.A[2] = hbf;   J.Bw[2] = Wt + 2 * H * H; J.C[2] = Vt;   J.bias[2] = bv;      J.mode[2] = 1;
    J.A[3] = relbf; J.Bw[3] = Wt + 3 * H * H; J.C[3] = PKbf; J.bias[3] = nullptr; J.mode[3] = 0;
    J.A[4] = relbf; J.Bw[4] = Wt + 4 * H * H; J.C[4] = PQbf; J.bias[4] = bpq;     J.mode[4] = 0;
    J.start[0] = 0;   J.start[1] = 96;  J.start[2] = 192;
    J.start[3] = 288; J.start[4] = 336; J.start[5] = 384;
    gemm_proj<<<384, 256>>>(J);
    cudaEventRecord(evP, 0);

    // --- fork: tables then flash on two streams ---
    cudaStreamWaitEvent(s1, evP, 0);
    gemm_tables<<<dim3(LPOS/128, S/128, 12), 256, 0, s1>>>(
        Qbf, Kbf, PKbf, PQbf, CKb, CQb, 0);
    cudaStreamWaitEvent(s2, evP, 0);
    gemm_tables<<<dim3(LPOS/128, S/128, 12), 256, 0, s2>>>(
        Qbf, Kbf, PKbf, PQbf, CKb, CQb, 6);

    flash_attn<<<dim3(S/128, NH/2, ZSPL), 256, FL_SMEM, s1>>>(
        Qbf, Kbf, Vt, CKb, CQb, mask, Opart, ML, 0);
    cudaEventRecord(evF1, s1);
    flash_attn<<<dim3(S/128, NH/2, ZSPL), 256, FL_SMEM, s2>>>(
        Qbf, Kbf, Vt, CKb, CQb, mask, Opart, ML, 6);
    cudaEventRecord(evF2, s2);

    // --- join back to default stream ---
    cudaStreamWaitEvent(0, evF1, 0);
    cudaStreamWaitEvent(0, evF2, 0);

    merge_attn<<<NH * S / 8, 256>>>(Opart, ML, CTXbf);

    // --- output projection + bias + residual ---
    gemm_out<<<dim3(6, 16), 256>>>(CTXbf, Wt + 5 * H * H, TMP, bo, hidden);

    // --- layernorm ---
    ln_kernel<<<S, 256>>>(TMP, gamma, beta, out);
}

// round 13
// speedup vs baseline: 12.7759x; 1.0736x over previous
#include <cuda_runtime.h>
#include <cuda_bf16.h>
#include <cstdint>

// ---------------------------------------------------------------------------
// BertAttention (DeBERTa) — round 13: saturated-tile fast path (scalar bias).
// B=1, S=2048, H=768, NH=12, D=64, SPAN=512
// ---------------------------------------------------------------------------

constexpr int S    = 2048;
constexpr int H    = 768;
constexpr int NH   = 12;
constexpr int D    = 64;
constexpr int LPOS = 1024;  // 2*SPAN
constexpr int ZSPL = 4;     // split-K factor over key sequence
constexpr float SCALE2 = 0.07216878364870322f * 1.4426950408889634f;
constexpr float NEGMAX = -3.402823466e38f;

using bf16 = __nv_bfloat16;

// ---------------------------- scratch (device globals) ---------------------
__device__ bf16   g_hbf  [S * H];
__device__ bf16   g_relbf[LPOS * H];
__device__ bf16   g_Wt   [6 * H * H];
__device__ bf16   g_Qbf  [S * H];
__device__ bf16   g_Kbf  [S * H];
__device__ bf16   g_Vt   [H * S];
__device__ bf16   g_PKbf [LPOS * H];
__device__ bf16   g_PQbf [LPOS * H];
__device__ bf16   g_CKb  [(size_t)NH * S * LPOS];
__device__ bf16   g_CQb  [(size_t)NH * S * LPOS + 256];
__device__ float  g_Opart[(size_t)ZSPL * NH * S * D];
__device__ float2 g_ML   [ZSPL * NH * S];
__device__ bf16   g_CTXbf[S * H];
__device__ float  g_TMP  [S * H];

// ---------------------------- PTX helpers ----------------------------------
__device__ __forceinline__ uint32_t smem_u32(const void* p) {
    uint32_t a;
    asm("{ .reg .u64 t; cvta.to.shared.u64 t, %1; cvt.u32.u64 %0, t; }"
        : "=r"(a) : "l"(p));
    return a;
}
__device__ __forceinline__ void cpasync16(uint32_t dst, const void* src) {
    asm volatile("cp.async.cg.shared.global [%0], [%1], 16;" :: "r"(dst), "l"(src));
}
#define CP_COMMIT() asm volatile("cp.async.commit_group;" ::: "memory")
#define CP_WAIT1()  asm volatile("cp.async.wait_group 1;" ::: "memory")
#define CP_WAIT0()  asm volatile("cp.async.wait_group 0;" ::: "memory")

__device__ __forceinline__ void ldsm4(uint32_t* r, uint32_t addr) {
    asm volatile("ldmatrix.sync.aligned.m8n8.x4.shared.b16 {%0,%1,%2,%3}, [%4];"
                 : "=r"(r[0]), "=r"(r[1]), "=r"(r[2]), "=r"(r[3]) : "r"(addr));
}
__device__ __forceinline__ void mma16816(float* c, const uint32_t* a, const uint32_t* b) {
    asm volatile(
        "mma.sync.aligned.m16n8k16.row.col.f32.bf16.bf16.f32 "
        "{%0,%1,%2,%3}, {%4,%5,%6,%7}, {%8,%9}, {%0,%1,%2,%3};"
        : "+f"(c[0]), "+f"(c[1]), "+f"(c[2]), "+f"(c[3])
        : "r"(a[0]), "r"(a[1]), "r"(a[2]), "r"(a[3]), "r"(b[0]), "r"(b[1]));
}
__device__ __forceinline__ uint32_t packbf2(float a, float b) {
    __nv_bfloat162 t = __float22bfloat162_rn(make_float2(a, b));
    return *(uint32_t*)&t;
}

__device__ __forceinline__ uint32_t swz(int row, int chunk) {
    return (uint32_t)(row * 64 + ((chunk ^ ((row >> 1) & 3)) << 4));
}
__device__ __forceinline__ uint32_t swz128(int row, int c16) {
    return (uint32_t)(row * 128 + ((c16 ^ (row & 7)) << 4));
}

// ---------------------------------------------------------------------------
// Shared GEMM mainloop (128x128 tile, K-major bf16, NT).
// ---------------------------------------------------------------------------
struct SmemPtrs { uint32_t uA, uB; };

template<typename LoadFn>
__device__ __forceinline__ void gemm_core(
    int nch, SmemPtrs sp, int tid, int lane, int wm, int wn,
    float (&acc)[4][4][4], LoadFn load_tiles)
{
    constexpr int ABYTES = 128 * 32 * 2;
    constexpr int BBYTES = 128 * 32 * 2;
    load_tiles(0, 0);
    CP_COMMIT();
    for (int ch = 0; ch < nch; ch++) {
        const int st = ch & 1;
        if (ch + 1 < nch) { load_tiles(ch + 1, st ^ 1); CP_COMMIT(); CP_WAIT1(); }
        else              { CP_WAIT0(); }
        __syncthreads();
        const uint32_t bA = sp.uA + st * ABYTES;
        const uint32_t bB = sp.uB + st * BBYTES;
        #pragma unroll
        for (int kk = 0; kk < 2; kk++) {
            uint32_t afr[4][4];
            #pragma unroll
            for (int i = 0; i < 4; i++) {
                int row = wm * 64 + i * 16 + (lane & 15);
                int chk = kk * 2 + (lane >> 4);
                ldsm4(afr[i], bA + swz(row, chk));
            }
            uint32_t bfr[4][2];
            #pragma unroll
            for (int p = 0; p < 2; p++) {
                uint32_t r4[4];
                int n   = wn * 32 + p * 16 + ((lane >> 4) << 3) + (lane & 7);
                int chk = kk * 2 + ((lane >> 3) & 1);
                ldsm4(r4, bB + swz(n, chk));
                bfr[2 * p][0] = r4[0]; bfr[2 * p][1] = r4[1];
                bfr[2 * p + 1][0] = r4[2]; bfr[2 * p + 1][1] = r4[3];
            }
            #pragma unroll
            for (int i = 0; i < 4; i++)
                #pragma unroll
                for (int j = 0; j < 4; j++)
                    mma16816(acc[i][j], afr[i], bfr[j]);
        }
        __syncthreads();
    }
}

// ---------------------------------------------------------------------------
// Fused projection kernel: 5 jobs (Q, K, V->Vt, PK, PQ) in one 1-D grid.
// ---------------------------------------------------------------------------
struct ProjJobs {
    const bf16* A[5];
    const bf16* Bw[5];
    bf16*       C[5];
    const float* bias[5];
    int mode[5];
    int start[6];
};

__global__ void __launch_bounds__(256) gemm_proj(ProjJobs J)
{
    constexpr int ABYTES = 128 * 32 * 2, BBYTES = 128 * 32 * 2;
    __shared__ __align__(1024) char sm[2 * (ABYTES + BBYTES)];
    SmemPtrs sp { smem_u32(sm), smem_u32(sm) + 2 * ABYTES };

    int bx = blockIdx.x;
    int j = 0;
    while (bx >= J.start[j + 1]) j++;
    const int local = bx - J.start[j];
    const int bm = (local / 6) * 128, bn = (local % 6) * 128;

    const int tid = threadIdx.x, lane = tid & 31, wid = tid >> 5;
    const int wm = wid & 1, wn = wid >> 1;

    const bf16* Arow = J.A[j] + (long)bm * H;
    const bf16* Brow = J.Bw[j] + (long)bn * H;

    auto load_tiles = [&](int ch, int st) {
        const bf16* Ak = Arow + ch * 32;
        #pragma unroll
        for (int i = tid; i < 512; i += 256) {
            int r = i >> 2, c = i & 3;
            cpasync16(sp.uA + st * ABYTES + swz(r, c), Ak + (long)r * H + c * 8);
        }
        const bf16* Bk = Brow + ch * 32;
        #pragma unroll
        for (int i = tid; i < 512; i += 256) {
            int r = i >> 2, c = i & 3;
            cpasync16(sp.uB + st * BBYTES + swz(r, c), Bk + (long)r * H + c * 8);
        }
    };

    float acc[4][4][4] = {};
    gemm_core(H / 32, sp, tid, lane, wm, wn, acc, load_tiles);

    bf16* C = J.C[j];
    const float* bias = J.bias[j];
    const int mode = J.mode[j];

    #pragma unroll
    for (int i = 0; i < 4; i++)
        #pragma unroll
        for (int jj = 0; jj < 4; jj++)
            #pragma unroll
            for (int half = 0; half < 2; half++) {
                const int r = bm + wm * 64 + i * 16 + (lane >> 2) + half * 8;
                const int c = bn + wn * 32 + jj * 8 + (lane & 3) * 2;
                const float v0 = acc[i][jj][half * 2];
                const float v1 = acc[i][jj][half * 2 + 1];
                float b0 = bias ? bias[c] : 0.f, b1 = bias ? bias[c + 1] : 0.f;
                if (mode == 0) {
                    *(__nv_bfloat162*)(C + (long)r * H + c) =
                        __float22bfloat162_rn(make_float2(v0 + b0, v1 + b1));
                } else {
                    C[(long)c * S + r]       = __float2bfloat16(v0 + b0);
                    C[(long)(c + 1) * S + r] = __float2bfloat16(v1 + b1);
                }
            }
}

// ---------------------------------------------------------------------------
// Fused tables kernel (head range via hbase).
// ---------------------------------------------------------------------------
constexpr int TB_STRIDE = 272;

__global__ void __launch_bounds__(256) gemm_tables(
    const bf16* __restrict__ Qb, const bf16* __restrict__ Kb,
    const bf16* __restrict__ PK, const bf16* __restrict__ PQ,
    bf16* __restrict__ CK, bf16* __restrict__ CQ, int hbase)
{
    constexpr int ABYTES = 128 * 32 * 2, BBYTES = 128 * 32 * 2;
    __shared__ __align__(1024) char sm[128 * TB_STRIDE];
    SmemPtrs sp { smem_u32(sm), smem_u32(sm) + 2 * ABYTES };

    const int z = blockIdx.z;
    const bool isCK = z < 6;
    const int h = hbase + (isCK ? z : z - 6);
    const bf16* A = (isCK ? Qb : Kb) + h * D;
    const bf16* B = (isCK ? PK : PQ) + h * D;
    bf16* C = (isCK ? CK : CQ) + (size_t)h * S * LPOS;

    const int tid = threadIdx.x, lane = tid & 31, wid = tid >> 5;
    const int wm = wid & 1, wn = wid >> 1;
    const int bm = blockIdx.y * 128, bn = blockIdx.x * 128;

    const bf16* Arow = A + (long)bm * H;
    const bf16* Brow = B + (long)bn * H;

    auto load_tiles = [&](int ch, int st) {
        const bf16* Ak = Arow + ch * 32;
        #pragma unroll
        for (int i = tid; i < 512; i += 256) {
            int r = i >> 2, c = i & 3;
            cpasync16(sp.uA + st * ABYTES + swz(r, c), Ak + (long)r * H + c * 8);
        }
        const bf16* Bk = Brow + ch * 32;
        #pragma unroll
        for (int i = tid; i < 512; i += 256) {
            int r = i >> 2, c = i & 3;
            cpasync16(sp.uB + st * BBYTES + swz(r, c), Bk + (long)r * H + c * 8);
        }
    };

    float acc[4][4][4] = {};
    gemm_core(D / 32, sp, tid, lane, wm, wn, acc, load_tiles);

    #pragma unroll
    for (int i = 0; i < 4; i++)
        #pragma unroll
        for (int jj = 0; jj < 4; jj++)
            #pragma unroll
            for (int half = 0; half < 2; half++) {
                const int rl = wm * 64 + i * 16 + (lane >> 2) + half * 8;
                const int cl = wn * 32 + jj * 8 + (lane & 3) * 2;
                *(uint32_t*)(sm + rl * TB_STRIDE + cl * 2) =
                    packbf2(acc[i][jj][half * 2], acc[i][jj][half * 2 + 1]);
            }
    __syncthreads();

    #pragma unroll
    for (int i = tid; i < 2048; i += 256) {
        int r = i >> 4, ch = i & 15;
        uint4 v = *(uint4*)(sm + r * TB_STRIDE + ch * 16);
        *(uint4*)(C + (long)(bm + r) * LPOS + bn + ch * 8) = v;
    }
}

// ---------------------------------------------------------------------------
// Output projection + bias + residual (fp32 out).
// ---------------------------------------------------------------------------
__global__ void __launch_bounds__(256) gemm_out(
    const bf16* __restrict__ A, const bf16* __restrict__ Bw,
    float* __restrict__ C, const float* __restrict__ bias,
    const float* __restrict__ res)
{
    constexpr int ABYTES = 128 * 32 * 2, BBYTES = 128 * 32 * 2;
    __shared__ __align__(1024) char sm[2 * (ABYTES + BBYTES)];
    SmemPtrs sp { smem_u32(sm), smem_u32(sm) + 2 * ABYTES };

    const int tid = threadIdx.x, lane = tid & 31, wid = tid >> 5;
    const int wm = wid & 1, wn = wid >> 1;
    const int bm = blockIdx.y * 128, bn = blockIdx.x * 128;

    const bf16* Arow = A + (long)bm * H;
    const bf16* Brow = Bw + (long)bn * H;

    auto load_tiles = [&](int ch, int st) {
        const bf16* Ak = Arow + ch * 32;
        #pragma unroll
        for (int i = tid; i < 512; i += 256) {
            int r = i >> 2, c = i & 3;
            cpasync16(sp.uA + st * ABYTES + swz(r, c), Ak + (long)r * H + c * 8);
        }
        const bf16* Bk = Brow + ch * 32;
        #pragma unroll
        for (int i = tid; i < 512; i += 256) {
            int r = i >> 2, c = i & 3;
            cpasync16(sp.uB + st * BBYTES + swz(r, c), Bk + (long)r * H + c * 8);
        }
    };

    float acc[4][4][4] = {};
    gemm_core(H / 32, sp, tid, lane, wm, wn, acc, load_tiles);

    #pragma unroll
    for (int i = 0; i < 4; i++)
        #pragma unroll
        for (int jj = 0; jj < 4; jj++)
            #pragma unroll
            for (int half = 0; half < 2; half++) {
                const int r = bm + wm * 64 + i * 16 + (lane >> 2) + half * 8;
                const int c = bn + wn * 32 + jj * 8 + (lane & 3) * 2;
                const float* rr = res + (long)r * H;
                *(float2*)(C + (long)r * H + c) =
                    make_float2(acc[i][jj][half * 2] + bias[c] + rr[c],
                                acc[i][jj][half * 2 + 1] + bias[c + 1] + rr[c + 1]);
            }
}

// ---------------------------------------------------------------------------
// Flash-fused attention: fast band path + saturated scalar path + general.
// ---------------------------------------------------------------------------
constexpr int CQ_W     = 144;
constexpr int CQ_ROWB  = CQ_W * 2;            // 288
constexpr int CQ_BYTES = 64 * CQ_ROWB;        // 18432
constexpr int CK_W     = 80;
constexpr int CK_ROWB  = CK_W * 2;            // 160
constexpr int CK_BYTES = 128 * CK_ROWB;       // 20480
constexpr int OFF_K    = 16384;
constexpr int OFF_V    = OFF_K + 16384;
constexpr int OFF_CQ   = OFF_V + 16384;
constexpr int OFF_CK   = OFF_CQ + CQ_BYTES;
constexpr int OFF_SAT  = OFF_CK + CK_BYTES;   // lo[512] + hi[512] bf16
constexpr int FL_SMEM  = OFF_SAT + 2048;      // 90112
constexpr int HTILES   = (S / 64) / ZSPL;     // 8 (slice = 512 keys)

__global__ void __launch_bounds__(256, 2) flash_attn(
    const bf16* __restrict__ Q, const bf16* __restrict__ K,
    const bf16* __restrict__ Vt,
    const bf16* __restrict__ CKb, const bf16* __restrict__ CQb,
    const int* __restrict__ mask,
    float* __restrict__ Opart, float2* __restrict__ ML, int hbase)
{
    extern __shared__ __align__(1024) char dyn[];
    const uint32_t uQ  = smem_u32(dyn);
    const uint32_t uK  = uQ + OFF_K;
    const uint32_t uV  = uQ + OFF_V;
    const uint32_t uCQ = uQ + OFF_CQ;
    const uint32_t uCK = uQ + OFF_CK;

    const int tid = threadIdx.x, lane = tid & 31, wid = tid >> 5;
    const int h = hbase + blockIdx.y, bm = blockIdx.x * 128;
    const int z = blockIdx.z;
    const int ct0 = z * HTILES;
    const int bmc = bm + 512;

    auto lbc = [&](int c) { return min(max(bmc - c, 0), 888) & ~7; };
    auto tile_fast = [&](int dRC) { return (dRC >= -448) && (dRC <= 320); };
    auto tile_sat  = [&](int dRC) { return (dRC >= 576) || (dRC <= -640); };

    {
        const bf16* Qg = Q + (long)bm * H + h * D;
        #pragma unroll
        for (int i = tid; i < 1024; i += 256) {
            int r = i >> 3, c = i & 7;
            cpasync16(uQ + swz128(r, c), Qg + (long)r * H + c * 8);
        }
    }
    CP_COMMIT();

    auto load_kv = [&](int ct, int st) {
        const int c0 = ct * 64;
        const uint32_t uk = uK + st * 8192;
        const uint32_t uv = uV + st * 8192;
        const bf16* Kg = K + (long)c0 * H + h * D;
        #pragma unroll
        for (int i = tid; i < 512; i += 256) {
            int r = i >> 3, c = i & 7;
            cpasync16(uk + swz128(r, c), Kg + (long)r * H + c * 8);
        }
        const bf16* Vg = Vt + (long)(h * D) * S + c0;
        #pragma unroll
        for (int i = tid; i < 512; i += 256) {
            int d = i >> 3, c = i & 7;
            cpasync16(uv + swz128(d, c), Vg + (long)d * S + c * 8);
        }
    };

    auto load_band = [&](int ct) {
        const int c0 = ct * 64;
        const int dRC = bm - c0;
        if (tile_sat(dRC)) return;             // no bands needed
        const bf16* CQg = CQb + ((size_t)h * S + c0) * LPOS;
        for (int i = tid; i < 64 * 18; i += 256) {
            int j = i / 18, ch = i % 18;
            int Lb = lbc(c0 + j);
            cpasync16(uCQ + j * CQ_ROWB + ch * 16,
                      CQg + (size_t)j * LPOS + Lb + ch * 8);
        }
        if (tile_fast(dRC)) {
            const bf16* CKg = CKb + ((size_t)h * S + bm) * LPOS;
            for (int i = tid; i < 128 * 9; i += 256) {
                int rb = i / 9, ch = i % 9;
                int Bal = (rb + dRC + 448) & ~7;
                cpasync16(uCK + rb * CK_ROWB + ch * 16,
                          CKg + (size_t)rb * LPOS + Bal + ch * 8);
            }
        }
    };

    load_kv(ct0, 0);
    CP_COMMIT();
    CP_WAIT1();          // Q done
    __syncthreads();

    // one-time: saturated cq column values (l=0, l=1023) for this key slice
    {
        const bf16* CQg = CQb + ((size_t)h * S + ct0 * 64) * LPOS;
        bf16* slo = (bf16*)(dyn + OFF_SAT);
        bf16* shi = slo + 512;
        for (int j = tid; j < 512; j += 256) {
            slo[j] = CQg[(size_t)j * LPOS];
            shi[j] = CQg[(size_t)j * LPOS + 1023];
        }
    }

    uint32_t qf[4][4];
    #pragma unroll
    for (int kk = 0; kk < 4; kk++) {
        int row = wid * 16 + (lane & 15);
        int c16 = kk * 2 + (lane >> 4);
        ldsm4(qf[kk], uQ + swz128(row, c16));
    }

    const int rb0 = wid * 16 + (lane >> 2);
    const int rb1 = rb0 + 8;
    const int r0 = bm + rb0;
    const int r1 = bm + rb1;
    const int m0v = mask[r0], m1v = mask[r1];
    const bf16* ck0 = CKb + ((size_t)h * S + r0) * LPOS;
    const bf16* ck1 = CKb + ((size_t)h * S + r1) * LPOS;
    // saturated ck scalars
    const float cklo0 = __bfloat162float(ck0[0]);
    const float ckhi0 = __bfloat162float(ck0[1023]);
    const float cklo1 = __bfloat162float(ck1[0]);
    const float ckhi1 = __bfloat162float(ck1[1023]);

    float m0 = NEGMAX, m1 = NEGMAX, l0 = 0.f, l1 = 0.f;
    float O[8][4] = {};

    for (int it = 0; it < HTILES; it++) {
        const int ct = ct0 + it;
        const int st = it & 1;

        load_band(ct);
        CP_COMMIT();
        if (it + 1 < HTILES) { load_kv(ct + 1, st ^ 1); CP_COMMIT(); CP_WAIT1(); }
        else                 { CP_WAIT0(); }
        __syncthreads();

        const uint32_t uk = uK + st * 8192;
        const uint32_t uv = uV + st * 8192;
        const bf16* sCQ = (const bf16*)(dyn + OFF_CQ);
        const bf16* sCK = (const bf16*)(dyn + OFF_CK);

        float sfr[8][4] = {};
        #pragma unroll
        for (int g = 0; g < 4; g++) {
            #pragma unroll
            for (int kk = 0; kk < 4; kk++) {
                uint32_t r4[4];
                int n   = g * 16 + ((lane >> 4) << 3) + (lane & 7);
                int c16 = kk * 2 + ((lane >> 3) & 1);
                ldsm4(r4, uk + swz128(n, c16));
                mma16816(sfr[2 * g],     qf[kk], r4);
                mma16816(sfr[2 * g + 1], qf[kk], r4 + 2);
            }
        }

        const int c0 = ct * 64;
        const int dRC = bm - c0;
        float tmx0 = NEGMAX, tmx1 = NEGMAX;

        if (tile_fast(dRC)) {
            const int ph = (rb0 + dRC + 448) & 7;
            const bf16* sk0 = sCK + rb0 * CK_W;
            const bf16* sk1 = sCK + rb1 * CK_W;
            #pragma unroll
            for (int nb = 0; nb < 8; nb++) {
                const int cl  = nb * 8 + (lane & 3) * 2;
                const int c   = c0 + cl;
                const int off = 64 - cl + ph;
                const int mc0 = mask[c], mc1 = mask[c + 1];
                const bf16* sq0 = sCQ + cl * CQ_W;
                const bf16* sq1 = sCQ + (cl + 1) * CQ_W;
                const int q0 = dRC + 512 - cl;
                const int t0 = q0 & 7, t1 = (q0 - 1) & 7;
                {
                    float v0 = (sfr[nb][0] + __bfloat162float(sk0[off])
                                + __bfloat162float(sq0[rb0 + t0])) * SCALE2;
                    float v1 = (sfr[nb][1] + __bfloat162float(sk0[off - 1])
                                + __bfloat162float(sq1[rb0 + t1])) * SCALE2;
                    if (!(m0v && mc0)) v0 = NEGMAX;
                    if (!(m0v && mc1)) v1 = NEGMAX;
                    sfr[nb][0] = v0; sfr[nb][1] = v1;
                    tmx0 = fmaxf(tmx0, fmaxf(v0, v1));
                }
                {
                    float v2 = (sfr[nb][2] + __bfloat162float(sk1[off])
                                + __bfloat162float(sq0[rb1 + t0])) * SCALE2;
                    float v3 = (sfr[nb][3] + __bfloat162float(sk1[off - 1])
                                + __bfloat162float(sq1[rb1 + t1])) * SCALE2;
                    if (!(m1v && mc0)) v2 = NEGMAX;
                    if (!(m1v && mc1)) v3 = NEGMAX;
                    sfr[nb][2] = v2; sfr[nb][3] = v3;
                    tmx1 = fmaxf(tmx1, fmaxf(v2, v3));
                }
            }
        } else if (tile_sat(dRC)) {
            const bool hiSat = dRC > 0;
            const float f0 = hiSat ? ckhi0 : cklo0;
            const float f1 = hiSat ? ckhi1 : cklo1;
            const bf16* scq = (const bf16*)(dyn + OFF_SAT) + (hiSat ? 512 : 0);
            const int jb = it * 64;            // slice-local column base
            #pragma unroll
            for (int nb = 0; nb < 8; nb++) {
                const int cl  = nb * 8 + (lane & 3) * 2;
                const int c   = c0 + cl;
                const int mc0 = mask[c], mc1 = mask[c + 1];
                const float cq0 = __bfloat162float(scq[jb + cl]);
                const float cq1 = __bfloat162float(scq[jb + cl + 1]);
                {
                    float v0 = (sfr[nb][0] + f0 + cq0) * SCALE2;
                    float v1 = (sfr[nb][1] + f0 + cq1) * SCALE2;
                    if (!(m0v && mc0)) v0 = NEGMAX;
                    if (!(m0v && mc1)) v1 = NEGMAX;
                    sfr[nb][0] = v0; sfr[nb][1] = v1;
                    tmx0 = fmaxf(tmx0, fmaxf(v0, v1));
                }
                {
                    float v2 = (sfr[nb][2] + f1 + cq0) * SCALE2;
                    float v3 = (sfr[nb][3] + f1 + cq1) * SCALE2;
                    if (!(m1v && mc0)) v2 = NEGMAX;
                    if (!(m1v && mc1)) v3 = NEGMAX;
                    sfr[nb][2] = v2; sfr[nb][3] = v3;
                    tmx1 = fmaxf(tmx1, fmaxf(v2, v3));
                }
            }
        } else {
            #pragma unroll
            for (int nb = 0; nb < 8; nb++) {
                const int cl = nb * 8 + (lane & 3) * 2;
                const int c  = c0 + cl;
                const int Lb0 = lbc(c);
                const int Lb1 = lbc(c + 1);
                const int mc0 = mask[c], mc1 = mask[c + 1];
                {
                    int la = min(max(r0 - c + 512, 0), LPOS - 1);
                    int lb = min(max(r0 - c + 511, 0), LPOS - 1);
                    float v0 = (sfr[nb][0] + __bfloat162float(ck0[la])
                                + __bfloat162float(sCQ[cl * CQ_W + (la - Lb0)])) * SCALE2;
                    float v1 = (sfr[nb][1] + __bfloat162float(ck0[lb])
                                + __bfloat162float(sCQ[(cl + 1) * CQ_W + (lb - Lb1)])) * SCALE2;
                    if (!(m0v && mc0)) v0 = NEGMAX;
                    if (!(m0v && mc1)) v1 = NEGMAX;
                    sfr[nb][0] = v0; sfr[nb][1] = v1;
                    tmx0 = fmaxf(tmx0, fmaxf(v0, v1));
                }
                {
                    int la = min(max(r1 - c + 512, 0), LPOS - 1);
                    int lb = min(max(r1 - c + 511, 0), LPOS - 1);
                    float v2 = (sfr[nb][2] + __bfloat162float(ck1[la])
                                + __bfloat162float(sCQ[cl * CQ_W + (la - Lb0)])) * SCALE2;
                    float v3 = (sfr[nb][3] + __bfloat162float(ck1[lb])
                                + __bfloat162float(sCQ[(cl + 1) * CQ_W + (lb - Lb1)])) * SCALE2;
                    if (!(m1v && mc0)) v2 = NEGMAX;
                    if (!(m1v && mc1)) v3 = NEGMAX;
                    sfr[nb][2] = v2; sfr[nb][3] = v3;
                    tmx1 = fmaxf(tmx1, fmaxf(v2, v3));
                }
            }
        }
        tmx0 = fmaxf(tmx0, __shfl_xor_sync(0xffffffffu, tmx0, 1));
        tmx0 = fmaxf(tmx0, __shfl_xor_sync(0xffffffffu, tmx0, 2));
        tmx1 = fmaxf(tmx1, __shfl_xor_sync(0xffffffffu, tmx1, 1));
        tmx1 = fmaxf(tmx1, __shfl_xor_sync(0xffffffffu, tmx1, 2));

        const float mn0 = fmaxf(m0, tmx0), mn1 = fmaxf(m1, tmx1);
        const float sc0 = exp2f(m0 - mn0), sc1 = exp2f(m1 - mn1);
        m0 = mn0; m1 = mn1;
        float rs0 = 0.f, rs1 = 0.f;
        #pragma unroll
        for (int nb = 0; nb < 8; nb++) {
            sfr[nb][0] = exp2f(sfr[nb][0] - mn0);
            sfr[nb][1] = exp2f(sfr[nb][1] - mn0);
            sfr[nb][2] = exp2f(sfr[nb][2] - mn1);
            sfr[nb][3] = exp2f(sfr[nb][3] - mn1);
            rs0 += sfr[nb][0] + sfr[nb][1];
            rs1 += sfr[nb][2] + sfr[nb][3];
        }
        rs0 += __shfl_xor_sync(0xffffffffu, rs0, 1);
        rs0 += __shfl_xor_sync(0xffffffffu, rs0, 2);
        rs1 += __shfl_xor_sync(0xffffffffu, rs1, 1);
        rs1 += __shfl_xor_sync(0xffffffffu, rs1, 2);
        l0 = l0 * sc0 + rs0;
        l1 = l1 * sc1 + rs1;
        #pragma unroll
        for (int df = 0; df < 8; df++) {
            O[df][0] *= sc0; O[df][1] *= sc0;
            O[df][2] *= sc1; O[df][3] *= sc1;
        }

        #pragma unroll
        for (int kk2 = 0; kk2 < 4; kk2++) {
            uint32_t pf[4];
            pf[0] = packbf2(sfr[2 * kk2][0],     sfr[2 * kk2][1]);
            pf[1] = packbf2(sfr[2 * kk2][2],     sfr[2 * kk2][3]);
            pf[2] = packbf2(sfr[2 * kk2 + 1][0], sfr[2 * kk2 + 1][1]);
            pf[3] = packbf2(sfr[2 * kk2 + 1][2], sfr[2 * kk2 + 1][3]);
            #pragma unroll
            for (int dg = 0; dg < 4; dg++) {
                uint32_t r4[4];
                int n   = dg * 16 + ((lane >> 4) << 3) + (lane & 7);
                int c16 = kk2 * 2 + ((lane >> 3) & 1);
                ldsm4(r4, uv + swz128(n, c16));
                mma16816(O[2 * dg],     pf, r4);
                mma16816(O[2 * dg + 1], pf, r4 + 2);
            }
        }
        __syncthreads();
    }

    const size_t base = ((size_t)z * NH + h) * S;
    if ((lane & 3) == 0) {
        ML[base + r0] = make_float2(m0, l0);
        ML[base + r1] = make_float2(m1, l1);
    }
    float* o0 = Opart + (base + r0) * D + (lane & 3) * 2;
    float* o1 = Opart + (base + r1) * D + (lane & 3) * 2;
    #pragma unroll
    for (int df = 0; df < 8; df++) {
        *(float2*)(o0 + df * 8) = make_float2(O[df][0], O[df][1]);
        *(float2*)(o1 + df * 8) = make_float2(O[df][2], O[df][3]);
    }
}

// ---------------------------------------------------------------------------
// Merge the ZSPL split-K slices (exp2 domain) -> normalized bf16 context.
// ---------------------------------------------------------------------------
__global__ void __launch_bounds__(256) merge_attn(
    const float* __restrict__ Opart, const float2* __restrict__ ML,
    bf16* __restrict__ CTX)
{
    const int p = blockIdx.x * 8 + (threadIdx.x >> 5);
    const int lane = threadIdx.x & 31;
    const int h = p / S, row = p % S;

    float2 ml[ZSPL];
    float M = NEGMAX;
    #pragma unroll
    for (int zz = 0; zz < ZSPL; zz++) {
        ml[zz] = ML[zz * NH * S + p];
        M = fmaxf(M, ml[zz].x);
    }
    float w[ZSPL], denom = 0.f;
    #pragma unroll
    for (int zz = 0; zz < ZSPL; zz++) {
        w[zz] = exp2f(ml[zz].x - M);
        denom += w[zz] * ml[zz].y;
    }
    const float inv = 1.0f / denom;

    const int d = lane * 2;
    float ax = 0.f, ay = 0.f;
    #pragma unroll
    for (int zz = 0; zz < ZSPL; zz++) {
        const float2 v = *(const float2*)(Opart + ((size_t)zz * NH * S + p) * D + d);
        ax += w[zz] * v.x;
        ay += w[zz] * v.y;
    }
    *(__nv_bfloat162*)(CTX + (long)row * H + h * D + d) =
        __float22bfloat162_rn(make_float2(ax * inv, ay * inv));
}

// ---------------------------------------------------------------------------
__global__ void cvt_bf16_2(const float* __restrict__ x0, bf16* __restrict__ y0, int n0,
                           const float* __restrict__ x1, bf16* __restrict__ y1, int n1)
{
    int i = blockIdx.x * 256 + threadIdx.x;
    if (i < n0) y0[i] = __float2bfloat16(x0[i]);
    else if (i < n0 + n1) y1[i - n0] = __float2bfloat16(x1[i - n0]);
}

struct P6 { const float* p[6]; };
__global__ void wtrans6(P6 srcs, bf16* __restrict__ Wt)
{
    __shared__ float t[32][33];
    const float* W = srcs.p[blockIdx.z];
    bf16* dst = Wt + (size_t)blockIdx.z * H * H;
    const int bx = blockIdx.x * 32, by = blockIdx.y * 32;
    #pragma unroll
    for (int i = threadIdx.y; i < 32; i += 8)
        t[i][threadIdx.x] = W[(long)(by + i) * H + bx + threadIdx.x];
    __syncthreads();
    #pragma unroll
    for (int i = threadIdx.y; i < 32; i += 8)
        dst[(long)(bx + i) * H + by + threadIdx.x] = __float2bfloat16(t[threadIdx.x][i]);
}

__global__ void ln_kernel(const float* __restrict__ x,
                          const float* __restrict__ gamma,
                          const float* __restrict__ beta,
                          float* __restrict__ out)
{
    __shared__ float rs[8], rq[8];
    const int s = blockIdx.x, tid = threadIdx.x;
    const float* row = x + (long)s * H;
    float a0 = row[tid], a1 = row[tid + 256], a2 = row[tid + 512];
    float sum = a0 + a1 + a2;
    float sq  = a0 * a0 + a1 * a1 + a2 * a2;
    #pragma unroll
    for (int o = 16; o > 0; o >>= 1) {
        sum += __shfl_xor_sync(0xffffffffu, sum, o);
        sq  += __shfl_xor_sync(0xffffffffu, sq,  o);
    }
    if ((tid & 31) == 0) { rs[tid >> 5] = sum; rq[tid >> 5] = sq; }
    __syncthreads();
    float ts = 0.f, tq = 0.f;
    #pragma unroll
    for (int w = 0; w < 8; w++) { ts += rs[w]; tq += rq[w]; }
    float mean = ts * (1.0f / H);
    float var  = tq * (1.0f / H) - mean * mean;
    float inv  = rsqrtf(var + 1e-7f);
    float* o = out + (long)s * H;
    o[tid]       = (a0 - mean) * inv * gamma[tid]       + beta[tid];
    o[tid + 256] = (a1 - mean) * inv * gamma[tid + 256] + beta[tid + 256];
    o[tid + 512] = (a2 - mean) * inv * gamma[tid + 512] + beta[tid + 512];
}

// ---------------------------------------------------------------------------
extern "C" void kernel_launch(void* const* d_in, const int* in_sizes, int n_in,
                              void* d_out, int out_size)
{
    const float* hidden = (const float*)d_in[0];
    const int*   mask   = (const int*)  d_in[1];
    const float* Wq     = (const float*)d_in[2];
    const float* bq     = (const float*)d_in[3];
    const float* Wk     = (const float*)d_in[4];
    const float* bk     = (const float*)d_in[5];
    const float* Wv     = (const float*)d_in[6];
    const float* bv     = (const float*)d_in[7];
    const float* rel    = (const float*)d_in[8];
    const float* Wpk    = (const float*)d_in[9];
    const float* Wpq    = (const float*)d_in[10];
    const float* bpq    = (const float*)d_in[11];
    const float* Wo     = (const float*)d_in[12];
    const float* bo     = (const float*)d_in[13];
    const float* gamma  = (const float*)d_in[14];
    const float* beta   = (const float*)d_in[15];
    float* out = (float*)d_out;

    bf16 *hbf, *relbf, *Wt, *Qbf, *Kbf, *Vt, *PKbf, *PQbf, *CKb, *CQb, *CTXbf;
    float *TMP, *Opart;
    float2* ML;
    cudaGetSymbolAddress((void**)&hbf,   g_hbf);
    cudaGetSymbolAddress((void**)&relbf, g_relbf);
    cudaGetSymbolAddress((void**)&Wt,    g_Wt);
    cudaGetSymbolAddress((void**)&Qbf,   g_Qbf);
    cudaGetSymbolAddress((void**)&Kbf,   g_Kbf);
    cudaGetSymbolAddress((void**)&Vt,    g_Vt);
    cudaGetSymbolAddress((void**)&PKbf,  g_PKbf);
    cudaGetSymbolAddress((void**)&PQbf,  g_PQbf);
    cudaGetSymbolAddress((void**)&CKb,   g_CKb);
    cudaGetSymbolAddress((void**)&CQb,   g_CQb);
    cudaGetSymbolAddress((void**)&Opart, g_Opart);
    cudaGetSymbolAddress((void**)&ML,    g_ML);
    cudaGetSymbolAddress((void**)&CTXbf, g_CTXbf);
    cudaGetSymbolAddress((void**)&TMP,   g_TMP);

    static cudaStream_t s1 = nullptr, s2 = nullptr;
    static cudaEvent_t evP = nullptr, evF1 = nullptr, evF2 = nullptr;
    static bool init_done = false;
    if (!init_done) {
        cudaFuncSetAttribute(flash_attn,
                             cudaFuncAttributeMaxDynamicSharedMemorySize, FL_SMEM);
        cudaStreamCreateWithFlags(&s1, cudaStreamNonBlocking);
        cudaStreamCreateWithFlags(&s2, cudaStreamNonBlocking);
        cudaEventCreateWithFlags(&evP,  cudaEventDisableTiming);
        cudaEventCreateWithFlags(&evF1, cudaEventDisableTiming);
        cudaEventCreateWithFlags(&evF2, cudaEventDisableTiming);
        init_done = true;
    }

    // --- conversions / transposes (default stream) ---
    cvt_bf16_2<<<(S * H + LPOS * H + 255) / 256, 256>>>(
        hidden, hbf, S * H, rel, relbf, LPOS * H);
    P6 w6; w6.p[0] = Wq; w6.p[1] = Wk; w6.p[2] = Wv;
    w6.p[3] = Wpk; w6.p[4] = Wpq; w6.p[5] = Wo;
    wtrans6<<<dim3(H/32, H/32, 6), dim3(32, 8)>>>(w6, Wt);

    // --- all five projections in one launch (default stream) ---
    ProjJobs J;
    J.A[0] = hbf;   J.Bw[0] = Wt + 0 * H * H; J.C[0] = Qbf;  J.bias[0] = bq;      J.mode[0] = 0;
    J.A[1] = hbf;   J.Bw[1] = Wt + 1 * H * H; J.C[1] = Kbf;  J.bias[1] = bk;      J.mode[1] = 0;
    J.A[2] = hbf;   J.Bw[2] = Wt + 2 * H * H; J.C[2] = Vt;   J.bias[2] = bv;      J.mode[2] = 1;
    J.A[3] = relbf; J.Bw[3] = Wt + 3 * H * H; J.C[3] = PKbf; J.bias[3] = nullptr; J.mode[3] = 0;
    J.A[4] = relbf; J.Bw[4] = Wt + 4 * H * H; J.C[4] = PQbf; J.bias[4] = bpq;     J.mode[4] = 0;
    J.start[0] = 0;   J.start[1] = 96;  J.start[2] = 192;
    J.start[3] = 288; J.start[4] = 336; J.start[5] = 384;
    gemm_proj<<<384, 256>>>(J);
    cudaEventRecord(evP, 0);

    // --- fork: tables then flash on two streams ---
    cudaStreamWaitEvent(s1, evP, 0);
    gemm_tables<<<dim3(LPOS/128, S/128, 12), 256, 0, s1>>>(
        Qbf, Kbf, PKbf, PQbf, CKb, CQb, 0);
    cudaStreamWaitEvent(s2, evP, 0);
    gemm_tables<<<dim3(LPOS/128, S/128, 12), 256, 0, s2>>>(
        Qbf, Kbf, PKbf, PQbf, CKb, CQb, 6);

    flash_attn<<<dim3(S/128, NH/2, ZSPL), 256, FL_SMEM, s1>>>(
        Qbf, Kbf, Vt, CKb, CQb, mask, Opart, ML, 0);
    cudaEventRecord(evF1, s1);
    flash_attn<<<dim3(S/128, NH/2, ZSPL), 256, FL_SMEM, s2>>>(
        Qbf, Kbf, Vt, CKb, CQb, mask, Opart, ML, 6);
    cudaEventRecord(evF2, s2);

    // --- join back to default stream ---
    cudaStreamWaitEvent(0, evF1, 0);
    cudaStreamWaitEvent(0, evF2, 0);

    merge_attn<<<NH * S / 8, 256>>>(Opart, ML, CTXbf);

    // --- output projection + bias + residual ---
    gemm_out<<<dim3(6, 16), 256>>>(CTXbf, Wt + 5 * H * H, TMP, bo, hidden);

    // --- layernorm ---
    ln_kernel<<<S, 256>>>(TMP, gamma, beta, out);
}

// round 15
// speedup vs baseline: 12.8032x; 1.0021x over previous
#include <cuda_runtime.h>
#include <cuda_bf16.h>
#include <cstdint>

// ---------------------------------------------------------------------------
// BertAttention (DeBERTa) — round 15: R14 changes with a capture-legal fork
// (root-event before side-stream work). B=1, S=2048, H=768, NH=12, D=64.
// ---------------------------------------------------------------------------

constexpr int S    = 2048;
constexpr int H    = 768;
constexpr int NH   = 12;
constexpr int D    = 64;
constexpr int LPOS = 1024;  // 2*SPAN
constexpr int ZSPL = 4;     // split-K factor over key sequence
constexpr float SCALE2 = 0.07216878364870322f * 1.4426950408889634f;
constexpr float NEGMAX = -3.402823466e38f;

using bf16 = __nv_bfloat16;

// ---------------------------- scratch (device globals) ---------------------
__device__ bf16   g_hbf  [S * H];
__device__ bf16   g_relbf[LPOS * H];
__device__ bf16   g_Wt   [6 * H * H];
__device__ bf16   g_Qbf  [S * H];
__device__ bf16   g_Kbf  [S * H];
__device__ bf16   g_Vt   [H * S];
__device__ bf16   g_PKbf [LPOS * H];
__device__ bf16   g_PQbf [LPOS * H];
__device__ bf16   g_CKb  [(size_t)NH * S * LPOS];
__device__ bf16   g_CQb  [(size_t)NH * S * LPOS + 256];
__device__ float  g_Opart[(size_t)ZSPL * NH * S * D];
__device__ float2 g_ML   [ZSPL * NH * S];
__device__ bf16   g_CTXbf[S * H];
__device__ float  g_TMP  [S * H];

// ---------------------------- PTX helpers ----------------------------------
__device__ __forceinline__ uint32_t smem_u32(const void* p) {
    uint32_t a;
    asm("{ .reg .u64 t; cvta.to.shared.u64 t, %1; cvt.u32.u64 %0, t; }"
        : "=r"(a) : "l"(p));
    return a;
}
__device__ __forceinline__ void cpasync16(uint32_t dst, const void* src) {
    asm volatile("cp.async.cg.shared.global [%0], [%1], 16;" :: "r"(dst), "l"(src));
}
#define CP_COMMIT() asm volatile("cp.async.commit_group;" ::: "memory")
#define CP_WAIT1()  asm volatile("cp.async.wait_group 1;" ::: "memory")
#define CP_WAIT0()  asm volatile("cp.async.wait_group 0;" ::: "memory")

__device__ __forceinline__ void ldsm4(uint32_t* r, uint32_t addr) {
    asm volatile("ldmatrix.sync.aligned.m8n8.x4.shared.b16 {%0,%1,%2,%3}, [%4];"
                 : "=r"(r[0]), "=r"(r[1]), "=r"(r[2]), "=r"(r[3]) : "r"(addr));
}
__device__ __forceinline__ void mma16816(float* c, const uint32_t* a, const uint32_t* b) {
    asm volatile(
        "mma.sync.aligned.m16n8k16.row.col.f32.bf16.bf16.f32 "
        "{%0,%1,%2,%3}, {%4,%5,%6,%7}, {%8,%9}, {%0,%1,%2,%3};"
        : "+f"(c[0]), "+f"(c[1]), "+f"(c[2]), "+f"(c[3])
        : "r"(a[0]), "r"(a[1]), "r"(a[2]), "r"(a[3]), "r"(b[0]), "r"(b[1]));
}
__device__ __forceinline__ uint32_t packbf2(float a, float b) {
    __nv_bfloat162 t = __float22bfloat162_rn(make_float2(a, b));
    return *(uint32_t*)&t;
}

__device__ __forceinline__ uint32_t swz(int row, int chunk) {
    return (uint32_t)(row * 64 + ((chunk ^ ((row >> 1) & 3)) << 4));
}
__device__ __forceinline__ uint32_t swz128(int row, int c16) {
    return (uint32_t)(row * 128 + ((c16 ^ (row & 7)) << 4));
}

// ---------------------------------------------------------------------------
// Shared GEMM mainloop (128x128 tile, K-major bf16, NT).
// ---------------------------------------------------------------------------
struct SmemPtrs { uint32_t uA, uB; };

template<typename LoadFn>
__device__ __forceinline__ void gemm_core(
    int nch, SmemPtrs sp, int tid, int lane, int wm, int wn,
    float (&acc)[4][4][4], LoadFn load_tiles)
{
    constexpr int ABYTES = 128 * 32 * 2;
    constexpr int BBYTES = 128 * 32 * 2;
    load_tiles(0, 0);
    CP_COMMIT();
    for (int ch = 0; ch < nch; ch++) {
        const int st = ch & 1;
        if (ch + 1 < nch) { load_tiles(ch + 1, st ^ 1); CP_COMMIT(); CP_WAIT1(); }
        else              { CP_WAIT0(); }
        __syncthreads();
        const uint32_t bA = sp.uA + st * ABYTES;
        const uint32_t bB = sp.uB + st * BBYTES;
        #pragma unroll
        for (int kk = 0; kk < 2; kk++) {
            uint32_t afr[4][4];
            #pragma unroll
            for (int i = 0; i < 4; i++) {
                int row = wm * 64 + i * 16 + (lane & 15);
                int chk = kk * 2 + (lane >> 4);
                ldsm4(afr[i], bA + swz(row, chk));
            }
            uint32_t bfr[4][2];
            #pragma unroll
            for (int p = 0; p < 2; p++) {
                uint32_t r4[4];
                int n   = wn * 32 + p * 16 + ((lane >> 4) << 3) + (lane & 7);
                int chk = kk * 2 + ((lane >> 3) & 1);
                ldsm4(r4, bB + swz(n, chk));
                bfr[2 * p][0] = r4[0]; bfr[2 * p][1] = r4[1];
                bfr[2 * p + 1][0] = r4[2]; bfr[2 * p + 1][1] = r4[3];
            }
            #pragma unroll
            for (int i = 0; i < 4; i++)
                #pragma unroll
                for (int j = 0; j < 4; j++)
                    mma16816(acc[i][j], afr[i], bfr[j]);
        }
        __syncthreads();
    }
}

// ---------------------------------------------------------------------------
// Fused projection kernel: 5 jobs (Q, K, V->Vt, PK, PQ) in one 1-D grid.
// ---------------------------------------------------------------------------
struct ProjJobs {
    const bf16* A[5];
    const bf16* Bw[5];
    bf16*       C[5];
    const float* bias[5];
    int mode[5];
    int start[6];
};

__global__ void __launch_bounds__(256) gemm_proj(ProjJobs J)
{
    constexpr int ABYTES = 128 * 32 * 2, BBYTES = 128 * 32 * 2;
    __shared__ __align__(1024) char sm[2 * (ABYTES + BBYTES)];
    SmemPtrs sp { smem_u32(sm), smem_u32(sm) + 2 * ABYTES };

    int bx = blockIdx.x;
    int j = 0;
    while (bx >= J.start[j + 1]) j++;
    const int local = bx - J.start[j];
    const int bm = (local / 6) * 128, bn = (local % 6) * 128;

    const int tid = threadIdx.x, lane = tid & 31, wid = tid >> 5;
    const int wm = wid & 1, wn = wid >> 1;

    const bf16* Arow = J.A[j] + (long)bm * H;
    const bf16* Brow = J.Bw[j] + (long)bn * H;

    auto load_tiles = [&](int ch, int st) {
        const bf16* Ak = Arow + ch * 32;
        #pragma unroll
        for (int i = tid; i < 512; i += 256) {
            int r = i >> 2, c = i & 3;
            cpasync16(sp.uA + st * ABYTES + swz(r, c), Ak + (long)r * H + c * 8);
        }
        const bf16* Bk = Brow + ch * 32;
        #pragma unroll
        for (int i = tid; i < 512; i += 256) {
            int r = i >> 2, c = i & 3;
            cpasync16(sp.uB + st * BBYTES + swz(r, c), Bk + (long)r * H + c * 8);
        }
    };

    float acc[4][4][4] = {};
    gemm_core(H / 32, sp, tid, lane, wm, wn, acc, load_tiles);

    bf16* C = J.C[j];
    const float* bias = J.bias[j];
    const int mode = J.mode[j];

    #pragma unroll
    for (int i = 0; i < 4; i++)
        #pragma unroll
        for (int jj = 0; jj < 4; jj++)
            #pragma unroll
            for (int half = 0; half < 2; half++) {
                const int r = bm + wm * 64 + i * 16 + (lane >> 2) + half * 8;
                const int c = bn + wn * 32 + jj * 8 + (lane & 3) * 2;
                const float v0 = acc[i][jj][half * 2];
                const float v1 = acc[i][jj][half * 2 + 1];
                float b0 = bias ? bias[c] : 0.f, b1 = bias ? bias[c + 1] : 0.f;
                if (mode == 0) {
                    *(__nv_bfloat162*)(C + (long)r * H + c) =
                        __float22bfloat162_rn(make_float2(v0 + b0, v1 + b1));
                } else {
                    C[(long)c * S + r]       = __float2bfloat16(v0 + b0);
                    C[(long)(c + 1) * S + r] = __float2bfloat16(v1 + b1);
                }
            }
}

// ---------------------------------------------------------------------------
// Single-shot tables kernel (K=64 fits one smem load, no pipeline).
// ---------------------------------------------------------------------------
constexpr int TB_STRIDE = 272;

__global__ void __launch_bounds__(256) gemm_tables(
    const bf16* __restrict__ Qb, const bf16* __restrict__ Kb,
    const bf16* __restrict__ PK, const bf16* __restrict__ PQ,
    bf16* __restrict__ CK, bf16* __restrict__ CQ, int hbase)
{
    __shared__ __align__(1024) char sm[128 * TB_STRIDE];  // 34816 >= 32768
    const uint32_t uA = smem_u32(sm);
    const uint32_t uB = uA + 16384;

    const int z = blockIdx.z;
    const bool isCK = z < 6;
    const int h = hbase + (isCK ? z : z - 6);
    const bf16* A = (isCK ? Qb : Kb) + h * D;
    const bf16* B = (isCK ? PK : PQ) + h * D;
    bf16* C = (isCK ? CK : CQ) + (size_t)h * S * LPOS;

    const int tid = threadIdx.x, lane = tid & 31, wid = tid >> 5;
    const int wm = wid & 1, wn = wid >> 1;
    const int bm = blockIdx.y * 128, bn = blockIdx.x * 128;

    {
        const bf16* Ag = A + (long)bm * H;
        #pragma unroll
        for (int i = tid; i < 1024; i += 256) {
            int r = i >> 3, c = i & 7;
            cpasync16(uA + swz128(r, c), Ag + (long)r * H + c * 8);
        }
        const bf16* Bg = B + (long)bn * H;
        #pragma unroll
        for (int i = tid; i < 1024; i += 256) {
            int r = i >> 3, c = i & 7;
            cpasync16(uB + swz128(r, c), Bg + (long)r * H + c * 8);
        }
    }
    CP_COMMIT();
    CP_WAIT0();
    __syncthreads();

    float acc[4][4][4] = {};
    #pragma unroll
    for (int kk = 0; kk < 4; kk++) {
        uint32_t afr[4][4];
        #pragma unroll
        for (int i = 0; i < 4; i++) {
            int row = wm * 64 + i * 16 + (lane & 15);
            int c16 = kk * 2 + (lane >> 4);
            ldsm4(afr[i], uA + swz128(row, c16));
        }
        uint32_t bfr[4][2];
        #pragma unroll
        for (int p = 0; p < 2; p++) {
            uint32_t r4[4];
            int n   = wn * 32 + p * 16 + ((lane >> 4) << 3) + (lane & 7);
            int c16 = kk * 2 + ((lane >> 3) & 1);
            ldsm4(r4, uB + swz128(n, c16));
            bfr[2 * p][0] = r4[0]; bfr[2 * p][1] = r4[1];
            bfr[2 * p + 1][0] = r4[2]; bfr[2 * p + 1][1] = r4[3];
        }
        #pragma unroll
        for (int i = 0; i < 4; i++)
            #pragma unroll
            for (int j = 0; j < 4; j++)
                mma16816(acc[i][j], afr[i], bfr[j]);
    }
    __syncthreads();

    #pragma unroll
    for (int i = 0; i < 4; i++)
        #pragma unroll
        for (int jj = 0; jj < 4; jj++)
            #pragma unroll
            for (int half = 0; half < 2; half++) {
                const int rl = wm * 64 + i * 16 + (lane >> 2) + half * 8;
                const int cl = wn * 32 + jj * 8 + (lane & 3) * 2;
                *(uint32_t*)(sm + rl * TB_STRIDE + cl * 2) =
                    packbf2(acc[i][jj][half * 2], acc[i][jj][half * 2 + 1]);
            }
    __syncthreads();

    #pragma unroll
    for (int i = tid; i < 2048; i += 256) {
        int r = i >> 4, ch = i & 15;
        uint4 v = *(uint4*)(sm + r * TB_STRIDE + ch * 16);
        *(uint4*)(C + (long)(bm + r) * LPOS + bn + ch * 8) = v;
    }
}

// ---------------------------------------------------------------------------
// Output projection + bias + residual (fp32 out).
// ---------------------------------------------------------------------------
__global__ void __launch_bounds__(256) gemm_out(
    const bf16* __restrict__ A, const bf16* __restrict__ Bw,
    float* __restrict__ C, const float* __restrict__ bias,
    const float* __restrict__ res)
{
    constexpr int ABYTES = 128 * 32 * 2, BBYTES = 128 * 32 * 2;
    __shared__ __align__(1024) char sm[2 * (ABYTES + BBYTES)];
    SmemPtrs sp { smem_u32(sm), smem_u32(sm) + 2 * ABYTES };

    const int tid = threadIdx.x, lane = tid & 31, wid = tid >> 5;
    const int wm = wid & 1, wn = wid >> 1;
    const int bm = blockIdx.y * 128, bn = blockIdx.x * 128;

    const bf16* Arow = A + (long)bm * H;
    const bf16* Brow = Bw + (long)bn * H;

    auto load_tiles = [&](int ch, int st) {
        const bf16* Ak = Arow + ch * 32;
        #pragma unroll
        for (int i = tid; i < 512; i += 256) {
            int r = i >> 2, c = i & 3;
            cpasync16(sp.uA + st * ABYTES + swz(r, c), Ak + (long)r * H + c * 8);
        }
        const bf16* Bk = Brow + ch * 32;
        #pragma unroll
        for (int i = tid; i < 512; i += 256) {
            int r = i >> 2, c = i & 3;
            cpasync16(sp.uB + st * BBYTES + swz(r, c), Bk + (long)r * H + c * 8);
        }
    };

    float acc[4][4][4] = {};
    gemm_core(H / 32, sp, tid, lane, wm, wn, acc, load_tiles);

    #pragma unroll
    for (int i = 0; i < 4; i++)
        #pragma unroll
        for (int jj = 0; jj < 4; jj++)
            #pragma unroll
            for (int half = 0; half < 2; half++) {
                const int r = bm + wm * 64 + i * 16 + (lane >> 2) + half * 8;
                const int c = bn + wn * 32 + jj * 8 + (lane & 3) * 2;
                const float* rr = res + (long)r * H;
                *(float2*)(C + (long)r * H + c) =
                    make_float2(acc[i][jj][half * 2] + bias[c] + rr[c],
                                acc[i][jj][half * 2 + 1] + bias[c + 1] + rr[c + 1]);
            }
}

// ---------------------------------------------------------------------------
// Flash-fused attention: fast/saturated/general paths, mask bit-packed.
// ---------------------------------------------------------------------------
constexpr int CQ_W     = 144;
constexpr int CQ_ROWB  = CQ_W * 2;
constexpr int CQ_BYTES = 64 * CQ_ROWB;
constexpr int CK_W     = 80;
constexpr int CK_ROWB  = CK_W * 2;
constexpr int CK_BYTES = 128 * CK_ROWB;
constexpr int OFF_K    = 16384;
constexpr int OFF_V    = OFF_K + 16384;
constexpr int OFF_CQ   = OFF_V + 16384;
constexpr int OFF_CK   = OFF_CQ + CQ_BYTES;
constexpr int OFF_SAT  = OFF_CK + CK_BYTES;
constexpr int FL_SMEM  = OFF_SAT + 2048;      // 90112
constexpr int HTILES   = (S / 64) / ZSPL;     // 8

__global__ void __launch_bounds__(256, 2) flash_attn(
    const bf16* __restrict__ Q, const bf16* __restrict__ K,
    const bf16* __restrict__ Vt,
    const bf16* __restrict__ CKb, const bf16* __restrict__ CQb,
    const int* __restrict__ mask,
    float* __restrict__ Opart, float2* __restrict__ ML, int hbase)
{
    extern __shared__ __align__(1024) char dyn[];
    const uint32_t uQ  = smem_u32(dyn);
    const uint32_t uK  = uQ + OFF_K;
    const uint32_t uV  = uQ + OFF_V;
    const uint32_t uCQ = uQ + OFF_CQ;
    const uint32_t uCK = uQ + OFF_CK;

    const int tid = threadIdx.x, lane = tid & 31, wid = tid >> 5;
    const int h = hbase + blockIdx.y, bm = blockIdx.x * 128;
    const int z = blockIdx.z;
    const int ct0 = z * HTILES;
    const int bmc = bm + 512;

    auto lbc = [&](int c) { return min(max(bmc - c, 0), 888) & ~7; };
    auto tile_fast = [&](int dRC) { return (dRC >= -448) && (dRC <= 320); };
    auto tile_sat  = [&](int dRC) { return (dRC >= 576) || (dRC <= -640); };

    {
        const bf16* Qg = Q + (long)bm * H + h * D;
        #pragma unroll
        for (int i = tid; i < 1024; i += 256) {
            int r = i >> 3, c = i & 7;
            cpasync16(uQ + swz128(r, c), Qg + (long)r * H + c * 8);
        }
    }
    CP_COMMIT();

    auto load_kv = [&](int ct, int st) {
        const int c0 = ct * 64;
        const uint32_t uk = uK + st * 8192;
        const uint32_t uv = uV + st * 8192;
        const bf16* Kg = K + (long)c0 * H + h * D;
        #pragma unroll
        for (int i = tid; i < 512; i += 256) {
            int r = i >> 3, c = i & 7;
            cpasync16(uk + swz128(r, c), Kg + (long)r * H + c * 8);
        }
        const bf16* Vg = Vt + (long)(h * D) * S + c0;
        #pragma unroll
        for (int i = tid; i < 512; i += 256) {
            int d = i >> 3, c = i & 7;
            cpasync16(uv + swz128(d, c), Vg + (long)d * S + c * 8);
        }
    };

    auto load_band = [&](int ct) {
        const int c0 = ct * 64;
        const int dRC = bm - c0;
        if (tile_sat(dRC)) return;
        const bf16* CQg = CQb + ((size_t)h * S + c0) * LPOS;
        for (int i = tid; i < 64 * 18; i += 256) {
            int j = i / 18, ch = i % 18;
            int Lb = lbc(c0 + j);
            cpasync16(uCQ + j * CQ_ROWB + ch * 16,
                      CQg + (size_t)j * LPOS + Lb + ch * 8);
        }
        if (tile_fast(dRC)) {
            const bf16* CKg = CKb + ((size_t)h * S + bm) * LPOS;
            for (int i = tid; i < 128 * 9; i += 256) {
                int rb = i / 9, ch = i % 9;
                int Bal = (rb + dRC + 448) & ~7;
                cpasync16(uCK + rb * CK_ROWB + ch * 16,
                          CKg + (size_t)rb * LPOS + Bal + ch * 8);
            }
        }
    };

    load_kv(ct0, 0);
    CP_COMMIT();
    CP_WAIT1();
    __syncthreads();

    // one-time: saturated cq column values for this key slice
    {
        const bf16* CQg = CQb + ((size_t)h * S + ct0 * 64) * LPOS;
        bf16* slo = (bf16*)(dyn + OFF_SAT);
        bf16* shi = slo + 512;
        for (int j = tid; j < 512; j += 256) {
            slo[j] = CQg[(size_t)j * LPOS];
            shi[j] = CQg[(size_t)j * LPOS + 1023];
        }
    }

    uint32_t qf[4][4];
    #pragma unroll
    for (int kk = 0; kk < 4; kk++) {
        int row = wid * 16 + (lane & 15);
        int c16 = kk * 2 + (lane >> 4);
        ldsm4(qf[kk], uQ + swz128(row, c16));
    }

    const int rb0 = wid * 16 + (lane >> 2);
    const int rb1 = rb0 + 8;
    const int r0 = bm + rb0;
    const int r1 = bm + rb1;
    const int m0v = mask[r0], m1v = mask[r1];
    const bf16* ck0 = CKb + ((size_t)h * S + r0) * LPOS;
    const bf16* ck1 = CKb + ((size_t)h * S + r1) * LPOS;
    const float cklo0 = __bfloat162float(ck0[0]);
    const float ckhi0 = __bfloat162float(ck0[1023]);
    const float cklo1 = __bfloat162float(ck1[0]);
    const float ckhi1 = __bfloat162float(ck1[1023]);

    // pack this thread's 128 mask bits for the whole slice
    uint32_t mbits[4] = {0, 0, 0, 0};
    {
        const int cb = (lane & 3) * 2;
        #pragma unroll
        for (int it = 0; it < 8; it++)
            #pragma unroll
            for (int nb = 0; nb < 8; nb++) {
                int c = (ct0 + it) * 64 + nb * 8 + cb;
                int k = it * 16 + nb * 2;
                uint32_t b = (mask[c] ? 1u : 0u) | ((mask[c + 1] ? 2u : 0u));
                mbits[k >> 5] |= b << (k & 31);
            }
    }

    float m0 = NEGMAX, m1 = NEGMAX, l0 = 0.f, l1 = 0.f;
    float O[8][4] = {};

    for (int it = 0; it < HTILES; it++) {
        const int ct = ct0 + it;
        const int st = it & 1;

        load_band(ct);
        CP_COMMIT();
        if (it + 1 < HTILES) { load_kv(ct + 1, st ^ 1); CP_COMMIT(); CP_WAIT1(); }
        else                 { CP_WAIT0(); }
        __syncthreads();

        const uint32_t uk = uK + st * 8192;
        const uint32_t uv = uV + st * 8192;
        const bf16* sCQ = (const bf16*)(dyn + OFF_CQ);
        const bf16* sCK = (const bf16*)(dyn + OFF_CK);

        float sfr[8][4] = {};
        #pragma unroll
        for (int g = 0; g < 4; g++) {
            #pragma unroll
            for (int kk = 0; kk < 4; kk++) {
                uint32_t r4[4];
                int n   = g * 16 + ((lane >> 4) << 3) + (lane & 7);
                int c16 = kk * 2 + ((lane >> 3) & 1);
                ldsm4(r4, uk + swz128(n, c16));
                mma16816(sfr[2 * g],     qf[kk], r4);
                mma16816(sfr[2 * g + 1], qf[kk], r4 + 2);
            }
        }

        const int c0 = ct * 64;
        const int dRC = bm - c0;
        const uint32_t mw = mbits[it >> 1] >> ((it & 1) * 16);
        float tmx0 = NEGMAX, tmx1 = NEGMAX;

        if (tile_fast(dRC)) {
            const int ph = (rb0 + dRC + 448) & 7;
            const bf16* sk0 = sCK + rb0 * CK_W;
            const bf16* sk1 = sCK + rb1 * CK_W;
            #pragma unroll
            for (int nb = 0; nb < 8; nb++) {
                const int cl  = nb * 8 + (lane & 3) * 2;
                const int off = 64 - cl + ph;
                const int mc0 = (mw >> (nb * 2)) & 1;
                const int mc1 = (mw >> (nb * 2 + 1)) & 1;
                const bf16* sq0 = sCQ + cl * CQ_W;
                const bf16* sq1 = sCQ + (cl + 1) * CQ_W;
                const int q0 = dRC + 512 - cl;
                const int t0 = q0 & 7, t1 = (q0 - 1) & 7;
                {
                    float v0 = (sfr[nb][0] + __bfloat162float(sk0[off])
                                + __bfloat162float(sq0[rb0 + t0])) * SCALE2;
                    float v1 = (sfr[nb][1] + __bfloat162float(sk0[off - 1])
                                + __bfloat162float(sq1[rb0 + t1])) * SCALE2;
                    if (!(m0v && mc0)) v0 = NEGMAX;
                    if (!(m0v && mc1)) v1 = NEGMAX;
                    sfr[nb][0] = v0; sfr[nb][1] = v1;
                    tmx0 = fmaxf(tmx0, fmaxf(v0, v1));
                }
                {
                    float v2 = (sfr[nb][2] + __bfloat162float(sk1[off])
                                + __bfloat162float(sq0[rb1 + t0])) * SCALE2;
                    float v3 = (sfr[nb][3] + __bfloat162float(sk1[off - 1])
                                + __bfloat162float(sq1[rb1 + t1])) * SCALE2;
                    if (!(m1v && mc0)) v2 = NEGMAX;
                    if (!(m1v && mc1)) v3 = NEGMAX;
                    sfr[nb][2] = v2; sfr[nb][3] = v3;
                    tmx1 = fmaxf(tmx1, fmaxf(v2, v3));
                }
            }
        } else if (tile_sat(dRC)) {
            const bool hiSat = dRC > 0;
            const float f0 = hiSat ? ckhi0 : cklo0;
            const float f1 = hiSat ? ckhi1 : cklo1;
            const bf16* scq = (const bf16*)(dyn + OFF_SAT) + (hiSat ? 512 : 0);
            const int jb = it * 64;
            #pragma unroll
            for (int nb = 0; nb < 8; nb++) {
                const int cl  = nb * 8 + (lane & 3) * 2;
                const int mc0 = (mw >> (nb * 2)) & 1;
                const int mc1 = (mw >> (nb * 2 + 1)) & 1;
                const float cq0 = __bfloat162float(scq[jb + cl]);
                const float cq1 = __bfloat162float(scq[jb + cl + 1]);
                {
                    float v0 = (sfr[nb][0] + f0 + cq0) * SCALE2;
                    float v1 = (sfr[nb][1] + f0 + cq1) * SCALE2;
                    if (!(m0v && mc0)) v0 = NEGMAX;
                    if (!(m0v && mc1)) v1 = NEGMAX;
                    sfr[nb][0] = v0; sfr[nb][1] = v1;
                    tmx0 = fmaxf(tmx0, fmaxf(v0, v1));
                }
                {
                    float v2 = (sfr[nb][2] + f1 + cq0) * SCALE2;
                    float v3 = (sfr[nb][3] + f1 + cq1) * SCALE2;
                    if (!(m1v && mc0)) v2 = NEGMAX;
                    if (!(m1v && mc1)) v3 = NEGMAX;
                    sfr[nb][2] = v2; sfr[nb][3] = v3;
                    tmx1 = fmaxf(tmx1, fmaxf(v2, v3));
                }
            }
        } else {
            #pragma unroll
            for (int nb = 0; nb < 8; nb++) {
                const int cl = nb * 8 + (lane & 3) * 2;
                const int c  = c0 + cl;
                const int Lb0 = lbc(c);
                const int Lb1 = lbc(c + 1);
                const int mc0 = (mw >> (nb * 2)) & 1;
                const int mc1 = (mw >> (nb * 2 + 1)) & 1;
                {
                    int la = min(max(r0 - c + 512, 0), LPOS - 1);
                    int lb = min(max(r0 - c + 511, 0), LPOS - 1);
                    float v0 = (sfr[nb][0] + __bfloat162float(ck0[la])
                                + __bfloat162float(sCQ[cl * CQ_W + (la - Lb0)])) * SCALE2;
                    float v1 = (sfr[nb][1] + __bfloat162float(ck0[lb])
                                + __bfloat162float(sCQ[(cl + 1) * CQ_W + (lb - Lb1)])) * SCALE2;
                    if (!(m0v && mc0)) v0 = NEGMAX;
                    if (!(m0v && mc1)) v1 = NEGMAX;
                    sfr[nb][0] = v0; sfr[nb][1] = v1;
                    tmx0 = fmaxf(tmx0, fmaxf(v0, v1));
                }
                {
                    int la = min(max(r1 - c + 512, 0), LPOS - 1);
                    int lb = min(max(r1 - c + 511, 0), LPOS - 1);
                    float v2 = (sfr[nb][2] + __bfloat162float(ck1[la])
                                + __bfloat162float(sCQ[cl * CQ_W + (la - Lb0)])) * SCALE2;
                    float v3 = (sfr[nb][3] + __bfloat162float(ck1[lb])
                                + __bfloat162float(sCQ[(cl + 1) * CQ_W + (lb - Lb1)])) * SCALE2;
                    if (!(m1v && mc0)) v2 = NEGMAX;
                    if (!(m1v && mc1)) v3 = NEGMAX;
                    sfr[nb][2] = v2; sfr[nb][3] = v3;
                    tmx1 = fmaxf(tmx1, fmaxf(v2, v3));
                }
            }
        }
        tmx0 = fmaxf(tmx0, __shfl_xor_sync(0xffffffffu, tmx0, 1));
        tmx0 = fmaxf(tmx0, __shfl_xor_sync(0xffffffffu, tmx0, 2));
        tmx1 = fmaxf(tmx1, __shfl_xor_sync(0xffffffffu, tmx1, 1));
        tmx1 = fmaxf(tmx1, __shfl_xor_sync(0xffffffffu, tmx1, 2));

        const float mn0 = fmaxf(m0, tmx0), mn1 = fmaxf(m1, tmx1);
        const float sc0 = exp2f(m0 - mn0), sc1 = exp2f(m1 - mn1);
        m0 = mn0; m1 = mn1;
        float rs0 = 0.f, rs1 = 0.f;
        #pragma unroll
        for (int nb = 0; nb < 8; nb++) {
            sfr[nb][0] = exp2f(sfr[nb][0] - mn0);
            sfr[nb][1] = exp2f(sfr[nb][1] - mn0);
            sfr[nb][2] = exp2f(sfr[nb][2] - mn1);
            sfr[nb][3] = exp2f(sfr[nb][3] - mn1);
            rs0 += sfr[nb][0] + sfr[nb][1];
            rs1 += sfr[nb][2] + sfr[nb][3];
        }
        rs0 += __shfl_xor_sync(0xffffffffu, rs0, 1);
        rs0 += __shfl_xor_sync(0xffffffffu, rs0, 2);
        rs1 += __shfl_xor_sync(0xffffffffu, rs1, 1);
        rs1 += __shfl_xor_sync(0xffffffffu, rs1, 2);
        l0 = l0 * sc0 + rs0;
        l1 = l1 * sc1 + rs1;
        #pragma unroll
        for (int df = 0; df < 8; df++) {
            O[df][0] *= sc0; O[df][1] *= sc0;
            O[df][2] *= sc1; O[df][3] *= sc1;
        }

        #pragma unroll
        for (int kk2 = 0; kk2 < 4; kk2++) {
            uint32_t pf[4];
            pf[0] = packbf2(sfr[2 * kk2][0],     sfr[2 * kk2][1]);
            pf[1] = packbf2(sfr[2 * kk2][2],     sfr[2 * kk2][3]);
            pf[2] = packbf2(sfr[2 * kk2 + 1][0], sfr[2 * kk2 + 1][1]);
            pf[3] = packbf2(sfr[2 * kk2 + 1][2], sfr[2 * kk2 + 1][3]);
            #pragma unroll
            for (int dg = 0; dg < 4; dg++) {
                uint32_t r4[4];
                int n   = dg * 16 + ((lane >> 4) << 3) + (lane & 7);
                int c16 = kk2 * 2 + ((lane >> 3) & 1);
                ldsm4(r4, uv + swz128(n, c16));
                mma16816(O[2 * dg],     pf, r4);
                mma16816(O[2 * dg + 1], pf, r4 + 2);
            }
        }
        __syncthreads();
    }

    const size_t base = ((size_t)z * NH + h) * S;
    if ((lane & 3) == 0) {
        ML[base + r0] = make_float2(m0, l0);
        ML[base + r1] = make_float2(m1, l1);
    }
    float* o0 = Opart + (base + r0) * D + (lane & 3) * 2;
    float* o1 = Opart + (base + r1) * D + (lane & 3) * 2;
    #pragma unroll
    for (int df = 0; df < 8; df++) {
        *(float2*)(o0 + df * 8) = make_float2(O[df][0], O[df][1]);
        *(float2*)(o1 + df * 8) = make_float2(O[df][2], O[df][3]);
    }
}

// ---------------------------------------------------------------------------
// Merge the ZSPL split-K slices (exp2 domain) -> normalized bf16 context.
// ---------------------------------------------------------------------------
__global__ void __launch_bounds__(256) merge_attn(
    const float* __restrict__ Opart, const float2* __restrict__ ML,
    bf16* __restrict__ CTX)
{
    const int p = blockIdx.x * 8 + (threadIdx.x >> 5);
    const int lane = threadIdx.x & 31;
    const int h = p / S, row = p % S;

    float2 ml[ZSPL];
    float M = NEGMAX;
    #pragma unroll
    for (int zz = 0; zz < ZSPL; zz++) {
        ml[zz] = ML[zz * NH * S + p];
        M = fmaxf(M, ml[zz].x);
    }
    float w[ZSPL], denom = 0.f;
    #pragma unroll
    for (int zz = 0; zz < ZSPL; zz++) {
        w[zz] = exp2f(ml[zz].x - M);
        denom += w[zz] * ml[zz].y;
    }
    const float inv = 1.0f / denom;

    const int d = lane * 2;
    float ax = 0.f, ay = 0.f;
    #pragma unroll
    for (int zz = 0; zz < ZSPL; zz++) {
        const float2 v = *(const float2*)(Opart + ((size_t)zz * NH * S + p) * D + d);
        ax += w[zz] * v.x;
        ay += w[zz] * v.y;
    }
    *(__nv_bfloat162*)(CTX + (long)row * H + h * D + d) =
        __float22bfloat162_rn(make_float2(ax * inv, ay * inv));
}

// ---------------------------------------------------------------------------
__global__ void cvt_bf16_2(const float* __restrict__ x0, bf16* __restrict__ y0, int n0,
                           const float* __restrict__ x1, bf16* __restrict__ y1, int n1)
{
    int i = blockIdx.x * 256 + threadIdx.x;
    if (i < n0) y0[i] = __float2bfloat16(x0[i]);
    else if (i < n0 + n1) y1[i - n0] = __float2bfloat16(x1[i - n0]);
}

struct P6 { const float* p[6]; };
__global__ void wtrans6(P6 srcs, bf16* __restrict__ Wt)
{
    __shared__ float t[32][33];
    const float* W = srcs.p[blockIdx.z];
    bf16* dst = Wt + (size_t)blockIdx.z * H * H;
    const int bx = blockIdx.x * 32, by = blockIdx.y * 32;
    #pragma unroll
    for (int i = threadIdx.y; i < 32; i += 8)
        t[i][threadIdx.x] = W[(long)(by + i) * H + bx + threadIdx.x];
    __syncthreads();
    #pragma unroll
    for (int i = threadIdx.y; i < 32; i += 8)
        dst[(long)(bx + i) * H + by + threadIdx.x] = __float2bfloat16(t[threadIdx.x][i]);
}

__global__ void ln_kernel(const float* __restrict__ x,
                          const float* __restrict__ gamma,
                          const float* __restrict__ beta,
                          float* __restrict__ out)
{
    __shared__ float rs[8], rq[8];
    const int s = blockIdx.x, tid = threadIdx.x;
    const float* row = x + (long)s * H;
    float a0 = row[tid], a1 = row[tid + 256], a2 = row[tid + 512];
    float sum = a0 + a1 + a2;
    float sq  = a0 * a0 + a1 * a1 + a2 * a2;
    #pragma unroll
    for (int o = 16; o > 0; o >>= 1) {
        sum += __shfl_xor_sync(0xffffffffu, sum, o);
        sq  += __shfl_xor_sync(0xffffffffu, sq,  o);
    }
    if ((tid & 31) == 0) { rs[tid >> 5] = sum; rq[tid >> 5] = sq; }
    __syncthreads();
    float ts = 0.f, tq = 0.f;
    #pragma unroll
    for (int w = 0; w < 8; w++) { ts += rs[w]; tq += rq[w]; }
    float mean = ts * (1.0f / H);
    float var  = tq * (1.0f / H) - mean * mean;
    float inv  = rsqrtf(var + 1e-7f);
    float* o = out + (long)s * H;
    o[tid]       = (a0 - mean) * inv * gamma[tid]       + beta[tid];
    o[tid + 256] = (a1 - mean) * inv * gamma[tid + 256] + beta[tid + 256];
    o[tid + 512] = (a2 - mean) * inv * gamma[tid + 512] + beta[tid + 512];
}

// ---------------------------------------------------------------------------
extern "C" void kernel_launch(void* const* d_in, const int* in_sizes, int n_in,
                              void* d_out, int out_size)
{
    const float* hidden = (const float*)d_in[0];
    const int*   mask   = (const int*)  d_in[1];
    const float* Wq     = (const float*)d_in[2];
    const float* bq     = (const float*)d_in[3];
    const float* Wk     = (const float*)d_in[4];
    const float* bk     = (const float*)d_in[5];
    const float* Wv     = (const float*)d_in[6];
    const float* bv     = (const float*)d_in[7];
    const float* rel    = (const float*)d_in[8];
    const float* Wpk    = (const float*)d_in[9];
    const float* Wpq    = (const float*)d_in[10];
    const float* bpq    = (const float*)d_in[11];
    const float* Wo     = (const float*)d_in[12];
    const float* bo     = (const float*)d_in[13];
    const float* gamma  = (const float*)d_in[14];
    const float* beta   = (const float*)d_in[15];
    float* out = (float*)d_out;

    bf16 *hbf, *relbf, *Wt, *Qbf, *Kbf, *Vt, *PKbf, *PQbf, *CKb, *CQb, *CTXbf;
    float *TMP, *Opart;
    float2* ML;
    cudaGetSymbolAddress((void**)&hbf,   g_hbf);
    cudaGetSymbolAddress((void**)&relbf, g_relbf);
    cudaGetSymbolAddress((void**)&Wt,    g_Wt);
    cudaGetSymbolAddress((void**)&Qbf,   g_Qbf);
    cudaGetSymbolAddress((void**)&Kbf,   g_Kbf);
    cudaGetSymbolAddress((void**)&Vt,    g_Vt);
    cudaGetSymbolAddress((void**)&PKbf,  g_PKbf);
    cudaGetSymbolAddress((void**)&PQbf,  g_PQbf);
    cudaGetSymbolAddress((void**)&CKb,   g_CKb);
    cudaGetSymbolAddress((void**)&CQb,   g_CQb);
    cudaGetSymbolAddress((void**)&Opart, g_Opart);
    cudaGetSymbolAddress((void**)&ML,    g_ML);
    cudaGetSymbolAddress((void**)&CTXbf, g_CTXbf);
    cudaGetSymbolAddress((void**)&TMP,   g_TMP);

    static cudaStream_t s1 = nullptr, s2 = nullptr;
    static cudaEvent_t evR = nullptr, evP = nullptr, evF1 = nullptr,
                       evF2 = nullptr, evW = nullptr;
    static bool init_done = false;
    if (!init_done) {
        cudaFuncSetAttribute(flash_attn,
                             cudaFuncAttributeMaxDynamicSharedMemorySize, FL_SMEM);
        cudaStreamCreateWithFlags(&s1, cudaStreamNonBlocking);
        cudaStreamCreateWithFlags(&s2, cudaStreamNonBlocking);
        cudaEventCreateWithFlags(&evR,  cudaEventDisableTiming);
        cudaEventCreateWithFlags(&evP,  cudaEventDisableTiming);
        cudaEventCreateWithFlags(&evF1, cudaEventDisableTiming);
        cudaEventCreateWithFlags(&evF2, cudaEventDisableTiming);
        cudaEventCreateWithFlags(&evW,  cudaEventDisableTiming);
        init_done = true;
    }

    // --- legal fork: root event on capture-origin stream BEFORE side work ---
    cudaEventRecord(evR, 0);
    cudaStreamWaitEvent(s1, evR, 0);

    // front: cvt (default) || wtrans (s1)
    cvt_bf16_2<<<(S * H + LPOS * H + 255) / 256, 256>>>(
        hidden, hbf, S * H, rel, relbf, LPOS * H);
    P6 w6; w6.p[0] = Wq; w6.p[1] = Wk; w6.p[2] = Wv;
    w6.p[3] = Wpk; w6.p[4] = Wpq; w6.p[5] = Wo;
    wtrans6<<<dim3(H/32, H/32, 6), dim3(32, 8), 0, s1>>>(w6, Wt);
    cudaEventRecord(evW, s1);
    cudaStreamWaitEvent(0, evW, 0);

    // --- all five projections in one launch (default stream) ---
    ProjJobs J;
    J.A[0] = hbf;   J.Bw[0] = Wt + 0 * H * H; J.C[0] = Qbf;  J.bias[0] = bq;      J.mode[0] = 0;
    J.A[1] = hbf;   J.Bw[1] = Wt + 1 * H * H; J.C[1] = Kbf;  J.bias[1] = bk;      J.mode[1] = 0;
    J.A[2] = hbf;   J.Bw[2] = Wt + 2 * H * H; J.C[2] = Vt;   J.bias[2] = bv;      J.mode[2] = 1;
    J.A[3] = relbf; J.Bw[3] = Wt + 3 * H * H; J.C[3] = PKbf; J.bias[3] = nullptr; J.mode[3] = 0;
    J.A[4] = relbf; J.Bw[4] = Wt + 4 * H * H; J.C[4] = PQbf; J.bias[4] = bpq;     J.mode[4] = 0;
    J.start[0] = 0;   J.start[1] = 96;  J.start[2] = 192;
    J.start[3] = 288; J.start[4] = 336; J.start[5] = 384;
    gemm_proj<<<384, 256>>>(J);
    cudaEventRecord(evP, 0);

    // --- fork: tables then flash on two streams ---
    cudaStreamWaitEvent(s1, evP, 0);
    gemm_tables<<<dim3(LPOS/128, S/128, 12), 256, 0, s1>>>(
        Qbf, Kbf, PKbf, PQbf, CKb, CQb, 0);
    cudaStreamWaitEvent(s2, evP, 0);
    gemm_tables<<<dim3(LPOS/128, S/128, 12), 256, 0, s2>>>(
        Qbf, Kbf, PKbf, PQbf, CKb, CQb, 6);

    flash_attn<<<dim3(S/128, NH/2, ZSPL), 256, FL_SMEM, s1>>>(
        Qbf, Kbf, Vt, CKb, CQb, mask, Opart, ML, 0);
    cudaEventRecord(evF1, s1);
    flash_attn<<<dim3(S/128, NH/2, ZSPL), 256, FL_SMEM, s2>>>(
        Qbf, Kbf, Vt, CKb, CQb, mask, Opart, ML, 6);
    cudaEventRecord(evF2, s2);

    // --- join back to default stream ---
    cudaStreamWaitEvent(0, evF1, 0);
    cudaStreamWaitEvent(0, evF2, 0);

    merge_attn<<<NH * S / 8, 256>>>(Opart, ML, CTXbf);

    // --- output projection + bias + residual ---
    gemm_out<<<dim3(6, 16), 256>>>(CTXbf, Wt + 5 * H * H, TMP, bo, hidden);

    // --- layernorm ---
    ln_kernel<<<S, 256>>>(TMP, gamma, beta, out);
}

// round 16
// speedup vs baseline: 13.0364x; 1.0182x over previous
#include <cuda_runtime.h>
#include <cuda_bf16.h>
#include <cstdint>

// ---------------------------------------------------------------------------
// BertAttention (DeBERTa) — round 16: per-half merge overlapped with the
// opposite flash stream. B=1, S=2048, H=768, NH=12, D=64, SPAN=512
// ---------------------------------------------------------------------------

constexpr int S    = 2048;
constexpr int H    = 768;
constexpr int NH   = 12;
constexpr int D    = 64;
constexpr int LPOS = 1024;  // 2*SPAN
constexpr int ZSPL = 4;     // split-K factor over key sequence
constexpr float SCALE2 = 0.07216878364870322f * 1.4426950408889634f;
constexpr float NEGMAX = -3.402823466e38f;

using bf16 = __nv_bfloat16;

// ---------------------------- scratch (device globals) ---------------------
__device__ bf16   g_hbf  [S * H];
__device__ bf16   g_relbf[LPOS * H];
__device__ bf16   g_Wt   [6 * H * H];
__device__ bf16   g_Qbf  [S * H];
__device__ bf16   g_Kbf  [S * H];
__device__ bf16   g_Vt   [H * S];
__device__ bf16   g_PKbf [LPOS * H];
__device__ bf16   g_PQbf [LPOS * H];
__device__ bf16   g_CKb  [(size_t)NH * S * LPOS];
__device__ bf16   g_CQb  [(size_t)NH * S * LPOS + 256];
__device__ float  g_Opart[(size_t)ZSPL * NH * S * D];
__device__ float2 g_ML   [ZSPL * NH * S];
__device__ bf16   g_CTXbf[S * H];
__device__ float  g_TMP  [S * H];

// ---------------------------- PTX helpers ----------------------------------
__device__ __forceinline__ uint32_t smem_u32(const void* p) {
    uint32_t a;
    asm("{ .reg .u64 t; cvta.to.shared.u64 t, %1; cvt.u32.u64 %0, t; }"
        : "=r"(a) : "l"(p));
    return a;
}
__device__ __forceinline__ void cpasync16(uint32_t dst, const void* src) {
    asm volatile("cp.async.cg.shared.global [%0], [%1], 16;" :: "r"(dst), "l"(src));
}
#define CP_COMMIT() asm volatile("cp.async.commit_group;" ::: "memory")
#define CP_WAIT1()  asm volatile("cp.async.wait_group 1;" ::: "memory")
#define CP_WAIT0()  asm volatile("cp.async.wait_group 0;" ::: "memory")

__device__ __forceinline__ void ldsm4(uint32_t* r, uint32_t addr) {
    asm volatile("ldmatrix.sync.aligned.m8n8.x4.shared.b16 {%0,%1,%2,%3}, [%4];"
                 : "=r"(r[0]), "=r"(r[1]), "=r"(r[2]), "=r"(r[3]) : "r"(addr));
}
__device__ __forceinline__ void mma16816(float* c, const uint32_t* a, const uint32_t* b) {
    asm volatile(
        "mma.sync.aligned.m16n8k16.row.col.f32.bf16.bf16.f32 "
        "{%0,%1,%2,%3}, {%4,%5,%6,%7}, {%8,%9}, {%0,%1,%2,%3};"
        : "+f"(c[0]), "+f"(c[1]), "+f"(c[2]), "+f"(c[3])
        : "r"(a[0]), "r"(a[1]), "r"(a[2]), "r"(a[3]), "r"(b[0]), "r"(b[1]));
}
__device__ __forceinline__ uint32_t packbf2(float a, float b) {
    __nv_bfloat162 t = __float22bfloat162_rn(make_float2(a, b));
    return *(uint32_t*)&t;
}

__device__ __forceinline__ uint32_t swz(int row, int chunk) {
    return (uint32_t)(row * 64 + ((chunk ^ ((row >> 1) & 3)) << 4));
}
__device__ __forceinline__ uint32_t swz128(int row, int c16) {
    return (uint32_t)(row * 128 + ((c16 ^ (row & 7)) << 4));
}

// ---------------------------------------------------------------------------
// Shared GEMM mainloop (128x128 tile, K-major bf16, NT).
// ---------------------------------------------------------------------------
struct SmemPtrs { uint32_t uA, uB; };

template<typename LoadFn>
__device__ __forceinline__ void gemm_core(
    int nch, SmemPtrs sp, int tid, int lane, int wm, int wn,
    float (&acc)[4][4][4], LoadFn load_tiles)
{
    constexpr int ABYTES = 128 * 32 * 2;
    constexpr int BBYTES = 128 * 32 * 2;
    load_tiles(0, 0);
    CP_COMMIT();
    for (int ch = 0; ch < nch; ch++) {
        const int st = ch & 1;
        if (ch + 1 < nch) { load_tiles(ch + 1, st ^ 1); CP_COMMIT(); CP_WAIT1(); }
        else              { CP_WAIT0(); }
        __syncthreads();
        const uint32_t bA = sp.uA + st * ABYTES;
        const uint32_t bB = sp.uB + st * BBYTES;
        #pragma unroll
        for (int kk = 0; kk < 2; kk++) {
            uint32_t afr[4][4];
            #pragma unroll
            for (int i = 0; i < 4; i++) {
                int row = wm * 64 + i * 16 + (lane & 15);
                int chk = kk * 2 + (lane >> 4);
                ldsm4(afr[i], bA + swz(row, chk));
            }
            uint32_t bfr[4][2];
            #pragma unroll
            for (int p = 0; p < 2; p++) {
                uint32_t r4[4];
                int n   = wn * 32 + p * 16 + ((lane >> 4) << 3) + (lane & 7);
                int chk = kk * 2 + ((lane >> 3) & 1);
                ldsm4(r4, bB + swz(n, chk));
                bfr[2 * p][0] = r4[0]; bfr[2 * p][1] = r4[1];
                bfr[2 * p + 1][0] = r4[2]; bfr[2 * p + 1][1] = r4[3];
            }
            #pragma unroll
            for (int i = 0; i < 4; i++)
                #pragma unroll
                for (int j = 0; j < 4; j++)
                    mma16816(acc[i][j], afr[i], bfr[j]);
        }
        __syncthreads();
    }
}

// ---------------------------------------------------------------------------
// Fused projection kernel: 5 jobs (Q, K, V->Vt, PK, PQ) in one 1-D grid.
// ---------------------------------------------------------------------------
struct ProjJobs {
    const bf16* A[5];
    const bf16* Bw[5];
    bf16*       C[5];
    const float* bias[5];
    int mode[5];
    int start[6];
};

__global__ void __launch_bounds__(256) gemm_proj(ProjJobs J)
{
    constexpr int ABYTES = 128 * 32 * 2, BBYTES = 128 * 32 * 2;
    __shared__ __align__(1024) char sm[2 * (ABYTES + BBYTES)];
    SmemPtrs sp { smem_u32(sm), smem_u32(sm) + 2 * ABYTES };

    int bx = blockIdx.x;
    int j = 0;
    while (bx >= J.start[j + 1]) j++;
    const int local = bx - J.start[j];
    const int bm = (local / 6) * 128, bn = (local % 6) * 128;

    const int tid = threadIdx.x, lane = tid & 31, wid = tid >> 5;
    const int wm = wid & 1, wn = wid >> 1;

    const bf16* Arow = J.A[j] + (long)bm * H;
    const bf16* Brow = J.Bw[j] + (long)bn * H;

    auto load_tiles = [&](int ch, int st) {
        const bf16* Ak = Arow + ch * 32;
        #pragma unroll
        for (int i = tid; i < 512; i += 256) {
            int r = i >> 2, c = i & 3;
            cpasync16(sp.uA + st * ABYTES + swz(r, c), Ak + (long)r * H + c * 8);
        }
        const bf16* Bk = Brow + ch * 32;
        #pragma unroll
        for (int i = tid; i < 512; i += 256) {
            int r = i >> 2, c = i & 3;
            cpasync16(sp.uB + st * BBYTES + swz(r, c), Bk + (long)r * H + c * 8);
        }
    };

    float acc[4][4][4] = {};
    gemm_core(H / 32, sp, tid, lane, wm, wn, acc, load_tiles);

    bf16* C = J.C[j];
    const float* bias = J.bias[j];
    const int mode = J.mode[j];

    #pragma unroll
    for (int i = 0; i < 4; i++)
        #pragma unroll
        for (int jj = 0; jj < 4; jj++)
            #pragma unroll
            for (int half = 0; half < 2; half++) {
                const int r = bm + wm * 64 + i * 16 + (lane >> 2) + half * 8;
                const int c = bn + wn * 32 + jj * 8 + (lane & 3) * 2;
                const float v0 = acc[i][jj][half * 2];
                const float v1 = acc[i][jj][half * 2 + 1];
                float b0 = bias ? bias[c] : 0.f, b1 = bias ? bias[c + 1] : 0.f;
                if (mode == 0) {
                    *(__nv_bfloat162*)(C + (long)r * H + c) =
                        __float22bfloat162_rn(make_float2(v0 + b0, v1 + b1));
                } else {
                    C[(long)c * S + r]       = __float2bfloat16(v0 + b0);
                    C[(long)(c + 1) * S + r] = __float2bfloat16(v1 + b1);
                }
            }
}

// ---------------------------------------------------------------------------
// Single-shot tables kernel (K=64 fits one smem load, no pipeline).
// ---------------------------------------------------------------------------
constexpr int TB_STRIDE = 272;

__global__ void __launch_bounds__(256) gemm_tables(
    const bf16* __restrict__ Qb, const bf16* __restrict__ Kb,
    const bf16* __restrict__ PK, const bf16* __restrict__ PQ,
    bf16* __restrict__ CK, bf16* __restrict__ CQ, int hbase)
{
    __shared__ __align__(1024) char sm[128 * TB_STRIDE];
    const uint32_t uA = smem_u32(sm);
    const uint32_t uB = uA + 16384;

    const int z = blockIdx.z;
    const bool isCK = z < 6;
    const int h = hbase + (isCK ? z : z - 6);
    const bf16* A = (isCK ? Qb : Kb) + h * D;
    const bf16* B = (isCK ? PK : PQ) + h * D;
    bf16* C = (isCK ? CK : CQ) + (size_t)h * S * LPOS;

    const int tid = threadIdx.x, lane = tid & 31, wid = tid >> 5;
    const int wm = wid & 1, wn = wid >> 1;
    const int bm = blockIdx.y * 128, bn = blockIdx.x * 128;

    {
        const bf16* Ag = A + (long)bm * H;
        #pragma unroll
        for (int i = tid; i < 1024; i += 256) {
            int r = i >> 3, c = i & 7;
            cpasync16(uA + swz128(r, c), Ag + (long)r * H + c * 8);
        }
        const bf16* Bg = B + (long)bn * H;
        #pragma unroll
        for (int i = tid; i < 1024; i += 256) {
            int r = i >> 3, c = i & 7;
            cpasync16(uB + swz128(r, c), Bg + (long)r * H + c * 8);
        }
    }
    CP_COMMIT();
    CP_WAIT0();
    __syncthreads();

    float acc[4][4][4] = {};
    #pragma unroll
    for (int kk = 0; kk < 4; kk++) {
        uint32_t afr[4][4];
        #pragma unroll
        for (int i = 0; i < 4; i++) {
            int row = wm * 64 + i * 16 + (lane & 15);
            int c16 = kk * 2 + (lane >> 4);
            ldsm4(afr[i], uA + swz128(row, c16));
        }
        uint32_t bfr[4][2];
        #pragma unroll
        for (int p = 0; p < 2; p++) {
            uint32_t r4[4];
            int n   = wn * 32 + p * 16 + ((lane >> 4) << 3) + (lane & 7);
            int c16 = kk * 2 + ((lane >> 3) & 1);
            ldsm4(r4, uB + swz128(n, c16));
            bfr[2 * p][0] = r4[0]; bfr[2 * p][1] = r4[1];
            bfr[2 * p + 1][0] = r4[2]; bfr[2 * p + 1][1] = r4[3];
        }
        #pragma unroll
        for (int i = 0; i < 4; i++)
            #pragma unroll
            for (int j = 0; j < 4; j++)
                mma16816(acc[i][j], afr[i], bfr[j]);
    }
    __syncthreads();

    #pragma unroll
    for (int i = 0; i < 4; i++)
        #pragma unroll
        for (int jj = 0; jj < 4; jj++)
            #pragma unroll
            for (int half = 0; half < 2; half++) {
                const int rl = wm * 64 + i * 16 + (lane >> 2) + half * 8;
                const int cl = wn * 32 + jj * 8 + (lane & 3) * 2;
                *(uint32_t*)(sm + rl * TB_STRIDE + cl * 2) =
                    packbf2(acc[i][jj][half * 2], acc[i][jj][half * 2 + 1]);
            }
    __syncthreads();

    #pragma unroll
    for (int i = tid; i < 2048; i += 256) {
        int r = i >> 4, ch = i & 15;
        uint4 v = *(uint4*)(sm + r * TB_STRIDE + ch * 16);
        *(uint4*)(C + (long)(bm + r) * LPOS + bn + ch * 8) = v;
    }
}

// ---------------------------------------------------------------------------
// Output projection + bias + residual (fp32 out).
// ---------------------------------------------------------------------------
__global__ void __launch_bounds__(256) gemm_out(
    const bf16* __restrict__ A, const bf16* __restrict__ Bw,
    float* __restrict__ C, const float* __restrict__ bias,
    const float* __restrict__ res)
{
    constexpr int ABYTES = 128 * 32 * 2, BBYTES = 128 * 32 * 2;
    __shared__ __align__(1024) char sm[2 * (ABYTES + BBYTES)];
    SmemPtrs sp { smem_u32(sm), smem_u32(sm) + 2 * ABYTES };

    const int tid = threadIdx.x, lane = tid & 31, wid = tid >> 5;
    const int wm = wid & 1, wn = wid >> 1;
    const int bm = blockIdx.y * 128, bn = blockIdx.x * 128;

    const bf16* Arow = A + (long)bm * H;
    const bf16* Brow = Bw + (long)bn * H;

    auto load_tiles = [&](int ch, int st) {
        const bf16* Ak = Arow + ch * 32;
        #pragma unroll
        for (int i = tid; i < 512; i += 256) {
            int r = i >> 2, c = i & 3;
            cpasync16(sp.uA + st * ABYTES + swz(r, c), Ak + (long)r * H + c * 8);
        }
        const bf16* Bk = Brow + ch * 32;
        #pragma unroll
        for (int i = tid; i < 512; i += 256) {
            int r = i >> 2, c = i & 3;
            cpasync16(sp.uB + st * BBYTES + swz(r, c), Bk + (long)r * H + c * 8);
        }
    };

    float acc[4][4][4] = {};
    gemm_core(H / 32, sp, tid, lane, wm, wn, acc, load_tiles);

    #pragma unroll
    for (int i = 0; i < 4; i++)
        #pragma unroll
        for (int jj = 0; jj < 4; jj++)
            #pragma unroll
            for (int half = 0; half < 2; half++) {
                const int r = bm + wm * 64 + i * 16 + (lane >> 2) + half * 8;
                const int c = bn + wn * 32 + jj * 8 + (lane & 3) * 2;
                const float* rr = res + (long)r * H;
                *(float2*)(C + (long)r * H + c) =
                    make_float2(acc[i][jj][half * 2] + bias[c] + rr[c],
                                acc[i][jj][half * 2 + 1] + bias[c + 1] + rr[c + 1]);
            }
}

// ---------------------------------------------------------------------------
// Flash-fused attention: fast/saturated/general paths, mask bit-packed.
// ---------------------------------------------------------------------------
constexpr int CQ_W     = 144;
constexpr int CQ_ROWB  = CQ_W * 2;
constexpr int CQ_BYTES = 64 * CQ_ROWB;
constexpr int CK_W     = 80;
constexpr int CK_ROWB  = CK_W * 2;
constexpr int CK_BYTES = 128 * CK_ROWB;
constexpr int OFF_K    = 16384;
constexpr int OFF_V    = OFF_K + 16384;
constexpr int OFF_CQ   = OFF_V + 16384;
constexpr int OFF_CK   = OFF_CQ + CQ_BYTES;
constexpr int OFF_SAT  = OFF_CK + CK_BYTES;
constexpr int FL_SMEM  = OFF_SAT + 2048;      // 90112
constexpr int HTILES   = (S / 64) / ZSPL;     // 8

__global__ void __launch_bounds__(256, 2) flash_attn(
    const bf16* __restrict__ Q, const bf16* __restrict__ K,
    const bf16* __restrict__ Vt,
    const bf16* __restrict__ CKb, const bf16* __restrict__ CQb,
    const int* __restrict__ mask,
    float* __restrict__ Opart, float2* __restrict__ ML, int hbase)
{
    extern __shared__ __align__(1024) char dyn[];
    const uint32_t uQ  = smem_u32(dyn);
    const uint32_t uK  = uQ + OFF_K;
    const uint32_t uV  = uQ + OFF_V;
    const uint32_t uCQ = uQ + OFF_CQ;
    const uint32_t uCK = uQ + OFF_CK;

    const int tid = threadIdx.x, lane = tid & 31, wid = tid >> 5;
    const int h = hbase + blockIdx.y, bm = blockIdx.x * 128;
    const int z = blockIdx.z;
    const int ct0 = z * HTILES;
    const int bmc = bm + 512;

    auto lbc = [&](int c) { return min(max(bmc - c, 0), 888) & ~7; };
    auto tile_fast = [&](int dRC) { return (dRC >= -448) && (dRC <= 320); };
    auto tile_sat  = [&](int dRC) { return (dRC >= 576) || (dRC <= -640); };

    {
        const bf16* Qg = Q + (long)bm * H + h * D;
        #pragma unroll
        for (int i = tid; i < 1024; i += 256) {
            int r = i >> 3, c = i & 7;
            cpasync16(uQ + swz128(r, c), Qg + (long)r * H + c * 8);
        }
    }
    CP_COMMIT();

    auto load_kv = [&](int ct, int st) {
        const int c0 = ct * 64;
        const uint32_t uk = uK + st * 8192;
        const uint32_t uv = uV + st * 8192;
        const bf16* Kg = K + (long)c0 * H + h * D;
        #pragma unroll
        for (int i = tid; i < 512; i += 256) {
            int r = i >> 3, c = i & 7;
            cpasync16(uk + swz128(r, c), Kg + (long)r * H + c * 8);
        }
        const bf16* Vg = Vt + (long)(h * D) * S + c0;
        #pragma unroll
        for (int i = tid; i < 512; i += 256) {
            int d = i >> 3, c = i & 7;
            cpasync16(uv + swz128(d, c), Vg + (long)d * S + c * 8);
        }
    };

    auto load_band = [&](int ct) {
        const int c0 = ct * 64;
        const int dRC = bm - c0;
        if (tile_sat(dRC)) return;
        const bf16* CQg = CQb + ((size_t)h * S + c0) * LPOS;
        for (int i = tid; i < 64 * 18; i += 256) {
            int j = i / 18, ch = i % 18;
            int Lb = lbc(c0 + j);
            cpasync16(uCQ + j * CQ_ROWB + ch * 16,
                      CQg + (size_t)j * LPOS + Lb + ch * 8);
        }
        if (tile_fast(dRC)) {
            const bf16* CKg = CKb + ((size_t)h * S + bm) * LPOS;
            for (int i = tid; i < 128 * 9; i += 256) {
                int rb = i / 9, ch = i % 9;
                int Bal = (rb + dRC + 448) & ~7;
                cpasync16(uCK + rb * CK_ROWB + ch * 16,
                          CKg + (size_t)rb * LPOS + Bal + ch * 8);
            }
        }
    };

    load_kv(ct0, 0);
    CP_COMMIT();
    CP_WAIT1();
    __syncthreads();

    // one-time: saturated cq column values for this key slice
    {
        const bf16* CQg = CQb + ((size_t)h * S + ct0 * 64) * LPOS;
        bf16* slo = (bf16*)(dyn + OFF_SAT);
        bf16* shi = slo + 512;
        for (int j = tid; j < 512; j += 256) {
            slo[j] = CQg[(size_t)j * LPOS];
            shi[j] = CQg[(size_t)j * LPOS + 1023];
        }
    }

    uint32_t qf[4][4];
    #pragma unroll
    for (int kk = 0; kk < 4; kk++) {
        int row = wid * 16 + (lane & 15);
        int c16 = kk * 2 + (lane >> 4);
        ldsm4(qf[kk], uQ + swz128(row, c16));
    }

    const int rb0 = wid * 16 + (lane >> 2);
    const int rb1 = rb0 + 8;
    const int r0 = bm + rb0;
    const int r1 = bm + rb1;
    const int m0v = mask[r0], m1v = mask[r1];
    const bf16* ck0 = CKb + ((size_t)h * S + r0) * LPOS;
    const bf16* ck1 = CKb + ((size_t)h * S + r1) * LPOS;
    const float cklo0 = __bfloat162float(ck0[0]);
    const float ckhi0 = __bfloat162float(ck0[1023]);
    const float cklo1 = __bfloat162float(ck1[0]);
    const float ckhi1 = __bfloat162float(ck1[1023]);

    // pack this thread's 128 mask bits for the whole slice
    uint32_t mbits[4] = {0, 0, 0, 0};
    {
        const int cb = (lane & 3) * 2;
        #pragma unroll
        for (int it = 0; it < 8; it++)
            #pragma unroll
            for (int nb = 0; nb < 8; nb++) {
                int c = (ct0 + it) * 64 + nb * 8 + cb;
                int k = it * 16 + nb * 2;
                uint32_t b = (mask[c] ? 1u : 0u) | ((mask[c + 1] ? 2u : 0u));
                mbits[k >> 5] |= b << (k & 31);
            }
    }

    float m0 = NEGMAX, m1 = NEGMAX, l0 = 0.f, l1 = 0.f;
    float O[8][4] = {};

    for (int it = 0; it < HTILES; it++) {
        const int ct = ct0 + it;
        const int st = it & 1;

        load_band(ct);
        CP_COMMIT();
        if (it + 1 < HTILES) { load_kv(ct + 1, st ^ 1); CP_COMMIT(); CP_WAIT1(); }
        else                 { CP_WAIT0(); }
        __syncthreads();

        const uint32_t uk = uK + st * 8192;
        const uint32_t uv = uV + st * 8192;
        const bf16* sCQ = (const bf16*)(dyn + OFF_CQ);
        const bf16* sCK = (const bf16*)(dyn + OFF_CK);

        float sfr[8][4] = {};
        #pragma unroll
        for (int g = 0; g < 4; g++) {
            #pragma unroll
            for (int kk = 0; kk < 4; kk++) {
                uint32_t r4[4];
                int n   = g * 16 + ((lane >> 4) << 3) + (lane & 7);
                int c16 = kk * 2 + ((lane >> 3) & 1);
                ldsm4(r4, uk + swz128(n, c16));
                mma16816(sfr[2 * g],     qf[kk], r4);
                mma16816(sfr[2 * g + 1], qf[kk], r4 + 2);
            }
        }

        const int c0 = ct * 64;
        const int dRC = bm - c0;
        const uint32_t mw = mbits[it >> 1] >> ((it & 1) * 16);
        float tmx0 = NEGMAX, tmx1 = NEGMAX;

        if (tile_fast(dRC)) {
            const int ph = (rb0 + dRC + 448) & 7;
            const bf16* sk0 = sCK + rb0 * CK_W;
            const bf16* sk1 = sCK + rb1 * CK_W;
            #pragma unroll
            for (int nb = 0; nb < 8; nb++) {
                const int cl  = nb * 8 + (lane & 3) * 2;
                const int off = 64 - cl + ph;
                const int mc0 = (mw >> (nb * 2)) & 1;
                const int mc1 = (mw >> (nb * 2 + 1)) & 1;
                const bf16* sq0 = sCQ + cl * CQ_W;
                const bf16* sq1 = sCQ + (cl + 1) * CQ_W;
                const int q0 = dRC + 512 - cl;
                const int t0 = q0 & 7, t1 = (q0 - 1) & 7;
                {
                    float v0 = (sfr[nb][0] + __bfloat162float(sk0[off])
                                + __bfloat162float(sq0[rb0 + t0])) * SCALE2;
                    float v1 = (sfr[nb][1] + __bfloat162float(sk0[off - 1])
                                + __bfloat162float(sq1[rb0 + t1])) * SCALE2;
                    if (!(m0v && mc0)) v0 = NEGMAX;
                    if (!(m0v && mc1)) v1 = NEGMAX;
                    sfr[nb][0] = v0; sfr[nb][1] = v1;
                    tmx0 = fmaxf(tmx0, fmaxf(v0, v1));
                }
                {
                    float v2 = (sfr[nb][2] + __bfloat162float(sk1[off])
                                + __bfloat162float(sq0[rb1 + t0])) * SCALE2;
                    float v3 = (sfr[nb][3] + __bfloat162float(sk1[off - 1])
                                + __bfloat162float(sq1[rb1 + t1])) * SCALE2;
                    if (!(m1v && mc0)) v2 = NEGMAX;
                    if (!(m1v && mc1)) v3 = NEGMAX;
                    sfr[nb][2] = v2; sfr[nb][3] = v3;
                    tmx1 = fmaxf(tmx1, fmaxf(v2, v3));
                }
            }
        } else if (tile_sat(dRC)) {
            const bool hiSat = dRC > 0;
            const float f0 = hiSat ? ckhi0 : cklo0;
            const float f1 = hiSat ? ckhi1 : cklo1;
            const bf16* scq = (const bf16*)(dyn + OFF_SAT) + (hiSat ? 512 : 0);
            const int jb = it * 64;
            #pragma unroll
            for (int nb = 0; nb < 8; nb++) {
                const int cl  = nb * 8 + (lane & 3) * 2;
                const int mc0 = (mw >> (nb * 2)) & 1;
                const int mc1 = (mw >> (nb * 2 + 1)) & 1;
                const float cq0 = __bfloat162float(scq[jb + cl]);
                const float cq1 = __bfloat162float(scq[jb + cl + 1]);
                {
                    float v0 = (sfr[nb][0] + f0 + cq0) * SCALE2;
                    float v1 = (sfr[nb][1] + f0 + cq1) * SCALE2;
                    if (!(m0v && mc0)) v0 = NEGMAX;
                    if (!(m0v && mc1)) v1 = NEGMAX;
                    sfr[nb][0] = v0; sfr[nb][1] = v1;
                    tmx0 = fmaxf(tmx0, fmaxf(v0, v1));
                }
                {
                    float v2 = (sfr[nb][2] + f1 + cq0) * SCALE2;
                    float v3 = (sfr[nb][3] + f1 + cq1) * SCALE2;
                    if (!(m1v && mc0)) v2 = NEGMAX;
                    if (!(m1v && mc1)) v3 = NEGMAX;
                    sfr[nb][2] = v2; sfr[nb][3] = v3;
                    tmx1 = fmaxf(tmx1, fmaxf(v2, v3));
                }
            }
        } else {
            #pragma unroll
            for (int nb = 0; nb < 8; nb++) {
                const int cl = nb * 8 + (lane & 3) * 2;
                const int c  = c0 + cl;
                const int Lb0 = lbc(c);
                const int Lb1 = lbc(c + 1);
                const int mc0 = (mw >> (nb * 2)) & 1;
                const int mc1 = (mw >> (nb * 2 + 1)) & 1;
                {
                    int la = min(max(r0 - c + 512, 0), LPOS - 1);
                    int lb = min(max(r0 - c + 511, 0), LPOS - 1);
                    float v0 = (sfr[nb][0] + __bfloat162float(ck0[la])
                                + __bfloat162float(sCQ[cl * CQ_W + (la - Lb0)])) * SCALE2;
                    float v1 = (sfr[nb][1] + __bfloat162float(ck0[lb])
                                + __bfloat162float(sCQ[(cl + 1) * CQ_W + (lb - Lb1)])) * SCALE2;
                    if (!(m0v && mc0)) v0 = NEGMAX;
                    if (!(m0v && mc1)) v1 = NEGMAX;
                    sfr[nb][0] = v0; sfr[nb][1] = v1;
                    tmx0 = fmaxf(tmx0, fmaxf(v0, v1));
                }
                {
                    int la = min(max(r1 - c + 512, 0), LPOS - 1);
                    int lb = min(max(r1 - c + 511, 0), LPOS - 1);
                    float v2 = (sfr[nb][2] + __bfloat162float(ck1[la])
                                + __bfloat162float(sCQ[cl * CQ_W + (la - Lb0)])) * SCALE2;
                    float v3 = (sfr[nb][3] + __bfloat162float(ck1[lb])
                                + __bfloat162float(sCQ[(cl + 1) * CQ_W + (lb - Lb1)])) * SCALE2;
                    if (!(m1v && mc0)) v2 = NEGMAX;
                    if (!(m1v && mc1)) v3 = NEGMAX;
                    sfr[nb][2] = v2; sfr[nb][3] = v3;
                    tmx1 = fmaxf(tmx1, fmaxf(v2, v3));
                }
            }
        }
        tmx0 = fmaxf(tmx0, __shfl_xor_sync(0xffffffffu, tmx0, 1));
        tmx0 = fmaxf(tmx0, __shfl_xor_sync(0xffffffffu, tmx0, 2));
        tmx1 = fmaxf(tmx1, __shfl_xor_sync(0xffffffffu, tmx1, 1));
        tmx1 = fmaxf(tmx1, __shfl_xor_sync(0xffffffffu, tmx1, 2));

        const float mn0 = fmaxf(m0, tmx0), mn1 = fmaxf(m1, tmx1);
        const float sc0 = exp2f(m0 - mn0), sc1 = exp2f(m1 - mn1);
        m0 = mn0; m1 = mn1;
        float rs0 = 0.f, rs1 = 0.f;
        #pragma unroll
        for (int nb = 0; nb < 8; nb++) {
            sfr[nb][0] = exp2f(sfr[nb][0] - mn0);
            sfr[nb][1] = exp2f(sfr[nb][1] - mn0);
            sfr[nb][2] = exp2f(sfr[nb][2] - mn1);
            sfr[nb][3] = exp2f(sfr[nb][3] - mn1);
            rs0 += sfr[nb][0] + sfr[nb][1];
            rs1 += sfr[nb][2] + sfr[nb][3];
        }
        rs0 += __shfl_xor_sync(0xffffffffu, rs0, 1);
        rs0 += __shfl_xor_sync(0xffffffffu, rs0, 2);
        rs1 += __shfl_xor_sync(0xffffffffu, rs1, 1);
        rs1 += __shfl_xor_sync(0xffffffffu, rs1, 2);
        l0 = l0 * sc0 + rs0;
        l1 = l1 * sc1 + rs1;
        #pragma unroll
        for (int df = 0; df < 8; df++) {
            O[df][0] *= sc0; O[df][1] *= sc0;
            O[df][2] *= sc1; O[df][3] *= sc1;
        }

        #pragma unroll
        for (int kk2 = 0; kk2 < 4; kk2++) {
            uint32_t pf[4];
            pf[0] = packbf2(sfr[2 * kk2][0],     sfr[2 * kk2][1]);
            pf[1] = packbf2(sfr[2 * kk2][2],     sfr[2 * kk2][3]);
            pf[2] = packbf2(sfr[2 * kk2 + 1][0], sfr[2 * kk2 + 1][1]);
            pf[3] = packbf2(sfr[2 * kk2 + 1][2], sfr[2 * kk2 + 1][3]);
            #pragma unroll
            for (int dg = 0; dg < 4; dg++) {
                uint32_t r4[4];
                int n   = dg * 16 + ((lane >> 4) << 3) + (lane & 7);
                int c16 = kk2 * 2 + ((lane >> 3) & 1);
                ldsm4(r4, uv + swz128(n, c16));
                mma16816(O[2 * dg],     pf, r4);
                mma16816(O[2 * dg + 1], pf, r4 + 2);
            }
        }
        __syncthreads();
    }

    const size_t base = ((size_t)z * NH + h) * S;
    if ((lane & 3) == 0) {
        ML[base + r0] = make_float2(m0, l0);
        ML[base + r1] = make_float2(m1, l1);
    }
    float* o0 = Opart + (base + r0) * D + (lane & 3) * 2;
    float* o1 = Opart + (base + r1) * D + (lane & 3) * 2;
    #pragma unroll
    for (int df = 0; df < 8; df++) {
        *(float2*)(o0 + df * 8) = make_float2(O[df][0], O[df][1]);
        *(float2*)(o1 + df * 8) = make_float2(O[df][2], O[df][3]);
    }
}

// ---------------------------------------------------------------------------
// Merge the ZSPL split-K slices for a 6-head half -> normalized bf16 context.
// ---------------------------------------------------------------------------
__global__ void __launch_bounds__(256) merge_attn(
    const float* __restrict__ Opart, const float2* __restrict__ ML,
    bf16* __restrict__ CTX, int hbase)
{
    const int p = blockIdx.x * 8 + (threadIdx.x >> 5);   // 0 .. 6*S-1
    const int lane = threadIdx.x & 31;
    const int h = hbase + p / S, row = p % S;
    const int q = h * S + row;

    float2 ml[ZSPL];
    float M = NEGMAX;
    #pragma unroll
    for (int zz = 0; zz < ZSPL; zz++) {
        ml[zz] = ML[zz * NH * S + q];
        M = fmaxf(M, ml[zz].x);
    }
    float w[ZSPL], denom = 0.f;
    #pragma unroll
    for (int zz = 0; zz < ZSPL; zz++) {
        w[zz] = exp2f(ml[zz].x - M);
        denom += w[zz] * ml[zz].y;
    }
    const float inv = 1.0f / denom;

    const int d = lane * 2;
    float ax = 0.f, ay = 0.f;
    #pragma unroll
    for (int zz = 0; zz < ZSPL; zz++) {
        const float2 v = *(const float2*)(Opart + ((size_t)zz * NH * S + q) * D + d);
        ax += w[zz] * v.x;
        ay += w[zz] * v.y;
    }
    *(__nv_bfloat162*)(CTX + (long)row * H + h * D + d) =
        __float22bfloat162_rn(make_float2(ax * inv, ay * inv));
}

// ---------------------------------------------------------------------------
__global__ void cvt_bf16_2(const float* __restrict__ x0, bf16* __restrict__ y0, int n0,
                           const float* __restrict__ x1, bf16* __restrict__ y1, int n1)
{
    int i = blockIdx.x * 256 + threadIdx.x;
    if (i < n0) y0[i] = __float2bfloat16(x0[i]);
    else if (i < n0 + n1) y1[i - n0] = __float2bfloat16(x1[i - n0]);
}

struct P6 { const float* p[6]; };
__global__ void wtrans6(P6 srcs, bf16* __restrict__ Wt)
{
    __shared__ float t[32][33];
    const float* W = srcs.p[blockIdx.z];
    bf16* dst = Wt + (size_t)blockIdx.z * H * H;
    const int bx = blockIdx.x * 32, by = blockIdx.y * 32;
    #pragma unroll
    for (int i = threadIdx.y; i < 32; i += 8)
        t[i][threadIdx.x] = W[(long)(by + i) * H + bx + threadIdx.x];
    __syncthreads();
    #pragma unroll
    for (int i = threadIdx.y; i < 32; i += 8)
        dst[(long)(bx + i) * H + by + threadIdx.x] = __float2bfloat16(t[threadIdx.x][i]);
}

__global__ void ln_kernel(const float* __restrict__ x,
                          const float* __restrict__ gamma,
                          const float* __restrict__ beta,
                          float* __restrict__ out)
{
    __shared__ float rs[8], rq[8];
    const int s = blockIdx.x, tid = threadIdx.x;
    const float* row = x + (long)s * H;
    float a0 = row[tid], a1 = row[tid + 256], a2 = row[tid + 512];
    float sum = a0 + a1 + a2;
    float sq  = a0 * a0 + a1 * a1 + a2 * a2;
    #pragma unroll
    for (int o = 16; o > 0; o >>= 1) {
        sum += __shfl_xor_sync(0xffffffffu, sum, o);
        sq  += __shfl_xor_sync(0xffffffffu, sq,  o);
    }
    if ((tid & 31) == 0) { rs[tid >> 5] = sum; rq[tid >> 5] = sq; }
    __syncthreads();
    float ts = 0.f, tq = 0.f;
    #pragma unroll
    for (int w = 0; w < 8; w++) { ts += rs[w]; tq += rq[w]; }
    float mean = ts * (1.0f / H);
    float var  = tq * (1.0f / H) - mean * mean;
    float inv  = rsqrtf(var + 1e-7f);
    float* o = out + (long)s * H;
    o[tid]       = (a0 - mean) * inv * gamma[tid]       + beta[tid];
    o[tid + 256] = (a1 - mean) * inv * gamma[tid + 256] + beta[tid + 256];
    o[tid + 512] = (a2 - mean) * inv * gamma[tid + 512] + beta[tid + 512];
}

// ---------------------------------------------------------------------------
extern "C" void kernel_launch(void* const* d_in, const int* in_sizes, int n_in,
                              void* d_out, int out_size)
{
    const float* hidden = (const float*)d_in[0];
    const int*   mask   = (const int*)  d_in[1];
    const float* Wq     = (const float*)d_in[2];
    const float* bq     = (const float*)d_in[3];
    const float* Wk     = (const float*)d_in[4];
    const float* bk     = (const float*)d_in[5];
    const float* Wv     = (const float*)d_in[6];
    const float* bv     = (const float*)d_in[7];
    const float* rel    = (const float*)d_in[8];
    const float* Wpk    = (const float*)d_in[9];
    const float* Wpq    = (const float*)d_in[10];
    const float* bpq    = (const float*)d_in[11];
    const float* Wo     = (const float*)d_in[12];
    const float* bo     = (const float*)d_in[13];
    const float* gamma  = (const float*)d_in[14];
    const float* beta   = (const float*)d_in[15];
    float* out = (float*)d_out;

    bf16 *hbf, *relbf, *Wt, *Qbf, *Kbf, *Vt, *PKbf, *PQbf, *CKb, *CQb, *CTXbf;
    float *TMP, *Opart;
    float2* ML;
    cudaGetSymbolAddress((void**)&hbf,   g_hbf);
    cudaGetSymbolAddress((void**)&relbf, g_relbf);
    cudaGetSymbolAddress((void**)&Wt,    g_Wt);
    cudaGetSymbolAddress((void**)&Qbf,   g_Qbf);
    cudaGetSymbolAddress((void**)&Kbf,   g_Kbf);
    cudaGetSymbolAddress((void**)&Vt,    g_Vt);
    cudaGetSymbolAddress((void**)&PKbf,  g_PKbf);
    cudaGetSymbolAddress((void**)&PQbf,  g_PQbf);
    cudaGetSymbolAddress((void**)&CKb,   g_CKb);
    cudaGetSymbolAddress((void**)&CQb,   g_CQb);
    cudaGetSymbolAddress((void**)&Opart, g_Opart);
    cudaGetSymbolAddress((void**)&ML,    g_ML);
    cudaGetSymbolAddress((void**)&CTXbf, g_CTXbf);
    cudaGetSymbolAddress((void**)&TMP,   g_TMP);

    static cudaStream_t s1 = nullptr, s2 = nullptr;
    static cudaEvent_t evR = nullptr, evP = nullptr, evM1 = nullptr,
                       evM2 = nullptr, evW = nullptr;
    static bool init_done = false;
    if (!init_done) {
        cudaFuncSetAttribute(flash_attn,
                             cudaFuncAttributeMaxDynamicSharedMemorySize, FL_SMEM);
        cudaStreamCreateWithFlags(&s1, cudaStreamNonBlocking);
        cudaStreamCreateWithFlags(&s2, cudaStreamNonBlocking);
        cudaEventCreateWithFlags(&evR,  cudaEventDisableTiming);
        cudaEventCreateWithFlags(&evP,  cudaEventDisableTiming);
        cudaEventCreateWithFlags(&evM1, cudaEventDisableTiming);
        cudaEventCreateWithFlags(&evM2, cudaEventDisableTiming);
        cudaEventCreateWithFlags(&evW,  cudaEventDisableTiming);
        init_done = true;
    }

    // --- legal fork: root event on capture-origin stream BEFORE side work ---
    cudaEventRecord(evR, 0);
    cudaStreamWaitEvent(s1, evR, 0);

    // front: cvt (default) || wtrans (s1)
    cvt_bf16_2<<<(S * H + LPOS * H + 255) / 256, 256>>>(
        hidden, hbf, S * H, rel, relbf, LPOS * H);
    P6 w6; w6.p[0] = Wq; w6.p[1] = Wk; w6.p[2] = Wv;
    w6.p[3] = Wpk; w6.p[4] = Wpq; w6.p[5] = Wo;
    wtrans6<<<dim3(H/32, H/32, 6), dim3(32, 8), 0, s1>>>(w6, Wt);
    cudaEventRecord(evW, s1);
    cudaStreamWaitEvent(0, evW, 0);

    // --- all five projections in one launch (default stream) ---
    ProjJobs J;
    J.A[0] = hbf;   J.Bw[0] = Wt + 0 * H * H; J.C[0] = Qbf;  J.bias[0] = bq;      J.mode[0] = 0;
    J.A[1] = hbf;   J.Bw[1] = Wt + 1 * H * H; J.C[1] = Kbf;  J.bias[1] = bk;      J.mode[1] = 0;
    J.A[2] = hbf;   J.Bw[2] = Wt + 2 * H * H; J.C[2] = Vt;   J.bias[2] = bv;      J.mode[2] = 1;
    J.A[3] = relbf; J.Bw[3] = Wt + 3 * H * H; J.C[3] = PKbf; J.bias[3] = nullptr; J.mode[3] = 0;
    J.A[4] = relbf; J.Bw[4] = Wt + 4 * H * H; J.C[4] = PQbf; J.bias[4] = bpq;     J.mode[4] = 0;
    J.start[0] = 0;   J.start[1] = 96;  J.start[2] = 192;
    J.start[3] = 288; J.start[4] = 336; J.start[5] = 384;
    gemm_proj<<<384, 256>>>(J);
    cudaEventRecord(evP, 0);

    // --- fork: tables -> flash -> per-half merge on two streams ---
    cudaStreamWaitEvent(s1, evP, 0);
    gemm_tables<<<dim3(LPOS/128, S/128, 12), 256, 0, s1>>>(
        Qbf, Kbf, PKbf, PQbf, CKb, CQb, 0);
    cudaStreamWaitEvent(s2, evP, 0);
    gemm_tables<<<dim3(LPOS/128, S/128, 12), 256, 0, s2>>>(
        Qbf, Kbf, PKbf, PQbf, CKb, CQb, 6);

    flash_attn<<<dim3(S/128, NH/2, ZSPL), 256, FL_SMEM, s1>>>(
        Qbf, Kbf, Vt, CKb, CQb, mask, Opart, ML, 0);
    merge_attn<<<6 * S / 8, 256, 0, s1>>>(Opart, ML, CTXbf, 0);
    cudaEventRecord(evM1, s1);

    flash_attn<<<dim3(S/128, NH/2, ZSPL), 256, FL_SMEM, s2>>>(
        Qbf, Kbf, Vt, CKb, CQb, mask, Opart, ML, 6);
    merge_attn<<<6 * S / 8, 256, 0, s2>>>(Opart, ML, CTXbf, 6);
    cudaEventRecord(evM2, s2);

    // --- join back to default stream ---
    cudaStreamWaitEvent(0, evM1, 0);
    cudaStreamWaitEvent(0, evM2, 0);

    // --- output projection + bias + residual ---
    gemm_out<<<dim3(6, 16), 256>>>(CTXbf, Wt + 5 * H * H, TMP, bo, hidden);

    // --- layernorm ---
    ln_kernel<<<S, 256>>>(TMP, gamma, beta, out);
}